// round 1
// baseline (speedup 1.0000x reference)
#include <cuda_runtime.h>
#include <math.h>

#define D_MODEL 5120
#define N_HEADS 8
#define D_KV    128
#define D_ROPE  16
#define D_HEAD  640
#define SPLIT   624
#define BB      2
#define SS      2048
#define ROWS    (BB*SS)          // 4096

// ---------------- scratch (device globals; no cudaMalloc allowed) ----------
__device__ __align__(16) float g_cq   [ROWS*D_KV];
__device__ __align__(16) float g_qbase[ROWS*N_HEADS*SPLIT];
__device__ __align__(16) float g_kbase[ROWS*N_HEADS*SPLIT];
__device__ __align__(16) float g_qrot [ROWS*N_HEADS*D_ROPE];
__device__ __align__(16) float g_krot [ROWS*N_HEADS*D_ROPE];
__device__ __align__(16) float g_q    [ROWS*D_MODEL];
__device__ __align__(16) float g_kf   [ROWS*D_MODEL];
__device__ __align__(16) float g_v    [ROWS*D_MODEL];
__device__ __align__(16) float g_sc   [(size_t)BB*N_HEADS*SS*SS];   // 268 MB
__device__ __align__(16) float g_ao   [ROWS*D_MODEL];

// ---------------- generic tiled SGEMM: C = alpha*A@B(^T) + bias ------------
// BM=BN=64, BK=16, 256 threads, 4x4 per thread. All dims assumed divisible.
#define BM 64
#define BN 64
#define BK 16

template<bool TRANSB>
__global__ void sgemm(
    int M, int N, int K,
    const float* __restrict__ A, int lda,
    const float* __restrict__ B, int ldb,
    float*       __restrict__ C, int ldc,
    const float* __restrict__ bias, float alpha,
    int zdiv,
    long long sA1, long long sA2,
    long long sB1, long long sB2,
    long long sC1, long long sC2)
{
    int z  = blockIdx.z;
    int z1 = z / zdiv, z2 = z % zdiv;
    A += z1*sA1 + z2*sA2;
    B += z1*sB1 + z2*sB2;
    C += z1*sC1 + z2*sC2;

    __shared__ float As[BK][BM+4];
    __shared__ float Bs[BK][BN+4];

    const int tid = threadIdx.x;
    const int tx  = tid & 15;
    const int ty  = tid >> 4;
    const int m0  = blockIdx.y * BM;
    const int n0  = blockIdx.x * BN;

    // A-tile loader indices (also used for B when TRANSB)
    const int ar = tid >> 2;          // 0..63 (row in tile)
    const int ak = (tid & 3) * 4;     // 0,4,8,12
    // B-tile (NN) loader indices
    const int bkr = tid >> 4;         // 0..15
    const int bc  = (tid & 15) * 4;   // 0..60

    float acc[4][4] = {};

    for (int k0 = 0; k0 < K; k0 += BK) {
        float4 av = *(const float4*)(A + (long long)(m0+ar)*lda + k0 + ak);
        As[ak+0][ar] = av.x; As[ak+1][ar] = av.y;
        As[ak+2][ar] = av.z; As[ak+3][ar] = av.w;
        if (TRANSB) {
            float4 bv = *(const float4*)(B + (long long)(n0+ar)*ldb + k0 + ak);
            Bs[ak+0][ar] = bv.x; Bs[ak+1][ar] = bv.y;
            Bs[ak+2][ar] = bv.z; Bs[ak+3][ar] = bv.w;
        } else {
            float4 bv = *(const float4*)(B + (long long)(k0+bkr)*ldb + n0 + bc);
            *(float4*)&Bs[bkr][bc] = bv;
        }
        __syncthreads();
        #pragma unroll
        for (int kk = 0; kk < BK; kk++) {
            float4 a = *(const float4*)&As[kk][ty*4];
            float4 b = *(const float4*)&Bs[kk][tx*4];
            float ai[4] = {a.x,a.y,a.z,a.w};
            float bj[4] = {b.x,b.y,b.z,b.w};
            #pragma unroll
            for (int i = 0; i < 4; i++)
                #pragma unroll
                for (int j = 0; j < 4; j++)
                    acc[i][j] = fmaf(ai[i], bj[j], acc[i][j]);
        }
        __syncthreads();
    }

    #pragma unroll
    for (int i = 0; i < 4; i++) {
        long long r = m0 + ty*4 + i;
        #pragma unroll
        for (int j = 0; j < 4; j++) {
            int c = n0 + tx*4 + j;
            float val = acc[i][j] * alpha;
            if (bias) val += bias[c];
            C[r*ldc + c] = val;
        }
    }
}

// ---------------- assemble q/k_full with RoPE; emit k_rot output -----------
__global__ void assemble_kernel(const float* __restrict__ qbase,
                                const float* __restrict__ qrot,
                                const float* __restrict__ kbase,
                                const float* __restrict__ krot,
                                float* __restrict__ q,
                                float* __restrict__ kf,
                                float* __restrict__ out_krot)
{
    long long idx = (long long)blockIdx.x * 256 + threadIdx.x;
    if (idx >= (long long)ROWS * D_MODEL) return;
    int d        = (int)(idx % D_HEAD);
    long long rh = idx / D_HEAD;        // row*8 + h
    int h        = (int)(rh & 7);
    long long row = rh >> 3;
    int s        = (int)(row & (SS - 1));

    if (d < SPLIT) {
        long long src = row * (long long)(N_HEADS*SPLIT) + h*SPLIT + d;
        q[idx]  = qbase[src];
        kf[idx] = kbase[src];
    } else {
        int dd = d - SPLIT;                 // 0..15
        long long base = row * (N_HEADS*D_ROPE) + h*D_ROPE;
        float qv, kv;
        if (dd < 8) {
            const float invf[4] = {1.0f, 0.1f, 0.01f, 0.001f}; // 10000^{-j/4}
            int j   = dd & 3;
            float f = ((float)s / 40.0f) * invf[j];
            float c = cosf(f), sn = sinf(f);
            if (dd < 4) {
                qv = qrot[base+dd]*c - qrot[base+dd+4]*sn;
                kv = krot[base+dd]*c - krot[base+dd+4]*sn;
            } else {
                qv = qrot[base+dd]*c + qrot[base+dd-4]*sn;
                kv = krot[base+dd]*c + krot[base+dd-4]*sn;
            }
        } else {
            qv = qrot[base+dd];
            kv = krot[base+dd];
        }
        q[idx]  = qv;
        kf[idx] = kv;
        out_krot[base + dd] = kv;
    }
}

// ---------------- row softmax over 2048 columns -----------------------------
__global__ void softmax2048(float* __restrict__ s)
{
    long long row = blockIdx.x;
    float* p = s + (row << 11);
    int t = threadIdx.x;

    float v[8];
    float m = -1e30f;
    #pragma unroll
    for (int i = 0; i < 8; i++) {
        v[i] = p[t + (i << 8)];
        m = fmaxf(m, v[i]);
    }
    __shared__ float red[256];
    red[t] = m; __syncthreads();
    for (int off = 128; off > 0; off >>= 1) {
        if (t < off) red[t] = fmaxf(red[t], red[t+off]);
        __syncthreads();
    }
    m = red[0];
    __syncthreads();

    float sum = 0.0f;
    #pragma unroll
    for (int i = 0; i < 8; i++) {
        v[i] = expf(v[i] - m);
        sum += v[i];
    }
    red[t] = sum; __syncthreads();
    for (int off = 128; off > 0; off >>= 1) {
        if (t < off) red[t] += red[t+off];
        __syncthreads();
    }
    float inv = 1.0f / red[0];
    #pragma unroll
    for (int i = 0; i < 8; i++)
        p[t + (i << 8)] = v[i] * inv;
}

// ---------------- host side --------------------------------------------------
static inline float* sym(const void* s)
{
    void* p = nullptr;
    cudaGetSymbolAddress(&p, s);
    return (float*)p;
}

static void gemm(bool transb, int M, int N, int K,
                 const float* A, int lda, const float* B, int ldb,
                 float* C, int ldc, const float* bias, float alpha,
                 int nz = 1, int zdiv = 1,
                 long long sA1 = 0, long long sA2 = 0,
                 long long sB1 = 0, long long sB2 = 0,
                 long long sC1 = 0, long long sC2 = 0)
{
    dim3 grid(N / BN, M / BM, nz);
    if (transb)
        sgemm<true ><<<grid, 256>>>(M,N,K,A,lda,B,ldb,C,ldc,bias,alpha,
                                    zdiv,sA1,sA2,sB1,sB2,sC1,sC2);
    else
        sgemm<false><<<grid, 256>>>(M,N,K,A,lda,B,ldb,C,ldc,bias,alpha,
                                    zdiv,sA1,sA2,sB1,sB2,sC1,sC2);
}

extern "C" void kernel_launch(void* const* d_in, const int* in_sizes, int n_in,
                              void* d_out, int out_size)
{
    const float* h     = (const float*)d_in[0];
    const float* W_dkv = (const float*)d_in[1];
    const float* b_dkv = (const float*)d_in[2];
    const float* W_dq  = (const float*)d_in[3];
    const float* b_dq  = (const float*)d_in[4];
    const float* W_uk  = (const float*)d_in[5];
    const float* b_uk  = (const float*)d_in[6];
    const float* W_uv  = (const float*)d_in[7];
    const float* b_uv  = (const float*)d_in[8];
    const float* W_uq  = (const float*)d_in[9];
    const float* b_uq  = (const float*)d_in[10];
    const float* W_qr  = (const float*)d_in[11];
    const float* b_qr  = (const float*)d_in[12];
    const float* W_kr  = (const float*)d_in[13];
    const float* b_kr  = (const float*)d_in[14];
    const float* W_o   = (const float*)d_in[15];
    const float* b_o   = (const float*)d_in[16];

    float* out      = (float*)d_out;
    float* out_ckv  = out + (long long)ROWS * D_MODEL;        // c_kv slot
    float* out_krot = out_ckv + (long long)ROWS * D_KV;       // k_rot slot

    float* cq = sym(g_cq);
    float* qb = sym(g_qbase);
    float* kb = sym(g_kbase);
    float* qr = sym(g_qrot);
    float* kr = sym(g_krot);
    float* q  = sym(g_q);
    float* kf = sym(g_kf);
    float* v  = sym(g_v);
    float* sc = sym(g_sc);
    float* ao = sym(g_ao);

    const float scale = 1.0f / sqrtf((float)D_HEAD);

    // --- down projections from h (K = 5120) ---
    gemm(false, ROWS, D_KV, D_MODEL, h, D_MODEL, W_dkv, D_KV, out_ckv, D_KV, b_dkv, 1.0f);
    gemm(false, ROWS, D_KV, D_MODEL, h, D_MODEL, W_dq,  D_KV, cq,      D_KV, b_dq,  1.0f);
    gemm(false, ROWS, N_HEADS*D_ROPE, D_MODEL, h, D_MODEL, W_kr, N_HEADS*D_ROPE, kr,
         N_HEADS*D_ROPE, b_kr, 1.0f);

    // --- up projections (K = 128) ---
    gemm(false, ROWS, N_HEADS*SPLIT, D_KV, out_ckv, D_KV, W_uk, N_HEADS*SPLIT,
         kb, N_HEADS*SPLIT, b_uk, 1.0f);
    gemm(false, ROWS, D_MODEL, D_KV, out_ckv, D_KV, W_uv, D_MODEL, v, D_MODEL, b_uv, 1.0f);
    gemm(false, ROWS, N_HEADS*SPLIT, D_KV, cq, D_KV, W_uq, N_HEADS*SPLIT,
         qb, N_HEADS*SPLIT, b_uq, 1.0f);
    gemm(false, ROWS, N_HEADS*D_ROPE, D_KV, cq, D_KV, W_qr, N_HEADS*D_ROPE,
         qr, N_HEADS*D_ROPE, b_qr, 1.0f);

    // --- assemble q / k_full with RoPE; write k_rot output ---
    {
        long long total = (long long)ROWS * D_MODEL;
        assemble_kernel<<<(unsigned)((total + 255) / 256), 256>>>(qb, qr, kb, kr,
                                                                  q, kf, out_krot);
    }

    // --- scores = scale * q @ k^T, batched over (b,h) ---
    gemm(true, SS, SS, D_HEAD,
         q,  D_MODEL, kf, D_MODEL, sc, SS, nullptr, scale,
         BB*N_HEADS, N_HEADS,
         (long long)SS*D_MODEL, (long long)D_HEAD,       // A: per-b, per-h
         (long long)SS*D_MODEL, (long long)D_HEAD,       // B
         (long long)N_HEADS*SS*SS, (long long)SS*SS);    // C

    // --- softmax over rows ---
    softmax2048<<<BB*N_HEADS*SS, 256>>>(sc);

    // --- attn_out = attn @ v, batched over (b,h) ---
    gemm(false, SS, D_HEAD, SS,
         sc, SS, v, D_MODEL, ao, D_MODEL, nullptr, 1.0f,
         BB*N_HEADS, N_HEADS,
         (long long)N_HEADS*SS*SS, (long long)SS*SS,
         (long long)SS*D_MODEL, (long long)D_HEAD,
         (long long)SS*D_MODEL, (long long)D_HEAD);

    // --- final projection ---
    gemm(false, ROWS, D_MODEL, D_MODEL, ao, D_MODEL, W_o, D_MODEL, out, D_MODEL, b_o, 1.0f);
}

// round 2
// speedup vs baseline: 2.4956x; 2.4956x over previous
#include <cuda_runtime.h>
#include <cuda_bf16.h>
#include <math.h>
#include <stdint.h>

#define D_MODEL 5120
#define N_HEADS 8
#define D_KV    128
#define D_ROPE  16
#define D_HEAD  640
#define SPLIT   624
#define BB      2
#define SS      2048
#define ROWS    (BB*SS)          // 4096

#define NCAT1   384              // dkv(128) + dq(128) + kr(128)
#define NCAT2   10112            // uk(4992) + uv(5120)
#define NCAT3   5120             // uq(4992) + qr(128)

// ---------------- scratch (device globals; no cudaMalloc allowed) ----------
__device__ __align__(16) float g_cat1[ROWS*NCAT1];
__device__ __align__(16) float g_kcat[(size_t)ROWS*NCAT2];
__device__ __align__(16) float g_qcat[(size_t)ROWS*NCAT3];
__device__ __align__(16) float g_q  [(size_t)ROWS*D_MODEL];
__device__ __align__(16) float g_kf [(size_t)ROWS*D_MODEL];
__device__ __align__(16) float g_vt [(size_t)ROWS*D_MODEL];
__device__ __align__(16) float g_sc [(size_t)BB*N_HEADS*SS*SS];
__device__ __align__(16) float g_ao [(size_t)ROWS*D_MODEL];
__device__ __align__(16) float g_w1T[NCAT1*D_MODEL];
__device__ __align__(16) float g_w2T[NCAT2*D_KV];
__device__ __align__(16) float g_w3T[NCAT3*D_KV];
__device__ __align__(16) float g_woT[(size_t)D_MODEL*D_MODEL];
__device__ __align__(16) float g_b1 [NCAT1];
__device__ __align__(16) float g_b2 [NCAT2];
__device__ __align__(16) float g_b3 [NCAT3];

// ---------------- bf16x3 tensor-core GEMM ----------------------------------
// C = alpha * A[M][K] @ B[N][K]^T + bias, fp32 in/out, bf16 hi/lo split MMA.
// CTA tile 128x128x32, 8 warps (2x4), warptile 64x32 via m16n8k16.

#define ASTR 18                      // b32 per row in smem (16 data + 2 pad)
#define SMM  (128*ASTR)              // one matrix, one stage (u32 count)

__device__ __forceinline__ uint32_t pack2(float a, float b) {
    __nv_bfloat162 t = __floats2bfloat162_rn(a, b);
    return *reinterpret_cast<const uint32_t*>(&t);
}

__device__ __forceinline__ void mma16816(float* c, const uint32_t* a, const uint32_t* b) {
    asm volatile(
        "mma.sync.aligned.m16n8k16.row.col.f32.bf16.bf16.f32 "
        "{%0,%1,%2,%3},{%4,%5,%6,%7},{%8,%9},{%0,%1,%2,%3};\n"
        : "+f"(c[0]), "+f"(c[1]), "+f"(c[2]), "+f"(c[3])
        : "r"(a[0]), "r"(a[1]), "r"(a[2]), "r"(a[3]), "r"(b[0]), "r"(b[1]));
}

__global__ void __launch_bounds__(256, 1)
gemm_bf16x3(int M, int N, int K,
            const float* __restrict__ A, int lda,
            const float* __restrict__ B, int ldb,
            float* __restrict__ C, int ldc,
            const float* __restrict__ bias, float alpha,
            int zdiv,
            long long sA1, long long sA2,
            long long sB1, long long sB2,
            long long sC1, long long sC2)
{
    extern __shared__ uint32_t sm[];
    uint32_t* Ah = sm;
    uint32_t* Al = sm + 2*SMM;
    uint32_t* Bh = sm + 4*SMM;
    uint32_t* Bl = sm + 6*SMM;

    {
        int z  = blockIdx.z;
        int z1 = z / zdiv, z2 = z % zdiv;
        A += z1*sA1 + z2*sA2;
        B += z1*sB1 + z2*sB2;
        C += z1*sC1 + z2*sC2;
    }

    const int tid  = threadIdx.x;
    const int lane = tid & 31, wid = tid >> 5;
    const int wm = (wid >> 2) * 64;
    const int wn = (wid & 3) * 32;
    const int g  = lane >> 2, tg = lane & 3;
    const int m0 = blockIdx.y * 128, n0 = blockIdx.x * 128;

    const int lc4 = (tid & 7) * 4;   // k offset (floats)
    const int lr  = tid >> 3;        // row 0..31
    const int cb  = lc4 >> 1;        // b32 col in smem

    const float* Aptr = A + (long long)(m0 + lr) * lda + lc4;
    const float* Bptr = B + (long long)(n0 + lr) * ldb + lc4;

    float4 ra[4], rb[4];
    float acc[4][4][4];
    #pragma unroll
    for (int i = 0; i < 4; i++)
        #pragma unroll
        for (int j = 0; j < 4; j++)
            #pragma unroll
            for (int k = 0; k < 4; k++) acc[i][j][k] = 0.0f;

    // prologue: load k-tile 0
    #pragma unroll
    for (int i = 0; i < 4; i++) {
        ra[i] = *(const float4*)(Aptr + (long long)(32*i)*lda);
        rb[i] = *(const float4*)(Bptr + (long long)(32*i)*ldb);
    }
    // write stage 0
    #pragma unroll
    for (int i = 0; i < 4; i++) {
        int r = lr + 32*i;
        uint32_t o = r*ASTR + cb;
        float hx = __bfloat162float(__float2bfloat16(ra[i].x));
        float hy = __bfloat162float(__float2bfloat16(ra[i].y));
        float hz = __bfloat162float(__float2bfloat16(ra[i].z));
        float hw = __bfloat162float(__float2bfloat16(ra[i].w));
        Ah[o]   = pack2(hx, hy);             Ah[o+1] = pack2(hz, hw);
        Al[o]   = pack2(ra[i].x-hx, ra[i].y-hy); Al[o+1] = pack2(ra[i].z-hz, ra[i].w-hw);
        hx = __bfloat162float(__float2bfloat16(rb[i].x));
        hy = __bfloat162float(__float2bfloat16(rb[i].y));
        hz = __bfloat162float(__float2bfloat16(rb[i].z));
        hw = __bfloat162float(__float2bfloat16(rb[i].w));
        Bh[o]   = pack2(hx, hy);             Bh[o+1] = pack2(hz, hw);
        Bl[o]   = pack2(rb[i].x-hx, rb[i].y-hy); Bl[o+1] = pack2(rb[i].z-hz, rb[i].w-hw);
    }
    __syncthreads();

    const int nk = K / 32;
    for (int t = 0; t < nk; t++) {
        if (t + 1 < nk) {
            const float* ap = Aptr + (t+1)*32;
            const float* bp = Bptr + (t+1)*32;
            #pragma unroll
            for (int i = 0; i < 4; i++) {
                ra[i] = *(const float4*)(ap + (long long)(32*i)*lda);
                rb[i] = *(const float4*)(bp + (long long)(32*i)*ldb);
            }
        }
        {
            const uint32_t st = (t & 1) * SMM;
            const uint32_t* ah = Ah + st;
            const uint32_t* al = Al + st;
            const uint32_t* bh = Bh + st;
            const uint32_t* bl = Bl + st;
            #pragma unroll
            for (int ks = 0; ks < 2; ks++) {
                uint32_t afh[4][4], afl[4][4], bfh[4][2], bfl[4][2];
                #pragma unroll
                for (int mt = 0; mt < 4; mt++) {
                    int b = (wm + mt*16 + g)*ASTR + ks*8 + tg;
                    afh[mt][0] = ah[b];           afh[mt][1] = ah[b + 8*ASTR];
                    afh[mt][2] = ah[b + 4];       afh[mt][3] = ah[b + 8*ASTR + 4];
                    afl[mt][0] = al[b];           afl[mt][1] = al[b + 8*ASTR];
                    afl[mt][2] = al[b + 4];       afl[mt][3] = al[b + 8*ASTR + 4];
                }
                #pragma unroll
                for (int nt = 0; nt < 4; nt++) {
                    int b = (wn + nt*8 + g)*ASTR + ks*8 + tg;
                    bfh[nt][0] = bh[b];  bfh[nt][1] = bh[b + 4];
                    bfl[nt][0] = bl[b];  bfl[nt][1] = bl[b + 4];
                }
                #pragma unroll
                for (int mt = 0; mt < 4; mt++)
                    #pragma unroll
                    for (int nt = 0; nt < 4; nt++) {
                        mma16816(acc[mt][nt], afh[mt], bfh[nt]);
                        mma16816(acc[mt][nt], afl[mt], bfh[nt]);
                        mma16816(acc[mt][nt], afh[mt], bfl[nt]);
                    }
            }
        }
        if (t + 1 < nk) {
            const uint32_t st = ((t+1) & 1) * SMM;
            #pragma unroll
            for (int i = 0; i < 4; i++) {
                int r = lr + 32*i;
                uint32_t o = st + r*ASTR + cb;
                float hx = __bfloat162float(__float2bfloat16(ra[i].x));
                float hy = __bfloat162float(__float2bfloat16(ra[i].y));
                float hz = __bfloat162float(__float2bfloat16(ra[i].z));
                float hw = __bfloat162float(__float2bfloat16(ra[i].w));
                Ah[o]   = pack2(hx, hy);             Ah[o+1] = pack2(hz, hw);
                Al[o]   = pack2(ra[i].x-hx, ra[i].y-hy); Al[o+1] = pack2(ra[i].z-hz, ra[i].w-hw);
                hx = __bfloat162float(__float2bfloat16(rb[i].x));
                hy = __bfloat162float(__float2bfloat16(rb[i].y));
                hz = __bfloat162float(__float2bfloat16(rb[i].z));
                hw = __bfloat162float(__float2bfloat16(rb[i].w));
                Bh[o]   = pack2(hx, hy);             Bh[o+1] = pack2(hz, hw);
                Bl[o]   = pack2(rb[i].x-hx, rb[i].y-hy); Bl[o+1] = pack2(rb[i].z-hz, rb[i].w-hw);
            }
        }
        __syncthreads();
    }

    // epilogue
    #pragma unroll
    for (int mt = 0; mt < 4; mt++) {
        int row = m0 + wm + mt*16 + g;
        #pragma unroll
        for (int nt = 0; nt < 4; nt++) {
            int col = n0 + wn + nt*8 + tg*2;
            float b0 = 0.0f, b1 = 0.0f;
            if (bias) { b0 = bias[col]; b1 = bias[col+1]; }
            float2 v0 = make_float2(acc[mt][nt][0]*alpha + b0, acc[mt][nt][1]*alpha + b1);
            float2 v1 = make_float2(acc[mt][nt][2]*alpha + b0, acc[mt][nt][3]*alpha + b1);
            *(float2*)(C + (long long)row*ldc + col)     = v0;
            *(float2*)(C + (long long)(row+8)*ldc + col) = v1;
        }
    }
}

// ---------------- fp32 transpose: out[n][m] = in[m][n] ---------------------
__global__ void transpose_k(const float* __restrict__ in, float* __restrict__ out,
                            int M, int N, int ldi, int ldo,
                            int zdiv,
                            long long si1, long long si2,
                            long long so1, long long so2)
{
    __shared__ float tile[32][33];
    int z = blockIdx.z, z1 = z / zdiv, z2 = z % zdiv;
    in  += z1*si1 + z2*si2;
    out += z1*so1 + z2*so2;

    int x = blockIdx.x*32 + threadIdx.x;   // n
    int y = blockIdx.y*32 + threadIdx.y;   // m
    #pragma unroll
    for (int i = 0; i < 32; i += 8)
        if (x < N && (y+i) < M)
            tile[threadIdx.y+i][threadIdx.x] = in[(long long)(y+i)*ldi + x];
    __syncthreads();
    x = blockIdx.y*32 + threadIdx.x;       // m
    y = blockIdx.x*32 + threadIdx.y;       // n
    #pragma unroll
    for (int i = 0; i < 32; i += 8)
        if (x < M && (y+i) < N)
            out[(long long)(y+i)*ldo + x] = tile[threadIdx.x][threadIdx.y+i];
}

// ---------------- assemble q/k_full with RoPE; emit k_rot output -----------
__global__ void assemble_kernel(const float* __restrict__ qcat,   // [ROWS][5120]
                                const float* __restrict__ kcat,   // [ROWS][10112]
                                const float* __restrict__ krsrc,  // cat1+256, stride 384
                                float* __restrict__ q,
                                float* __restrict__ kf,
                                float* __restrict__ out_krot)
{
    long long idx = (long long)blockIdx.x * 256 + threadIdx.x;
    if (idx >= (long long)ROWS * D_MODEL) return;
    int d         = (int)(idx % D_HEAD);
    long long rh  = idx / D_HEAD;
    int h         = (int)(rh & 7);
    long long row = rh >> 3;
    int s         = (int)(row & (SS - 1));

    if (d < SPLIT) {
        q[idx]  = qcat[row*(long long)NCAT3 + h*SPLIT + d];
        kf[idx] = kcat[row*(long long)NCAT2 + h*SPLIT + d];
    } else {
        int dd = d - SPLIT;                       // 0..15
        long long qb = row*(long long)NCAT3 + 4992 + h*D_ROPE;
        long long kb = row*(long long)NCAT1 + h*D_ROPE;
        float qv, kv;
        if (dd < 8) {
            const float invf[4] = {1.0f, 0.1f, 0.01f, 0.001f};
            int j   = dd & 3;
            float f = ((float)s / 40.0f) * invf[j];
            float c = cosf(f), sn = sinf(f);
            if (dd < 4) {
                qv = qcat[qb+dd]*c - qcat[qb+dd+4]*sn;
                kv = krsrc[kb+dd]*c - krsrc[kb+dd+4]*sn;
            } else {
                qv = qcat[qb+dd]*c + qcat[qb+dd-4]*sn;
                kv = krsrc[kb+dd]*c + krsrc[kb+dd-4]*sn;
            }
        } else {
            qv = qcat[qb+dd];
            kv = krsrc[kb+dd];
        }
        q[idx]  = qv;
        kf[idx] = kv;
        out_krot[row*(N_HEADS*D_ROPE) + h*D_ROPE + dd] = kv;
    }
}

// ---------------- c_kv output copy ------------------------------------------
__global__ void copy_ckv(const float* __restrict__ cat1, float* __restrict__ out)
{
    int idx = blockIdx.x * 256 + threadIdx.x;
    if (idx < ROWS * D_KV)
        out[idx] = cat1[(idx >> 7) * NCAT1 + (idx & 127)];
}

// ---------------- row softmax over 2048 columns ------------------------------
__global__ void softmax2048(float* __restrict__ s)
{
    long long row = blockIdx.x;
    float* p = s + (row << 11);
    int t = threadIdx.x;

    float v[8];
    float m = -1e30f;
    #pragma unroll
    for (int i = 0; i < 8; i++) {
        v[i] = p[t + (i << 8)];
        m = fmaxf(m, v[i]);
    }
    __shared__ float red[256];
    red[t] = m; __syncthreads();
    for (int off = 128; off > 0; off >>= 1) {
        if (t < off) red[t] = fmaxf(red[t], red[t+off]);
        __syncthreads();
    }
    m = red[0];
    __syncthreads();

    float sum = 0.0f;
    #pragma unroll
    for (int i = 0; i < 8; i++) {
        v[i] = expf(v[i] - m);
        sum += v[i];
    }
    red[t] = sum; __syncthreads();
    for (int off = 128; off > 0; off >>= 1) {
        if (t < off) red[t] += red[t+off];
        __syncthreads();
    }
    float inv = 1.0f / red[0];
    #pragma unroll
    for (int i = 0; i < 8; i++)
        p[t + (i << 8)] = v[i] * inv;
}

// ---------------- host side ---------------------------------------------------
static inline float* sym(const void* s)
{
    void* p = nullptr;
    cudaGetSymbolAddress(&p, s);
    return (float*)p;
}

#define GEMM_SMEM (8*SMM*4)

static void gemm(int M, int N, int K,
                 const float* A, int lda, const float* B, int ldb,
                 float* C, int ldc, const float* bias, float alpha,
                 int nz = 1, int zdiv = 1,
                 long long sA1 = 0, long long sA2 = 0,
                 long long sB1 = 0, long long sB2 = 0,
                 long long sC1 = 0, long long sC2 = 0)
{
    dim3 grid(N / 128, M / 128, nz);
    gemm_bf16x3<<<grid, 256, GEMM_SMEM>>>(M, N, K, A, lda, B, ldb, C, ldc,
                                          bias, alpha, zdiv,
                                          sA1, sA2, sB1, sB2, sC1, sC2);
}

static void transpose(const float* in, float* out, int M, int N, int ldi, int ldo,
                      int nz = 1, int zdiv = 1,
                      long long si1 = 0, long long si2 = 0,
                      long long so1 = 0, long long so2 = 0)
{
    dim3 grid((N + 31)/32, (M + 31)/32, nz);
    transpose_k<<<grid, dim3(32, 8)>>>(in, out, M, N, ldi, ldo, zdiv, si1, si2, so1, so2);
}

extern "C" void kernel_launch(void* const* d_in, const int* in_sizes, int n_in,
                              void* d_out, int out_size)
{
    const float* h     = (const float*)d_in[0];
    const float* W_dkv = (const float*)d_in[1];
    const float* b_dkv = (const float*)d_in[2];
    const float* W_dq  = (const float*)d_in[3];
    const float* b_dq  = (const float*)d_in[4];
    const float* W_uk  = (const float*)d_in[5];
    const float* b_uk  = (const float*)d_in[6];
    const float* W_uv  = (const float*)d_in[7];
    const float* b_uv  = (const float*)d_in[8];
    const float* W_uq  = (const float*)d_in[9];
    const float* b_uq  = (const float*)d_in[10];
    const float* W_qr  = (const float*)d_in[11];
    const float* b_qr  = (const float*)d_in[12];
    const float* W_kr  = (const float*)d_in[13];
    const float* b_kr  = (const float*)d_in[14];
    const float* W_o   = (const float*)d_in[15];
    const float* b_o   = (const float*)d_in[16];

    float* out      = (float*)d_out;
    float* out_ckv  = out + (long long)ROWS * D_MODEL;
    float* out_krot = out_ckv + (long long)ROWS * D_KV;

    float* cat1 = sym(g_cat1);
    float* kcat = sym(g_kcat);
    float* qcat = sym(g_qcat);
    float* q    = sym(g_q);
    float* kf   = sym(g_kf);
    float* vt   = sym(g_vt);
    float* sc   = sym(g_sc);
    float* ao   = sym(g_ao);
    float* w1T  = sym(g_w1T);
    float* w2T  = sym(g_w2T);
    float* w3T  = sym(g_w3T);
    float* woT  = sym(g_woT);
    float* b1   = sym(g_b1);
    float* b2   = sym(g_b2);
    float* b3   = sym(g_b3);

    cudaFuncSetAttribute(gemm_bf16x3, cudaFuncAttributeMaxDynamicSharedMemorySize, GEMM_SMEM);

    const float scale = 1.0f / sqrtf((float)D_HEAD);

    // --- bias concatenation ---
    cudaMemcpyAsync(b1,       b_dkv, 128*sizeof(float),  cudaMemcpyDeviceToDevice, 0);
    cudaMemcpyAsync(b1+128,   b_dq,  128*sizeof(float),  cudaMemcpyDeviceToDevice, 0);
    cudaMemcpyAsync(b1+256,   b_kr,  128*sizeof(float),  cudaMemcpyDeviceToDevice, 0);
    cudaMemcpyAsync(b2,       b_uk,  4992*sizeof(float), cudaMemcpyDeviceToDevice, 0);
    cudaMemcpyAsync(b2+4992,  b_uv,  5120*sizeof(float), cudaMemcpyDeviceToDevice, 0);
    cudaMemcpyAsync(b3,       b_uq,  4992*sizeof(float), cudaMemcpyDeviceToDevice, 0);
    cudaMemcpyAsync(b3+4992,  b_qr,  128*sizeof(float),  cudaMemcpyDeviceToDevice, 0);

    // --- weight transposes (to [N][K]) ---
    transpose(W_dkv, w1T,               D_MODEL, D_KV, D_KV, D_MODEL);
    transpose(W_dq,  w1T + 128*D_MODEL, D_MODEL, D_KV, D_KV, D_MODEL);
    transpose(W_kr,  w1T + 256*D_MODEL, D_MODEL, D_KV, D_KV, D_MODEL);
    transpose(W_uk,  w2T,               D_KV, 4992, 4992, D_KV);
    transpose(W_uv,  w2T + 4992*D_KV,   D_KV, 5120, 5120, D_KV);
    transpose(W_uq,  w3T,               D_KV, 4992, 4992, D_KV);
    transpose(W_qr,  w3T + 4992*D_KV,   D_KV, 128, 128, D_KV);
    transpose(W_o,   woT,               D_MODEL, D_MODEL, D_MODEL, D_MODEL);

    // --- G1: [ckv | cq | krot] = h @ [W_dkv|W_dq|W_kr] + b ---
    gemm(ROWS, NCAT1, D_MODEL, h, D_MODEL, w1T, D_MODEL, cat1, NCAT1, b1, 1.0f);
    copy_ckv<<<(ROWS*D_KV + 255)/256, 256>>>(cat1, out_ckv);

    // --- G2: [kbase | v] = ckv @ [W_uk|W_uv] + b ---
    gemm(ROWS, NCAT2, D_KV, cat1, NCAT1, w2T, D_KV, kcat, NCAT2, b2, 1.0f);

    // --- G3: [qbase | qrot] = cq @ [W_uq|W_qr] + b ---
    gemm(ROWS, NCAT3, D_KV, cat1 + 128, NCAT1, w3T, D_KV, qcat, NCAT3, b3, 1.0f);

    // --- assemble q / k_full with RoPE; write k_rot output ---
    {
        long long total = (long long)ROWS * D_MODEL;
        assemble_kernel<<<(unsigned)((total + 255)/256), 256>>>(
            qcat, kcat, cat1 + 256, q, kf, out_krot);
    }

    // --- scores = scale * q @ k^T, batched over (b,h) ---
    gemm(SS, SS, D_HEAD,
         q,  D_MODEL, kf, D_MODEL, sc, SS, nullptr, scale,
         BB*N_HEADS, N_HEADS,
         (long long)SS*D_MODEL, (long long)D_HEAD,
         (long long)SS*D_MODEL, (long long)D_HEAD,
         (long long)N_HEADS*SS*SS, (long long)SS*SS);

    // --- softmax ---
    softmax2048<<<BB*N_HEADS*SS, 256>>>(sc);

    // --- transpose v (from kcat cols 4992..) to [b][h][d][s] ---
    transpose(kcat + 4992, vt, SS, D_HEAD, NCAT2, SS,
              BB*N_HEADS, N_HEADS,
              (long long)SS*NCAT2, (long long)D_HEAD,
              (long long)N_HEADS*D_HEAD*SS, (long long)D_HEAD*SS);

    // --- attn_out = attn @ v, batched over (b,h) ---
    gemm(SS, D_HEAD, SS,
         sc, SS, vt, SS, ao, D_MODEL, nullptr, 1.0f,
         BB*N_HEADS, N_HEADS,
         (long long)N_HEADS*SS*SS, (long long)SS*SS,
         (long long)N_HEADS*D_HEAD*SS, (long long)D_HEAD*SS,
         (long long)SS*D_MODEL, (long long)D_HEAD);

    // --- final projection ---
    gemm(ROWS, D_MODEL, D_MODEL, ao, D_MODEL, woT, D_MODEL, out, D_MODEL, b_o, 1.0f);
}

// round 4
// speedup vs baseline: 2.6444x; 1.0596x over previous
#include <cuda_runtime.h>
#include <cuda_bf16.h>
#include <math.h>
#include <stdint.h>

#define D_MODEL 5120
#define N_HEADS 8
#define D_KV    128
#define D_ROPE  16
#define D_HEAD  640
#define SPLIT   624
#define BB      2
#define SS      2048
#define ROWS    (BB*SS)          // 4096
#define NCAT1   384
#define NCAT2   10112
#define NCAT3   5120

typedef __nv_bfloat16 bf16;

// ---------------- scratch (device globals) ----------------------------------
__device__ __align__(16) float g_cat1 [ROWS*NCAT1];
__device__ __align__(16) bf16  g_cat1h[ROWS*NCAT1];
__device__ __align__(16) bf16  g_cat1l[ROWS*NCAT1];
__device__ __align__(16) float g_kcat [(size_t)ROWS*NCAT2];
__device__ __align__(16) float g_qcat [(size_t)ROWS*NCAT3];
__device__ __align__(16) bf16  g_hh [(size_t)ROWS*D_MODEL];
__device__ __align__(16) bf16  g_hl [(size_t)ROWS*D_MODEL];
__device__ __align__(16) bf16  g_qh [(size_t)ROWS*D_MODEL];
__device__ __align__(16) bf16  g_ql [(size_t)ROWS*D_MODEL];
__device__ __align__(16) bf16  g_kfh[(size_t)ROWS*D_MODEL];
__device__ __align__(16) bf16  g_kfl[(size_t)ROWS*D_MODEL];
__device__ __align__(16) bf16  g_vth[(size_t)ROWS*D_MODEL];
__device__ __align__(16) bf16  g_vtl[(size_t)ROWS*D_MODEL];
__device__ __align__(16) float g_sc [(size_t)BB*N_HEADS*SS*SS];
__device__ __align__(16) bf16  g_ath[(size_t)BB*N_HEADS*SS*SS];
__device__ __align__(16) bf16  g_atl[(size_t)BB*N_HEADS*SS*SS];
__device__ __align__(16) bf16  g_aoh[(size_t)ROWS*D_MODEL];
__device__ __align__(16) bf16  g_aol[(size_t)ROWS*D_MODEL];
__device__ __align__(16) bf16  g_w1h[NCAT1*D_MODEL];
__device__ __align__(16) bf16  g_w1l[NCAT1*D_MODEL];
__device__ __align__(16) bf16  g_w2h[NCAT2*D_KV];
__device__ __align__(16) bf16  g_w2l[NCAT2*D_KV];
__device__ __align__(16) bf16  g_w3h[NCAT3*D_KV];
__device__ __align__(16) bf16  g_w3l[NCAT3*D_KV];
__device__ __align__(16) bf16  g_woh[(size_t)D_MODEL*D_MODEL];
__device__ __align__(16) bf16  g_wol[(size_t)D_MODEL*D_MODEL];
__device__ __align__(16) float g_b1 [NCAT1];
__device__ __align__(16) float g_b2 [NCAT2];
__device__ __align__(16) float g_b3 [NCAT3];

// ---------------- PTX helpers ------------------------------------------------
__device__ __forceinline__ uint32_t smem_u32(const void* p) {
    uint32_t a;
    asm("{ .reg .u64 t; cvta.to.shared.u64 t, %1; cvt.u32.u64 %0, t; }"
        : "=r"(a) : "l"(p));
    return a;
}

__device__ __forceinline__ void cp16(uint32_t dst, const void* src) {
    asm volatile("cp.async.cg.shared.global [%0], [%1], 16;\n"
                 :: "r"(dst), "l"(__cvta_generic_to_global(src)));
}
#define CP_COMMIT() asm volatile("cp.async.commit_group;\n" ::: "memory")
#define CP_WAIT1()  asm volatile("cp.async.wait_group 1;\n" ::: "memory")
#define CP_WAIT0()  asm volatile("cp.async.wait_group 0;\n" ::: "memory")

__device__ __forceinline__ void ldm4(uint32_t* r, uint32_t a) {
    asm volatile("ldmatrix.sync.aligned.m8n8.x4.shared.b16 {%0,%1,%2,%3}, [%4];"
                 : "=r"(r[0]), "=r"(r[1]), "=r"(r[2]), "=r"(r[3]) : "r"(a));
}

__device__ __forceinline__ void mma16816(float* c, const uint32_t* a, const uint32_t* b) {
    asm volatile(
        "mma.sync.aligned.m16n8k16.row.col.f32.bf16.bf16.f32 "
        "{%0,%1,%2,%3},{%4,%5,%6,%7},{%8,%9},{%0,%1,%2,%3};\n"
        : "+f"(c[0]), "+f"(c[1]), "+f"(c[2]), "+f"(c[3])
        : "r"(a[0]), "r"(a[1]), "r"(a[2]), "r"(a[3]), "r"(b[0]), "r"(b[1]));
}

__device__ __forceinline__ void split_bf16(float v, bf16& h, bf16& l) {
    h = __float2bfloat16(v);
    l = __float2bfloat16(v - __bfloat162float(h));
}

// ---------------- bf16x3 mma.sync GEMM ---------------------------------------
// C = alpha*A@B^T + bias; A[M][K], B[N][K], bf16 hi/lo inputs, fp32 accum.
// CTA tile 128x128, k-tile 64, 3-stage cp.async pipeline, ldmatrix frags.
// 8 warps (2x4), warptile 64x32, sites 4x4 m16n8, 3 MMAs per site (hi/lo split).

#define STAGE_BYTES 65536                 // Ah 16K | Al 16K | Bh 16K | Bl 16K
#define GEMM_SMEM   (3*STAGE_BYTES)

__global__ void __launch_bounds__(256, 1)
gemm_mma(int M, int N, int K,
         const bf16* __restrict__ Ah_, const bf16* __restrict__ Al_, long long lda,
         const bf16* __restrict__ Bh_, const bf16* __restrict__ Bl_, long long ldb,
         float* __restrict__ C, bf16* __restrict__ Ch, bf16* __restrict__ Cl,
         long long ldc,
         const float* __restrict__ bias, float alpha,
         int zdiv,
         long long sA1, long long sA2,
         long long sB1, long long sB2,
         long long sC1, long long sC2)
{
    extern __shared__ __align__(1024) char smem[];
    const uint32_t sb = smem_u32(smem);

    {
        int z  = blockIdx.z;
        int z1 = z / zdiv, z2 = z % zdiv;
        Ah_ += z1*sA1 + z2*sA2;  Al_ += z1*sA1 + z2*sA2;
        Bh_ += z1*sB1 + z2*sB2;  Bl_ += z1*sB1 + z2*sB2;
        long long co = z1*sC1 + z2*sC2;
        if (C)  C  += co;
        if (Ch) { Ch += co; Cl += co; }
    }

    const int tid  = threadIdx.x;
    const int wid  = tid >> 5;
    const int lane = tid & 31;
    const int wm   = (wid >> 2) * 64;
    const int wn   = (wid & 3) * 32;
    const int g    = lane >> 2, tg = lane & 3;
    const int m0   = blockIdx.y * 128;
    const int n0   = blockIdx.x * 128;

    // loader indexing: 2 threads per row (128 rows), 4 x 16B chunks each
    const int lrow = tid >> 1;
    const int half = tid & 1;
    const bf16* pAh = Ah_ + (long long)(m0 + lrow)*lda;
    const bf16* pAl = Al_ + (long long)(m0 + lrow)*lda;
    const bf16* pBh = Bh_ + (long long)(n0 + lrow)*ldb;
    const bf16* pBl = Bl_ + (long long)(n0 + lrow)*ldb;
    const uint32_t lswz = (uint32_t)(lrow & 7);

    const int nk = K / 64;

    // fragment lane constants
    const int piece = lane >> 3, rr = lane & 7;
    const int rowA  = wm + (piece & 1)*8 + rr;     // + mt*16
    const int rowB  = wn + (piece >> 1)*8 + rr;    // + ntp*16
    const int cA    = piece >> 1;                   // chunk bit from piece
    const int cB    = piece & 1;

    float acc[4][4][4];
    #pragma unroll
    for (int i = 0; i < 4; i++)
        #pragma unroll
        for (int j = 0; j < 4; j++)
            #pragma unroll
            for (int k = 0; k < 4; k++) acc[i][j][k] = 0.0f;

    // ---- stage issue ----
    #define ISSUE(t) do {                                                     \
        uint32_t s0_ = sb + ((t) % 3) * STAGE_BYTES;                          \
        const int k0_ = (t) * 64;                                             \
        _Pragma("unroll")                                                     \
        for (int j = 0; j < 4; j++) {                                         \
            int ch_ = half*4 + j;                                             \
            uint32_t d_ = (uint32_t)(lrow*128 + (((uint32_t)ch_ ^ lswz) << 4)); \
            cp16(s0_ +         d_, pAh + k0_ + ch_*8);                        \
            cp16(s0_ + 16384 + d_, pAl + k0_ + ch_*8);                        \
            cp16(s0_ + 32768 + d_, pBh + k0_ + ch_*8);                        \
            cp16(s0_ + 49152 + d_, pBl + k0_ + ch_*8);                        \
        }                                                                     \
        CP_COMMIT();                                                          \
    } while (0)

    ISSUE(0);
    if (nk > 1) ISSUE(1);

    for (int t = 0; t < nk; t++) {
        if (t + 1 < nk) { CP_WAIT1(); } else { CP_WAIT0(); }
        __syncthreads();
        if (t + 2 < nk) ISSUE(t + 2);

        const uint32_t Ab = sb + (t % 3) * STAGE_BYTES;
        const uint32_t Bb = Ab + 32768;

        #pragma unroll
        for (int ks = 0; ks < 4; ks++) {
            uint32_t ah[4][4], al[4][4], bh[4][2], bl[4][2];
            const uint32_t aoff = (uint32_t)(rowA*128 + (((ks*2 + cA) ^ (rowA & 7)) << 4));
            const uint32_t boff = (uint32_t)(rowB*128 + (((ks*2 + cB) ^ (rowB & 7)) << 4));
            #pragma unroll
            for (int mt = 0; mt < 4; mt++) {
                ldm4(ah[mt], Ab +          aoff + mt*2048);
                ldm4(al[mt], Ab + 16384 +  aoff + mt*2048);
            }
            #pragma unroll
            for (int ntp = 0; ntp < 2; ntp++) {
                uint32_t rb[4];
                ldm4(rb, Bb +          boff + ntp*2048);
                bh[ntp*2][0]   = rb[0]; bh[ntp*2][1]   = rb[1];
                bh[ntp*2+1][0] = rb[2]; bh[ntp*2+1][1] = rb[3];
                ldm4(rb, Bb + 16384 +  boff + ntp*2048);
                bl[ntp*2][0]   = rb[0]; bl[ntp*2][1]   = rb[1];
                bl[ntp*2+1][0] = rb[2]; bl[ntp*2+1][1] = rb[3];
            }
            #pragma unroll
            for (int mt = 0; mt < 4; mt++)
                #pragma unroll
                for (int nt = 0; nt < 4; nt++) {
                    mma16816(acc[mt][nt], ah[mt], bh[nt]);
                    mma16816(acc[mt][nt], al[mt], bh[nt]);
                    mma16816(acc[mt][nt], ah[mt], bl[nt]);
                }
        }
    }

    // ---- epilogue: direct register stores ----
    #pragma unroll
    for (int mt = 0; mt < 4; mt++) {
        int row = m0 + wm + mt*16 + g;
        #pragma unroll
        for (int nt = 0; nt < 4; nt++) {
            int col = n0 + wn + nt*8 + tg*2;
            float b0 = 0.0f, b1 = 0.0f;
            if (bias) { b0 = bias[col]; b1 = bias[col+1]; }
            float v00 = acc[mt][nt][0]*alpha + b0;
            float v01 = acc[mt][nt][1]*alpha + b1;
            float v10 = acc[mt][nt][2]*alpha + b0;
            float v11 = acc[mt][nt][3]*alpha + b1;
            if (C) {
                *(float2*)(C + (long long)row*ldc + col)     = make_float2(v00, v01);
                *(float2*)(C + (long long)(row+8)*ldc + col) = make_float2(v10, v11);
            }
            if (Ch) {
                bf16 h0, l0, h1, l1;
                split_bf16(v00, h0, l0); split_bf16(v01, h1, l1);
                *(uint32_t*)(Ch + (long long)row*ldc + col) = ((uint32_t)*(uint16_t*)&h1 << 16) | *(uint16_t*)&h0;
                *(uint32_t*)(Cl + (long long)row*ldc + col) = ((uint32_t)*(uint16_t*)&l1 << 16) | *(uint16_t*)&l0;
                split_bf16(v10, h0, l0); split_bf16(v11, h1, l1);
                *(uint32_t*)(Ch + (long long)(row+8)*ldc + col) = ((uint32_t)*(uint16_t*)&h1 << 16) | *(uint16_t*)&h0;
                *(uint32_t*)(Cl + (long long)(row+8)*ldc + col) = ((uint32_t)*(uint16_t*)&l1 << 16) | *(uint16_t*)&l0;
            }
        }
    }
}

// ---------------- elementwise fp32 -> bf16 hi/lo ----------------------------
__global__ void convert_split_k(const float* __restrict__ in,
                                bf16* __restrict__ oh, bf16* __restrict__ ol,
                                long long n)
{
    long long i = (long long)blockIdx.x * 256 + threadIdx.x;
    if (i < n) {
        bf16 h, l; split_bf16(in[i], h, l);
        oh[i] = h; ol[i] = l;
    }
}

// ---------------- fp32 transpose -> bf16 hi/lo: out[n][m] = in[m][n] --------
__global__ void transpose_split_k(const float* __restrict__ in,
                                  bf16* __restrict__ oh, bf16* __restrict__ ol,
                                  int M, int N, int ldi, int ldo,
                                  int zdiv,
                                  long long si1, long long si2,
                                  long long so1, long long so2)
{
    __shared__ float tile[32][33];
    int z = blockIdx.z, z1 = z / zdiv, z2 = z % zdiv;
    in += z1*si1 + z2*si2;
    oh += z1*so1 + z2*so2;
    ol += z1*so1 + z2*so2;

    int x = blockIdx.x*32 + threadIdx.x;   // n
    int y = blockIdx.y*32 + threadIdx.y;   // m
    #pragma unroll
    for (int i = 0; i < 32; i += 8)
        if (x < N && (y+i) < M)
            tile[threadIdx.y+i][threadIdx.x] = in[(long long)(y+i)*ldi + x];
    __syncthreads();
    x = blockIdx.y*32 + threadIdx.x;       // m
    y = blockIdx.x*32 + threadIdx.y;       // n
    #pragma unroll
    for (int i = 0; i < 32; i += 8)
        if (x < M && (y+i) < N) {
            bf16 h, l; split_bf16(tile[threadIdx.x][threadIdx.y+i], h, l);
            oh[(long long)(y+i)*ldo + x] = h;
            ol[(long long)(y+i)*ldo + x] = l;
        }
}

// ---------------- assemble q/k_full (RoPE) -> bf16 hi/lo; emit k_rot --------
__global__ void assemble_kernel(const float* __restrict__ qcat,
                                const float* __restrict__ kcat,
                                const float* __restrict__ krsrc,
                                bf16* __restrict__ qh, bf16* __restrict__ ql,
                                bf16* __restrict__ kfh, bf16* __restrict__ kfl,
                                float* __restrict__ out_krot)
{
    long long idx = (long long)blockIdx.x * 256 + threadIdx.x;
    if (idx >= (long long)ROWS * D_MODEL) return;
    int d         = (int)(idx % D_HEAD);
    long long rh  = idx / D_HEAD;
    int h         = (int)(rh & 7);
    long long row = rh >> 3;
    int s         = (int)(row & (SS - 1));

    float qv, kv;
    if (d < SPLIT) {
        qv = qcat[row*(long long)NCAT3 + h*SPLIT + d];
        kv = kcat[row*(long long)NCAT2 + h*SPLIT + d];
    } else {
        int dd = d - SPLIT;
        long long qb = row*(long long)NCAT3 + 4992 + h*D_ROPE;
        long long kb = row*(long long)NCAT1 + h*D_ROPE;
        if (dd < 8) {
            const float invf[4] = {1.0f, 0.1f, 0.01f, 0.001f};
            int j   = dd & 3;
            float f = ((float)s / 40.0f) * invf[j];
            float c = cosf(f), sn = sinf(f);
            if (dd < 4) {
                qv = qcat[qb+dd]*c - qcat[qb+dd+4]*sn;
                kv = krsrc[kb+dd]*c - krsrc[kb+dd+4]*sn;
            } else {
                qv = qcat[qb+dd]*c + qcat[qb+dd-4]*sn;
                kv = krsrc[kb+dd]*c + krsrc[kb+dd-4]*sn;
            }
        } else {
            qv = qcat[qb+dd];
            kv = krsrc[kb+dd];
        }
        out_krot[row*(N_HEADS*D_ROPE) + h*D_ROPE + dd] = kv;
    }
    bf16 hh, ll;
    split_bf16(qv, hh, ll);  qh[idx] = hh;  ql[idx] = ll;
    split_bf16(kv, hh, ll);  kfh[idx] = hh; kfl[idx] = ll;
}

// ---------------- c_kv output copy -------------------------------------------
__global__ void copy_ckv(const float* __restrict__ cat1, float* __restrict__ out)
{
    int idx = blockIdx.x * 256 + threadIdx.x;
    if (idx < ROWS * D_KV)
        out[idx] = cat1[(idx >> 7) * NCAT1 + (idx & 127)];
}

// ---------------- row softmax (2048 cols) -> bf16 hi/lo ----------------------
__global__ void softmax2048(const float* __restrict__ s,
                            bf16* __restrict__ oh, bf16* __restrict__ ol)
{
    long long row = blockIdx.x;
    const float* p = s + (row << 11);
    bf16* ph = oh + (row << 11);
    bf16* pl = ol + (row << 11);
    int t = threadIdx.x;

    float v[8];
    float m = -1e30f;
    #pragma unroll
    for (int i = 0; i < 8; i++) {
        v[i] = p[t + (i << 8)];
        m = fmaxf(m, v[i]);
    }
    __shared__ float red[256];
    red[t] = m; __syncthreads();
    for (int off = 128; off > 0; off >>= 1) {
        if (t < off) red[t] = fmaxf(red[t], red[t+off]);
        __syncthreads();
    }
    m = red[0];
    __syncthreads();

    float sum = 0.0f;
    #pragma unroll
    for (int i = 0; i < 8; i++) {
        v[i] = expf(v[i] - m);
        sum += v[i];
    }
    red[t] = sum; __syncthreads();
    for (int off = 128; off > 0; off >>= 1) {
        if (t < off) red[t] += red[t+off];
        __syncthreads();
    }
    float inv = 1.0f / red[0];
    #pragma unroll
    for (int i = 0; i < 8; i++) {
        bf16 hh, ll; split_bf16(v[i] * inv, hh, ll);
        ph[t + (i << 8)] = hh;
        pl[t + (i << 8)] = ll;
    }
}

// ---------------- host side ----------------------------------------------------
static inline void* symv(const void* s)
{
    void* p = nullptr;
    cudaGetSymbolAddress(&p, s);
    return p;
}

static void gemm(int M, int N, int K,
                 const bf16* Ah, const bf16* Al, long long lda,
                 const bf16* Bh, const bf16* Bl, long long ldb,
                 float* C, bf16* Ch, bf16* Cl, long long ldc,
                 const float* bias, float alpha,
                 int nz = 1, int zdiv = 1,
                 long long sA1 = 0, long long sA2 = 0,
                 long long sB1 = 0, long long sB2 = 0,
                 long long sC1 = 0, long long sC2 = 0)
{
    dim3 grid(N / 128, M / 128, nz);
    gemm_mma<<<grid, 256, GEMM_SMEM>>>(M, N, K, Ah, Al, lda, Bh, Bl, ldb,
                                       C, Ch, Cl, ldc, bias, alpha, zdiv,
                                       sA1, sA2, sB1, sB2, sC1, sC2);
}

static void tsplit(const float* in, bf16* oh, bf16* ol, int M, int N, int ldi, int ldo,
                   int nz = 1, int zdiv = 1,
                   long long si1 = 0, long long si2 = 0,
                   long long so1 = 0, long long so2 = 0)
{
    dim3 grid((N + 31)/32, (M + 31)/32, nz);
    transpose_split_k<<<grid, dim3(32, 8)>>>(in, oh, ol, M, N, ldi, ldo,
                                             zdiv, si1, si2, so1, so2);
}

extern "C" void kernel_launch(void* const* d_in, const int* in_sizes, int n_in,
                              void* d_out, int out_size)
{
    const float* h     = (const float*)d_in[0];
    const float* W_dkv = (const float*)d_in[1];
    const float* b_dkv = (const float*)d_in[2];
    const float* W_dq  = (const float*)d_in[3];
    const float* b_dq  = (const float*)d_in[4];
    const float* W_uk  = (const float*)d_in[5];
    const float* b_uk  = (const float*)d_in[6];
    const float* W_uv  = (const float*)d_in[7];
    const float* b_uv  = (const float*)d_in[8];
    const float* W_uq  = (const float*)d_in[9];
    const float* b_uq  = (const float*)d_in[10];
    const float* W_qr  = (const float*)d_in[11];
    const float* b_qr  = (const float*)d_in[12];
    const float* W_kr  = (const float*)d_in[13];
    const float* b_kr  = (const float*)d_in[14];
    const float* W_o   = (const float*)d_in[15];
    const float* b_o   = (const float*)d_in[16];

    float* out      = (float*)d_out;
    float* out_ckv  = out + (long long)ROWS * D_MODEL;
    float* out_krot = out_ckv + (long long)ROWS * D_KV;

    float* cat1  = (float*)symv(g_cat1);
    bf16*  cat1h = (bf16*)symv(g_cat1h);
    bf16*  cat1l = (bf16*)symv(g_cat1l);
    float* kcat  = (float*)symv(g_kcat);
    float* qcat  = (float*)symv(g_qcat);
    bf16*  hh    = (bf16*)symv(g_hh);
    bf16*  hl    = (bf16*)symv(g_hl);
    bf16*  qh    = (bf16*)symv(g_qh);
    bf16*  ql    = (bf16*)symv(g_ql);
    bf16*  kfh   = (bf16*)symv(g_kfh);
    bf16*  kfl   = (bf16*)symv(g_kfl);
    bf16*  vth   = (bf16*)symv(g_vth);
    bf16*  vtl   = (bf16*)symv(g_vtl);
    float* sc    = (float*)symv(g_sc);
    bf16*  ath   = (bf16*)symv(g_ath);
    bf16*  atl   = (bf16*)symv(g_atl);
    bf16*  aoh   = (bf16*)symv(g_aoh);
    bf16*  aol   = (bf16*)symv(g_aol);
    bf16*  w1h   = (bf16*)symv(g_w1h);
    bf16*  w1l   = (bf16*)symv(g_w1l);
    bf16*  w2h   = (bf16*)symv(g_w2h);
    bf16*  w2l   = (bf16*)symv(g_w2l);
    bf16*  w3h   = (bf16*)symv(g_w3h);
    bf16*  w3l   = (bf16*)symv(g_w3l);
    bf16*  woh   = (bf16*)symv(g_woh);
    bf16*  wol   = (bf16*)symv(g_wol);
    float* b1    = (float*)symv(g_b1);
    float* b2    = (float*)symv(g_b2);
    float* b3    = (float*)symv(g_b3);

    cudaFuncSetAttribute(gemm_mma, cudaFuncAttributeMaxDynamicSharedMemorySize, GEMM_SMEM);

    const float scale = 1.0f / sqrtf((float)D_HEAD);

    // --- bias concatenation ---
    cudaMemcpyAsync(b1,      b_dkv, 128*sizeof(float),  cudaMemcpyDeviceToDevice, 0);
    cudaMemcpyAsync(b1+128,  b_dq,  128*sizeof(float),  cudaMemcpyDeviceToDevice, 0);
    cudaMemcpyAsync(b1+256,  b_kr,  128*sizeof(float),  cudaMemcpyDeviceToDevice, 0);
    cudaMemcpyAsync(b2,      b_uk,  4992*sizeof(float), cudaMemcpyDeviceToDevice, 0);
    cudaMemcpyAsync(b2+4992, b_uv,  5120*sizeof(float), cudaMemcpyDeviceToDevice, 0);
    cudaMemcpyAsync(b3,      b_uq,  4992*sizeof(float), cudaMemcpyDeviceToDevice, 0);
    cudaMemcpyAsync(b3+4992, b_qr,  128*sizeof(float),  cudaMemcpyDeviceToDevice, 0);

    // --- weight transposes + split to bf16 hi/lo ([N][K] layout) ---
    tsplit(W_dkv, w1h,               w1l,               D_MODEL, D_KV, D_KV, D_MODEL);
    tsplit(W_dq,  w1h + 128*D_MODEL, w1l + 128*D_MODEL, D_MODEL, D_KV, D_KV, D_MODEL);
    tsplit(W_kr,  w1h + 256*D_MODEL, w1l + 256*D_MODEL, D_MODEL, D_KV, D_KV, D_MODEL);
    tsplit(W_uk,  w2h,               w2l,               D_KV, 4992, 4992, D_KV);
    tsplit(W_uv,  w2h + 4992*D_KV,   w2l + 4992*D_KV,   D_KV, 5120, 5120, D_KV);
    tsplit(W_uq,  w3h,               w3l,               D_KV, 4992, 4992, D_KV);
    tsplit(W_qr,  w3h + 4992*D_KV,   w3l + 4992*D_KV,   D_KV, 128, 128, D_KV);
    tsplit(W_o,   woh,               wol,               D_MODEL, D_MODEL, D_MODEL, D_MODEL);

    // --- h -> bf16 hi/lo ---
    {
        long long n = (long long)ROWS * D_MODEL;
        convert_split_k<<<(unsigned)((n + 255)/256), 256>>>(h, hh, hl, n);
    }

    // --- G1: [ckv | cq | krot] = h @ W1 + b1 (fp32 + hi/lo out) ---
    gemm(ROWS, NCAT1, D_MODEL, hh, hl, D_MODEL, w1h, w1l, D_MODEL,
         cat1, cat1h, cat1l, NCAT1, b1, 1.0f);
    copy_ckv<<<(ROWS*D_KV + 255)/256, 256>>>(cat1, out_ckv);

    // --- G2: [kbase | v] = ckv @ W2 + b2 (fp32 out) ---
    gemm(ROWS, NCAT2, D_KV, cat1h, cat1l, NCAT1, w2h, w2l, D_KV,
         kcat, nullptr, nullptr, NCAT2, b2, 1.0f);

    // --- G3: [qbase | qrot] = cq @ W3 + b3 (fp32 out) ---
    gemm(ROWS, NCAT3, D_KV, cat1h + 128, cat1l + 128, NCAT1, w3h, w3l, D_KV,
         qcat, nullptr, nullptr, NCAT3, b3, 1.0f);

    // --- assemble q / k_full (RoPE) -> hi/lo; write k_rot ---
    {
        long long total = (long long)ROWS * D_MODEL;
        assemble_kernel<<<(unsigned)((total + 255)/256), 256>>>(
            qcat, kcat, cat1 + 256, qh, ql, kfh, kfl, out_krot);
    }

    // --- scores = scale * q @ k^T, batched (b,h) ---
    gemm(SS, SS, D_HEAD,
         qh, ql, D_MODEL, kfh, kfl, D_MODEL,
         sc, nullptr, nullptr, SS, nullptr, scale,
         BB*N_HEADS, N_HEADS,
         (long long)SS*D_MODEL, (long long)D_HEAD,
         (long long)SS*D_MODEL, (long long)D_HEAD,
         (long long)N_HEADS*SS*SS, (long long)SS*SS);

    // --- softmax -> attn hi/lo ---
    softmax2048<<<BB*N_HEADS*SS, 256>>>(sc, ath, atl);

    // --- v^T: kcat cols 4992.. -> vt[b][h][d][s] hi/lo ---
    tsplit(kcat + 4992, vth, vtl, SS, D_HEAD, NCAT2, SS,
           BB*N_HEADS, N_HEADS,
           (long long)SS*NCAT2, (long long)D_HEAD,
           (long long)N_HEADS*D_HEAD*SS, (long long)D_HEAD*SS);

    // --- attn_out = attn @ v (hi/lo out only) ---
    gemm(SS, D_HEAD, SS,
         ath, atl, SS, vth, vtl, SS,
         nullptr, aoh, aol, D_MODEL, nullptr, 1.0f,
         BB*N_HEADS, N_HEADS,
         (long long)N_HEADS*SS*SS, (long long)SS*SS,
         (long long)N_HEADS*D_HEAD*SS, (long long)D_HEAD*SS,
         (long long)SS*D_MODEL, (long long)D_HEAD);

    // --- final projection ---
    gemm(ROWS, D_MODEL, D_MODEL, aoh, aol, D_MODEL, woh, wol, D_MODEL,
         out, nullptr, nullptr, D_MODEL, b_o, 1.0f);
}

// round 5
// speedup vs baseline: 6.0560x; 2.2901x over previous
#include <cuda_runtime.h>
#include <cuda_bf16.h>
#include <math.h>
#include <stdint.h>

#define D_MODEL 5120
#define N_HEADS 8
#define D_KV    128
#define D_ROPE  16
#define D_HEAD  640
#define SPLIT   624
#define BB      2
#define SS      2048
#define ROWS    (BB*SS)          // 4096
#define NCAT1   384              // dkv(128) + dq(128) + kr(128)
#define KAUG    192              // 128 latent + 16 rope + 48 zero pad

typedef __nv_bfloat16 bf16;

// ---------------- scratch (device globals) ----------------------------------
__device__ __align__(16) float g_cat1 [ROWS*NCAT1];
__device__ __align__(16) bf16  g_cat1h[ROWS*NCAT1];
__device__ __align__(16) bf16  g_cat1l[ROWS*NCAT1];
__device__ __align__(16) bf16  g_hh  [(size_t)ROWS*D_MODEL];
__device__ __align__(16) bf16  g_hl  [(size_t)ROWS*D_MODEL];
__device__ __align__(16) bf16  g_w1h [NCAT1*D_MODEL];
__device__ __align__(16) bf16  g_w1l [NCAT1*D_MODEL];
__device__ __align__(16) bf16  g_wqrh[128*128];
__device__ __align__(16) bf16  g_wqrl[128*128];
__device__ __align__(16) bf16  g_uqph[8*128*640];
__device__ __align__(16) bf16  g_uqpl[8*128*640];
__device__ __align__(16) bf16  g_ukph[8*128*640];
__device__ __align__(16) bf16  g_ukpl[8*128*640];
__device__ __align__(16) bf16  g_wqkh[1024*128];
__device__ __align__(16) bf16  g_wqkl[1024*128];
__device__ __align__(16) float g_bqk [1024];
__device__ __align__(16) float g_qrot[ROWS*128];
__device__ __align__(16) float g_qe  [(size_t)ROWS*1024];
__device__ __align__(16) bf16  g_qph [(size_t)16*SS*KAUG];
__device__ __align__(16) bf16  g_qpl [(size_t)16*SS*KAUG];
__device__ __align__(16) bf16  g_kph [(size_t)16*SS*KAUG];
__device__ __align__(16) bf16  g_kpl [(size_t)16*SS*KAUG];
__device__ __align__(16) float g_sc  [(size_t)BB*N_HEADS*SS*SS];
__device__ __align__(16) bf16  g_ath [(size_t)BB*N_HEADS*SS*SS];
__device__ __align__(16) bf16  g_atl [(size_t)BB*N_HEADS*SS*SS];
__device__ __align__(16) bf16  g_ckvth[BB*128*SS];
__device__ __align__(16) bf16  g_ckvtl[BB*128*SS];
__device__ __align__(16) bf16  g_lath[(size_t)ROWS*1024];
__device__ __align__(16) bf16  g_latl[(size_t)ROWS*1024];
__device__ __align__(16) bf16  g_uvsh[128*D_MODEL];
__device__ __align__(16) bf16  g_uvsl[128*D_MODEL];
__device__ __align__(16) bf16  g_woh [(size_t)D_MODEL*D_MODEL];
__device__ __align__(16) bf16  g_wol [(size_t)D_MODEL*D_MODEL];
__device__ __align__(16) bf16  g_wcth[(size_t)D_MODEL*1024];
__device__ __align__(16) bf16  g_wctl[(size_t)D_MODEL*1024];
__device__ __align__(16) float g_b1  [NCAT1];
__device__ __align__(16) float g_beff[D_MODEL];

// ---------------- PTX helpers ------------------------------------------------
__device__ __forceinline__ uint32_t smem_u32(const void* p) {
    uint32_t a;
    asm("{ .reg .u64 t; cvta.to.shared.u64 t, %1; cvt.u32.u64 %0, t; }"
        : "=r"(a) : "l"(p));
    return a;
}

__device__ __forceinline__ void cp16(uint32_t dst, const void* src) {
    asm volatile("cp.async.cg.shared.global [%0], [%1], 16;\n"
                 :: "r"(dst), "l"(__cvta_generic_to_global(src)));
}
#define CP_COMMIT() asm volatile("cp.async.commit_group;\n" ::: "memory")
#define CP_WAIT1()  asm volatile("cp.async.wait_group 1;\n" ::: "memory")
#define CP_WAIT0()  asm volatile("cp.async.wait_group 0;\n" ::: "memory")

__device__ __forceinline__ void ldm4(uint32_t* r, uint32_t a) {
    asm volatile("ldmatrix.sync.aligned.m8n8.x4.shared.b16 {%0,%1,%2,%3}, [%4];"
                 : "=r"(r[0]), "=r"(r[1]), "=r"(r[2]), "=r"(r[3]) : "r"(a));
}

__device__ __forceinline__ void mma16816(float* c, const uint32_t* a, const uint32_t* b) {
    asm volatile(
        "mma.sync.aligned.m16n8k16.row.col.f32.bf16.bf16.f32 "
        "{%0,%1,%2,%3},{%4,%5,%6,%7},{%8,%9},{%0,%1,%2,%3};\n"
        : "+f"(c[0]), "+f"(c[1]), "+f"(c[2]), "+f"(c[3])
        : "r"(a[0]), "r"(a[1]), "r"(a[2]), "r"(a[3]), "r"(b[0]), "r"(b[1]));
}

__device__ __forceinline__ void split_bf16(float v, bf16& h, bf16& l) {
    h = __float2bfloat16(v);
    l = __float2bfloat16(v - __bfloat162float(h));
}

// ---------------- bf16x3 mma.sync GEMM ---------------------------------------
#define STAGE_BYTES 65536
#define GEMM_SMEM   (3*STAGE_BYTES)

__global__ void __launch_bounds__(256, 1)
gemm_mma(int M, int N, int K,
         const bf16* __restrict__ Ah_, const bf16* __restrict__ Al_, long long lda,
         const bf16* __restrict__ Bh_, const bf16* __restrict__ Bl_, long long ldb,
         float* __restrict__ C, bf16* __restrict__ Ch, bf16* __restrict__ Cl,
         long long ldc,
         const float* __restrict__ bias, float alpha,
         int zdiv,
         long long sA1, long long sA2,
         long long sB1, long long sB2,
         long long sC1, long long sC2)
{
    extern __shared__ __align__(1024) char smem[];
    const uint32_t sb = smem_u32(smem);

    {
        int z  = blockIdx.z;
        int z1 = z / zdiv, z2 = z % zdiv;
        Ah_ += z1*sA1 + z2*sA2;  Al_ += z1*sA1 + z2*sA2;
        Bh_ += z1*sB1 + z2*sB2;  Bl_ += z1*sB1 + z2*sB2;
        long long co = z1*sC1 + z2*sC2;
        if (C)  C  += co;
        if (Ch) { Ch += co; Cl += co; }
    }

    const int tid  = threadIdx.x;
    const int wid  = tid >> 5;
    const int lane = tid & 31;
    const int wm   = (wid >> 2) * 64;
    const int wn   = (wid & 3) * 32;
    const int g    = lane >> 2, tg = lane & 3;
    const int m0   = blockIdx.y * 128;
    const int n0   = blockIdx.x * 128;

    const int lrow = tid >> 1;
    const int half = tid & 1;
    const bf16* pAh = Ah_ + (long long)(m0 + lrow)*lda;
    const bf16* pAl = Al_ + (long long)(m0 + lrow)*lda;
    const bf16* pBh = Bh_ + (long long)(n0 + lrow)*ldb;
    const bf16* pBl = Bl_ + (long long)(n0 + lrow)*ldb;
    const uint32_t lswz = (uint32_t)(lrow & 7);

    const int nk = K / 64;

    const int piece = lane >> 3, rr = lane & 7;
    const int rowA  = wm + (piece & 1)*8 + rr;
    const int rowB  = wn + (piece >> 1)*8 + rr;
    const int cA    = piece >> 1;
    const int cB    = piece & 1;

    float acc[4][4][4];
    #pragma unroll
    for (int i = 0; i < 4; i++)
        #pragma unroll
        for (int j = 0; j < 4; j++)
            #pragma unroll
            for (int k = 0; k < 4; k++) acc[i][j][k] = 0.0f;

    #define ISSUE(t) do {                                                     \
        uint32_t s0_ = sb + ((t) % 3) * STAGE_BYTES;                          \
        const int k0_ = (t) * 64;                                             \
        _Pragma("unroll")                                                     \
        for (int j = 0; j < 4; j++) {                                         \
            int ch_ = half*4 + j;                                             \
            uint32_t d_ = (uint32_t)(lrow*128 + (((uint32_t)ch_ ^ lswz) << 4)); \
            cp16(s0_ +         d_, pAh + k0_ + ch_*8);                        \
            cp16(s0_ + 16384 + d_, pAl + k0_ + ch_*8);                        \
            cp16(s0_ + 32768 + d_, pBh + k0_ + ch_*8);                        \
            cp16(s0_ + 49152 + d_, pBl + k0_ + ch_*8);                        \
        }                                                                     \
        CP_COMMIT();                                                          \
    } while (0)

    ISSUE(0);
    if (nk > 1) ISSUE(1);

    for (int t = 0; t < nk; t++) {
        if (t + 1 < nk) { CP_WAIT1(); } else { CP_WAIT0(); }
        __syncthreads();
        if (t + 2 < nk) ISSUE(t + 2);

        const uint32_t Ab = sb + (t % 3) * STAGE_BYTES;
        const uint32_t Bb = Ab + 32768;

        #pragma unroll
        for (int ks = 0; ks < 4; ks++) {
            uint32_t ah[4][4], al[4][4], bh[4][2], bl[4][2];
            const uint32_t aoff = (uint32_t)(rowA*128 + (((ks*2 + cA) ^ (rowA & 7)) << 4));
            const uint32_t boff = (uint32_t)(rowB*128 + (((ks*2 + cB) ^ (rowB & 7)) << 4));
            #pragma unroll
            for (int mt = 0; mt < 4; mt++) {
                ldm4(ah[mt], Ab +          aoff + mt*2048);
                ldm4(al[mt], Ab + 16384 +  aoff + mt*2048);
            }
            #pragma unroll
            for (int ntp = 0; ntp < 2; ntp++) {
                uint32_t rb[4];
                ldm4(rb, Bb +          boff + ntp*2048);
                bh[ntp*2][0]   = rb[0]; bh[ntp*2][1]   = rb[1];
                bh[ntp*2+1][0] = rb[2]; bh[ntp*2+1][1] = rb[3];
                ldm4(rb, Bb + 16384 +  boff + ntp*2048);
                bl[ntp*2][0]   = rb[0]; bl[ntp*2][1]   = rb[1];
                bl[ntp*2+1][0] = rb[2]; bl[ntp*2+1][1] = rb[3];
            }
            #pragma unroll
            for (int mt = 0; mt < 4; mt++)
                #pragma unroll
                for (int nt = 0; nt < 4; nt++) {
                    mma16816(acc[mt][nt], ah[mt], bh[nt]);
                    mma16816(acc[mt][nt], al[mt], bh[nt]);
                    mma16816(acc[mt][nt], ah[mt], bl[nt]);
                }
        }
    }

    #pragma unroll
    for (int mt = 0; mt < 4; mt++) {
        int row = m0 + wm + mt*16 + g;
        #pragma unroll
        for (int nt = 0; nt < 4; nt++) {
            int col = n0 + wn + nt*8 + tg*2;
            float b0 = 0.0f, b1 = 0.0f;
            if (bias) { b0 = bias[col]; b1 = bias[col+1]; }
            float v00 = acc[mt][nt][0]*alpha + b0;
            float v01 = acc[mt][nt][1]*alpha + b1;
            float v10 = acc[mt][nt][2]*alpha + b0;
            float v11 = acc[mt][nt][3]*alpha + b1;
            if (C) {
                *(float2*)(C + (long long)row*ldc + col)     = make_float2(v00, v01);
                *(float2*)(C + (long long)(row+8)*ldc + col) = make_float2(v10, v11);
            }
            if (Ch) {
                bf16 h0, l0, h1, l1;
                split_bf16(v00, h0, l0); split_bf16(v01, h1, l1);
                *(uint32_t*)(Ch + (long long)row*ldc + col) = ((uint32_t)*(uint16_t*)&h1 << 16) | *(uint16_t*)&h0;
                *(uint32_t*)(Cl + (long long)row*ldc + col) = ((uint32_t)*(uint16_t*)&l1 << 16) | *(uint16_t*)&l0;
                split_bf16(v10, h0, l0); split_bf16(v11, h1, l1);
                *(uint32_t*)(Ch + (long long)(row+8)*ldc + col) = ((uint32_t)*(uint16_t*)&h1 << 16) | *(uint16_t*)&h0;
                *(uint32_t*)(Cl + (long long)(row+8)*ldc + col) = ((uint32_t)*(uint16_t*)&l1 << 16) | *(uint16_t*)&l0;
            }
        }
    }
}

// ---------------- elementwise fp32 -> bf16 hi/lo ------------------------------
__global__ void convert_split_k(const float* __restrict__ in,
                                bf16* __restrict__ oh, bf16* __restrict__ ol,
                                long long n)
{
    long long i = (long long)blockIdx.x * 256 + threadIdx.x;
    if (i < n) {
        bf16 h, l; split_bf16(in[i], h, l);
        oh[i] = h; ol[i] = l;
    }
}

// ---------------- fp32 transpose -> bf16 hi/lo --------------------------------
__global__ void transpose_split_k(const float* __restrict__ in,
                                  bf16* __restrict__ oh, bf16* __restrict__ ol,
                                  int M, int N, int ldi, int ldo,
                                  int zdiv,
                                  long long si1, long long si2,
                                  long long so1, long long so2)
{
    __shared__ float tile[32][33];
    int z = blockIdx.z, z1 = z / zdiv, z2 = z % zdiv;
    in += z1*si1 + z2*si2;
    oh += z1*so1 + z2*so2;
    ol += z1*so1 + z2*so2;

    int x = blockIdx.x*32 + threadIdx.x;   // n
    int y = blockIdx.y*32 + threadIdx.y;   // m
    #pragma unroll
    for (int i = 0; i < 32; i += 8)
        if (x < N && (y+i) < M)
            tile[threadIdx.y+i][threadIdx.x] = in[(long long)(y+i)*ldi + x];
    __syncthreads();
    x = blockIdx.y*32 + threadIdx.x;       // m
    y = blockIdx.x*32 + threadIdx.y;       // n
    #pragma unroll
    for (int i = 0; i < 32; i += 8)
        if (x < M && (y+i) < N) {
            bf16 h, l; split_bf16(tile[threadIdx.x][threadIdx.y+i], h, l);
            oh[(long long)(y+i)*ldo + x] = h;
            ol[(long long)(y+i)*ldo + x] = l;
        }
}

// ---------------- pad+split W_uq / W_uk into [8][128][640] --------------------
__global__ void pad_split_uqk(const float* __restrict__ Wuq,
                              const float* __restrict__ Wuk,
                              bf16* __restrict__ uqh, bf16* __restrict__ uql,
                              bf16* __restrict__ ukh, bf16* __restrict__ ukl)
{
    int idx = blockIdx.x * 256 + threadIdx.x;
    if (idx >= 8*128*640) return;
    int e = idx % 640;
    int c = (idx / 640) & 127;
    int h = idx / (640*128);
    float vq = 0.0f, vk = 0.0f;
    if (e < SPLIT) {
        vq = Wuq[c*4992 + h*SPLIT + e];
        vk = Wuk[c*4992 + h*SPLIT + e];
    }
    bf16 hh, ll;
    split_bf16(vq, hh, ll); uqh[idx] = hh; uql[idx] = ll;
    split_bf16(vk, hh, ll); ukh[idx] = hh; ukl[idx] = ll;
}

// ---------------- bqk[h*128+c'] = sum_e b_uq[h*624+e] * W_uk[c', h*624+e] -----
__global__ void bqk_kernel(const float* __restrict__ b_uq,
                           const float* __restrict__ W_uk,
                           float* __restrict__ bqk)
{
    int c = threadIdx.x;   // 0..127
    int h = blockIdx.x;    // 0..7
    float acc = 0.0f;
    const float* wrow = W_uk + c*4992 + h*SPLIT;
    const float* brow = b_uq + h*SPLIT;
    for (int e = 0; e < SPLIT; e++)
        acc += brow[e] * wrow[e];
    bqk[h*128 + c] = acc;
}

// ---------------- b_eff[o] = b_o[o] + sum_d b_uv[d]*W_o[d][o] -----------------
__global__ void beff_kernel(const float* __restrict__ b_uv,
                            const float* __restrict__ W_o,
                            const float* __restrict__ b_o,
                            float* __restrict__ be)
{
    int o = blockIdx.x * 256 + threadIdx.x;
    if (o >= D_MODEL) return;
    float acc = b_o[o];
    for (int d = 0; d < D_MODEL; d++)
        acc += b_uv[d] * W_o[(size_t)d*D_MODEL + o];
    be[o] = acc;
}

// ---------------- assemble augmented Q'/K' (rope) + emit k_rot ----------------
__global__ void assemble_qk(const float* __restrict__ qe,
                            const float* __restrict__ qrot,
                            const float* __restrict__ cat1,
                            bf16* __restrict__ qph, bf16* __restrict__ qpl,
                            bf16* __restrict__ kph, bf16* __restrict__ kpl,
                            float* __restrict__ out_krot)
{
    long long idx = (long long)blockIdx.x * 256 + threadIdx.x;
    if (idx >= (long long)16*SS*KAUG) return;
    int j  = (int)(idx % KAUG);
    int s  = (int)((idx / KAUG) & (SS - 1));
    int bh = (int)(idx / ((long long)KAUG*SS));
    int b  = bh >> 3, h = bh & 7;
    long long row = (long long)b*SS + s;

    float qv = 0.0f, kv = 0.0f;
    if (j < 128) {
        qv = qe[row*1024 + h*128 + j];
        kv = cat1[row*NCAT1 + j];
    } else if (j < 144) {
        int dd = j - 128;
        long long qb = row*128 + h*D_ROPE;
        long long kb = row*NCAT1 + 256 + h*D_ROPE;
        if (dd < 8) {
            const float invf[4] = {1.0f, 0.1f, 0.01f, 0.001f};
            float f = ((float)s / 40.0f) * invf[dd & 3];
            float c_ = cosf(f), sn = sinf(f);
            if (dd < 4) {
                qv = qrot[qb+dd]*c_ - qrot[qb+dd+4]*sn;
                kv = cat1[kb+dd]*c_ - cat1[kb+dd+4]*sn;
            } else {
                qv = qrot[qb+dd]*c_ + qrot[qb+dd-4]*sn;
                kv = cat1[kb+dd]*c_ + cat1[kb+dd-4]*sn;
            }
        } else {
            qv = qrot[qb+dd];
            kv = cat1[kb+dd];
        }
        out_krot[row*128 + h*D_ROPE + dd] = kv;
    }
    bf16 hh, ll;
    split_bf16(qv, hh, ll); qph[idx] = hh; qpl[idx] = ll;
    split_bf16(kv, hh, ll); kph[idx] = hh; kpl[idx] = ll;
}

// ---------------- c_kv output copy ---------------------------------------------
__global__ void copy_ckv(const float* __restrict__ cat1, float* __restrict__ out)
{
    int idx = blockIdx.x * 256 + threadIdx.x;
    if (idx < ROWS * D_KV)
        out[idx] = cat1[(idx >> 7) * NCAT1 + (idx & 127)];
}

// ---------------- row softmax (2048 cols) -> bf16 hi/lo ------------------------
__global__ void softmax2048(const float* __restrict__ s,
                            bf16* __restrict__ oh, bf16* __restrict__ ol)
{
    long long row = blockIdx.x;
    const float* p = s + (row << 11);
    bf16* ph = oh + (row << 11);
    bf16* pl = ol + (row << 11);
    int t = threadIdx.x;

    float v[8];
    float m = -1e30f;
    #pragma unroll
    for (int i = 0; i < 8; i++) {
        v[i] = p[t + (i << 8)];
        m = fmaxf(m, v[i]);
    }
    __shared__ float red[256];
    red[t] = m; __syncthreads();
    for (int off = 128; off > 0; off >>= 1) {
        if (t < off) red[t] = fmaxf(red[t], red[t+off]);
        __syncthreads();
    }
    m = red[0];
    __syncthreads();

    float sum = 0.0f;
    #pragma unroll
    for (int i = 0; i < 8; i++) {
        v[i] = expf(v[i] - m);
        sum += v[i];
    }
    red[t] = sum; __syncthreads();
    for (int off = 128; off > 0; off >>= 1) {
        if (t < off) red[t] += red[t+off];
        __syncthreads();
    }
    float inv = 1.0f / red[0];
    #pragma unroll
    for (int i = 0; i < 8; i++) {
        bf16 hh, ll; split_bf16(v[i] * inv, hh, ll);
        ph[t + (i << 8)] = hh;
        pl[t + (i << 8)] = ll;
    }
}

// ---------------- host side ------------------------------------------------------
static inline void* symv(const void* s)
{
    void* p = nullptr;
    cudaGetSymbolAddress(&p, s);
    return p;
}

static void gemm(int M, int N, int K,
                 const bf16* Ah, const bf16* Al, long long lda,
                 const bf16* Bh, const bf16* Bl, long long ldb,
                 float* C, bf16* Ch, bf16* Cl, long long ldc,
                 const float* bias, float alpha,
                 int nz = 1, int zdiv = 1,
                 long long sA1 = 0, long long sA2 = 0,
                 long long sB1 = 0, long long sB2 = 0,
                 long long sC1 = 0, long long sC2 = 0)
{
    dim3 grid(N / 128, M / 128, nz);
    gemm_mma<<<grid, 256, GEMM_SMEM>>>(M, N, K, Ah, Al, lda, Bh, Bl, ldb,
                                       C, Ch, Cl, ldc, bias, alpha, zdiv,
                                       sA1, sA2, sB1, sB2, sC1, sC2);
}

static void tsplit(const float* in, bf16* oh, bf16* ol, int M, int N, int ldi, int ldo,
                   int nz = 1, int zdiv = 1,
                   long long si1 = 0, long long si2 = 0,
                   long long so1 = 0, long long so2 = 0)
{
    dim3 grid((N + 31)/32, (M + 31)/32, nz);
    transpose_split_k<<<grid, dim3(32, 8)>>>(in, oh, ol, M, N, ldi, ldo,
                                             zdiv, si1, si2, so1, so2);
}

extern "C" void kernel_launch(void* const* d_in, const int* in_sizes, int n_in,
                              void* d_out, int out_size)
{
    const float* h     = (const float*)d_in[0];
    const float* W_dkv = (const float*)d_in[1];
    const float* b_dkv = (const float*)d_in[2];
    const float* W_dq  = (const float*)d_in[3];
    const float* b_dq  = (const float*)d_in[4];
    const float* W_uk  = (const float*)d_in[5];
    const float* b_uk  = (const float*)d_in[6];   // absorbed: softmax-invariant terms dropped
    const float* W_uv  = (const float*)d_in[7];
    const float* b_uv  = (const float*)d_in[8];
    const float* W_uq  = (const float*)d_in[9];
    const float* b_uq  = (const float*)d_in[10];
    const float* W_qr  = (const float*)d_in[11];
    const float* b_qr  = (const float*)d_in[12];
    const float* W_kr  = (const float*)d_in[13];
    const float* b_kr  = (const float*)d_in[14];
    const float* W_o   = (const float*)d_in[15];
    const float* b_o   = (const float*)d_in[16];
    (void)b_uk;

    float* out      = (float*)d_out;
    float* out_ckv  = out + (long long)ROWS * D_MODEL;
    float* out_krot = out_ckv + (long long)ROWS * D_KV;

    float* cat1  = (float*)symv(g_cat1);
    bf16*  cat1h = (bf16*)symv(g_cat1h);
    bf16*  cat1l = (bf16*)symv(g_cat1l);
    bf16*  hh    = (bf16*)symv(g_hh);
    bf16*  hl    = (bf16*)symv(g_hl);
    bf16*  w1h   = (bf16*)symv(g_w1h);
    bf16*  w1l   = (bf16*)symv(g_w1l);
    bf16*  wqrh  = (bf16*)symv(g_wqrh);
    bf16*  wqrl  = (bf16*)symv(g_wqrl);
    bf16*  uqph  = (bf16*)symv(g_uqph);
    bf16*  uqpl  = (bf16*)symv(g_uqpl);
    bf16*  ukph  = (bf16*)symv(g_ukph);
    bf16*  ukpl  = (bf16*)symv(g_ukpl);
    bf16*  wqkh  = (bf16*)symv(g_wqkh);
    bf16*  wqkl  = (bf16*)symv(g_wqkl);
    float* bqk   = (float*)symv(g_bqk);
    float* qrot  = (float*)symv(g_qrot);
    float* qe    = (float*)symv(g_qe);
    bf16*  qph   = (bf16*)symv(g_qph);
    bf16*  qpl   = (bf16*)symv(g_qpl);
    bf16*  kph   = (bf16*)symv(g_kph);
    bf16*  kpl   = (bf16*)symv(g_kpl);
    float* sc    = (float*)symv(g_sc);
    bf16*  ath   = (bf16*)symv(g_ath);
    bf16*  atl   = (bf16*)symv(g_atl);
    bf16*  ckvth = (bf16*)symv(g_ckvth);
    bf16*  ckvtl = (bf16*)symv(g_ckvtl);
    bf16*  lath  = (bf16*)symv(g_lath);
    bf16*  latl  = (bf16*)symv(g_latl);
    bf16*  uvsh  = (bf16*)symv(g_uvsh);
    bf16*  uvsl  = (bf16*)symv(g_uvsl);
    bf16*  woh   = (bf16*)symv(g_woh);
    bf16*  wol   = (bf16*)symv(g_wol);
    bf16*  wcth  = (bf16*)symv(g_wcth);
    bf16*  wctl  = (bf16*)symv(g_wctl);
    float* b1    = (float*)symv(g_b1);
    float* beff  = (float*)symv(g_beff);

    cudaFuncSetAttribute(gemm_mma, cudaFuncAttributeMaxDynamicSharedMemorySize, GEMM_SMEM);

    const float scale = 1.0f / sqrtf((float)D_HEAD);

    // ---- weight/bias preprocessing ----
    cudaMemcpyAsync(b1,      b_dkv, 128*sizeof(float), cudaMemcpyDeviceToDevice, 0);
    cudaMemcpyAsync(b1+128,  b_dq,  128*sizeof(float), cudaMemcpyDeviceToDevice, 0);
    cudaMemcpyAsync(b1+256,  b_kr,  128*sizeof(float), cudaMemcpyDeviceToDevice, 0);

    tsplit(W_dkv, w1h,               w1l,               D_MODEL, D_KV, D_KV, D_MODEL);
    tsplit(W_dq,  w1h + 128*D_MODEL, w1l + 128*D_MODEL, D_MODEL, D_KV, D_KV, D_MODEL);
    tsplit(W_kr,  w1h + 256*D_MODEL, w1l + 256*D_MODEL, D_MODEL, D_KV, D_KV, D_MODEL);
    tsplit(W_qr,  wqrh, wqrl, D_KV, 128, 128, D_KV);
    tsplit(W_o,   woh,  wol,  D_MODEL, D_MODEL, D_MODEL, D_MODEL);

    pad_split_uqk<<<(8*128*640 + 255)/256, 256>>>(W_uq, W_uk, uqph, uqpl, ukph, ukpl);
    convert_split_k<<<(128*D_MODEL + 255)/256, 256>>>(W_uv, uvsh, uvsl, 128*D_MODEL);
    bqk_kernel<<<8, 128>>>(b_uq, W_uk, bqk);
    beff_kernel<<<(D_MODEL + 255)/256, 256>>>(b_uv, W_o, b_o, beff);

    // Wqk^T[h][c'][c] = sum_e W_uk[c',e] W_uq[c,e]  (batched per head)
    gemm(128, 128, 640, ukph, ukpl, 640, uqph, uqpl, 640,
         nullptr, wqkh, wqkl, 128, nullptr, 1.0f,
         8, 8, 0, (long long)128*640, 0, (long long)128*640, 0, (long long)128*128);

    // WcombT[o][h*128+c] = sum_d W_o[h*640+d][o] * W_uv[c][h*640+d]
    gemm(D_MODEL, 128, 640, woh, wol, D_MODEL, uvsh, uvsl, D_MODEL,
         nullptr, wcth, wctl, 1024, nullptr, 1.0f,
         8, 8, 0, 640, 0, 640, 0, 128);

    // ---- activations ----
    {
        long long n = (long long)ROWS * D_MODEL;
        convert_split_k<<<(unsigned)((n + 255)/256), 256>>>(h, hh, hl, n);
    }

    // G1: [ckv | cq | kr_pre] = h @ W1 + b1
    gemm(ROWS, NCAT1, D_MODEL, hh, hl, D_MODEL, w1h, w1l, D_MODEL,
         cat1, cat1h, cat1l, NCAT1, b1, 1.0f);
    copy_ckv<<<(ROWS*D_KV + 255)/256, 256>>>(cat1, out_ckv);

    // q_rot_pre = c_q @ W_qr + b_qr
    gemm(ROWS, 128, 128, cat1h + 128, cat1l + 128, NCAT1, wqrh, wqrl, 128,
         qrot, nullptr, nullptr, 128, b_qr, 1.0f);

    // qe = c_q @ Wqk + bqk   [4096, 1024]
    gemm(ROWS, 1024, 128, cat1h + 128, cat1l + 128, NCAT1, wqkh, wqkl, 128,
         qe, nullptr, nullptr, 1024, bqk, 1.0f);

    // assemble augmented Q'/K' (rope applied), emit k_rot output
    {
        long long total = (long long)16*SS*KAUG;
        assemble_qk<<<(unsigned)((total + 255)/256), 256>>>(
            qe, qrot, cat1, qph, qpl, kph, kpl, out_krot);
    }

    // scores = scale * Q' @ K'^T  (batched over 16 bh)
    gemm(SS, SS, KAUG, qph, qpl, KAUG, kph, kpl, KAUG,
         sc, nullptr, nullptr, SS, nullptr, scale,
         16, 16,
         0, (long long)SS*KAUG,
         0, (long long)SS*KAUG,
         0, (long long)SS*SS);

    // softmax -> attn hi/lo
    softmax2048<<<BB*N_HEADS*SS, 256>>>(sc, ath, atl);

    // c_kv^T per batch: [b][128][2048]
    tsplit(cat1, ckvth, ckvtl, SS, 128, NCAT1, SS,
           BB, 1, (long long)SS*NCAT1, 0, (long long)128*SS, 0);

    // lat[b,s,h*128+c] = sum_t attn[b,h,s,t] * c_kv[b,t,c]
    gemm(SS, 128, SS, ath, atl, SS, ckvth, ckvtl, SS,
         nullptr, lath, latl, 1024, nullptr, 1.0f,
         16, 8,
         (long long)N_HEADS*SS*SS, (long long)SS*SS,
         (long long)128*SS, 0,
         (long long)SS*1024, 128);

    // out = lat @ Wcomb + (b_uv@W_o + b_o)
    gemm(ROWS, D_MODEL, 1024, lath, latl, 1024, wcth, wctl, 1024,
         out, nullptr, nullptr, D_MODEL, beff, 1.0f);
}

// round 7
// speedup vs baseline: 6.6203x; 1.0932x over previous
#include <cuda_runtime.h>
#include <cuda_bf16.h>
#include <math.h>
#include <stdint.h>

#define D_MODEL 5120
#define N_HEADS 8
#define D_KV    128
#define D_ROPE  16
#define D_HEAD  640
#define SPLIT   624
#define BB      2
#define SS      2048
#define ROWS    (BB*SS)          // 4096
#define NCAT1   384              // dkv(128) + dq(128) + kr(128)
#define KAUG    192              // 128 latent + 16 rope + 48 zero pad
#define NQE     1152             // 1024 (Wqk) + 128 (Wqr)

typedef __nv_bfloat16 bf16;

// ---------------- scratch (device globals) ----------------------------------
__device__ __align__(16) float g_cat1 [ROWS*NCAT1];
__device__ __align__(16) bf16  g_cat1h[ROWS*NCAT1];
__device__ __align__(16) bf16  g_cat1l[ROWS*NCAT1];
__device__ __align__(16) bf16  g_hh  [(size_t)ROWS*D_MODEL];
__device__ __align__(16) bf16  g_hl  [(size_t)ROWS*D_MODEL];
__device__ __align__(16) bf16  g_w1h [NCAT1*D_MODEL];
__device__ __align__(16) bf16  g_w1l [NCAT1*D_MODEL];
__device__ __align__(16) bf16  g_uqph[8*128*640];
__device__ __align__(16) bf16  g_uqpl[8*128*640];
__device__ __align__(16) bf16  g_ukph[8*128*640];
__device__ __align__(16) bf16  g_ukpl[8*128*640];
__device__ __align__(16) bf16  g_wqkrh[NQE*128];
__device__ __align__(16) bf16  g_wqkrl[NQE*128];
__device__ __align__(16) float g_bqkr[NQE];
__device__ __align__(16) float g_qe  [(size_t)ROWS*NQE];
__device__ __align__(16) bf16  g_qph [(size_t)16*SS*KAUG];
__device__ __align__(16) bf16  g_qpl [(size_t)16*SS*KAUG];
__device__ __align__(16) bf16  g_kph [(size_t)16*SS*KAUG];
__device__ __align__(16) bf16  g_kpl [(size_t)16*SS*KAUG];
__device__ __align__(16) bf16  g_ckvth[BB*128*SS];
__device__ __align__(16) bf16  g_ckvtl[BB*128*SS];
__device__ __align__(16) bf16  g_lath[(size_t)ROWS*1024];
__device__ __align__(16) bf16  g_latl[(size_t)ROWS*1024];
__device__ __align__(16) bf16  g_uvsh[128*D_MODEL];
__device__ __align__(16) bf16  g_uvsl[128*D_MODEL];
__device__ __align__(16) bf16  g_woh [(size_t)D_MODEL*D_MODEL];
__device__ __align__(16) bf16  g_wol [(size_t)D_MODEL*D_MODEL];
__device__ __align__(16) bf16  g_wcth[(size_t)D_MODEL*1024];
__device__ __align__(16) bf16  g_wctl[(size_t)D_MODEL*1024];
__device__ __align__(16) float g_b1  [NCAT1];
__device__ __align__(16) float g_beff[D_MODEL];

// ---------------- PTX helpers ------------------------------------------------
__device__ __forceinline__ uint32_t smem_u32(const void* p) {
    uint32_t a;
    asm("{ .reg .u64 t; cvta.to.shared.u64 t, %1; cvt.u32.u64 %0, t; }"
        : "=r"(a) : "l"(p));
    return a;
}

__device__ __forceinline__ void cp16(uint32_t dst, const void* src) {
    asm volatile("cp.async.cg.shared.global [%0], [%1], 16;\n"
                 :: "r"(dst), "l"(__cvta_generic_to_global(src)));
}
#define CP_COMMIT() asm volatile("cp.async.commit_group;\n" ::: "memory")
#define CP_WAIT1()  asm volatile("cp.async.wait_group 1;\n" ::: "memory")
#define CP_WAIT0()  asm volatile("cp.async.wait_group 0;\n" ::: "memory")

__device__ __forceinline__ void ldm4(uint32_t* r, uint32_t a) {
    asm volatile("ldmatrix.sync.aligned.m8n8.x4.shared.b16 {%0,%1,%2,%3}, [%4];"
                 : "=r"(r[0]), "=r"(r[1]), "=r"(r[2]), "=r"(r[3]) : "r"(a));
}

__device__ __forceinline__ void mma16816(float* c, const uint32_t* a, const uint32_t* b) {
    asm volatile(
        "mma.sync.aligned.m16n8k16.row.col.f32.bf16.bf16.f32 "
        "{%0,%1,%2,%3},{%4,%5,%6,%7},{%8,%9},{%0,%1,%2,%3};\n"
        : "+f"(c[0]), "+f"(c[1]), "+f"(c[2]), "+f"(c[3])
        : "r"(a[0]), "r"(a[1]), "r"(a[2]), "r"(a[3]), "r"(b[0]), "r"(b[1]));
}

__device__ __forceinline__ uint32_t pack2(float a, float b) {
    __nv_bfloat162 t = __floats2bfloat162_rn(a, b);
    return *reinterpret_cast<const uint32_t*>(&t);
}

__device__ __forceinline__ void split_bf16(float v, bf16& h, bf16& l) {
    h = __float2bfloat16(v);
    l = __float2bfloat16(v - __bfloat162float(h));
}

__device__ __forceinline__ void split_pack(float a, float b, uint32_t& ph, uint32_t& pl) {
    bf16 ha = __float2bfloat16(a), hb = __float2bfloat16(b);
    ph = ((uint32_t)*(uint16_t*)&hb << 16) | (uint32_t)*(uint16_t*)&ha;
    pl = pack2(a - __bfloat162float(ha), b - __bfloat162float(hb));
}

// ---------------- bf16x3 mma.sync GEMM ---------------------------------------
#define STAGE_BYTES 65536
#define GEMM_SMEM   (3*STAGE_BYTES)

__global__ void __launch_bounds__(256, 1)
gemm_mma(int M, int N, int K,
         const bf16* __restrict__ Ah_, const bf16* __restrict__ Al_, long long lda,
         const bf16* __restrict__ Bh_, const bf16* __restrict__ Bl_, long long ldb,
         float* __restrict__ C, bf16* __restrict__ Ch, bf16* __restrict__ Cl,
         long long ldc,
         const float* __restrict__ bias, float alpha,
         int zdiv,
         long long sA1, long long sA2,
         long long sB1, long long sB2,
         long long sC1, long long sC2)
{
    extern __shared__ __align__(1024) char smem[];
    const uint32_t sb = smem_u32(smem);

    {
        int z  = blockIdx.z;
        int z1 = z / zdiv, z2 = z % zdiv;
        Ah_ += z1*sA1 + z2*sA2;  Al_ += z1*sA1 + z2*sA2;
        Bh_ += z1*sB1 + z2*sB2;  Bl_ += z1*sB1 + z2*sB2;
        long long co = z1*sC1 + z2*sC2;
        if (C)  C  += co;
        if (Ch) { Ch += co; Cl += co; }
    }

    const int tid  = threadIdx.x;
    const int wid  = tid >> 5;
    const int lane = tid & 31;
    const int wm   = (wid >> 2) * 64;
    const int wn   = (wid & 3) * 32;
    const int g    = lane >> 2, tg = lane & 3;
    const int m0   = blockIdx.y * 128;
    const int n0   = blockIdx.x * 128;

    const int lrow = tid >> 1;
    const int half = tid & 1;
    const bf16* pAh = Ah_ + (long long)(m0 + lrow)*lda;
    const bf16* pAl = Al_ + (long long)(m0 + lrow)*lda;
    const bf16* pBh = Bh_ + (long long)(n0 + lrow)*ldb;
    const bf16* pBl = Bl_ + (long long)(n0 + lrow)*ldb;
    const uint32_t lswz = (uint32_t)(lrow & 7);

    const int nk = K / 64;

    const int piece = lane >> 3, rr = lane & 7;
    const int rowA  = wm + (piece & 1)*8 + rr;
    const int rowB  = wn + (piece >> 1)*8 + rr;
    const int cA    = piece >> 1;
    const int cB    = piece & 1;

    float acc[4][4][4];
    #pragma unroll
    for (int i = 0; i < 4; i++)
        #pragma unroll
        for (int j = 0; j < 4; j++)
            #pragma unroll
            for (int k = 0; k < 4; k++) acc[i][j][k] = 0.0f;

    #define ISSUE(t) do {                                                     \
        uint32_t s0_ = sb + ((t) % 3) * STAGE_BYTES;                          \
        const int k0_ = (t) * 64;                                             \
        _Pragma("unroll")                                                     \
        for (int j = 0; j < 4; j++) {                                         \
            int ch_ = half*4 + j;                                             \
            uint32_t d_ = (uint32_t)(lrow*128 + (((uint32_t)ch_ ^ lswz) << 4)); \
            cp16(s0_ +         d_, pAh + k0_ + ch_*8);                        \
            cp16(s0_ + 16384 + d_, pAl + k0_ + ch_*8);                        \
            cp16(s0_ + 32768 + d_, pBh + k0_ + ch_*8);                        \
            cp16(s0_ + 49152 + d_, pBl + k0_ + ch_*8);                        \
        }                                                                     \
        CP_COMMIT();                                                          \
    } while (0)

    ISSUE(0);
    if (nk > 1) ISSUE(1);

    for (int t = 0; t < nk; t++) {
        if (t + 1 < nk) { CP_WAIT1(); } else { CP_WAIT0(); }
        __syncthreads();
        if (t + 2 < nk) ISSUE(t + 2);

        const uint32_t Ab = sb + (t % 3) * STAGE_BYTES;
        const uint32_t Bb = Ab + 32768;

        #pragma unroll
        for (int ks = 0; ks < 4; ks++) {
            uint32_t ah[4][4], al[4][4], bh[4][2], bl[4][2];
            const uint32_t aoff = (uint32_t)(rowA*128 + (((ks*2 + cA) ^ (rowA & 7)) << 4));
            const uint32_t boff = (uint32_t)(rowB*128 + (((ks*2 + cB) ^ (rowB & 7)) << 4));
            #pragma unroll
            for (int mt = 0; mt < 4; mt++) {
                ldm4(ah[mt], Ab +          aoff + mt*2048);
                ldm4(al[mt], Ab + 16384 +  aoff + mt*2048);
            }
            #pragma unroll
            for (int ntp = 0; ntp < 2; ntp++) {
                uint32_t rb[4];
                ldm4(rb, Bb +          boff + ntp*2048);
                bh[ntp*2][0]   = rb[0]; bh[ntp*2][1]   = rb[1];
                bh[ntp*2+1][0] = rb[2]; bh[ntp*2+1][1] = rb[3];
                ldm4(rb, Bb + 16384 +  boff + ntp*2048);
                bl[ntp*2][0]   = rb[0]; bl[ntp*2][1]   = rb[1];
                bl[ntp*2+1][0] = rb[2]; bl[ntp*2+1][1] = rb[3];
            }
            #pragma unroll
            for (int mt = 0; mt < 4; mt++)
                #pragma unroll
                for (int nt = 0; nt < 4; nt++) {
                    mma16816(acc[mt][nt], ah[mt], bh[nt]);
                    mma16816(acc[mt][nt], al[mt], bh[nt]);
                    mma16816(acc[mt][nt], ah[mt], bl[nt]);
                }
        }
    }

    #pragma unroll
    for (int mt = 0; mt < 4; mt++) {
        int row = m0 + wm + mt*16 + g;
        #pragma unroll
        for (int nt = 0; nt < 4; nt++) {
            int col = n0 + wn + nt*8 + tg*2;
            float b0 = 0.0f, b1 = 0.0f;
            if (bias) { b0 = bias[col]; b1 = bias[col+1]; }
            float v00 = acc[mt][nt][0]*alpha + b0;
            float v01 = acc[mt][nt][1]*alpha + b1;
            float v10 = acc[mt][nt][2]*alpha + b0;
            float v11 = acc[mt][nt][3]*alpha + b1;
            if (C) {
                *(float2*)(C + (long long)row*ldc + col)     = make_float2(v00, v01);
                *(float2*)(C + (long long)(row+8)*ldc + col) = make_float2(v10, v11);
            }
            if (Ch) {
                uint32_t ph, pl;
                split_pack(v00, v01, ph, pl);
                *(uint32_t*)(Ch + (long long)row*ldc + col) = ph;
                *(uint32_t*)(Cl + (long long)row*ldc + col) = pl;
                split_pack(v10, v11, ph, pl);
                *(uint32_t*)(Ch + (long long)(row+8)*ldc + col) = ph;
                *(uint32_t*)(Cl + (long long)(row+8)*ldc + col) = pl;
            }
        }
    }
}

// ---------------- fused flash attention ---------------------------------------
// grid (SS/64, 16). Per CTA: 64 q-rows of head bh. Computes lat = softmax(QK^T*scale)@V.
// Q'[64x192], K' chunks [64x192], V chunks [128 lat x 64 keys] all bf16 hi/lo.
#define FA_NC    32
#define FA_STG   81920                       // K 49152 + V 32768
#define FA_Q     0
#define FA_S0    49152
#define FA_P     212992
#define FA_REDM  229376
#define FA_REDS  230400
#define FA_SMEM  231424

__global__ void __launch_bounds__(256, 1)
flash_attn(const bf16* __restrict__ qph, const bf16* __restrict__ qpl,
           const bf16* __restrict__ kph, const bf16* __restrict__ kpl,
           const bf16* __restrict__ vth, const bf16* __restrict__ vtl,
           bf16* __restrict__ lath, bf16* __restrict__ latl,
           float scale)
{
    extern __shared__ __align__(1024) char smem[];
    const uint32_t sb = smem_u32(smem);

    const int tid  = threadIdx.x;
    const int wid  = tid >> 5;
    const int lane = tid & 31;
    const int wm2  = wid >> 2;       // 0/1 : 32-row half
    const int wn4  = wid & 3;        // 0..3
    const int g    = lane >> 2, tg = lane & 3;
    const int piece = lane >> 3, rr = lane & 7;

    const int bh = blockIdx.y;
    const int b  = bh >> 3;
    const int qb = blockIdx.x;

    const bf16* qbh = qph + ((size_t)bh*SS + (size_t)qb*64)*KAUG;
    const bf16* qbl = qpl + ((size_t)bh*SS + (size_t)qb*64)*KAUG;
    const bf16* kbh = kph + (size_t)bh*SS*KAUG;
    const bf16* kbl = kpl + (size_t)bh*SS*KAUG;
    const bf16* vbh = vth + (size_t)b*128*SS;
    const bf16* vbl = vtl + (size_t)b*128*SS;

    // ---- load Q (once) ----
    #pragma unroll
    for (int i = 0; i < 6; i++) {
        int idx = i*256 + tid;               // 0..1535
        int row = idx / 24, cc = idx % 24;
        int kt = cc >> 3, c8 = cc & 7;
        uint32_t d = (uint32_t)(kt*8192 + row*128 + (((uint32_t)c8 ^ (row & 7)) << 4));
        cp16(sb + FA_Q +         d, qbh + row*KAUG + cc*8);
        cp16(sb + FA_Q + 24576 + d, qbl + row*KAUG + cc*8);
    }
    CP_COMMIT();

    #define FA_ISSUE(t) do {                                                   \
        uint32_t st_ = sb + FA_S0 + ((t) & 1) * FA_STG;                        \
        const int t0_ = (t) * 64;                                              \
        _Pragma("unroll")                                                      \
        for (int i = 0; i < 6; i++) {                                          \
            int idx = i*256 + tid;                                             \
            int row = idx / 24, cc = idx % 24;                                 \
            int kt = cc >> 3, c8 = cc & 7;                                     \
            uint32_t d = (uint32_t)(kt*8192 + row*128 + (((uint32_t)c8 ^ (row & 7)) << 4)); \
            cp16(st_ +         d, kbh + (size_t)(t0_+row)*KAUG + cc*8);        \
            cp16(st_ + 24576 + d, kbl + (size_t)(t0_+row)*KAUG + cc*8);        \
        }                                                                      \
        _Pragma("unroll")                                                      \
        for (int i = 0; i < 4; i++) {                                          \
            int idx = i*256 + tid;                                             \
            int row = idx >> 3, c8 = idx & 7;                                  \
            uint32_t d = (uint32_t)(row*128 + (((uint32_t)c8 ^ (row & 7)) << 4)); \
            cp16(st_ + 49152 + d, vbh + (size_t)row*SS + t0_ + c8*8);          \
            cp16(st_ + 65536 + d, vbl + (size_t)row*SS + t0_ + c8*8);          \
        }                                                                      \
        CP_COMMIT();                                                           \
    } while (0)

    FA_ISSUE(0);

    float accv[2][4][4];
    #pragma unroll
    for (int i = 0; i < 2; i++)
        #pragma unroll
        for (int j = 0; j < 4; j++)
            #pragma unroll
            for (int k = 0; k < 4; k++) accv[i][j][k] = 0.0f;
    float Mrow[4] = {-1e30f, -1e30f, -1e30f, -1e30f};
    float Lrow[4] = {0.0f, 0.0f, 0.0f, 0.0f};

    float* redm = (float*)(smem + FA_REDM);
    float* reds = (float*)(smem + FA_REDS);

    for (int t = 0; t < FA_NC; t++) {
        CP_WAIT0();
        __syncthreads();
        if (t + 1 < FA_NC) FA_ISSUE(t + 1);

        const uint32_t KB = sb + FA_S0 + (t & 1) * FA_STG;
        const uint32_t VB = KB + 49152;

        // ---- S = Q K'^T ----
        float sacc[2][2][4];
        #pragma unroll
        for (int i = 0; i < 2; i++)
            #pragma unroll
            for (int j = 0; j < 2; j++)
                #pragma unroll
                for (int k = 0; k < 4; k++) sacc[i][j][k] = 0.0f;

        #pragma unroll
        for (int ks = 0; ks < 12; ks++) {
            const int kt = ks >> 2, ks2 = ks & 3;
            uint32_t ah[2][4], al[2][4];
            #pragma unroll
            for (int mt = 0; mt < 2; mt++) {
                int rowA = wm2*32 + mt*16 + (piece & 1)*8 + rr;
                uint32_t off = (uint32_t)(kt*8192 + rowA*128 +
                    (((ks2*2 + (piece >> 1)) ^ (rowA & 7)) << 4));
                ldm4(ah[mt], sb + FA_Q +         off);
                ldm4(al[mt], sb + FA_Q + 24576 + off);
            }
            int rowB = wn4*16 + (piece >> 1)*8 + rr;
            uint32_t offB = (uint32_t)(kt*8192 + rowB*128 +
                (((ks2*2 + (piece & 1)) ^ (rowB & 7)) << 4));
            uint32_t rbh[4], rbl[4];
            ldm4(rbh, KB +         offB);
            ldm4(rbl, KB + 24576 + offB);
            #pragma unroll
            for (int mt = 0; mt < 2; mt++)
                #pragma unroll
                for (int nt = 0; nt < 2; nt++) {
                    mma16816(sacc[mt][nt], ah[mt], rbh + nt*2);
                    mma16816(sacc[mt][nt], al[mt], rbh + nt*2);
                    mma16816(sacc[mt][nt], ah[mt], rbl + nt*2);
                }
        }

        // ---- online softmax ----
        float mloc[4] = {-1e30f, -1e30f, -1e30f, -1e30f};
        #pragma unroll
        for (int mt = 0; mt < 2; mt++)
            #pragma unroll
            for (int nt = 0; nt < 2; nt++)
                #pragma unroll
                for (int c = 0; c < 4; c++) {
                    sacc[mt][nt][c] *= scale;
                    int slot = mt*2 + (c >> 1);
                    mloc[slot] = fmaxf(mloc[slot], sacc[mt][nt][c]);
                }
        #pragma unroll
        for (int s = 0; s < 4; s++) {
            mloc[s] = fmaxf(mloc[s], __shfl_xor_sync(0xffffffffu, mloc[s], 1));
            mloc[s] = fmaxf(mloc[s], __shfl_xor_sync(0xffffffffu, mloc[s], 2));
        }
        if (tg == 0) {
            #pragma unroll
            for (int mt = 0; mt < 2; mt++)
                #pragma unroll
                for (int h2 = 0; h2 < 2; h2++) {
                    int r = wm2*32 + mt*16 + h2*8 + g;
                    redm[wn4*64 + r] = mloc[mt*2 + h2];
                }
        }
        __syncthreads();

        float fsc[4];
        #pragma unroll
        for (int mt = 0; mt < 2; mt++)
            #pragma unroll
            for (int h2 = 0; h2 < 2; h2++) {
                int r = wm2*32 + mt*16 + h2*8 + g;
                float cm = fmaxf(fmaxf(redm[r], redm[64 + r]),
                                 fmaxf(redm[128 + r], redm[192 + r]));
                int slot = mt*2 + h2;
                float mn = fmaxf(Mrow[slot], cm);
                fsc[slot] = __expf(Mrow[slot] - mn);
                Mrow[slot] = mn;
            }

        float sl[4] = {0.0f, 0.0f, 0.0f, 0.0f};
        #pragma unroll
        for (int mt = 0; mt < 2; mt++)
            #pragma unroll
            for (int nt = 0; nt < 2; nt++)
                #pragma unroll
                for (int c = 0; c < 4; c++) {
                    int slot = mt*2 + (c >> 1);
                    float p = __expf(sacc[mt][nt][c] - Mrow[slot]);
                    sacc[mt][nt][c] = p;
                    sl[slot] += p;
                }
        // rescale running output
        #pragma unroll
        for (int mt = 0; mt < 2; mt++)
            #pragma unroll
            for (int nt = 0; nt < 4; nt++)
                #pragma unroll
                for (int c = 0; c < 4; c++)
                    accv[mt][nt][c] *= fsc[mt*2 + (c >> 1)];
        #pragma unroll
        for (int s = 0; s < 4; s++) {
            sl[s] += __shfl_xor_sync(0xffffffffu, sl[s], 1);
            sl[s] += __shfl_xor_sync(0xffffffffu, sl[s], 2);
        }
        if (tg == 0) {
            #pragma unroll
            for (int mt = 0; mt < 2; mt++)
                #pragma unroll
                for (int h2 = 0; h2 < 2; h2++) {
                    int r = wm2*32 + mt*16 + h2*8 + g;
                    reds[wn4*64 + r] = sl[mt*2 + h2];
                }
        }
        // write P hi/lo to smem
        #pragma unroll
        for (int mt = 0; mt < 2; mt++)
            #pragma unroll
            for (int nt = 0; nt < 2; nt++)
                #pragma unroll
                for (int h2 = 0; h2 < 2; h2++) {
                    int r = wm2*32 + mt*16 + h2*8 + g;
                    int cidx = wn4*2 + nt;
                    uint32_t addr = (uint32_t)(r*128 + ((cidx ^ (r & 7)) << 4) + tg*4);
                    uint32_t ph, pl;
                    split_pack(sacc[mt][nt][2*h2], sacc[mt][nt][2*h2+1], ph, pl);
                    *(uint32_t*)(smem + FA_P +        addr) = ph;
                    *(uint32_t*)(smem + FA_P + 8192 + addr) = pl;
                }
        __syncthreads();

        #pragma unroll
        for (int mt = 0; mt < 2; mt++)
            #pragma unroll
            for (int h2 = 0; h2 < 2; h2++) {
                int r = wm2*32 + mt*16 + h2*8 + g;
                float ssum = reds[r] + reds[64 + r] + reds[128 + r] + reds[192 + r];
                int slot = mt*2 + h2;
                Lrow[slot] = Lrow[slot] * fsc[slot] + ssum;
            }

        // ---- PV: accv += P @ V^T ----
        #pragma unroll
        for (int ksv = 0; ksv < 4; ksv++) {
            uint32_t pah[2][4], pal[2][4];
            #pragma unroll
            for (int mt = 0; mt < 2; mt++) {
                int rowA = wm2*32 + mt*16 + (piece & 1)*8 + rr;
                uint32_t off = (uint32_t)(rowA*128 +
                    (((ksv*2 + (piece >> 1)) ^ (rowA & 7)) << 4));
                ldm4(pah[mt], sb + FA_P +        off);
                ldm4(pal[mt], sb + FA_P + 8192 + off);
            }
            uint32_t vh[2][4], vl[2][4];
            #pragma unroll
            for (int ntp = 0; ntp < 2; ntp++) {
                int rowB = wn4*32 + ntp*16 + (piece >> 1)*8 + rr;
                uint32_t offB = (uint32_t)(rowB*128 +
                    (((ksv*2 + (piece & 1)) ^ (rowB & 7)) << 4));
                ldm4(vh[ntp], VB +         offB);
                ldm4(vl[ntp], VB + 16384 + offB);
            }
            #pragma unroll
            for (int mt = 0; mt < 2; mt++)
                #pragma unroll
                for (int nt = 0; nt < 4; nt++) {
                    const uint32_t* bhp = vh[nt >> 1] + (nt & 1)*2;
                    const uint32_t* blp = vl[nt >> 1] + (nt & 1)*2;
                    mma16816(accv[mt][nt], pah[mt], bhp);
                    mma16816(accv[mt][nt], pal[mt], bhp);
                    mma16816(accv[mt][nt], pah[mt], blp);
                }
        }
    }

    // ---- finalize: out = accv / L ----
    float inv[4];
    #pragma unroll
    for (int s = 0; s < 4; s++) inv[s] = 1.0f / Lrow[s];

    const int h = bh & 7;
    #pragma unroll
    for (int mt = 0; mt < 2; mt++) {
        #pragma unroll
        for (int nt = 0; nt < 4; nt++) {
            int col = h*128 + wn4*32 + nt*8 + tg*2;
            #pragma unroll
            for (int h2 = 0; h2 < 2; h2++) {
                long long row = (long long)b*SS + qb*64 + wm2*32 + mt*16 + h2*8 + g;
                float v0 = accv[mt][nt][2*h2]   * inv[mt*2 + h2];
                float v1 = accv[mt][nt][2*h2+1] * inv[mt*2 + h2];
                uint32_t ph, pl;
                split_pack(v0, v1, ph, pl);
                *(uint32_t*)(lath + row*1024 + col) = ph;
                *(uint32_t*)(latl + row*1024 + col) = pl;
            }
        }
    }
}

// ---------------- elementwise fp32 -> bf16 hi/lo ------------------------------
__global__ void convert_split_k(const float* __restrict__ in,
                                bf16* __restrict__ oh, bf16* __restrict__ ol,
                                long long n)
{
    long long i = (long long)blockIdx.x * 256 + threadIdx.x;
    if (i < n) {
        bf16 h, l; split_bf16(in[i], h, l);
        oh[i] = h; ol[i] = l;
    }
}

// ---------------- fp32 transpose -> bf16 hi/lo --------------------------------
__global__ void transpose_split_k(const float* __restrict__ in,
                                  bf16* __restrict__ oh, bf16* __restrict__ ol,
                                  int M, int N, int ldi, int ldo,
                                  int zdiv,
                                  long long si1, long long si2,
                                  long long so1, long long so2)
{
    __shared__ float tile[32][33];
    int z = blockIdx.z, z1 = z / zdiv, z2 = z % zdiv;
    in += z1*si1 + z2*si2;
    oh += z1*so1 + z2*so2;
    ol += z1*so1 + z2*so2;

    int x = blockIdx.x*32 + threadIdx.x;   // n
    int y = blockIdx.y*32 + threadIdx.y;   // m
    #pragma unroll
    for (int i = 0; i < 32; i += 8)
        if (x < N && (y+i) < M)
            tile[threadIdx.y+i][threadIdx.x] = in[(long long)(y+i)*ldi + x];
    __syncthreads();
    x = blockIdx.y*32 + threadIdx.x;       // m
    y = blockIdx.x*32 + threadIdx.y;       // n
    #pragma unroll
    for (int i = 0; i < 32; i += 8)
        if (x < M && (y+i) < N) {
            bf16 h, l; split_bf16(tile[threadIdx.x][threadIdx.y+i], h, l);
            oh[(long long)(y+i)*ldo + x] = h;
            ol[(long long)(y+i)*ldo + x] = l;
        }
}

// ---------------- pad+split W_uq / W_uk into [8][128][640] --------------------
__global__ void pad_split_uqk(const float* __restrict__ Wuq,
                              const float* __restrict__ Wuk,
                              bf16* __restrict__ uqh, bf16* __restrict__ uql,
                              bf16* __restrict__ ukh, bf16* __restrict__ ukl)
{
    int idx = blockIdx.x * 256 + threadIdx.x;
    if (idx >= 8*128*640) return;
    int e = idx % 640;
    int c = (idx / 640) & 127;
    int h = idx / (640*128);
    float vq = 0.0f, vk = 0.0f;
    if (e < SPLIT) {
        vq = Wuq[c*4992 + h*SPLIT + e];
        vk = Wuk[c*4992 + h*SPLIT + e];
    }
    bf16 hh, ll;
    split_bf16(vq, hh, ll); uqh[idx] = hh; uql[idx] = ll;
    split_bf16(vk, hh, ll); ukh[idx] = hh; ukl[idx] = ll;
}

// ---------------- bqk[h*128+c'] = sum_e b_uq[h*624+e] * W_uk[c', h*624+e] -----
__global__ void bqk_kernel(const float* __restrict__ b_uq,
                           const float* __restrict__ W_uk,
                           float* __restrict__ bqk)
{
    int c = threadIdx.x;   // 0..127
    int h = blockIdx.x;    // 0..7
    float acc = 0.0f;
    const float* wrow = W_uk + c*4992 + h*SPLIT;
    const float* brow = b_uq + h*SPLIT;
    for (int e = 0; e < SPLIT; e++)
        acc += brow[e] * wrow[e];
    bqk[h*128 + c] = acc;
}

// ---------------- b_eff[o] = b_o[o] + sum_d b_uv[d]*W_o[d][o] -----------------
__global__ void beff_kernel(const float* __restrict__ b_uv,
                            const float* __restrict__ W_o,
                            const float* __restrict__ b_o,
                            float* __restrict__ be)
{
    int o = blockIdx.x * 256 + threadIdx.x;
    if (o >= D_MODEL) return;
    float acc = b_o[o];
    for (int d = 0; d < D_MODEL; d++)
        acc += b_uv[d] * W_o[(size_t)d*D_MODEL + o];
    be[o] = acc;
}

// ---------------- assemble augmented Q'/K' (rope) + emit k_rot ----------------
__global__ void assemble_qk(const float* __restrict__ qe,    // [ROWS][1152]
                            const float* __restrict__ cat1,
                            bf16* __restrict__ qph, bf16* __restrict__ qpl,
                            bf16* __restrict__ kph, bf16* __restrict__ kpl,
                            float* __restrict__ out_krot)
{
    long long idx = (long long)blockIdx.x * 256 + threadIdx.x;
    if (idx >= (long long)16*SS*KAUG) return;
    int j  = (int)(idx % KAUG);
    int s  = (int)((idx / KAUG) & (SS - 1));
    int bh = (int)(idx / ((long long)KAUG*SS));
    int b  = bh >> 3, h = bh & 7;
    long long row = (long long)b*SS + s;

    float qv = 0.0f, kv = 0.0f;
    if (j < 128) {
        qv = qe[row*NQE + h*128 + j];
        kv = cat1[row*NCAT1 + j];
    } else if (j < 144) {
        int dd = j - 128;
        long long qb = row*NQE + 1024 + h*D_ROPE;
        long long kb = row*NCAT1 + 256 + h*D_ROPE;
        if (dd < 8) {
            const float invf[4] = {1.0f, 0.1f, 0.01f, 0.001f};
            float f = ((float)s / 40.0f) * invf[dd & 3];
            float c_ = cosf(f), sn = sinf(f);
            if (dd < 4) {
                qv = qe[qb+dd]*c_ - qe[qb+dd+4]*sn;
                kv = cat1[kb+dd]*c_ - cat1[kb+dd+4]*sn;
            } else {
                qv = qe[qb+dd]*c_ + qe[qb+dd-4]*sn;
                kv = cat1[kb+dd]*c_ + cat1[kb+dd-4]*sn;
            }
        } else {
            qv = qe[qb+dd];
            kv = cat1[kb+dd];
        }
        out_krot[row*128 + h*D_ROPE + dd] = kv;
    }
    bf16 hh, ll;
    split_bf16(qv, hh, ll); qph[idx] = hh; qpl[idx] = ll;
    split_bf16(kv, hh, ll); kph[idx] = hh; kpl[idx] = ll;
}

// ---------------- c_kv output copy ---------------------------------------------
__global__ void copy_ckv(const float* __restrict__ cat1, float* __restrict__ out)
{
    int idx = blockIdx.x * 256 + threadIdx.x;
    if (idx < ROWS * D_KV)
        out[idx] = cat1[(idx >> 7) * NCAT1 + (idx & 127)];
}

// ---------------- host side ------------------------------------------------------
static inline void* symv(const void* s)
{
    void* p = nullptr;
    cudaGetSymbolAddress(&p, s);
    return p;
}

static void gemm(int M, int N, int K,
                 const bf16* Ah, const bf16* Al, long long lda,
                 const bf16* Bh, const bf16* Bl, long long ldb,
                 float* C, bf16* Ch, bf16* Cl, long long ldc,
                 const float* bias, float alpha,
                 int nz = 1, int zdiv = 1,
                 long long sA1 = 0, long long sA2 = 0,
                 long long sB1 = 0, long long sB2 = 0,
                 long long sC1 = 0, long long sC2 = 0)
{
    dim3 grid(N / 128, M / 128, nz);
    gemm_mma<<<grid, 256, GEMM_SMEM>>>(M, N, K, Ah, Al, lda, Bh, Bl, ldb,
                                       C, Ch, Cl, ldc, bias, alpha, zdiv,
                                       sA1, sA2, sB1, sB2, sC1, sC2);
}

static void tsplit(const float* in, bf16* oh, bf16* ol, int M, int N, int ldi, int ldo,
                   int nz = 1, int zdiv = 1,
                   long long si1 = 0, long long si2 = 0,
                   long long so1 = 0, long long so2 = 0)
{
    dim3 grid((N + 31)/32, (M + 31)/32, nz);
    transpose_split_k<<<grid, dim3(32, 8)>>>(in, oh, ol, M, N, ldi, ldo,
                                             zdiv, si1, si2, so1, so2);
}

extern "C" void kernel_launch(void* const* d_in, const int* in_sizes, int n_in,
                              void* d_out, int out_size)
{
    const float* h     = (const float*)d_in[0];
    const float* W_dkv = (const float*)d_in[1];
    const float* b_dkv = (const float*)d_in[2];
    const float* W_dq  = (const float*)d_in[3];
    const float* b_dq  = (const float*)d_in[4];
    const float* W_uk  = (const float*)d_in[5];
    const float* b_uk  = (const float*)d_in[6];   // softmax-invariant terms dropped
    const float* W_uv  = (const float*)d_in[7];
    const float* b_uv  = (const float*)d_in[8];
    const float* W_uq  = (const float*)d_in[9];
    const float* b_uq  = (const float*)d_in[10];
    const float* W_qr  = (const float*)d_in[11];
    const float* b_qr  = (const float*)d_in[12];
    const float* W_kr  = (const float*)d_in[13];
    const float* b_kr  = (const float*)d_in[14];
    const float* W_o   = (const float*)d_in[15];
    const float* b_o   = (const float*)d_in[16];
    (void)b_uk;

    float* out      = (float*)d_out;
    float* out_ckv  = out + (long long)ROWS * D_MODEL;
    float* out_krot = out_ckv + (long long)ROWS * D_KV;

    float* cat1  = (float*)symv(g_cat1);
    bf16*  cat1h = (bf16*)symv(g_cat1h);
    bf16*  cat1l = (bf16*)symv(g_cat1l);
    bf16*  hh    = (bf16*)symv(g_hh);
    bf16*  hl    = (bf16*)symv(g_hl);
    bf16*  w1h   = (bf16*)symv(g_w1h);
    bf16*  w1l   = (bf16*)symv(g_w1l);
    bf16*  uqph  = (bf16*)symv(g_uqph);
    bf16*  uqpl  = (bf16*)symv(g_uqpl);
    bf16*  ukph  = (bf16*)symv(g_ukph);
    bf16*  ukpl  = (bf16*)symv(g_ukpl);
    bf16*  wqkrh = (bf16*)symv(g_wqkrh);
    bf16*  wqkrl = (bf16*)symv(g_wqkrl);
    float* bqkr  = (float*)symv(g_bqkr);
    float* qe    = (float*)symv(g_qe);
    bf16*  qph   = (bf16*)symv(g_qph);
    bf16*  qpl   = (bf16*)symv(g_qpl);
    bf16*  kph   = (bf16*)symv(g_kph);
    bf16*  kpl   = (bf16*)symv(g_kpl);
    bf16*  ckvth = (bf16*)symv(g_ckvth);
    bf16*  ckvtl = (bf16*)symv(g_ckvtl);
    bf16*  lath  = (bf16*)symv(g_lath);
    bf16*  latl  = (bf16*)symv(g_latl);
    bf16*  uvsh  = (bf16*)symv(g_uvsh);
    bf16*  uvsl  = (bf16*)symv(g_uvsl);
    bf16*  woh   = (bf16*)symv(g_woh);
    bf16*  wol   = (bf16*)symv(g_wol);
    bf16*  wcth  = (bf16*)symv(g_wcth);
    bf16*  wctl  = (bf16*)symv(g_wctl);
    float* b1    = (float*)symv(g_b1);
    float* beff  = (float*)symv(g_beff);

    cudaFuncSetAttribute(gemm_mma, cudaFuncAttributeMaxDynamicSharedMemorySize, GEMM_SMEM);
    cudaFuncSetAttribute(flash_attn, cudaFuncAttributeMaxDynamicSharedMemorySize, FA_SMEM);

    const float scale = 1.0f / sqrtf((float)D_HEAD);

    // ---- weight/bias preprocessing ----
    cudaMemcpyAsync(b1,        b_dkv, 128*sizeof(float), cudaMemcpyDeviceToDevice, 0);
    cudaMemcpyAsync(b1+128,    b_dq,  128*sizeof(float), cudaMemcpyDeviceToDevice, 0);
    cudaMemcpyAsync(b1+256,    b_kr,  128*sizeof(float), cudaMemcpyDeviceToDevice, 0);
    cudaMemcpyAsync(bqkr+1024, b_qr,  128*sizeof(float), cudaMemcpyDeviceToDevice, 0);

    tsplit(W_dkv, w1h,               w1l,               D_MODEL, D_KV, D_KV, D_MODEL);
    tsplit(W_dq,  w1h + 128*D_MODEL, w1l + 128*D_MODEL, D_MODEL, D_KV, D_KV, D_MODEL);
    tsplit(W_kr,  w1h + 256*D_MODEL, w1l + 256*D_MODEL, D_MODEL, D_KV, D_KV, D_MODEL);
    tsplit(W_qr,  wqkrh + 1024*128,  wqkrl + 1024*128,  D_KV, 128, 128, D_KV);
    tsplit(W_o,   woh,  wol,  D_MODEL, D_MODEL, D_MODEL, D_MODEL);

    pad_split_uqk<<<(8*128*640 + 255)/256, 256>>>(W_uq, W_uk, uqph, uqpl, ukph, ukpl);
    convert_split_k<<<(128*D_MODEL + 255)/256, 256>>>(W_uv, uvsh, uvsl, 128*D_MODEL);
    bqk_kernel<<<8, 128>>>(b_uq, W_uk, bqkr);
    beff_kernel<<<(D_MODEL + 255)/256, 256>>>(b_uv, W_o, b_o, beff);

    // Wqk^T[h][c'][c] into rows 0..1023 of wqkr
    gemm(128, 128, 640, ukph, ukpl, 640, uqph, uqpl, 640,
         nullptr, wqkrh, wqkrl, 128, nullptr, 1.0f,
         8, 8, 0, (long long)128*640, 0, (long long)128*640, 0, (long long)128*128);

    // WcombT[o][h*128+c] = sum_d W_o[h*640+d][o] * W_uv[c][h*640+d]
    gemm(D_MODEL, 128, 640, woh, wol, D_MODEL, uvsh, uvsl, D_MODEL,
         nullptr, wcth, wctl, 1024, nullptr, 1.0f,
         8, 8, 0, 640, 0, 640, 0, 128);

    // ---- activations ----
    {
        long long n = (long long)ROWS * D_MODEL;
        convert_split_k<<<(unsigned)((n + 255)/256), 256>>>(h, hh, hl, n);
    }

    // G1: [ckv | cq | kr_pre] = h @ W1 + b1
    gemm(ROWS, NCAT1, D_MODEL, hh, hl, D_MODEL, w1h, w1l, D_MODEL,
         cat1, cat1h, cat1l, NCAT1, b1, 1.0f);
    copy_ckv<<<(ROWS*D_KV + 255)/256, 256>>>(cat1, out_ckv);

    // qe = c_q @ [Wqk | Wqr] + [bqk | b_qr]   [4096, 1152]
    gemm(ROWS, NQE, 128, cat1h + 128, cat1l + 128, NCAT1, wqkrh, wqkrl, 128,
         qe, nullptr, nullptr, NQE, bqkr, 1.0f);

    // assemble augmented Q'/K' (rope applied), emit k_rot output
    {
        long long total = (long long)16*SS*KAUG;
        assemble_qk<<<(unsigned)((total + 255)/256), 256>>>(
            qe, cat1, qph, qpl, kph, kpl, out_krot);
    }

    // c_kv^T per batch: [b][128][2048]
    tsplit(cat1, ckvth, ckvtl, SS, 128, NCAT1, SS,
           BB, 1, (long long)SS*NCAT1, 0, (long long)128*SS, 0);

    // fused attention: lat = softmax(scale * Q'K'^T) @ c_kv
    flash_attn<<<dim3(SS/64, 16), 256, FA_SMEM>>>(
        qph, qpl, kph, kpl, ckvth, ckvtl, lath, latl, scale);

    // out = lat @ Wcomb + (b_uv@W_o + b_o)
    gemm(ROWS, D_MODEL, 1024, lath, latl, 1024, wcth, wctl, 1024,
         out, nullptr, nullptr, D_MODEL, beff, 1.0f);
}

// round 8
// speedup vs baseline: 8.6952x; 1.3134x over previous
#include <cuda_runtime.h>
#include <cuda_bf16.h>
#include <math.h>
#include <stdint.h>

#define D_MODEL 5120
#define N_HEADS 8
#define D_KV    128
#define D_ROPE  16
#define D_HEAD  640
#define SPLIT   624
#define BB      2
#define SS      2048
#define ROWS    (BB*SS)          // 4096
#define NCAT1   384              // dkv(128) + dq(128) + kr(128)
#define KAUG    192              // 128 latent + 16 rope + 48 zero pad
#define NQE     1152             // 1024 (Wqk) + 128 (Wqr)

typedef __nv_bfloat16 bf16;

// ---------------- scratch (device globals) ----------------------------------
__device__ __align__(16) float g_cat1 [ROWS*NCAT1];
__device__ __align__(16) bf16  g_cat1h[ROWS*NCAT1];
__device__ __align__(16) bf16  g_cat1l[ROWS*NCAT1];
__device__ __align__(16) bf16  g_hh  [(size_t)ROWS*D_MODEL];
__device__ __align__(16) bf16  g_hl  [(size_t)ROWS*D_MODEL];
__device__ __align__(16) bf16  g_w1h [NCAT1*D_MODEL];
__device__ __align__(16) bf16  g_w1l [NCAT1*D_MODEL];
__device__ __align__(16) bf16  g_uqph[8*128*640];
__device__ __align__(16) bf16  g_uqpl[8*128*640];
__device__ __align__(16) bf16  g_ukph[8*128*640];
__device__ __align__(16) bf16  g_ukpl[8*128*640];
__device__ __align__(16) bf16  g_wqkrh[NQE*128];
__device__ __align__(16) bf16  g_wqkrl[NQE*128];
__device__ __align__(16) float g_bqkr[NQE];
__device__ __align__(16) float g_qe  [(size_t)ROWS*NQE];
__device__ __align__(16) bf16  g_qph [(size_t)16*SS*KAUG];
__device__ __align__(16) bf16  g_qpl [(size_t)16*SS*KAUG];
__device__ __align__(16) bf16  g_kph [(size_t)16*SS*KAUG];
__device__ __align__(16) bf16  g_kpl [(size_t)16*SS*KAUG];
__device__ __align__(16) bf16  g_ckvth[BB*128*SS];
__device__ __align__(16) bf16  g_ckvtl[BB*128*SS];
__device__ __align__(16) bf16  g_lath[(size_t)ROWS*1024];
__device__ __align__(16) bf16  g_latl[(size_t)ROWS*1024];
__device__ __align__(16) bf16  g_uvsh[128*D_MODEL];
__device__ __align__(16) bf16  g_uvsl[128*D_MODEL];
__device__ __align__(16) bf16  g_woh [(size_t)D_MODEL*D_MODEL];
__device__ __align__(16) bf16  g_wol [(size_t)D_MODEL*D_MODEL];
__device__ __align__(16) bf16  g_wcth[(size_t)D_MODEL*1024];
__device__ __align__(16) bf16  g_wctl[(size_t)D_MODEL*1024];
__device__ __align__(16) float g_b1  [NCAT1];
__device__ __align__(16) float g_beff[D_MODEL];
__device__ __align__(16) float g_beffp[16*D_MODEL];

// ---------------- streams/events (created at load, before harness checkpoints)
struct AuxStreams {
    cudaStream_t s1, s2;
    cudaEvent_t  evFork, evA, evB;
    AuxStreams() {
        cudaStreamCreateWithFlags(&s1, cudaStreamNonBlocking);
        cudaStreamCreateWithFlags(&s2, cudaStreamNonBlocking);
        cudaEventCreateWithFlags(&evFork, cudaEventDisableTiming);
        cudaEventCreateWithFlags(&evA,    cudaEventDisableTiming);
        cudaEventCreateWithFlags(&evB,    cudaEventDisableTiming);
    }
};
static AuxStreams g_aux;

// ---------------- PTX helpers ------------------------------------------------
__device__ __forceinline__ uint32_t smem_u32(const void* p) {
    uint32_t a;
    asm("{ .reg .u64 t; cvta.to.shared.u64 t, %1; cvt.u32.u64 %0, t; }"
        : "=r"(a) : "l"(p));
    return a;
}

__device__ __forceinline__ void cp16(uint32_t dst, const void* src) {
    asm volatile("cp.async.cg.shared.global [%0], [%1], 16;\n"
                 :: "r"(dst), "l"(__cvta_generic_to_global(src)));
}
#define CP_COMMIT() asm volatile("cp.async.commit_group;\n" ::: "memory")
#define CP_WAIT1()  asm volatile("cp.async.wait_group 1;\n" ::: "memory")
#define CP_WAIT0()  asm volatile("cp.async.wait_group 0;\n" ::: "memory")

__device__ __forceinline__ void ldm4(uint32_t* r, uint32_t a) {
    asm volatile("ldmatrix.sync.aligned.m8n8.x4.shared.b16 {%0,%1,%2,%3}, [%4];"
                 : "=r"(r[0]), "=r"(r[1]), "=r"(r[2]), "=r"(r[3]) : "r"(a));
}

__device__ __forceinline__ void mma16816(float* c, const uint32_t* a, const uint32_t* b) {
    asm volatile(
        "mma.sync.aligned.m16n8k16.row.col.f32.bf16.bf16.f32 "
        "{%0,%1,%2,%3},{%4,%5,%6,%7},{%8,%9},{%0,%1,%2,%3};\n"
        : "+f"(c[0]), "+f"(c[1]), "+f"(c[2]), "+f"(c[3])
        : "r"(a[0]), "r"(a[1]), "r"(a[2]), "r"(a[3]), "r"(b[0]), "r"(b[1]));
}

__device__ __forceinline__ uint32_t pack2(float a, float b) {
    __nv_bfloat162 t = __floats2bfloat162_rn(a, b);
    return *reinterpret_cast<const uint32_t*>(&t);
}

__device__ __forceinline__ void split_bf16(float v, bf16& h, bf16& l) {
    h = __float2bfloat16(v);
    l = __float2bfloat16(v - __bfloat162float(h));
}

__device__ __forceinline__ void split_pack(float a, float b, uint32_t& ph, uint32_t& pl) {
    bf16 ha = __float2bfloat16(a), hb = __float2bfloat16(b);
    ph = ((uint32_t)*(uint16_t*)&hb << 16) | (uint32_t)*(uint16_t*)&ha;
    pl = pack2(a - __bfloat162float(ha), b - __bfloat162float(hb));
}

// ---------------- bf16x3 mma.sync GEMM ---------------------------------------
#define STAGE_BYTES 65536
#define GEMM_SMEM   (3*STAGE_BYTES)

__global__ void __launch_bounds__(256, 1)
gemm_mma(int M, int N, int K,
         const bf16* __restrict__ Ah_, const bf16* __restrict__ Al_, long long lda,
         const bf16* __restrict__ Bh_, const bf16* __restrict__ Bl_, long long ldb,
         float* __restrict__ C, bf16* __restrict__ Ch, bf16* __restrict__ Cl,
         long long ldc,
         const float* __restrict__ bias, float alpha,
         int zdiv,
         long long sA1, long long sA2,
         long long sB1, long long sB2,
         long long sC1, long long sC2)
{
    extern __shared__ __align__(1024) char smem[];
    const uint32_t sb = smem_u32(smem);

    {
        int z  = blockIdx.z;
        int z1 = z / zdiv, z2 = z % zdiv;
        Ah_ += z1*sA1 + z2*sA2;  Al_ += z1*sA1 + z2*sA2;
        Bh_ += z1*sB1 + z2*sB2;  Bl_ += z1*sB1 + z2*sB2;
        long long co = z1*sC1 + z2*sC2;
        if (C)  C  += co;
        if (Ch) { Ch += co; Cl += co; }
    }

    const int tid  = threadIdx.x;
    const int wid  = tid >> 5;
    const int lane = tid & 31;
    const int wm   = (wid >> 2) * 64;
    const int wn   = (wid & 3) * 32;
    const int g    = lane >> 2, tg = lane & 3;
    const int m0   = blockIdx.y * 128;
    const int n0   = blockIdx.x * 128;

    const int lrow = tid >> 1;
    const int half = tid & 1;
    const bf16* pAh = Ah_ + (long long)(m0 + lrow)*lda;
    const bf16* pAl = Al_ + (long long)(m0 + lrow)*lda;
    const bf16* pBh = Bh_ + (long long)(n0 + lrow)*ldb;
    const bf16* pBl = Bl_ + (long long)(n0 + lrow)*ldb;
    const uint32_t lswz = (uint32_t)(lrow & 7);

    const int nk = K / 64;

    const int piece = lane >> 3, rr = lane & 7;
    const int rowA  = wm + (piece & 1)*8 + rr;
    const int rowB  = wn + (piece >> 1)*8 + rr;
    const int cA    = piece >> 1;
    const int cB    = piece & 1;

    float acc[4][4][4];
    #pragma unroll
    for (int i = 0; i < 4; i++)
        #pragma unroll
        for (int j = 0; j < 4; j++)
            #pragma unroll
            for (int k = 0; k < 4; k++) acc[i][j][k] = 0.0f;

    #define ISSUE(t) do {                                                     \
        uint32_t s0_ = sb + ((t) % 3) * STAGE_BYTES;                          \
        const int k0_ = (t) * 64;                                             \
        _Pragma("unroll")                                                     \
        for (int j = 0; j < 4; j++) {                                         \
            int ch_ = half*4 + j;                                             \
            uint32_t d_ = (uint32_t)(lrow*128 + (((uint32_t)ch_ ^ lswz) << 4)); \
            cp16(s0_ +         d_, pAh + k0_ + ch_*8);                        \
            cp16(s0_ + 16384 + d_, pAl + k0_ + ch_*8);                        \
            cp16(s0_ + 32768 + d_, pBh + k0_ + ch_*8);                        \
            cp16(s0_ + 49152 + d_, pBl + k0_ + ch_*8);                        \
        }                                                                     \
        CP_COMMIT();                                                          \
    } while (0)

    ISSUE(0);
    if (nk > 1) ISSUE(1);

    for (int t = 0; t < nk; t++) {
        if (t + 1 < nk) { CP_WAIT1(); } else { CP_WAIT0(); }
        __syncthreads();
        if (t + 2 < nk) ISSUE(t + 2);

        const uint32_t Ab = sb + (t % 3) * STAGE_BYTES;
        const uint32_t Bb = Ab + 32768;

        #pragma unroll
        for (int ks = 0; ks < 4; ks++) {
            uint32_t ah[4][4], al[4][4], bh[4][2], bl[4][2];
            const uint32_t aoff = (uint32_t)(rowA*128 + (((ks*2 + cA) ^ (rowA & 7)) << 4));
            const uint32_t boff = (uint32_t)(rowB*128 + (((ks*2 + cB) ^ (rowB & 7)) << 4));
            #pragma unroll
            for (int mt = 0; mt < 4; mt++) {
                ldm4(ah[mt], Ab +          aoff + mt*2048);
                ldm4(al[mt], Ab + 16384 +  aoff + mt*2048);
            }
            #pragma unroll
            for (int ntp = 0; ntp < 2; ntp++) {
                uint32_t rb[4];
                ldm4(rb, Bb +          boff + ntp*2048);
                bh[ntp*2][0]   = rb[0]; bh[ntp*2][1]   = rb[1];
                bh[ntp*2+1][0] = rb[2]; bh[ntp*2+1][1] = rb[3];
                ldm4(rb, Bb + 16384 +  boff + ntp*2048);
                bl[ntp*2][0]   = rb[0]; bl[ntp*2][1]   = rb[1];
                bl[ntp*2+1][0] = rb[2]; bl[ntp*2+1][1] = rb[3];
            }
            #pragma unroll
            for (int mt = 0; mt < 4; mt++)
                #pragma unroll
                for (int nt = 0; nt < 4; nt++) {
                    mma16816(acc[mt][nt], ah[mt], bh[nt]);
                    mma16816(acc[mt][nt], al[mt], bh[nt]);
                    mma16816(acc[mt][nt], ah[mt], bl[nt]);
                }
        }
    }

    #pragma unroll
    for (int mt = 0; mt < 4; mt++) {
        int row = m0 + wm + mt*16 + g;
        #pragma unroll
        for (int nt = 0; nt < 4; nt++) {
            int col = n0 + wn + nt*8 + tg*2;
            float b0 = 0.0f, b1 = 0.0f;
            if (bias) { b0 = bias[col]; b1 = bias[col+1]; }
            float v00 = acc[mt][nt][0]*alpha + b0;
            float v01 = acc[mt][nt][1]*alpha + b1;
            float v10 = acc[mt][nt][2]*alpha + b0;
            float v11 = acc[mt][nt][3]*alpha + b1;
            if (C) {
                *(float2*)(C + (long long)row*ldc + col)     = make_float2(v00, v01);
                *(float2*)(C + (long long)(row+8)*ldc + col) = make_float2(v10, v11);
            }
            if (Ch) {
                uint32_t ph, pl;
                split_pack(v00, v01, ph, pl);
                *(uint32_t*)(Ch + (long long)row*ldc + col) = ph;
                *(uint32_t*)(Cl + (long long)row*ldc + col) = pl;
                split_pack(v10, v11, ph, pl);
                *(uint32_t*)(Ch + (long long)(row+8)*ldc + col) = ph;
                *(uint32_t*)(Cl + (long long)(row+8)*ldc + col) = pl;
            }
        }
    }
}

// ---------------- fused flash attention ---------------------------------------
#define FA_NC    32
#define FA_STG   81920                       // K 49152 + V 32768
#define FA_Q     0
#define FA_S0    49152
#define FA_P     212992
#define FA_REDM  229376
#define FA_REDS  230400
#define FA_SMEM  231424

__global__ void __launch_bounds__(256, 1)
flash_attn(const bf16* __restrict__ qph, const bf16* __restrict__ qpl,
           const bf16* __restrict__ kph, const bf16* __restrict__ kpl,
           const bf16* __restrict__ vth, const bf16* __restrict__ vtl,
           bf16* __restrict__ lath, bf16* __restrict__ latl,
           float scale)
{
    extern __shared__ __align__(1024) char smem[];
    const uint32_t sb = smem_u32(smem);

    const int tid  = threadIdx.x;
    const int wid  = tid >> 5;
    const int lane = tid & 31;
    const int wm2  = wid >> 2;
    const int wn4  = wid & 3;
    const int g    = lane >> 2, tg = lane & 3;
    const int piece = lane >> 3, rr = lane & 7;

    const int bh = blockIdx.y;
    const int b  = bh >> 3;
    const int qb = blockIdx.x;

    const bf16* qbh = qph + ((size_t)bh*SS + (size_t)qb*64)*KAUG;
    const bf16* qbl = qpl + ((size_t)bh*SS + (size_t)qb*64)*KAUG;
    const bf16* kbh = kph + (size_t)bh*SS*KAUG;
    const bf16* kbl = kpl + (size_t)bh*SS*KAUG;
    const bf16* vbh = vth + (size_t)b*128*SS;
    const bf16* vbl = vtl + (size_t)b*128*SS;

    #pragma unroll
    for (int i = 0; i < 6; i++) {
        int idx = i*256 + tid;
        int row = idx / 24, cc = idx % 24;
        int kt = cc >> 3, c8 = cc & 7;
        uint32_t d = (uint32_t)(kt*8192 + row*128 + (((uint32_t)c8 ^ (row & 7)) << 4));
        cp16(sb + FA_Q +         d, qbh + row*KAUG + cc*8);
        cp16(sb + FA_Q + 24576 + d, qbl + row*KAUG + cc*8);
    }
    CP_COMMIT();

    #define FA_ISSUE(t) do {                                                   \
        uint32_t st_ = sb + FA_S0 + ((t) & 1) * FA_STG;                        \
        const int t0_ = (t) * 64;                                              \
        _Pragma("unroll")                                                      \
        for (int i = 0; i < 6; i++) {                                          \
            int idx = i*256 + tid;                                             \
            int row = idx / 24, cc = idx % 24;                                 \
            int kt = cc >> 3, c8 = cc & 7;                                     \
            uint32_t d = (uint32_t)(kt*8192 + row*128 + (((uint32_t)c8 ^ (row & 7)) << 4)); \
            cp16(st_ +         d, kbh + (size_t)(t0_+row)*KAUG + cc*8);        \
            cp16(st_ + 24576 + d, kbl + (size_t)(t0_+row)*KAUG + cc*8);        \
        }                                                                      \
        _Pragma("unroll")                                                      \
        for (int i = 0; i < 4; i++) {                                          \
            int idx = i*256 + tid;                                             \
            int row = idx >> 3, c8 = idx & 7;                                  \
            uint32_t d = (uint32_t)(row*128 + (((uint32_t)c8 ^ (row & 7)) << 4)); \
            cp16(st_ + 49152 + d, vbh + (size_t)row*SS + t0_ + c8*8);          \
            cp16(st_ + 65536 + d, vbl + (size_t)row*SS + t0_ + c8*8);          \
        }                                                                      \
        CP_COMMIT();                                                           \
    } while (0)

    FA_ISSUE(0);

    float accv[2][4][4];
    #pragma unroll
    for (int i = 0; i < 2; i++)
        #pragma unroll
        for (int j = 0; j < 4; j++)
            #pragma unroll
            for (int k = 0; k < 4; k++) accv[i][j][k] = 0.0f;
    float Mrow[4] = {-1e30f, -1e30f, -1e30f, -1e30f};
    float Lrow[4] = {0.0f, 0.0f, 0.0f, 0.0f};

    float* redm = (float*)(smem + FA_REDM);
    float* reds = (float*)(smem + FA_REDS);

    for (int t = 0; t < FA_NC; t++) {
        CP_WAIT0();
        __syncthreads();
        if (t + 1 < FA_NC) FA_ISSUE(t + 1);

        const uint32_t KB = sb + FA_S0 + (t & 1) * FA_STG;
        const uint32_t VB = KB + 49152;

        float sacc[2][2][4];
        #pragma unroll
        for (int i = 0; i < 2; i++)
            #pragma unroll
            for (int j = 0; j < 2; j++)
                #pragma unroll
                for (int k = 0; k < 4; k++) sacc[i][j][k] = 0.0f;

        #pragma unroll
        for (int ks = 0; ks < 12; ks++) {
            const int kt = ks >> 2, ks2 = ks & 3;
            uint32_t ah[2][4], al[2][4];
            #pragma unroll
            for (int mt = 0; mt < 2; mt++) {
                int rowA = wm2*32 + mt*16 + (piece & 1)*8 + rr;
                uint32_t off = (uint32_t)(kt*8192 + rowA*128 +
                    (((ks2*2 + (piece >> 1)) ^ (rowA & 7)) << 4));
                ldm4(ah[mt], sb + FA_Q +         off);
                ldm4(al[mt], sb + FA_Q + 24576 + off);
            }
            int rowB = wn4*16 + (piece >> 1)*8 + rr;
            uint32_t offB = (uint32_t)(kt*8192 + rowB*128 +
                (((ks2*2 + (piece & 1)) ^ (rowB & 7)) << 4));
            uint32_t rbh[4], rbl[4];
            ldm4(rbh, KB +         offB);
            ldm4(rbl, KB + 24576 + offB);
            #pragma unroll
            for (int mt = 0; mt < 2; mt++)
                #pragma unroll
                for (int nt = 0; nt < 2; nt++) {
                    mma16816(sacc[mt][nt], ah[mt], rbh + nt*2);
                    mma16816(sacc[mt][nt], al[mt], rbh + nt*2);
                    mma16816(sacc[mt][nt], ah[mt], rbl + nt*2);
                }
        }

        float mloc[4] = {-1e30f, -1e30f, -1e30f, -1e30f};
        #pragma unroll
        for (int mt = 0; mt < 2; mt++)
            #pragma unroll
            for (int nt = 0; nt < 2; nt++)
                #pragma unroll
                for (int c = 0; c < 4; c++) {
                    sacc[mt][nt][c] *= scale;
                    int slot = mt*2 + (c >> 1);
                    mloc[slot] = fmaxf(mloc[slot], sacc[mt][nt][c]);
                }
        #pragma unroll
        for (int s = 0; s < 4; s++) {
            mloc[s] = fmaxf(mloc[s], __shfl_xor_sync(0xffffffffu, mloc[s], 1));
            mloc[s] = fmaxf(mloc[s], __shfl_xor_sync(0xffffffffu, mloc[s], 2));
        }
        if (tg == 0) {
            #pragma unroll
            for (int mt = 0; mt < 2; mt++)
                #pragma unroll
                for (int h2 = 0; h2 < 2; h2++) {
                    int r = wm2*32 + mt*16 + h2*8 + g;
                    redm[wn4*64 + r] = mloc[mt*2 + h2];
                }
        }
        __syncthreads();

        float fsc[4];
        #pragma unroll
        for (int mt = 0; mt < 2; mt++)
            #pragma unroll
            for (int h2 = 0; h2 < 2; h2++) {
                int r = wm2*32 + mt*16 + h2*8 + g;
                float cm = fmaxf(fmaxf(redm[r], redm[64 + r]),
                                 fmaxf(redm[128 + r], redm[192 + r]));
                int slot = mt*2 + h2;
                float mn = fmaxf(Mrow[slot], cm);
                fsc[slot] = __expf(Mrow[slot] - mn);
                Mrow[slot] = mn;
            }

        float sl[4] = {0.0f, 0.0f, 0.0f, 0.0f};
        #pragma unroll
        for (int mt = 0; mt < 2; mt++)
            #pragma unroll
            for (int nt = 0; nt < 2; nt++)
                #pragma unroll
                for (int c = 0; c < 4; c++) {
                    int slot = mt*2 + (c >> 1);
                    float p = __expf(sacc[mt][nt][c] - Mrow[slot]);
                    sacc[mt][nt][c] = p;
                    sl[slot] += p;
                }
        #pragma unroll
        for (int mt = 0; mt < 2; mt++)
            #pragma unroll
            for (int nt = 0; nt < 4; nt++)
                #pragma unroll
                for (int c = 0; c < 4; c++)
                    accv[mt][nt][c] *= fsc[mt*2 + (c >> 1)];
        #pragma unroll
        for (int s = 0; s < 4; s++) {
            sl[s] += __shfl_xor_sync(0xffffffffu, sl[s], 1);
            sl[s] += __shfl_xor_sync(0xffffffffu, sl[s], 2);
        }
        if (tg == 0) {
            #pragma unroll
            for (int mt = 0; mt < 2; mt++)
                #pragma unroll
                for (int h2 = 0; h2 < 2; h2++) {
                    int r = wm2*32 + mt*16 + h2*8 + g;
                    reds[wn4*64 + r] = sl[mt*2 + h2];
                }
        }
        #pragma unroll
        for (int mt = 0; mt < 2; mt++)
            #pragma unroll
            for (int nt = 0; nt < 2; nt++)
                #pragma unroll
                for (int h2 = 0; h2 < 2; h2++) {
                    int r = wm2*32 + mt*16 + h2*8 + g;
                    int cidx = wn4*2 + nt;
                    uint32_t addr = (uint32_t)(r*128 + ((cidx ^ (r & 7)) << 4) + tg*4);
                    uint32_t ph, pl;
                    split_pack(sacc[mt][nt][2*h2], sacc[mt][nt][2*h2+1], ph, pl);
                    *(uint32_t*)(smem + FA_P +        addr) = ph;
                    *(uint32_t*)(smem + FA_P + 8192 + addr) = pl;
                }
        __syncthreads();

        #pragma unroll
        for (int mt = 0; mt < 2; mt++)
            #pragma unroll
            for (int h2 = 0; h2 < 2; h2++) {
                int r = wm2*32 + mt*16 + h2*8 + g;
                float ssum = reds[r] + reds[64 + r] + reds[128 + r] + reds[192 + r];
                int slot = mt*2 + h2;
                Lrow[slot] = Lrow[slot] * fsc[slot] + ssum;
            }

        #pragma unroll
        for (int ksv = 0; ksv < 4; ksv++) {
            uint32_t pah[2][4], pal[2][4];
            #pragma unroll
            for (int mt = 0; mt < 2; mt++) {
                int rowA = wm2*32 + mt*16 + (piece & 1)*8 + rr;
                uint32_t off = (uint32_t)(rowA*128 +
                    (((ksv*2 + (piece >> 1)) ^ (rowA & 7)) << 4));
                ldm4(pah[mt], sb + FA_P +        off);
                ldm4(pal[mt], sb + FA_P + 8192 + off);
            }
            uint32_t vh[2][4], vl[2][4];
            #pragma unroll
            for (int ntp = 0; ntp < 2; ntp++) {
                int rowB = wn4*32 + ntp*16 + (piece >> 1)*8 + rr;
                uint32_t offB = (uint32_t)(rowB*128 +
                    (((ksv*2 + (piece & 1)) ^ (rowB & 7)) << 4));
                ldm4(vh[ntp], VB +         offB);
                ldm4(vl[ntp], VB + 16384 + offB);
            }
            #pragma unroll
            for (int mt = 0; mt < 2; mt++)
                #pragma unroll
                for (int nt = 0; nt < 4; nt++) {
                    const uint32_t* bhp = vh[nt >> 1] + (nt & 1)*2;
                    const uint32_t* blp = vl[nt >> 1] + (nt & 1)*2;
                    mma16816(accv[mt][nt], pah[mt], bhp);
                    mma16816(accv[mt][nt], pal[mt], bhp);
                    mma16816(accv[mt][nt], pah[mt], blp);
                }
        }
    }

    float inv[4];
    #pragma unroll
    for (int s = 0; s < 4; s++) inv[s] = 1.0f / Lrow[s];

    const int h = bh & 7;
    #pragma unroll
    for (int mt = 0; mt < 2; mt++) {
        #pragma unroll
        for (int nt = 0; nt < 4; nt++) {
            int col = h*128 + wn4*32 + nt*8 + tg*2;
            #pragma unroll
            for (int h2 = 0; h2 < 2; h2++) {
                long long row = (long long)b*SS + qb*64 + wm2*32 + mt*16 + h2*8 + g;
                float v0 = accv[mt][nt][2*h2]   * inv[mt*2 + h2];
                float v1 = accv[mt][nt][2*h2+1] * inv[mt*2 + h2];
                uint32_t ph, pl;
                split_pack(v0, v1, ph, pl);
                *(uint32_t*)(lath + row*1024 + col) = ph;
                *(uint32_t*)(latl + row*1024 + col) = pl;
            }
        }
    }
}

// ---------------- elementwise fp32 -> bf16 hi/lo ------------------------------
__global__ void convert_split_k(const float* __restrict__ in,
                                bf16* __restrict__ oh, bf16* __restrict__ ol,
                                long long n)
{
    long long i = (long long)blockIdx.x * 256 + threadIdx.x;
    if (i < n) {
        bf16 h, l; split_bf16(in[i], h, l);
        oh[i] = h; ol[i] = l;
    }
}

// ---------------- fp32 transpose -> bf16 hi/lo --------------------------------
__global__ void transpose_split_k(const float* __restrict__ in,
                                  bf16* __restrict__ oh, bf16* __restrict__ ol,
                                  int M, int N, int ldi, int ldo,
                                  int zdiv,
                                  long long si1, long long si2,
                                  long long so1, long long so2)
{
    __shared__ float tile[32][33];
    int z = blockIdx.z, z1 = z / zdiv, z2 = z % zdiv;
    in += z1*si1 + z2*si2;
    oh += z1*so1 + z2*so2;
    ol += z1*so1 + z2*so2;

    int x = blockIdx.x*32 + threadIdx.x;   // n
    int y = blockIdx.y*32 + threadIdx.y;   // m
    #pragma unroll
    for (int i = 0; i < 32; i += 8)
        if (x < N && (y+i) < M)
            tile[threadIdx.y+i][threadIdx.x] = in[(long long)(y+i)*ldi + x];
    __syncthreads();
    x = blockIdx.y*32 + threadIdx.x;       // m
    y = blockIdx.x*32 + threadIdx.y;       // n
    #pragma unroll
    for (int i = 0; i < 32; i += 8)
        if (x < M && (y+i) < N) {
            bf16 h, l; split_bf16(tile[threadIdx.x][threadIdx.y+i], h, l);
            oh[(long long)(y+i)*ldo + x] = h;
            ol[(long long)(y+i)*ldo + x] = l;
        }
}

// ---------------- pad+split W_uq / W_uk into [8][128][640] --------------------
__global__ void pad_split_uqk(const float* __restrict__ Wuq,
                              const float* __restrict__ Wuk,
                              bf16* __restrict__ uqh, bf16* __restrict__ uql,
                              bf16* __restrict__ ukh, bf16* __restrict__ ukl)
{
    int idx = blockIdx.x * 256 + threadIdx.x;
    if (idx >= 8*128*640) return;
    int e = idx % 640;
    int c = (idx / 640) & 127;
    int h = idx / (640*128);
    float vq = 0.0f, vk = 0.0f;
    if (e < SPLIT) {
        vq = Wuq[c*4992 + h*SPLIT + e];
        vk = Wuk[c*4992 + h*SPLIT + e];
    }
    bf16 hh, ll;
    split_bf16(vq, hh, ll); uqh[idx] = hh; uql[idx] = ll;
    split_bf16(vk, hh, ll); ukh[idx] = hh; ukl[idx] = ll;
}

// ---------------- bqk[h*128+c'] = sum_e b_uq[h*624+e] * W_uk[c', h*624+e] -----
__global__ void bqk_kernel(const float* __restrict__ b_uq,
                           const float* __restrict__ W_uk,
                           float* __restrict__ bqk)
{
    int c = threadIdx.x;
    int h = blockIdx.x;
    float acc = 0.0f;
    const float* wrow = W_uk + c*4992 + h*SPLIT;
    const float* brow = b_uq + h*SPLIT;
    for (int e = 0; e < SPLIT; e++)
        acc += brow[e] * wrow[e];
    bqk[h*128 + c] = acc;
}

// ---------------- beff: two-phase deterministic partial reduction --------------
__global__ void beff_partial(const float* __restrict__ b_uv,
                             const float* __restrict__ W_o,
                             float* __restrict__ part)
{
    int o   = blockIdx.x * 256 + threadIdx.x;   // 0..5119
    int seg = blockIdx.y;                        // 0..15
    float acc = 0.0f;
    int d0 = seg * (D_MODEL/16);
    #pragma unroll 4
    for (int d = d0; d < d0 + D_MODEL/16; d++)
        acc += b_uv[d] * W_o[(size_t)d*D_MODEL + o];
    part[(size_t)seg*D_MODEL + o] = acc;
}

__global__ void beff_reduce(const float* __restrict__ part,
                            const float* __restrict__ b_o,
                            float* __restrict__ be)
{
    int o = blockIdx.x * 256 + threadIdx.x;
    if (o >= D_MODEL) return;
    float acc = b_o[o];
    #pragma unroll
    for (int s = 0; s < 16; s++)
        acc += part[(size_t)s*D_MODEL + o];
    be[o] = acc;
}

// ---------------- assemble augmented Q'/K' (rope) + emit k_rot ----------------
__global__ void assemble_qk(const float* __restrict__ qe,
                            const float* __restrict__ cat1,
                            bf16* __restrict__ qph, bf16* __restrict__ qpl,
                            bf16* __restrict__ kph, bf16* __restrict__ kpl,
                            float* __restrict__ out_krot)
{
    long long idx = (long long)blockIdx.x * 256 + threadIdx.x;
    if (idx >= (long long)16*SS*KAUG) return;
    int j  = (int)(idx % KAUG);
    int s  = (int)((idx / KAUG) & (SS - 1));
    int bh = (int)(idx / ((long long)KAUG*SS));
    int b  = bh >> 3, h = bh & 7;
    long long row = (long long)b*SS + s;

    float qv = 0.0f, kv = 0.0f;
    if (j < 128) {
        qv = qe[row*NQE + h*128 + j];
        kv = cat1[row*NCAT1 + j];
    } else if (j < 144) {
        int dd = j - 128;
        long long qb = row*NQE + 1024 + h*D_ROPE;
        long long kb = row*NCAT1 + 256 + h*D_ROPE;
        if (dd < 8) {
            const float invf[4] = {1.0f, 0.1f, 0.01f, 0.001f};
            float f = ((float)s / 40.0f) * invf[dd & 3];
            float c_ = cosf(f), sn = sinf(f);
            if (dd < 4) {
                qv = qe[qb+dd]*c_ - qe[qb+dd+4]*sn;
                kv = cat1[kb+dd]*c_ - cat1[kb+dd+4]*sn;
            } else {
                qv = qe[qb+dd]*c_ + qe[qb+dd-4]*sn;
                kv = cat1[kb+dd]*c_ + cat1[kb+dd-4]*sn;
            }
        } else {
            qv = qe[qb+dd];
            kv = cat1[kb+dd];
        }
        out_krot[row*128 + h*D_ROPE + dd] = kv;
    }
    bf16 hh, ll;
    split_bf16(qv, hh, ll); qph[idx] = hh; qpl[idx] = ll;
    split_bf16(kv, hh, ll); kph[idx] = hh; kpl[idx] = ll;
}

// ---------------- c_kv output copy ---------------------------------------------
__global__ void copy_ckv(const float* __restrict__ cat1, float* __restrict__ out)
{
    int idx = blockIdx.x * 256 + threadIdx.x;
    if (idx < ROWS * D_KV)
        out[idx] = cat1[(idx >> 7) * NCAT1 + (idx & 127)];
}

// ---------------- host side ------------------------------------------------------
static inline void* symv(const void* s)
{
    void* p = nullptr;
    cudaGetSymbolAddress(&p, s);
    return p;
}

static void gemm_on(cudaStream_t st, int M, int N, int K,
                    const bf16* Ah, const bf16* Al, long long lda,
                    const bf16* Bh, const bf16* Bl, long long ldb,
                    float* C, bf16* Ch, bf16* Cl, long long ldc,
                    const float* bias, float alpha,
                    int nz = 1, int zdiv = 1,
                    long long sA1 = 0, long long sA2 = 0,
                    long long sB1 = 0, long long sB2 = 0,
                    long long sC1 = 0, long long sC2 = 0)
{
    dim3 grid(N / 128, M / 128, nz);
    gemm_mma<<<grid, 256, GEMM_SMEM, st>>>(M, N, K, Ah, Al, lda, Bh, Bl, ldb,
                                           C, Ch, Cl, ldc, bias, alpha, zdiv,
                                           sA1, sA2, sB1, sB2, sC1, sC2);
}

static void tsplit_on(cudaStream_t st, const float* in, bf16* oh, bf16* ol,
                      int M, int N, int ldi, int ldo,
                      int nz = 1, int zdiv = 1,
                      long long si1 = 0, long long si2 = 0,
                      long long so1 = 0, long long so2 = 0)
{
    dim3 grid((N + 31)/32, (M + 31)/32, nz);
    transpose_split_k<<<grid, dim3(32, 8), 0, st>>>(in, oh, ol, M, N, ldi, ldo,
                                                    zdiv, si1, si2, so1, so2);
}

extern "C" void kernel_launch(void* const* d_in, const int* in_sizes, int n_in,
                              void* d_out, int out_size)
{
    const float* h     = (const float*)d_in[0];
    const float* W_dkv = (const float*)d_in[1];
    const float* b_dkv = (const float*)d_in[2];
    const float* W_dq  = (const float*)d_in[3];
    const float* b_dq  = (const float*)d_in[4];
    const float* W_uk  = (const float*)d_in[5];
    const float* b_uk  = (const float*)d_in[6];   // softmax-invariant terms dropped
    const float* W_uv  = (const float*)d_in[7];
    const float* b_uv  = (const float*)d_in[8];
    const float* W_uq  = (const float*)d_in[9];
    const float* b_uq  = (const float*)d_in[10];
    const float* W_qr  = (const float*)d_in[11];
    const float* b_qr  = (const float*)d_in[12];
    const float* W_kr  = (const float*)d_in[13];
    const float* b_kr  = (const float*)d_in[14];
    const float* W_o   = (const float*)d_in[15];
    const float* b_o   = (const float*)d_in[16];
    (void)b_uk;

    float* out      = (float*)d_out;
    float* out_ckv  = out + (long long)ROWS * D_MODEL;
    float* out_krot = out_ckv + (long long)ROWS * D_KV;

    float* cat1  = (float*)symv(g_cat1);
    bf16*  cat1h = (bf16*)symv(g_cat1h);
    bf16*  cat1l = (bf16*)symv(g_cat1l);
    bf16*  hh    = (bf16*)symv(g_hh);
    bf16*  hl    = (bf16*)symv(g_hl);
    bf16*  w1h   = (bf16*)symv(g_w1h);
    bf16*  w1l   = (bf16*)symv(g_w1l);
    bf16*  uqph  = (bf16*)symv(g_uqph);
    bf16*  uqpl  = (bf16*)symv(g_uqpl);
    bf16*  ukph  = (bf16*)symv(g_ukph);
    bf16*  ukpl  = (bf16*)symv(g_ukpl);
    bf16*  wqkrh = (bf16*)symv(g_wqkrh);
    bf16*  wqkrl = (bf16*)symv(g_wqkrl);
    float* bqkr  = (float*)symv(g_bqkr);
    float* qe    = (float*)symv(g_qe);
    bf16*  qph   = (bf16*)symv(g_qph);
    bf16*  qpl   = (bf16*)symv(g_qpl);
    bf16*  kph   = (bf16*)symv(g_kph);
    bf16*  kpl   = (bf16*)symv(g_kpl);
    bf16*  ckvth = (bf16*)symv(g_ckvth);
    bf16*  ckvtl = (bf16*)symv(g_ckvtl);
    bf16*  lath  = (bf16*)symv(g_lath);
    bf16*  latl  = (bf16*)symv(g_latl);
    bf16*  uvsh  = (bf16*)symv(g_uvsh);
    bf16*  uvsl  = (bf16*)symv(g_uvsl);
    bf16*  woh   = (bf16*)symv(g_woh);
    bf16*  wol   = (bf16*)symv(g_wol);
    bf16*  wcth  = (bf16*)symv(g_wcth);
    bf16*  wctl  = (bf16*)symv(g_wctl);
    float* b1    = (float*)symv(g_b1);
    float* beff  = (float*)symv(g_beff);
    float* beffp = (float*)symv(g_beffp);

    cudaFuncSetAttribute(gemm_mma, cudaFuncAttributeMaxDynamicSharedMemorySize, GEMM_SMEM);
    cudaFuncSetAttribute(flash_attn, cudaFuncAttributeMaxDynamicSharedMemorySize, FA_SMEM);

    const float scale = 1.0f / sqrtf((float)D_HEAD);
    cudaStream_t s0 = 0, s1 = g_aux.s1, s2 = g_aux.s2;

    // ---- fork side streams off the captured origin ----
    cudaEventRecord(g_aux.evFork, s0);
    cudaStreamWaitEvent(s1, g_aux.evFork, 0);
    cudaStreamWaitEvent(s2, g_aux.evFork, 0);

    // ======== s1: Wqk-absorption chain (needed by qe GEMM) ========
    cudaMemcpyAsync(bqkr+1024, b_qr, 128*sizeof(float), cudaMemcpyDeviceToDevice, s1);
    tsplit_on(s1, W_qr, wqkrh + 1024*128, wqkrl + 1024*128, D_KV, 128, 128, D_KV);
    pad_split_uqk<<<(8*128*640 + 255)/256, 256, 0, s1>>>(W_uq, W_uk, uqph, uqpl, ukph, ukpl);
    bqk_kernel<<<8, 128, 0, s1>>>(b_uq, W_uk, bqkr);
    gemm_on(s1, 128, 128, 640, ukph, ukpl, 640, uqph, uqpl, 640,
            nullptr, wqkrh, wqkrl, 128, nullptr, 1.0f,
            8, 8, 0, (long long)128*640, 0, (long long)128*640, 0, (long long)128*128);
    cudaEventRecord(g_aux.evA, s1);

    // ======== s2: W_o/W_uv-absorption chain (needed by final GEMM) ========
    convert_split_k<<<(128*D_MODEL + 255)/256, 256, 0, s2>>>(W_uv, uvsh, uvsl, 128*D_MODEL);
    tsplit_on(s2, W_o, woh, wol, D_MODEL, D_MODEL, D_MODEL, D_MODEL);
    gemm_on(s2, D_MODEL, 128, 640, woh, wol, D_MODEL, uvsh, uvsl, D_MODEL,
            nullptr, wcth, wctl, 1024, nullptr, 1.0f,
            8, 8, 0, 640, 0, 640, 0, 128);
    beff_partial<<<dim3(D_MODEL/256, 16), 256, 0, s2>>>(b_uv, W_o, beffp);
    beff_reduce<<<(D_MODEL + 255)/256, 256, 0, s2>>>(beffp, b_o, beff);
    cudaEventRecord(g_aux.evB, s2);

    // ======== s0: activation critical path ========
    cudaMemcpyAsync(b1,      b_dkv, 128*sizeof(float), cudaMemcpyDeviceToDevice, s0);
    cudaMemcpyAsync(b1+128,  b_dq,  128*sizeof(float), cudaMemcpyDeviceToDevice, s0);
    cudaMemcpyAsync(b1+256,  b_kr,  128*sizeof(float), cudaMemcpyDeviceToDevice, s0);
    tsplit_on(s0, W_dkv, w1h,               w1l,               D_MODEL, D_KV, D_KV, D_MODEL);
    tsplit_on(s0, W_dq,  w1h + 128*D_MODEL, w1l + 128*D_MODEL, D_MODEL, D_KV, D_KV, D_MODEL);
    tsplit_on(s0, W_kr,  w1h + 256*D_MODEL, w1l + 256*D_MODEL, D_MODEL, D_KV, D_KV, D_MODEL);
    {
        long long n = (long long)ROWS * D_MODEL;
        convert_split_k<<<(unsigned)((n + 255)/256), 256, 0, s0>>>(h, hh, hl, n);
    }

    // G1: [ckv | cq | kr_pre] = h @ W1 + b1
    gemm_on(s0, ROWS, NCAT1, D_MODEL, hh, hl, D_MODEL, w1h, w1l, D_MODEL,
            cat1, cat1h, cat1l, NCAT1, b1, 1.0f);
    copy_ckv<<<(ROWS*D_KV + 255)/256, 256, 0, s0>>>(cat1, out_ckv);

    // join s1 before qe
    cudaStreamWaitEvent(s0, g_aux.evA, 0);

    // qe = c_q @ [Wqk | Wqr] + [bqk | b_qr]
    gemm_on(s0, ROWS, NQE, 128, cat1h + 128, cat1l + 128, NCAT1, wqkrh, wqkrl, 128,
            qe, nullptr, nullptr, NQE, bqkr, 1.0f);

    {
        long long total = (long long)16*SS*KAUG;
        assemble_qk<<<(unsigned)((total + 255)/256), 256, 0, s0>>>(
            qe, cat1, qph, qpl, kph, kpl, out_krot);
    }

    // c_kv^T per batch
    tsplit_on(s0, cat1, ckvth, ckvtl, SS, 128, NCAT1, SS,
              BB, 1, (long long)SS*NCAT1, 0, (long long)128*SS, 0);

    // fused attention
    flash_attn<<<dim3(SS/64, 16), 256, FA_SMEM, s0>>>(
        qph, qpl, kph, kpl, ckvth, ckvtl, lath, latl, scale);

    // join s2 before final GEMM
    cudaStreamWaitEvent(s0, g_aux.evB, 0);

    // out = lat @ Wcomb + beff
    gemm_on(s0, ROWS, D_MODEL, 1024, lath, latl, 1024, wcth, wctl, 1024,
            out, nullptr, nullptr, D_MODEL, beff, 1.0f);
}

// round 9
// speedup vs baseline: 8.9928x; 1.0342x over previous
#include <cuda_runtime.h>
#include <cuda_bf16.h>
#include <math.h>
#include <stdint.h>

#define D_MODEL 5120
#define N_HEADS 8
#define D_KV    128
#define D_ROPE  16
#define D_HEAD  640
#define SPLIT   624
#define BB      2
#define SS      2048
#define ROWS    (BB*SS)          // 4096
#define NCAT1   384              // dkv(128) + dq(128) + kr(128)
#define KAUG    192              // smem layout width; only 144 cols real
#define NQE     1152             // 1024 (Wqk) + 128 (Wqr)

typedef __nv_bfloat16 bf16;

// ---------------- scratch (device globals) ----------------------------------
__device__ __align__(16) float g_cat1 [ROWS*NCAT1];
__device__ __align__(16) bf16  g_cat1h[ROWS*NCAT1];
__device__ __align__(16) bf16  g_cat1l[ROWS*NCAT1];
__device__ __align__(16) bf16  g_hh  [(size_t)ROWS*D_MODEL];
__device__ __align__(16) bf16  g_hl  [(size_t)ROWS*D_MODEL];
__device__ __align__(16) bf16  g_w1h [NCAT1*D_MODEL];
__device__ __align__(16) bf16  g_w1l [NCAT1*D_MODEL];
__device__ __align__(16) bf16  g_uqph[8*128*640];
__device__ __align__(16) bf16  g_uqpl[8*128*640];
__device__ __align__(16) bf16  g_ukph[8*128*640];
__device__ __align__(16) bf16  g_ukpl[8*128*640];
__device__ __align__(16) bf16  g_wqkrh[NQE*128];
__device__ __align__(16) bf16  g_wqkrl[NQE*128];
__device__ __align__(16) float g_bqkr[NQE];
__device__ __align__(16) float g_qe  [(size_t)ROWS*NQE];
__device__ __align__(16) bf16  g_qph [(size_t)16*SS*KAUG];
__device__ __align__(16) bf16  g_qpl [(size_t)16*SS*KAUG];
__device__ __align__(16) bf16  g_kph [(size_t)16*SS*KAUG];
__device__ __align__(16) bf16  g_kpl [(size_t)16*SS*KAUG];
__device__ __align__(16) bf16  g_ckvth[BB*128*SS];
__device__ __align__(16) bf16  g_ckvtl[BB*128*SS];
__device__ __align__(16) bf16  g_lath[(size_t)ROWS*1024];
__device__ __align__(16) bf16  g_latl[(size_t)ROWS*1024];
__device__ __align__(16) bf16  g_uvsh[128*D_MODEL];
__device__ __align__(16) bf16  g_uvsl[128*D_MODEL];
__device__ __align__(16) bf16  g_woh [(size_t)D_MODEL*D_MODEL];
__device__ __align__(16) bf16  g_wol [(size_t)D_MODEL*D_MODEL];
__device__ __align__(16) bf16  g_wcth[(size_t)D_MODEL*1024];
__device__ __align__(16) bf16  g_wctl[(size_t)D_MODEL*1024];
__device__ __align__(16) float g_b1  [NCAT1];
__device__ __align__(16) float g_beff[D_MODEL];
__device__ __align__(16) float g_beffp[16*D_MODEL];

// ---------------- streams/events ---------------------------------------------
struct AuxStreams {
    cudaStream_t s1, s2;
    cudaEvent_t  evFork, evA, evB, evG1, evCk, evF0, evH0;
    AuxStreams() {
        cudaStreamCreateWithFlags(&s1, cudaStreamNonBlocking);
        cudaStreamCreateWithFlags(&s2, cudaStreamNonBlocking);
        cudaEventCreateWithFlags(&evFork, cudaEventDisableTiming);
        cudaEventCreateWithFlags(&evA,    cudaEventDisableTiming);
        cudaEventCreateWithFlags(&evB,    cudaEventDisableTiming);
        cudaEventCreateWithFlags(&evG1,   cudaEventDisableTiming);
        cudaEventCreateWithFlags(&evCk,   cudaEventDisableTiming);
        cudaEventCreateWithFlags(&evF0,   cudaEventDisableTiming);
        cudaEventCreateWithFlags(&evH0,   cudaEventDisableTiming);
    }
};
static AuxStreams g_aux;

// ---------------- PTX helpers ------------------------------------------------
__device__ __forceinline__ uint32_t smem_u32(const void* p) {
    uint32_t a;
    asm("{ .reg .u64 t; cvta.to.shared.u64 t, %1; cvt.u32.u64 %0, t; }"
        : "=r"(a) : "l"(p));
    return a;
}

__device__ __forceinline__ void cp16(uint32_t dst, const void* src) {
    asm volatile("cp.async.cg.shared.global [%0], [%1], 16;\n"
                 :: "r"(dst), "l"(__cvta_generic_to_global(src)));
}
#define CP_COMMIT() asm volatile("cp.async.commit_group;\n" ::: "memory")
#define CP_WAIT1()  asm volatile("cp.async.wait_group 1;\n" ::: "memory")
#define CP_WAIT0()  asm volatile("cp.async.wait_group 0;\n" ::: "memory")

__device__ __forceinline__ void ldm4(uint32_t* r, uint32_t a) {
    asm volatile("ldmatrix.sync.aligned.m8n8.x4.shared.b16 {%0,%1,%2,%3}, [%4];"
                 : "=r"(r[0]), "=r"(r[1]), "=r"(r[2]), "=r"(r[3]) : "r"(a));
}

__device__ __forceinline__ void mma16816(float* c, const uint32_t* a, const uint32_t* b) {
    asm volatile(
        "mma.sync.aligned.m16n8k16.row.col.f32.bf16.bf16.f32 "
        "{%0,%1,%2,%3},{%4,%5,%6,%7},{%8,%9},{%0,%1,%2,%3};\n"
        : "+f"(c[0]), "+f"(c[1]), "+f"(c[2]), "+f"(c[3])
        : "r"(a[0]), "r"(a[1]), "r"(a[2]), "r"(a[3]), "r"(b[0]), "r"(b[1]));
}

__device__ __forceinline__ uint32_t pack2(float a, float b) {
    __nv_bfloat162 t = __floats2bfloat162_rn(a, b);
    return *reinterpret_cast<const uint32_t*>(&t);
}

__device__ __forceinline__ void split_bf16(float v, bf16& h, bf16& l) {
    h = __float2bfloat16(v);
    l = __float2bfloat16(v - __bfloat162float(h));
}

__device__ __forceinline__ void split_pack(float a, float b, uint32_t& ph, uint32_t& pl) {
    bf16 ha = __float2bfloat16(a), hb = __float2bfloat16(b);
    ph = ((uint32_t)*(uint16_t*)&hb << 16) | (uint32_t)*(uint16_t*)&ha;
    pl = pack2(a - __bfloat162float(ha), b - __bfloat162float(hb));
}

// ---------------- bf16x3 mma.sync GEMM ---------------------------------------
#define STAGE_BYTES 65536
#define GEMM_SMEM   (3*STAGE_BYTES)

__global__ void __launch_bounds__(256, 1)
gemm_mma(int M, int N, int K,
         const bf16* __restrict__ Ah_, const bf16* __restrict__ Al_, long long lda,
         const bf16* __restrict__ Bh_, const bf16* __restrict__ Bl_, long long ldb,
         float* __restrict__ C, bf16* __restrict__ Ch, bf16* __restrict__ Cl,
         long long ldc,
         const float* __restrict__ bias, float alpha,
         int zdiv,
         long long sA1, long long sA2,
         long long sB1, long long sB2,
         long long sC1, long long sC2)
{
    extern __shared__ __align__(1024) char smem[];
    const uint32_t sb = smem_u32(smem);

    {
        int z  = blockIdx.z;
        int z1 = z / zdiv, z2 = z % zdiv;
        Ah_ += z1*sA1 + z2*sA2;  Al_ += z1*sA1 + z2*sA2;
        Bh_ += z1*sB1 + z2*sB2;  Bl_ += z1*sB1 + z2*sB2;
        long long co = z1*sC1 + z2*sC2;
        if (C)  C  += co;
        if (Ch) { Ch += co; Cl += co; }
    }

    const int tid  = threadIdx.x;
    const int wid  = tid >> 5;
    const int lane = tid & 31;
    const int wm   = (wid >> 2) * 64;
    const int wn   = (wid & 3) * 32;
    const int g    = lane >> 2, tg = lane & 3;
    const int m0   = blockIdx.y * 128;
    const int n0   = blockIdx.x * 128;

    const int lrow = tid >> 1;
    const int half = tid & 1;
    const bf16* pAh = Ah_ + (long long)(m0 + lrow)*lda;
    const bf16* pAl = Al_ + (long long)(m0 + lrow)*lda;
    const bf16* pBh = Bh_ + (long long)(n0 + lrow)*ldb;
    const bf16* pBl = Bl_ + (long long)(n0 + lrow)*ldb;
    const uint32_t lswz = (uint32_t)(lrow & 7);

    const int nk = K / 64;

    const int piece = lane >> 3, rr = lane & 7;
    const int rowA  = wm + (piece & 1)*8 + rr;
    const int rowB  = wn + (piece >> 1)*8 + rr;
    const int cA    = piece >> 1;
    const int cB    = piece & 1;

    float acc[4][4][4];
    #pragma unroll
    for (int i = 0; i < 4; i++)
        #pragma unroll
        for (int j = 0; j < 4; j++)
            #pragma unroll
            for (int k = 0; k < 4; k++) acc[i][j][k] = 0.0f;

    #define ISSUE(t) do {                                                     \
        uint32_t s0_ = sb + ((t) % 3) * STAGE_BYTES;                          \
        const int k0_ = (t) * 64;                                             \
        _Pragma("unroll")                                                     \
        for (int j = 0; j < 4; j++) {                                         \
            int ch_ = half*4 + j;                                             \
            uint32_t d_ = (uint32_t)(lrow*128 + (((uint32_t)ch_ ^ lswz) << 4)); \
            cp16(s0_ +         d_, pAh + k0_ + ch_*8);                        \
            cp16(s0_ + 16384 + d_, pAl + k0_ + ch_*8);                        \
            cp16(s0_ + 32768 + d_, pBh + k0_ + ch_*8);                        \
            cp16(s0_ + 49152 + d_, pBl + k0_ + ch_*8);                        \
        }                                                                     \
        CP_COMMIT();                                                          \
    } while (0)

    ISSUE(0);
    if (nk > 1) ISSUE(1);

    for (int t = 0; t < nk; t++) {
        if (t + 1 < nk) { CP_WAIT1(); } else { CP_WAIT0(); }
        __syncthreads();
        if (t + 2 < nk) ISSUE(t + 2);

        const uint32_t Ab = sb + (t % 3) * STAGE_BYTES;
        const uint32_t Bb = Ab + 32768;

        #pragma unroll
        for (int ks = 0; ks < 4; ks++) {
            uint32_t ah[4][4], al[4][4], bh[4][2], bl[4][2];
            const uint32_t aoff = (uint32_t)(rowA*128 + (((ks*2 + cA) ^ (rowA & 7)) << 4));
            const uint32_t boff = (uint32_t)(rowB*128 + (((ks*2 + cB) ^ (rowB & 7)) << 4));
            #pragma unroll
            for (int mt = 0; mt < 4; mt++) {
                ldm4(ah[mt], Ab +          aoff + mt*2048);
                ldm4(al[mt], Ab + 16384 +  aoff + mt*2048);
            }
            #pragma unroll
            for (int ntp = 0; ntp < 2; ntp++) {
                uint32_t rb[4];
                ldm4(rb, Bb +          boff + ntp*2048);
                bh[ntp*2][0]   = rb[0]; bh[ntp*2][1]   = rb[1];
                bh[ntp*2+1][0] = rb[2]; bh[ntp*2+1][1] = rb[3];
                ldm4(rb, Bb + 16384 +  boff + ntp*2048);
                bl[ntp*2][0]   = rb[0]; bl[ntp*2][1]   = rb[1];
                bl[ntp*2+1][0] = rb[2]; bl[ntp*2+1][1] = rb[3];
            }
            #pragma unroll
            for (int mt = 0; mt < 4; mt++)
                #pragma unroll
                for (int nt = 0; nt < 4; nt++) {
                    mma16816(acc[mt][nt], ah[mt], bh[nt]);
                    mma16816(acc[mt][nt], al[mt], bh[nt]);
                    mma16816(acc[mt][nt], ah[mt], bl[nt]);
                }
        }
    }

    #pragma unroll
    for (int mt = 0; mt < 4; mt++) {
        int row = m0 + wm + mt*16 + g;
        #pragma unroll
        for (int nt = 0; nt < 4; nt++) {
            int col = n0 + wn + nt*8 + tg*2;
            float b0 = 0.0f, b1 = 0.0f;
            if (bias) { b0 = bias[col]; b1 = bias[col+1]; }
            float v00 = acc[mt][nt][0]*alpha + b0;
            float v01 = acc[mt][nt][1]*alpha + b1;
            float v10 = acc[mt][nt][2]*alpha + b0;
            float v11 = acc[mt][nt][3]*alpha + b1;
            if (C) {
                *(float2*)(C + (long long)row*ldc + col)     = make_float2(v00, v01);
                *(float2*)(C + (long long)(row+8)*ldc + col) = make_float2(v10, v11);
            }
            if (Ch) {
                uint32_t ph, pl;
                split_pack(v00, v01, ph, pl);
                *(uint32_t*)(Ch + (long long)row*ldc + col) = ph;
                *(uint32_t*)(Cl + (long long)row*ldc + col) = pl;
                split_pack(v10, v11, ph, pl);
                *(uint32_t*)(Ch + (long long)(row+8)*ldc + col) = ph;
                *(uint32_t*)(Cl + (long long)(row+8)*ldc + col) = pl;
            }
        }
    }
}

// ---------------- fused flash attention ---------------------------------------
// 144 real K-dims (9 k-steps of 16); smem layout keeps 192-wide tiles.
#define FA_NC    32
#define FA_STG   81920                       // K 49152 + V 32768
#define FA_Q     0
#define FA_S0    49152
#define FA_P     212992
#define FA_REDM  229376
#define FA_REDS  230400
#define FA_SMEM  231424
#define FA_NKS   9

__global__ void __launch_bounds__(256, 1)
flash_attn(const bf16* __restrict__ qph, const bf16* __restrict__ qpl,
           const bf16* __restrict__ kph, const bf16* __restrict__ kpl,
           const bf16* __restrict__ vth, const bf16* __restrict__ vtl,
           bf16* __restrict__ lath, bf16* __restrict__ latl,
           float scale, int bh_base)
{
    extern __shared__ __align__(1024) char smem[];
    const uint32_t sb = smem_u32(smem);

    const int tid  = threadIdx.x;
    const int wid  = tid >> 5;
    const int lane = tid & 31;
    const int wm2  = wid >> 2;
    const int wn4  = wid & 3;
    const int g    = lane >> 2, tg = lane & 3;
    const int piece = lane >> 3, rr = lane & 7;

    const int bh = blockIdx.y + bh_base;
    const int b  = bh >> 3;
    const int qb = blockIdx.x;

    const bf16* qbh = qph + ((size_t)bh*SS + (size_t)qb*64)*KAUG;
    const bf16* qbl = qpl + ((size_t)bh*SS + (size_t)qb*64)*KAUG;
    const bf16* kbh = kph + (size_t)bh*SS*KAUG;
    const bf16* kbl = kpl + (size_t)bh*SS*KAUG;
    const bf16* vbh = vth + (size_t)b*128*SS;
    const bf16* vbl = vtl + (size_t)b*128*SS;

    #pragma unroll
    for (int i = 0; i < 6; i++) {
        int idx = i*256 + tid;
        int row = idx / 24, cc = idx % 24;
        if (cc < 18) {                      // only 144 real cols
            int kt = cc >> 3, c8 = cc & 7;
            uint32_t d = (uint32_t)(kt*8192 + row*128 + (((uint32_t)c8 ^ (row & 7)) << 4));
            cp16(sb + FA_Q +         d, qbh + row*KAUG + cc*8);
            cp16(sb + FA_Q + 24576 + d, qbl + row*KAUG + cc*8);
        }
    }
    CP_COMMIT();

    #define FA_ISSUE(t) do {                                                   \
        uint32_t st_ = sb + FA_S0 + ((t) & 1) * FA_STG;                        \
        const int t0_ = (t) * 64;                                              \
        _Pragma("unroll")                                                      \
        for (int i = 0; i < 6; i++) {                                          \
            int idx = i*256 + tid;                                             \
            int row = idx / 24, cc = idx % 24;                                 \
            if (cc < 18) {                                                     \
                int kt = cc >> 3, c8 = cc & 7;                                 \
                uint32_t d = (uint32_t)(kt*8192 + row*128 + (((uint32_t)c8 ^ (row & 7)) << 4)); \
                cp16(st_ +         d, kbh + (size_t)(t0_+row)*KAUG + cc*8);    \
                cp16(st_ + 24576 + d, kbl + (size_t)(t0_+row)*KAUG + cc*8);    \
            }                                                                  \
        }                                                                      \
        _Pragma("unroll")                                                      \
        for (int i = 0; i < 4; i++) {                                          \
            int idx = i*256 + tid;                                             \
            int row = idx >> 3, c8 = idx & 7;                                  \
            uint32_t d = (uint32_t)(row*128 + (((uint32_t)c8 ^ (row & 7)) << 4)); \
            cp16(st_ + 49152 + d, vbh + (size_t)row*SS + t0_ + c8*8);          \
            cp16(st_ + 65536 + d, vbl + (size_t)row*SS + t0_ + c8*8);          \
        }                                                                      \
        CP_COMMIT();                                                           \
    } while (0)

    FA_ISSUE(0);

    float accv[2][4][4];
    #pragma unroll
    for (int i = 0; i < 2; i++)
        #pragma unroll
        for (int j = 0; j < 4; j++)
            #pragma unroll
            for (int k = 0; k < 4; k++) accv[i][j][k] = 0.0f;
    float Mrow[4] = {-1e30f, -1e30f, -1e30f, -1e30f};
    float Lrow[4] = {0.0f, 0.0f, 0.0f, 0.0f};

    float* redm = (float*)(smem + FA_REDM);
    float* reds = (float*)(smem + FA_REDS);

    for (int t = 0; t < FA_NC; t++) {
        CP_WAIT0();
        __syncthreads();
        if (t + 1 < FA_NC) FA_ISSUE(t + 1);

        const uint32_t KB = sb + FA_S0 + (t & 1) * FA_STG;
        const uint32_t VB = KB + 49152;

        float sacc[2][2][4];
        #pragma unroll
        for (int i = 0; i < 2; i++)
            #pragma unroll
            for (int j = 0; j < 2; j++)
                #pragma unroll
                for (int k = 0; k < 4; k++) sacc[i][j][k] = 0.0f;

        #pragma unroll
        for (int ks = 0; ks < FA_NKS; ks++) {
            const int kt = ks >> 2, ks2 = ks & 3;
            uint32_t ah[2][4], al[2][4];
            #pragma unroll
            for (int mt = 0; mt < 2; mt++) {
                int rowA = wm2*32 + mt*16 + (piece & 1)*8 + rr;
                uint32_t off = (uint32_t)(kt*8192 + rowA*128 +
                    (((ks2*2 + (piece >> 1)) ^ (rowA & 7)) << 4));
                ldm4(ah[mt], sb + FA_Q +         off);
                ldm4(al[mt], sb + FA_Q + 24576 + off);
            }
            int rowB = wn4*16 + (piece >> 1)*8 + rr;
            uint32_t offB = (uint32_t)(kt*8192 + rowB*128 +
                (((ks2*2 + (piece & 1)) ^ (rowB & 7)) << 4));
            uint32_t rbh[4], rbl[4];
            ldm4(rbh, KB +         offB);
            ldm4(rbl, KB + 24576 + offB);
            #pragma unroll
            for (int mt = 0; mt < 2; mt++)
                #pragma unroll
                for (int nt = 0; nt < 2; nt++) {
                    mma16816(sacc[mt][nt], ah[mt], rbh + nt*2);
                    mma16816(sacc[mt][nt], al[mt], rbh + nt*2);
                    mma16816(sacc[mt][nt], ah[mt], rbl + nt*2);
                }
        }

        float mloc[4] = {-1e30f, -1e30f, -1e30f, -1e30f};
        #pragma unroll
        for (int mt = 0; mt < 2; mt++)
            #pragma unroll
            for (int nt = 0; nt < 2; nt++)
                #pragma unroll
                for (int c = 0; c < 4; c++) {
                    sacc[mt][nt][c] *= scale;
                    int slot = mt*2 + (c >> 1);
                    mloc[slot] = fmaxf(mloc[slot], sacc[mt][nt][c]);
                }
        #pragma unroll
        for (int s = 0; s < 4; s++) {
            mloc[s] = fmaxf(mloc[s], __shfl_xor_sync(0xffffffffu, mloc[s], 1));
            mloc[s] = fmaxf(mloc[s], __shfl_xor_sync(0xffffffffu, mloc[s], 2));
        }
        if (tg == 0) {
            #pragma unroll
            for (int mt = 0; mt < 2; mt++)
                #pragma unroll
                for (int h2 = 0; h2 < 2; h2++) {
                    int r = wm2*32 + mt*16 + h2*8 + g;
                    redm[wn4*64 + r] = mloc[mt*2 + h2];
                }
        }
        __syncthreads();

        float fsc[4];
        #pragma unroll
        for (int mt = 0; mt < 2; mt++)
            #pragma unroll
            for (int h2 = 0; h2 < 2; h2++) {
                int r = wm2*32 + mt*16 + h2*8 + g;
                float cm = fmaxf(fmaxf(redm[r], redm[64 + r]),
                                 fmaxf(redm[128 + r], redm[192 + r]));
                int slot = mt*2 + h2;
                float mn = fmaxf(Mrow[slot], cm);
                fsc[slot] = __expf(Mrow[slot] - mn);
                Mrow[slot] = mn;
            }

        float sl[4] = {0.0f, 0.0f, 0.0f, 0.0f};
        #pragma unroll
        for (int mt = 0; mt < 2; mt++)
            #pragma unroll
            for (int nt = 0; nt < 2; nt++)
                #pragma unroll
                for (int c = 0; c < 4; c++) {
                    int slot = mt*2 + (c >> 1);
                    float p = __expf(sacc[mt][nt][c] - Mrow[slot]);
                    sacc[mt][nt][c] = p;
                    sl[slot] += p;
                }
        #pragma unroll
        for (int mt = 0; mt < 2; mt++)
            #pragma unroll
            for (int nt = 0; nt < 4; nt++)
                #pragma unroll
                for (int c = 0; c < 4; c++)
                    accv[mt][nt][c] *= fsc[mt*2 + (c >> 1)];
        #pragma unroll
        for (int s = 0; s < 4; s++) {
            sl[s] += __shfl_xor_sync(0xffffffffu, sl[s], 1);
            sl[s] += __shfl_xor_sync(0xffffffffu, sl[s], 2);
        }
        if (tg == 0) {
            #pragma unroll
            for (int mt = 0; mt < 2; mt++)
                #pragma unroll
                for (int h2 = 0; h2 < 2; h2++) {
                    int r = wm2*32 + mt*16 + h2*8 + g;
                    reds[wn4*64 + r] = sl[mt*2 + h2];
                }
        }
        #pragma unroll
        for (int mt = 0; mt < 2; mt++)
            #pragma unroll
            for (int nt = 0; nt < 2; nt++)
                #pragma unroll
                for (int h2 = 0; h2 < 2; h2++) {
                    int r = wm2*32 + mt*16 + h2*8 + g;
                    int cidx = wn4*2 + nt;
                    uint32_t addr = (uint32_t)(r*128 + ((cidx ^ (r & 7)) << 4) + tg*4);
                    uint32_t ph, pl;
                    split_pack(sacc[mt][nt][2*h2], sacc[mt][nt][2*h2+1], ph, pl);
                    *(uint32_t*)(smem + FA_P +        addr) = ph;
                    *(uint32_t*)(smem + FA_P + 8192 + addr) = pl;
                }
        __syncthreads();

        #pragma unroll
        for (int mt = 0; mt < 2; mt++)
            #pragma unroll
            for (int h2 = 0; h2 < 2; h2++) {
                int r = wm2*32 + mt*16 + h2*8 + g;
                float ssum = reds[r] + reds[64 + r] + reds[128 + r] + reds[192 + r];
                int slot = mt*2 + h2;
                Lrow[slot] = Lrow[slot] * fsc[slot] + ssum;
            }

        #pragma unroll
        for (int ksv = 0; ksv < 4; ksv++) {
            uint32_t pah[2][4], pal[2][4];
            #pragma unroll
            for (int mt = 0; mt < 2; mt++) {
                int rowA = wm2*32 + mt*16 + (piece & 1)*8 + rr;
                uint32_t off = (uint32_t)(rowA*128 +
                    (((ksv*2 + (piece >> 1)) ^ (rowA & 7)) << 4));
                ldm4(pah[mt], sb + FA_P +        off);
                ldm4(pal[mt], sb + FA_P + 8192 + off);
            }
            uint32_t vh[2][4], vl[2][4];
            #pragma unroll
            for (int ntp = 0; ntp < 2; ntp++) {
                int rowB = wn4*32 + ntp*16 + (piece >> 1)*8 + rr;
                uint32_t offB = (uint32_t)(rowB*128 +
                    (((ksv*2 + (piece & 1)) ^ (rowB & 7)) << 4));
                ldm4(vh[ntp], VB +         offB);
                ldm4(vl[ntp], VB + 16384 + offB);
            }
            #pragma unroll
            for (int mt = 0; mt < 2; mt++)
                #pragma unroll
                for (int nt = 0; nt < 4; nt++) {
                    const uint32_t* bhp = vh[nt >> 1] + (nt & 1)*2;
                    const uint32_t* blp = vl[nt >> 1] + (nt & 1)*2;
                    mma16816(accv[mt][nt], pah[mt], bhp);
                    mma16816(accv[mt][nt], pal[mt], bhp);
                    mma16816(accv[mt][nt], pah[mt], blp);
                }
        }
    }

    float inv[4];
    #pragma unroll
    for (int s = 0; s < 4; s++) inv[s] = 1.0f / Lrow[s];

    const int h = bh & 7;
    #pragma unroll
    for (int mt = 0; mt < 2; mt++) {
        #pragma unroll
        for (int nt = 0; nt < 4; nt++) {
            int col = h*128 + wn4*32 + nt*8 + tg*2;
            #pragma unroll
            for (int h2 = 0; h2 < 2; h2++) {
                long long row = (long long)b*SS + qb*64 + wm2*32 + mt*16 + h2*8 + g;
                float v0 = accv[mt][nt][2*h2]   * inv[mt*2 + h2];
                float v1 = accv[mt][nt][2*h2+1] * inv[mt*2 + h2];
                uint32_t ph, pl;
                split_pack(v0, v1, ph, pl);
                *(uint32_t*)(lath + row*1024 + col) = ph;
                *(uint32_t*)(latl + row*1024 + col) = pl;
            }
        }
    }
}

// ---------------- elementwise fp32 -> bf16 hi/lo ------------------------------
__global__ void convert_split_k(const float* __restrict__ in,
                                bf16* __restrict__ oh, bf16* __restrict__ ol,
                                long long n)
{
    long long i = (long long)blockIdx.x * 256 + threadIdx.x;
    if (i < n) {
        bf16 h, l; split_bf16(in[i], h, l);
        oh[i] = h; ol[i] = l;
    }
}

// ---------------- fp32 transpose -> bf16 hi/lo --------------------------------
__global__ void transpose_split_k(const float* __restrict__ in,
                                  bf16* __restrict__ oh, bf16* __restrict__ ol,
                                  int M, int N, int ldi, int ldo,
                                  int zdiv,
                                  long long si1, long long si2,
                                  long long so1, long long so2)
{
    __shared__ float tile[32][33];
    int z = blockIdx.z, z1 = z / zdiv, z2 = z % zdiv;
    in += z1*si1 + z2*si2;
    oh += z1*so1 + z2*so2;
    ol += z1*so1 + z2*so2;

    int x = blockIdx.x*32 + threadIdx.x;
    int y = blockIdx.y*32 + threadIdx.y;
    #pragma unroll
    for (int i = 0; i < 32; i += 8)
        if (x < N && (y+i) < M)
            tile[threadIdx.y+i][threadIdx.x] = in[(long long)(y+i)*ldi + x];
    __syncthreads();
    x = blockIdx.y*32 + threadIdx.x;
    y = blockIdx.x*32 + threadIdx.y;
    #pragma unroll
    for (int i = 0; i < 32; i += 8)
        if (x < M && (y+i) < N) {
            bf16 h, l; split_bf16(tile[threadIdx.x][threadIdx.y+i], h, l);
            oh[(long long)(y+i)*ldo + x] = h;
            ol[(long long)(y+i)*ldo + x] = l;
        }
}

// ---------------- pad+split W_uq / W_uk into [8][128][640] --------------------
__global__ void pad_split_uqk(const float* __restrict__ Wuq,
                              const float* __restrict__ Wuk,
                              bf16* __restrict__ uqh, bf16* __restrict__ uql,
                              bf16* __restrict__ ukh, bf16* __restrict__ ukl)
{
    int idx = blockIdx.x * 256 + threadIdx.x;
    if (idx >= 8*128*640) return;
    int e = idx % 640;
    int c = (idx / 640) & 127;
    int h = idx / (640*128);
    float vq = 0.0f, vk = 0.0f;
    if (e < SPLIT) {
        vq = Wuq[c*4992 + h*SPLIT + e];
        vk = Wuk[c*4992 + h*SPLIT + e];
    }
    bf16 hh, ll;
    split_bf16(vq, hh, ll); uqh[idx] = hh; uql[idx] = ll;
    split_bf16(vk, hh, ll); ukh[idx] = hh; ukl[idx] = ll;
}

// ---------------- bqk -----------------------------------------------------------
__global__ void bqk_kernel(const float* __restrict__ b_uq,
                           const float* __restrict__ W_uk,
                           float* __restrict__ bqk)
{
    int c = threadIdx.x;
    int h = blockIdx.x;
    float acc = 0.0f;
    const float* wrow = W_uk + c*4992 + h*SPLIT;
    const float* brow = b_uq + h*SPLIT;
    for (int e = 0; e < SPLIT; e++)
        acc += brow[e] * wrow[e];
    bqk[h*128 + c] = acc;
}

// ---------------- beff: two-phase deterministic partial reduction --------------
__global__ void beff_partial(const float* __restrict__ b_uv,
                             const float* __restrict__ W_o,
                             float* __restrict__ part)
{
    int o   = blockIdx.x * 256 + threadIdx.x;
    int seg = blockIdx.y;
    float acc = 0.0f;
    int d0 = seg * (D_MODEL/16);
    #pragma unroll 4
    for (int d = d0; d < d0 + D_MODEL/16; d++)
        acc += b_uv[d] * W_o[(size_t)d*D_MODEL + o];
    part[(size_t)seg*D_MODEL + o] = acc;
}

__global__ void beff_reduce(const float* __restrict__ part,
                            const float* __restrict__ b_o,
                            float* __restrict__ be)
{
    int o = blockIdx.x * 256 + threadIdx.x;
    if (o >= D_MODEL) return;
    float acc = b_o[o];
    #pragma unroll
    for (int s = 0; s < 16; s++)
        acc += part[(size_t)s*D_MODEL + o];
    be[o] = acc;
}

// ---------------- assemble augmented Q'/K' (rope) + emit k_rot ----------------
__global__ void assemble_qk(const float* __restrict__ qe,
                            const float* __restrict__ cat1,
                            bf16* __restrict__ qph, bf16* __restrict__ qpl,
                            bf16* __restrict__ kph, bf16* __restrict__ kpl,
                            float* __restrict__ out_krot)
{
    long long idx = (long long)blockIdx.x * 256 + threadIdx.x;
    if (idx >= (long long)16*SS*KAUG) return;
    int j  = (int)(idx % KAUG);
    int s  = (int)((idx / KAUG) & (SS - 1));
    int bh = (int)(idx / ((long long)KAUG*SS));
    int b  = bh >> 3, h = bh & 7;
    long long row = (long long)b*SS + s;

    float qv = 0.0f, kv = 0.0f;
    if (j < 128) {
        qv = qe[row*NQE + h*128 + j];
        kv = cat1[row*NCAT1 + j];
    } else if (j < 144) {
        int dd = j - 128;
        long long qb = row*NQE + 1024 + h*D_ROPE;
        long long kb = row*NCAT1 + 256 + h*D_ROPE;
        if (dd < 8) {
            const float invf[4] = {1.0f, 0.1f, 0.01f, 0.001f};
            float f = ((float)s / 40.0f) * invf[dd & 3];
            float c_ = cosf(f), sn = sinf(f);
            if (dd < 4) {
                qv = qe[qb+dd]*c_ - qe[qb+dd+4]*sn;
                kv = cat1[kb+dd]*c_ - cat1[kb+dd+4]*sn;
            } else {
                qv = qe[qb+dd]*c_ + qe[qb+dd-4]*sn;
                kv = cat1[kb+dd]*c_ + cat1[kb+dd-4]*sn;
            }
        } else {
            qv = qe[qb+dd];
            kv = cat1[kb+dd];
        }
        out_krot[row*128 + h*D_ROPE + dd] = kv;
    } else {
        return;   // cols 144..191 never read by flash (loads guarded)
    }
    bf16 hh, ll;
    split_bf16(qv, hh, ll); qph[idx] = hh; qpl[idx] = ll;
    split_bf16(kv, hh, ll); kph[idx] = hh; kpl[idx] = ll;
}

// ---------------- c_kv output copy ---------------------------------------------
__global__ void copy_ckv(const float* __restrict__ cat1, float* __restrict__ out)
{
    int idx = blockIdx.x * 256 + threadIdx.x;
    if (idx < ROWS * D_KV)
        out[idx] = cat1[(idx >> 7) * NCAT1 + (idx & 127)];
}

// ---------------- host side ------------------------------------------------------
static inline void* symv(const void* s)
{
    void* p = nullptr;
    cudaGetSymbolAddress(&p, s);
    return p;
}

static void gemm_on(cudaStream_t st, int M, int N, int K,
                    const bf16* Ah, const bf16* Al, long long lda,
                    const bf16* Bh, const bf16* Bl, long long ldb,
                    float* C, bf16* Ch, bf16* Cl, long long ldc,
                    const float* bias, float alpha,
                    int nz = 1, int zdiv = 1,
                    long long sA1 = 0, long long sA2 = 0,
                    long long sB1 = 0, long long sB2 = 0,
                    long long sC1 = 0, long long sC2 = 0)
{
    dim3 grid(N / 128, M / 128, nz);
    gemm_mma<<<grid, 256, GEMM_SMEM, st>>>(M, N, K, Ah, Al, lda, Bh, Bl, ldb,
                                           C, Ch, Cl, ldc, bias, alpha, zdiv,
                                           sA1, sA2, sB1, sB2, sC1, sC2);
}

static void tsplit_on(cudaStream_t st, const float* in, bf16* oh, bf16* ol,
                      int M, int N, int ldi, int ldo,
                      int nz = 1, int zdiv = 1,
                      long long si1 = 0, long long si2 = 0,
                      long long so1 = 0, long long so2 = 0)
{
    dim3 grid((N + 31)/32, (M + 31)/32, nz);
    transpose_split_k<<<grid, dim3(32, 8), 0, st>>>(in, oh, ol, M, N, ldi, ldo,
                                                    zdiv, si1, si2, so1, so2);
}

extern "C" void kernel_launch(void* const* d_in, const int* in_sizes, int n_in,
                              void* d_out, int out_size)
{
    const float* h     = (const float*)d_in[0];
    const float* W_dkv = (const float*)d_in[1];
    const float* b_dkv = (const float*)d_in[2];
    const float* W_dq  = (const float*)d_in[3];
    const float* b_dq  = (const float*)d_in[4];
    const float* W_uk  = (const float*)d_in[5];
    const float* b_uk  = (const float*)d_in[6];
    const float* W_uv  = (const float*)d_in[7];
    const float* b_uv  = (const float*)d_in[8];
    const float* W_uq  = (const float*)d_in[9];
    const float* b_uq  = (const float*)d_in[10];
    const float* W_qr  = (const float*)d_in[11];
    const float* b_qr  = (const float*)d_in[12];
    const float* W_kr  = (const float*)d_in[13];
    const float* b_kr  = (const float*)d_in[14];
    const float* W_o   = (const float*)d_in[15];
    const float* b_o   = (const float*)d_in[16];
    (void)b_uk;

    float* out      = (float*)d_out;
    float* out_ckv  = out + (long long)ROWS * D_MODEL;
    float* out_krot = out_ckv + (long long)ROWS * D_KV;

    float* cat1  = (float*)symv(g_cat1);
    bf16*  cat1h = (bf16*)symv(g_cat1h);
    bf16*  cat1l = (bf16*)symv(g_cat1l);
    bf16*  hh    = (bf16*)symv(g_hh);
    bf16*  hl    = (bf16*)symv(g_hl);
    bf16*  w1h   = (bf16*)symv(g_w1h);
    bf16*  w1l   = (bf16*)symv(g_w1l);
    bf16*  uqph  = (bf16*)symv(g_uqph);
    bf16*  uqpl  = (bf16*)symv(g_uqpl);
    bf16*  ukph  = (bf16*)symv(g_ukph);
    bf16*  ukpl  = (bf16*)symv(g_ukpl);
    bf16*  wqkrh = (bf16*)symv(g_wqkrh);
    bf16*  wqkrl = (bf16*)symv(g_wqkrl);
    float* bqkr  = (float*)symv(g_bqkr);
    float* qe    = (float*)symv(g_qe);
    bf16*  qph   = (bf16*)symv(g_qph);
    bf16*  qpl   = (bf16*)symv(g_qpl);
    bf16*  kph   = (bf16*)symv(g_kph);
    bf16*  kpl   = (bf16*)symv(g_kpl);
    bf16*  ckvth = (bf16*)symv(g_ckvth);
    bf16*  ckvtl = (bf16*)symv(g_ckvtl);
    bf16*  lath  = (bf16*)symv(g_lath);
    bf16*  latl  = (bf16*)symv(g_latl);
    bf16*  uvsh  = (bf16*)symv(g_uvsh);
    bf16*  uvsl  = (bf16*)symv(g_uvsl);
    bf16*  woh   = (bf16*)symv(g_woh);
    bf16*  wol   = (bf16*)symv(g_wol);
    bf16*  wcth  = (bf16*)symv(g_wcth);
    bf16*  wctl  = (bf16*)symv(g_wctl);
    float* b1    = (float*)symv(g_b1);
    float* beff  = (float*)symv(g_beff);
    float* beffp = (float*)symv(g_beffp);

    cudaFuncSetAttribute(gemm_mma, cudaFuncAttributeMaxDynamicSharedMemorySize, GEMM_SMEM);
    cudaFuncSetAttribute(flash_attn, cudaFuncAttributeMaxDynamicSharedMemorySize, FA_SMEM);

    const float scale = 1.0f / sqrtf((float)D_HEAD);
    cudaStream_t s0 = 0, s1 = g_aux.s1, s2 = g_aux.s2;

    // ---- fork side streams ----
    cudaEventRecord(g_aux.evFork, s0);
    cudaStreamWaitEvent(s1, g_aux.evFork, 0);
    cudaStreamWaitEvent(s2, g_aux.evFork, 0);

    // ======== s1: Wqk-absorption chain ========
    cudaMemcpyAsync(bqkr+1024, b_qr, 128*sizeof(float), cudaMemcpyDeviceToDevice, s1);
    tsplit_on(s1, W_qr, wqkrh + 1024*128, wqkrl + 1024*128, D_KV, 128, 128, D_KV);
    pad_split_uqk<<<(8*128*640 + 255)/256, 256, 0, s1>>>(W_uq, W_uk, uqph, uqpl, ukph, ukpl);
    bqk_kernel<<<8, 128, 0, s1>>>(b_uq, W_uk, bqkr);
    gemm_on(s1, 128, 128, 640, ukph, ukpl, 640, uqph, uqpl, 640,
            nullptr, wqkrh, wqkrl, 128, nullptr, 1.0f,
            8, 8, 0, (long long)128*640, 0, (long long)128*640, 0, (long long)128*128);
    cudaEventRecord(g_aux.evA, s1);

    // ======== s2: W_o/W_uv-absorption chain ========
    convert_split_k<<<(128*D_MODEL + 255)/256, 256, 0, s2>>>(W_uv, uvsh, uvsl, 128*D_MODEL);
    tsplit_on(s2, W_o, woh, wol, D_MODEL, D_MODEL, D_MODEL, D_MODEL);
    gemm_on(s2, D_MODEL, 128, 640, woh, wol, D_MODEL, uvsh, uvsl, D_MODEL,
            nullptr, wcth, wctl, 1024, nullptr, 1.0f,
            8, 8, 0, 640, 0, 640, 0, 128);
    beff_partial<<<dim3(D_MODEL/256, 16), 256, 0, s2>>>(b_uv, W_o, beffp);
    beff_reduce<<<(D_MODEL + 255)/256, 256, 0, s2>>>(beffp, b_o, beff);
    cudaEventRecord(g_aux.evB, s2);

    // ======== s0: activation critical path ========
    cudaMemcpyAsync(b1,      b_dkv, 128*sizeof(float), cudaMemcpyDeviceToDevice, s0);
    cudaMemcpyAsync(b1+128,  b_dq,  128*sizeof(float), cudaMemcpyDeviceToDevice, s0);
    cudaMemcpyAsync(b1+256,  b_kr,  128*sizeof(float), cudaMemcpyDeviceToDevice, s0);
    tsplit_on(s0, W_dkv, w1h,               w1l,               D_MODEL, D_KV, D_KV, D_MODEL);
    tsplit_on(s0, W_dq,  w1h + 128*D_MODEL, w1l + 128*D_MODEL, D_MODEL, D_KV, D_KV, D_MODEL);
    tsplit_on(s0, W_kr,  w1h + 256*D_MODEL, w1l + 256*D_MODEL, D_MODEL, D_KV, D_KV, D_MODEL);
    {
        long long n = (long long)ROWS * D_MODEL;
        convert_split_k<<<(unsigned)((n + 255)/256), 256, 0, s0>>>(h, hh, hl, n);
    }

    // G1: [ckv | cq | kr_pre] = h @ W1 + b1
    gemm_on(s0, ROWS, NCAT1, D_MODEL, hh, hl, D_MODEL, w1h, w1l, D_MODEL,
            cat1, cat1h, cat1l, NCAT1, b1, 1.0f);
    cudaEventRecord(g_aux.evG1, s0);
    copy_ckv<<<(ROWS*D_KV + 255)/256, 256, 0, s0>>>(cat1, out_ckv);

    // s2: c_kv^T (depends only on G1) in parallel with qe/assemble
    cudaStreamWaitEvent(s2, g_aux.evG1, 0);
    tsplit_on(s2, cat1, ckvth, ckvtl, SS, 128, NCAT1, SS,
              BB, 1, (long long)SS*NCAT1, 0, (long long)128*SS, 0);
    cudaEventRecord(g_aux.evCk, s2);

    // join s1 before qe
    cudaStreamWaitEvent(s0, g_aux.evA, 0);

    // qe = c_q @ [Wqk | Wqr] + [bqk | b_qr]
    gemm_on(s0, ROWS, NQE, 128, cat1h + 128, cat1l + 128, NCAT1, wqkrh, wqkrl, 128,
            qe, nullptr, nullptr, NQE, bqkr, 1.0f);

    {
        long long total = (long long)16*SS*KAUG;
        assemble_qk<<<(unsigned)((total + 255)/256), 256, 0, s0>>>(
            qe, cat1, qph, qpl, kph, kpl, out_krot);
    }

    // flash, batch-split: b=0 then b=1
    cudaStreamWaitEvent(s0, g_aux.evCk, 0);
    flash_attn<<<dim3(SS/64, 8), 256, FA_SMEM, s0>>>(
        qph, qpl, kph, kpl, ckvth, ckvtl, lath, latl, scale, 0);
    cudaEventRecord(g_aux.evF0, s0);
    flash_attn<<<dim3(SS/64, 8), 256, FA_SMEM, s0>>>(
        qph, qpl, kph, kpl, ckvth, ckvtl, lath, latl, scale, 8);

    // s1: final GEMM half 0 (rows of b=0) overlaps with flash b=1
    cudaStreamWaitEvent(s1, g_aux.evF0, 0);
    cudaStreamWaitEvent(s1, g_aux.evB, 0);
    gemm_on(s1, SS, D_MODEL, 1024, lath, latl, 1024, wcth, wctl, 1024,
            out, nullptr, nullptr, D_MODEL, beff, 1.0f);
    cudaEventRecord(g_aux.evH0, s1);

    // s0: final GEMM half 1 (rows of b=1)
    cudaStreamWaitEvent(s0, g_aux.evB, 0);
    gemm_on(s0, SS, D_MODEL, 1024,
            lath + (long long)SS*1024, latl + (long long)SS*1024, 1024,
            wcth, wctl, 1024,
            out + (long long)SS*D_MODEL, nullptr, nullptr, D_MODEL, beff, 1.0f);

    // join s1 back before capture end
    cudaStreamWaitEvent(s0, g_aux.evH0, 0);
}

// round 10
// speedup vs baseline: 9.3959x; 1.0448x over previous
#include <cuda_runtime.h>
#include <cuda_bf16.h>
#include <math.h>
#include <stdint.h>

#define D_MODEL 5120
#define N_HEADS 8
#define D_KV    128
#define D_ROPE  16
#define D_HEAD  640
#define SPLIT   624
#define BB      2
#define SS      2048
#define ROWS    (BB*SS)          // 4096
#define NCAT1   384              // dkv(128) + dq(128) + kr(128)
#define KAUG    192              // smem layout width; only 144 cols real
#define NQE     1152             // 1024 (Wqk) + 128 (Wqr)

typedef __nv_bfloat16 bf16;

// ---------------- scratch (device globals) ----------------------------------
__device__ __align__(16) float g_cat1 [ROWS*NCAT1];
__device__ __align__(16) bf16  g_cat1h[ROWS*NCAT1];
__device__ __align__(16) bf16  g_cat1l[ROWS*NCAT1];
__device__ __align__(16) bf16  g_hh  [(size_t)ROWS*D_MODEL];
__device__ __align__(16) bf16  g_hl  [(size_t)ROWS*D_MODEL];
__device__ __align__(16) bf16  g_w1h [NCAT1*D_MODEL];
__device__ __align__(16) bf16  g_w1l [NCAT1*D_MODEL];
__device__ __align__(16) bf16  g_uqph[8*128*640];
__device__ __align__(16) bf16  g_uqpl[8*128*640];
__device__ __align__(16) bf16  g_ukph[8*128*640];
__device__ __align__(16) bf16  g_ukpl[8*128*640];
__device__ __align__(16) bf16  g_wqkrh[NQE*128];
__device__ __align__(16) bf16  g_wqkrl[NQE*128];
__device__ __align__(16) float g_bqkr[NQE];
__device__ __align__(16) float g_qe  [(size_t)ROWS*NQE];
__device__ __align__(16) bf16  g_qph [(size_t)16*SS*KAUG];
__device__ __align__(16) bf16  g_qpl [(size_t)16*SS*KAUG];
__device__ __align__(16) bf16  g_kph [(size_t)16*SS*KAUG];
__device__ __align__(16) bf16  g_kpl [(size_t)16*SS*KAUG];
__device__ __align__(16) bf16  g_ckvth[BB*128*SS];
__device__ __align__(16) bf16  g_ckvtl[BB*128*SS];
__device__ __align__(16) bf16  g_lath[(size_t)ROWS*1024];
__device__ __align__(16) bf16  g_latl[(size_t)ROWS*1024];
__device__ __align__(16) bf16  g_uvsh[128*D_MODEL];
__device__ __align__(16) bf16  g_uvsl[128*D_MODEL];
__device__ __align__(16) bf16  g_woh [(size_t)D_MODEL*D_MODEL];
__device__ __align__(16) bf16  g_wol [(size_t)D_MODEL*D_MODEL];
__device__ __align__(16) bf16  g_wcth[(size_t)D_MODEL*1024];
__device__ __align__(16) bf16  g_wctl[(size_t)D_MODEL*1024];
__device__ __align__(16) float g_b1  [NCAT1];
__device__ __align__(16) float g_beff[D_MODEL];
__device__ __align__(16) float g_beffp[16*D_MODEL];

// ---------------- streams/events ---------------------------------------------
struct AuxStreams {
    cudaStream_t s1, s2, s3;
    cudaEvent_t  evFork, evW1, evA, evB, evF0, evF1, evH0;
    AuxStreams() {
        cudaStreamCreateWithFlags(&s1, cudaStreamNonBlocking);
        cudaStreamCreateWithFlags(&s2, cudaStreamNonBlocking);
        cudaStreamCreateWithFlags(&s3, cudaStreamNonBlocking);
        cudaEventCreateWithFlags(&evFork, cudaEventDisableTiming);
        cudaEventCreateWithFlags(&evW1,   cudaEventDisableTiming);
        cudaEventCreateWithFlags(&evA,    cudaEventDisableTiming);
        cudaEventCreateWithFlags(&evB,    cudaEventDisableTiming);
        cudaEventCreateWithFlags(&evF0,   cudaEventDisableTiming);
        cudaEventCreateWithFlags(&evF1,   cudaEventDisableTiming);
        cudaEventCreateWithFlags(&evH0,   cudaEventDisableTiming);
    }
};
static AuxStreams g_aux;

// ---------------- PTX helpers ------------------------------------------------
__device__ __forceinline__ uint32_t smem_u32(const void* p) {
    uint32_t a;
    asm("{ .reg .u64 t; cvta.to.shared.u64 t, %1; cvt.u32.u64 %0, t; }"
        : "=r"(a) : "l"(p));
    return a;
}

__device__ __forceinline__ void cp16(uint32_t dst, const void* src) {
    asm volatile("cp.async.cg.shared.global [%0], [%1], 16;\n"
                 :: "r"(dst), "l"(__cvta_generic_to_global(src)));
}
#define CP_COMMIT() asm volatile("cp.async.commit_group;\n" ::: "memory")
#define CP_WAIT1()  asm volatile("cp.async.wait_group 1;\n" ::: "memory")
#define CP_WAIT0()  asm volatile("cp.async.wait_group 0;\n" ::: "memory")

__device__ __forceinline__ void ldm4(uint32_t* r, uint32_t a) {
    asm volatile("ldmatrix.sync.aligned.m8n8.x4.shared.b16 {%0,%1,%2,%3}, [%4];"
                 : "=r"(r[0]), "=r"(r[1]), "=r"(r[2]), "=r"(r[3]) : "r"(a));
}

__device__ __forceinline__ void mma16816(float* c, const uint32_t* a, const uint32_t* b) {
    asm volatile(
        "mma.sync.aligned.m16n8k16.row.col.f32.bf16.bf16.f32 "
        "{%0,%1,%2,%3},{%4,%5,%6,%7},{%8,%9},{%0,%1,%2,%3};\n"
        : "+f"(c[0]), "+f"(c[1]), "+f"(c[2]), "+f"(c[3])
        : "r"(a[0]), "r"(a[1]), "r"(a[2]), "r"(a[3]), "r"(b[0]), "r"(b[1]));
}

__device__ __forceinline__ uint32_t pack2(float a, float b) {
    __nv_bfloat162 t = __floats2bfloat162_rn(a, b);
    return *reinterpret_cast<const uint32_t*>(&t);
}

__device__ __forceinline__ void split_bf16(float v, bf16& h, bf16& l) {
    h = __float2bfloat16(v);
    l = __float2bfloat16(v - __bfloat162float(h));
}

__device__ __forceinline__ void split_pack(float a, float b, uint32_t& ph, uint32_t& pl) {
    bf16 ha = __float2bfloat16(a), hb = __float2bfloat16(b);
    ph = ((uint32_t)*(uint16_t*)&hb << 16) | (uint32_t)*(uint16_t*)&ha;
    pl = pack2(a - __bfloat162float(ha), b - __bfloat162float(hb));
}

// ---------------- bf16x3 mma.sync GEMM ---------------------------------------
#define STAGE_BYTES 65536
#define GEMM_SMEM   (3*STAGE_BYTES)

__global__ void __launch_bounds__(256, 1)
gemm_mma(int M, int N, int K,
         const bf16* __restrict__ Ah_, const bf16* __restrict__ Al_, long long lda,
         const bf16* __restrict__ Bh_, const bf16* __restrict__ Bl_, long long ldb,
         float* __restrict__ C, bf16* __restrict__ Ch, bf16* __restrict__ Cl,
         long long ldc,
         const float* __restrict__ bias, float alpha,
         int zdiv,
         long long sA1, long long sA2,
         long long sB1, long long sB2,
         long long sC1, long long sC2)
{
    extern __shared__ __align__(1024) char smem[];
    const uint32_t sb = smem_u32(smem);

    {
        int z  = blockIdx.z;
        int z1 = z / zdiv, z2 = z % zdiv;
        Ah_ += z1*sA1 + z2*sA2;  Al_ += z1*sA1 + z2*sA2;
        Bh_ += z1*sB1 + z2*sB2;  Bl_ += z1*sB1 + z2*sB2;
        long long co = z1*sC1 + z2*sC2;
        if (C)  C  += co;
        if (Ch) { Ch += co; Cl += co; }
    }

    const int tid  = threadIdx.x;
    const int wid  = tid >> 5;
    const int lane = tid & 31;
    const int wm   = (wid >> 2) * 64;
    const int wn   = (wid & 3) * 32;
    const int g    = lane >> 2, tg = lane & 3;
    const int m0   = blockIdx.y * 128;
    const int n0   = blockIdx.x * 128;

    const int lrow = tid >> 1;
    const int half = tid & 1;
    const bf16* pAh = Ah_ + (long long)(m0 + lrow)*lda;
    const bf16* pAl = Al_ + (long long)(m0 + lrow)*lda;
    const bf16* pBh = Bh_ + (long long)(n0 + lrow)*ldb;
    const bf16* pBl = Bl_ + (long long)(n0 + lrow)*ldb;
    const uint32_t lswz = (uint32_t)(lrow & 7);

    const int nk = K / 64;

    const int piece = lane >> 3, rr = lane & 7;
    const int rowA  = wm + (piece & 1)*8 + rr;
    const int rowB  = wn + (piece >> 1)*8 + rr;
    const int cA    = piece >> 1;
    const int cB    = piece & 1;

    float acc[4][4][4];
    #pragma unroll
    for (int i = 0; i < 4; i++)
        #pragma unroll
        for (int j = 0; j < 4; j++)
            #pragma unroll
            for (int k = 0; k < 4; k++) acc[i][j][k] = 0.0f;

    #define ISSUE(t) do {                                                     \
        uint32_t s0_ = sb + ((t) % 3) * STAGE_BYTES;                          \
        const int k0_ = (t) * 64;                                             \
        _Pragma("unroll")                                                     \
        for (int j = 0; j < 4; j++) {                                         \
            int ch_ = half*4 + j;                                             \
            uint32_t d_ = (uint32_t)(lrow*128 + (((uint32_t)ch_ ^ lswz) << 4)); \
            cp16(s0_ +         d_, pAh + k0_ + ch_*8);                        \
            cp16(s0_ + 16384 + d_, pAl + k0_ + ch_*8);                        \
            cp16(s0_ + 32768 + d_, pBh + k0_ + ch_*8);                        \
            cp16(s0_ + 49152 + d_, pBl + k0_ + ch_*8);                        \
        }                                                                     \
        CP_COMMIT();                                                          \
    } while (0)

    ISSUE(0);
    if (nk > 1) ISSUE(1);

    for (int t = 0; t < nk; t++) {
        if (t + 1 < nk) { CP_WAIT1(); } else { CP_WAIT0(); }
        __syncthreads();
        if (t + 2 < nk) ISSUE(t + 2);

        const uint32_t Ab = sb + (t % 3) * STAGE_BYTES;
        const uint32_t Bb = Ab + 32768;

        #pragma unroll
        for (int ks = 0; ks < 4; ks++) {
            uint32_t ah[4][4], al[4][4], bh[4][2], bl[4][2];
            const uint32_t aoff = (uint32_t)(rowA*128 + (((ks*2 + cA) ^ (rowA & 7)) << 4));
            const uint32_t boff = (uint32_t)(rowB*128 + (((ks*2 + cB) ^ (rowB & 7)) << 4));
            #pragma unroll
            for (int mt = 0; mt < 4; mt++) {
                ldm4(ah[mt], Ab +          aoff + mt*2048);
                ldm4(al[mt], Ab + 16384 +  aoff + mt*2048);
            }
            #pragma unroll
            for (int ntp = 0; ntp < 2; ntp++) {
                uint32_t rb[4];
                ldm4(rb, Bb +          boff + ntp*2048);
                bh[ntp*2][0]   = rb[0]; bh[ntp*2][1]   = rb[1];
                bh[ntp*2+1][0] = rb[2]; bh[ntp*2+1][1] = rb[3];
                ldm4(rb, Bb + 16384 +  boff + ntp*2048);
                bl[ntp*2][0]   = rb[0]; bl[ntp*2][1]   = rb[1];
                bl[ntp*2+1][0] = rb[2]; bl[ntp*2+1][1] = rb[3];
            }
            #pragma unroll
            for (int mt = 0; mt < 4; mt++)
                #pragma unroll
                for (int nt = 0; nt < 4; nt++) {
                    mma16816(acc[mt][nt], ah[mt], bh[nt]);
                    mma16816(acc[mt][nt], al[mt], bh[nt]);
                    mma16816(acc[mt][nt], ah[mt], bl[nt]);
                }
        }
    }

    #pragma unroll
    for (int mt = 0; mt < 4; mt++) {
        int row = m0 + wm + mt*16 + g;
        #pragma unroll
        for (int nt = 0; nt < 4; nt++) {
            int col = n0 + wn + nt*8 + tg*2;
            float b0 = 0.0f, b1 = 0.0f;
            if (bias) { b0 = bias[col]; b1 = bias[col+1]; }
            float v00 = acc[mt][nt][0]*alpha + b0;
            float v01 = acc[mt][nt][1]*alpha + b1;
            float v10 = acc[mt][nt][2]*alpha + b0;
            float v11 = acc[mt][nt][3]*alpha + b1;
            if (C) {
                *(float2*)(C + (long long)row*ldc + col)     = make_float2(v00, v01);
                *(float2*)(C + (long long)(row+8)*ldc + col) = make_float2(v10, v11);
            }
            if (Ch) {
                uint32_t ph, pl;
                split_pack(v00, v01, ph, pl);
                *(uint32_t*)(Ch + (long long)row*ldc + col) = ph;
                *(uint32_t*)(Cl + (long long)row*ldc + col) = pl;
                split_pack(v10, v11, ph, pl);
                *(uint32_t*)(Ch + (long long)(row+8)*ldc + col) = ph;
                *(uint32_t*)(Cl + (long long)(row+8)*ldc + col) = pl;
            }
        }
    }
}

// ---------------- fused flash attention ---------------------------------------
#define FA_NC    32
#define FA_STG   81920                       // K 49152 + V 32768
#define FA_Q     0
#define FA_S0    49152
#define FA_P     212992
#define FA_REDM  229376
#define FA_REDS  230400
#define FA_SMEM  231424
#define FA_NKS   9

__global__ void __launch_bounds__(256, 1)
flash_attn(const bf16* __restrict__ qph, const bf16* __restrict__ qpl,
           const bf16* __restrict__ kph, const bf16* __restrict__ kpl,
           const bf16* __restrict__ vth, const bf16* __restrict__ vtl,
           bf16* __restrict__ lath, bf16* __restrict__ latl,
           float scale, int bh_base)
{
    extern __shared__ __align__(1024) char smem[];
    const uint32_t sb = smem_u32(smem);

    const int tid  = threadIdx.x;
    const int wid  = tid >> 5;
    const int lane = tid & 31;
    const int wm2  = wid >> 2;
    const int wn4  = wid & 3;
    const int g    = lane >> 2, tg = lane & 3;
    const int piece = lane >> 3, rr = lane & 7;

    const int bh = blockIdx.y + bh_base;
    const int b  = bh >> 3;
    const int qb = blockIdx.x;

    const bf16* qbh = qph + ((size_t)bh*SS + (size_t)qb*64)*KAUG;
    const bf16* qbl = qpl + ((size_t)bh*SS + (size_t)qb*64)*KAUG;
    const bf16* kbh = kph + (size_t)bh*SS*KAUG;
    const bf16* kbl = kpl + (size_t)bh*SS*KAUG;
    const bf16* vbh = vth + (size_t)b*128*SS;
    const bf16* vbl = vtl + (size_t)b*128*SS;

    #pragma unroll
    for (int i = 0; i < 6; i++) {
        int idx = i*256 + tid;
        int row = idx / 24, cc = idx % 24;
        if (cc < 18) {
            int kt = cc >> 3, c8 = cc & 7;
            uint32_t d = (uint32_t)(kt*8192 + row*128 + (((uint32_t)c8 ^ (row & 7)) << 4));
            cp16(sb + FA_Q +         d, qbh + row*KAUG + cc*8);
            cp16(sb + FA_Q + 24576 + d, qbl + row*KAUG + cc*8);
        }
    }
    CP_COMMIT();

    #define FA_ISSUE(t) do {                                                   \
        uint32_t st_ = sb + FA_S0 + ((t) & 1) * FA_STG;                        \
        const int t0_ = (t) * 64;                                              \
        _Pragma("unroll")                                                      \
        for (int i = 0; i < 6; i++) {                                          \
            int idx = i*256 + tid;                                             \
            int row = idx / 24, cc = idx % 24;                                 \
            if (cc < 18) {                                                     \
                int kt = cc >> 3, c8 = cc & 7;                                 \
                uint32_t d = (uint32_t)(kt*8192 + row*128 + (((uint32_t)c8 ^ (row & 7)) << 4)); \
                cp16(st_ +         d, kbh + (size_t)(t0_+row)*KAUG + cc*8);    \
                cp16(st_ + 24576 + d, kbl + (size_t)(t0_+row)*KAUG + cc*8);    \
            }                                                                  \
        }                                                                      \
        _Pragma("unroll")                                                      \
        for (int i = 0; i < 4; i++) {                                          \
            int idx = i*256 + tid;                                             \
            int row = idx >> 3, c8 = idx & 7;                                  \
            uint32_t d = (uint32_t)(row*128 + (((uint32_t)c8 ^ (row & 7)) << 4)); \
            cp16(st_ + 49152 + d, vbh + (size_t)row*SS + t0_ + c8*8);          \
            cp16(st_ + 65536 + d, vbl + (size_t)row*SS + t0_ + c8*8);          \
        }                                                                      \
        CP_COMMIT();                                                           \
    } while (0)

    FA_ISSUE(0);

    float accv[2][4][4];
    #pragma unroll
    for (int i = 0; i < 2; i++)
        #pragma unroll
        for (int j = 0; j < 4; j++)
            #pragma unroll
            for (int k = 0; k < 4; k++) accv[i][j][k] = 0.0f;
    float Mrow[4] = {-1e30f, -1e30f, -1e30f, -1e30f};
    float Lrow[4] = {0.0f, 0.0f, 0.0f, 0.0f};

    float* redm = (float*)(smem + FA_REDM);
    float* reds = (float*)(smem + FA_REDS);

    for (int t = 0; t < FA_NC; t++) {
        CP_WAIT0();
        __syncthreads();
        if (t + 1 < FA_NC) FA_ISSUE(t + 1);

        const uint32_t KB = sb + FA_S0 + (t & 1) * FA_STG;
        const uint32_t VB = KB + 49152;

        float sacc[2][2][4];
        #pragma unroll
        for (int i = 0; i < 2; i++)
            #pragma unroll
            for (int j = 0; j < 2; j++)
                #pragma unroll
                for (int k = 0; k < 4; k++) sacc[i][j][k] = 0.0f;

        #pragma unroll
        for (int ks = 0; ks < FA_NKS; ks++) {
            const int kt = ks >> 2, ks2 = ks & 3;
            uint32_t ah[2][4], al[2][4];
            #pragma unroll
            for (int mt = 0; mt < 2; mt++) {
                int rowA = wm2*32 + mt*16 + (piece & 1)*8 + rr;
                uint32_t off = (uint32_t)(kt*8192 + rowA*128 +
                    (((ks2*2 + (piece >> 1)) ^ (rowA & 7)) << 4));
                ldm4(ah[mt], sb + FA_Q +         off);
                ldm4(al[mt], sb + FA_Q + 24576 + off);
            }
            int rowB = wn4*16 + (piece >> 1)*8 + rr;
            uint32_t offB = (uint32_t)(kt*8192 + rowB*128 +
                (((ks2*2 + (piece & 1)) ^ (rowB & 7)) << 4));
            uint32_t rbh[4], rbl[4];
            ldm4(rbh, KB +         offB);
            ldm4(rbl, KB + 24576 + offB);
            #pragma unroll
            for (int mt = 0; mt < 2; mt++)
                #pragma unroll
                for (int nt = 0; nt < 2; nt++) {
                    mma16816(sacc[mt][nt], ah[mt], rbh + nt*2);
                    mma16816(sacc[mt][nt], al[mt], rbh + nt*2);
                    mma16816(sacc[mt][nt], ah[mt], rbl + nt*2);
                }
        }

        float mloc[4] = {-1e30f, -1e30f, -1e30f, -1e30f};
        #pragma unroll
        for (int mt = 0; mt < 2; mt++)
            #pragma unroll
            for (int nt = 0; nt < 2; nt++)
                #pragma unroll
                for (int c = 0; c < 4; c++) {
                    sacc[mt][nt][c] *= scale;
                    int slot = mt*2 + (c >> 1);
                    mloc[slot] = fmaxf(mloc[slot], sacc[mt][nt][c]);
                }
        #pragma unroll
        for (int s = 0; s < 4; s++) {
            mloc[s] = fmaxf(mloc[s], __shfl_xor_sync(0xffffffffu, mloc[s], 1));
            mloc[s] = fmaxf(mloc[s], __shfl_xor_sync(0xffffffffu, mloc[s], 2));
        }
        if (tg == 0) {
            #pragma unroll
            for (int mt = 0; mt < 2; mt++)
                #pragma unroll
                for (int h2 = 0; h2 < 2; h2++) {
                    int r = wm2*32 + mt*16 + h2*8 + g;
                    redm[wn4*64 + r] = mloc[mt*2 + h2];
                }
        }
        __syncthreads();

        float fsc[4];
        #pragma unroll
        for (int mt = 0; mt < 2; mt++)
            #pragma unroll
            for (int h2 = 0; h2 < 2; h2++) {
                int r = wm2*32 + mt*16 + h2*8 + g;
                float cm = fmaxf(fmaxf(redm[r], redm[64 + r]),
                                 fmaxf(redm[128 + r], redm[192 + r]));
                int slot = mt*2 + h2;
                float mn = fmaxf(Mrow[slot], cm);
                fsc[slot] = __expf(Mrow[slot] - mn);
                Mrow[slot] = mn;
            }

        float sl[4] = {0.0f, 0.0f, 0.0f, 0.0f};
        #pragma unroll
        for (int mt = 0; mt < 2; mt++)
            #pragma unroll
            for (int nt = 0; nt < 2; nt++)
                #pragma unroll
                for (int c = 0; c < 4; c++) {
                    int slot = mt*2 + (c >> 1);
                    float p = __expf(sacc[mt][nt][c] - Mrow[slot]);
                    sacc[mt][nt][c] = p;
                    sl[slot] += p;
                }
        #pragma unroll
        for (int mt = 0; mt < 2; mt++)
            #pragma unroll
            for (int nt = 0; nt < 4; nt++)
                #pragma unroll
                for (int c = 0; c < 4; c++)
                    accv[mt][nt][c] *= fsc[mt*2 + (c >> 1)];
        #pragma unroll
        for (int s = 0; s < 4; s++) {
            sl[s] += __shfl_xor_sync(0xffffffffu, sl[s], 1);
            sl[s] += __shfl_xor_sync(0xffffffffu, sl[s], 2);
        }
        if (tg == 0) {
            #pragma unroll
            for (int mt = 0; mt < 2; mt++)
                #pragma unroll
                for (int h2 = 0; h2 < 2; h2++) {
                    int r = wm2*32 + mt*16 + h2*8 + g;
                    reds[wn4*64 + r] = sl[mt*2 + h2];
                }
        }
        #pragma unroll
        for (int mt = 0; mt < 2; mt++)
            #pragma unroll
            for (int nt = 0; nt < 2; nt++)
                #pragma unroll
                for (int h2 = 0; h2 < 2; h2++) {
                    int r = wm2*32 + mt*16 + h2*8 + g;
                    int cidx = wn4*2 + nt;
                    uint32_t addr = (uint32_t)(r*128 + ((cidx ^ (r & 7)) << 4) + tg*4);
                    uint32_t ph, pl;
                    split_pack(sacc[mt][nt][2*h2], sacc[mt][nt][2*h2+1], ph, pl);
                    *(uint32_t*)(smem + FA_P +        addr) = ph;
                    *(uint32_t*)(smem + FA_P + 8192 + addr) = pl;
                }
        __syncthreads();

        #pragma unroll
        for (int mt = 0; mt < 2; mt++)
            #pragma unroll
            for (int h2 = 0; h2 < 2; h2++) {
                int r = wm2*32 + mt*16 + h2*8 + g;
                float ssum = reds[r] + reds[64 + r] + reds[128 + r] + reds[192 + r];
                int slot = mt*2 + h2;
                Lrow[slot] = Lrow[slot] * fsc[slot] + ssum;
            }

        #pragma unroll
        for (int ksv = 0; ksv < 4; ksv++) {
            uint32_t pah[2][4], pal[2][4];
            #pragma unroll
            for (int mt = 0; mt < 2; mt++) {
                int rowA = wm2*32 + mt*16 + (piece & 1)*8 + rr;
                uint32_t off = (uint32_t)(rowA*128 +
                    (((ksv*2 + (piece >> 1)) ^ (rowA & 7)) << 4));
                ldm4(pah[mt], sb + FA_P +        off);
                ldm4(pal[mt], sb + FA_P + 8192 + off);
            }
            uint32_t vh[2][4], vl[2][4];
            #pragma unroll
            for (int ntp = 0; ntp < 2; ntp++) {
                int rowB = wn4*32 + ntp*16 + (piece >> 1)*8 + rr;
                uint32_t offB = (uint32_t)(rowB*128 +
                    (((ksv*2 + (piece & 1)) ^ (rowB & 7)) << 4));
                ldm4(vh[ntp], VB +         offB);
                ldm4(vl[ntp], VB + 16384 + offB);
            }
            #pragma unroll
            for (int mt = 0; mt < 2; mt++)
                #pragma unroll
                for (int nt = 0; nt < 4; nt++) {
                    const uint32_t* bhp = vh[nt >> 1] + (nt & 1)*2;
                    const uint32_t* blp = vl[nt >> 1] + (nt & 1)*2;
                    mma16816(accv[mt][nt], pah[mt], bhp);
                    mma16816(accv[mt][nt], pal[mt], bhp);
                    mma16816(accv[mt][nt], pah[mt], blp);
                }
        }
    }

    float inv[4];
    #pragma unroll
    for (int s = 0; s < 4; s++) inv[s] = 1.0f / Lrow[s];

    const int h = bh & 7;
    #pragma unroll
    for (int mt = 0; mt < 2; mt++) {
        #pragma unroll
        for (int nt = 0; nt < 4; nt++) {
            int col = h*128 + wn4*32 + nt*8 + tg*2;
            #pragma unroll
            for (int h2 = 0; h2 < 2; h2++) {
                long long row = (long long)b*SS + qb*64 + wm2*32 + mt*16 + h2*8 + g;
                float v0 = accv[mt][nt][2*h2]   * inv[mt*2 + h2];
                float v1 = accv[mt][nt][2*h2+1] * inv[mt*2 + h2];
                uint32_t ph, pl;
                split_pack(v0, v1, ph, pl);
                *(uint32_t*)(lath + row*1024 + col) = ph;
                *(uint32_t*)(latl + row*1024 + col) = pl;
            }
        }
    }
}

// ---------------- elementwise fp32 -> bf16 hi/lo ------------------------------
__global__ void convert_split_k(const float* __restrict__ in,
                                bf16* __restrict__ oh, bf16* __restrict__ ol,
                                long long n)
{
    long long i = (long long)blockIdx.x * 256 + threadIdx.x;
    if (i < n) {
        bf16 h, l; split_bf16(in[i], h, l);
        oh[i] = h; ol[i] = l;
    }
}

// ---------------- fp32 transpose -> bf16 hi/lo --------------------------------
__global__ void transpose_split_k(const float* __restrict__ in,
                                  bf16* __restrict__ oh, bf16* __restrict__ ol,
                                  int M, int N, int ldi, int ldo,
                                  int zdiv,
                                  long long si1, long long si2,
                                  long long so1, long long so2)
{
    __shared__ float tile[32][33];
    int z = blockIdx.z, z1 = z / zdiv, z2 = z % zdiv;
    in += z1*si1 + z2*si2;
    oh += z1*so1 + z2*so2;
    ol += z1*so1 + z2*so2;

    int x = blockIdx.x*32 + threadIdx.x;
    int y = blockIdx.y*32 + threadIdx.y;
    #pragma unroll
    for (int i = 0; i < 32; i += 8)
        if (x < N && (y+i) < M)
            tile[threadIdx.y+i][threadIdx.x] = in[(long long)(y+i)*ldi + x];
    __syncthreads();
    x = blockIdx.y*32 + threadIdx.x;
    y = blockIdx.x*32 + threadIdx.y;
    #pragma unroll
    for (int i = 0; i < 32; i += 8)
        if (x < M && (y+i) < N) {
            bf16 h, l; split_bf16(tile[threadIdx.x][threadIdx.y+i], h, l);
            oh[(long long)(y+i)*ldo + x] = h;
            ol[(long long)(y+i)*ldo + x] = l;
        }
}

// ---------------- pad+split W_uq / W_uk into [8][128][640] --------------------
__global__ void pad_split_uqk(const float* __restrict__ Wuq,
                              const float* __restrict__ Wuk,
                              bf16* __restrict__ uqh, bf16* __restrict__ uql,
                              bf16* __restrict__ ukh, bf16* __restrict__ ukl)
{
    int idx = blockIdx.x * 256 + threadIdx.x;
    if (idx >= 8*128*640) return;
    int e = idx % 640;
    int c = (idx / 640) & 127;
    int h = idx / (640*128);
    float vq = 0.0f, vk = 0.0f;
    if (e < SPLIT) {
        vq = Wuq[c*4992 + h*SPLIT + e];
        vk = Wuk[c*4992 + h*SPLIT + e];
    }
    bf16 hh, ll;
    split_bf16(vq, hh, ll); uqh[idx] = hh; uql[idx] = ll;
    split_bf16(vk, hh, ll); ukh[idx] = hh; ukl[idx] = ll;
}

// ---------------- bqk -----------------------------------------------------------
__global__ void bqk_kernel(const float* __restrict__ b_uq,
                           const float* __restrict__ W_uk,
                           float* __restrict__ bqk)
{
    int c = threadIdx.x;
    int h = blockIdx.x;
    float acc = 0.0f;
    const float* wrow = W_uk + c*4992 + h*SPLIT;
    const float* brow = b_uq + h*SPLIT;
    for (int e = 0; e < SPLIT; e++)
        acc += brow[e] * wrow[e];
    bqk[h*128 + c] = acc;
}

// ---------------- beff ----------------------------------------------------------
__global__ void beff_partial(const float* __restrict__ b_uv,
                             const float* __restrict__ W_o,
                             float* __restrict__ part)
{
    int o   = blockIdx.x * 256 + threadIdx.x;
    int seg = blockIdx.y;
    float acc = 0.0f;
    int d0 = seg * (D_MODEL/16);
    #pragma unroll 4
    for (int d = d0; d < d0 + D_MODEL/16; d++)
        acc += b_uv[d] * W_o[(size_t)d*D_MODEL + o];
    part[(size_t)seg*D_MODEL + o] = acc;
}

__global__ void beff_reduce(const float* __restrict__ part,
                            const float* __restrict__ b_o,
                            float* __restrict__ be)
{
    int o = blockIdx.x * 256 + threadIdx.x;
    if (o >= D_MODEL) return;
    float acc = b_o[o];
    #pragma unroll
    for (int s = 0; s < 16; s++)
        acc += part[(size_t)s*D_MODEL + o];
    be[o] = acc;
}

// ---------------- assemble Q'/K' (rope) for 8 bh, emit k_rot -------------------
__global__ void assemble_qk(const float* __restrict__ qe,
                            const float* __restrict__ cat1,
                            bf16* __restrict__ qph, bf16* __restrict__ qpl,
                            bf16* __restrict__ kph, bf16* __restrict__ kpl,
                            float* __restrict__ out_krot, int bh_base)
{
    long long idx = (long long)blockIdx.x * 256 + threadIdx.x;
    if (idx >= (long long)8*SS*KAUG) return;
    int j  = (int)(idx % KAUG);
    int s  = (int)((idx / KAUG) & (SS - 1));
    int bh = (int)(idx / ((long long)KAUG*SS)) + bh_base;
    long long gidx = (long long)bh*SS*KAUG + (long long)s*KAUG + j;
    int b  = bh >> 3, h = bh & 7;
    long long row = (long long)b*SS + s;

    float qv = 0.0f, kv = 0.0f;
    if (j < 128) {
        qv = qe[row*NQE + h*128 + j];
        kv = cat1[row*NCAT1 + j];
    } else if (j < 144) {
        int dd = j - 128;
        long long qb = row*NQE + 1024 + h*D_ROPE;
        long long kb = row*NCAT1 + 256 + h*D_ROPE;
        if (dd < 8) {
            const float invf[4] = {1.0f, 0.1f, 0.01f, 0.001f};
            float f = ((float)s / 40.0f) * invf[dd & 3];
            float c_ = cosf(f), sn = sinf(f);
            if (dd < 4) {
                qv = qe[qb+dd]*c_ - qe[qb+dd+4]*sn;
                kv = cat1[kb+dd]*c_ - cat1[kb+dd+4]*sn;
            } else {
                qv = qe[qb+dd]*c_ + qe[qb+dd-4]*sn;
                kv = cat1[kb+dd]*c_ + cat1[kb+dd-4]*sn;
            }
        } else {
            qv = qe[qb+dd];
            kv = cat1[kb+dd];
        }
        out_krot[row*128 + h*D_ROPE + dd] = kv;
    } else {
        return;
    }
    bf16 hh, ll;
    split_bf16(qv, hh, ll); qph[gidx] = hh; qpl[gidx] = ll;
    split_bf16(kv, hh, ll); kph[gidx] = hh; kpl[gidx] = ll;
}

// ---------------- c_kv output copy (per-batch) ---------------------------------
__global__ void copy_ckv(const float* __restrict__ cat1, float* __restrict__ out,
                         int row0)
{
    int idx = blockIdx.x * 256 + threadIdx.x;
    if (idx < SS * D_KV) {
        int row = row0 + (idx >> 7);
        out[(long long)row*D_KV + (idx & 127)] = cat1[(long long)row*NCAT1 + (idx & 127)];
    }
}

// ---------------- host side ------------------------------------------------------
static inline void* symv(const void* s)
{
    void* p = nullptr;
    cudaGetSymbolAddress(&p, s);
    return p;
}

static void gemm_on(cudaStream_t st, int M, int N, int K,
                    const bf16* Ah, const bf16* Al, long long lda,
                    const bf16* Bh, const bf16* Bl, long long ldb,
                    float* C, bf16* Ch, bf16* Cl, long long ldc,
                    const float* bias, float alpha,
                    int nz = 1, int zdiv = 1,
                    long long sA1 = 0, long long sA2 = 0,
                    long long sB1 = 0, long long sB2 = 0,
                    long long sC1 = 0, long long sC2 = 0)
{
    dim3 grid(N / 128, M / 128, nz);
    gemm_mma<<<grid, 256, GEMM_SMEM, st>>>(M, N, K, Ah, Al, lda, Bh, Bl, ldb,
                                           C, Ch, Cl, ldc, bias, alpha, zdiv,
                                           sA1, sA2, sB1, sB2, sC1, sC2);
}

static void tsplit_on(cudaStream_t st, const float* in, bf16* oh, bf16* ol,
                      int M, int N, int ldi, int ldo)
{
    dim3 grid((N + 31)/32, (M + 31)/32, 1);
    transpose_split_k<<<grid, dim3(32, 8), 0, st>>>(in, oh, ol, M, N, ldi, ldo,
                                                    1, 0, 0, 0, 0);
}

extern "C" void kernel_launch(void* const* d_in, const int* in_sizes, int n_in,
                              void* d_out, int out_size)
{
    const float* h     = (const float*)d_in[0];
    const float* W_dkv = (const float*)d_in[1];
    const float* b_dkv = (const float*)d_in[2];
    const float* W_dq  = (const float*)d_in[3];
    const float* b_dq  = (const float*)d_in[4];
    const float* W_uk  = (const float*)d_in[5];
    const float* b_uk  = (const float*)d_in[6];
    const float* W_uv  = (const float*)d_in[7];
    const float* b_uv  = (const float*)d_in[8];
    const float* W_uq  = (const float*)d_in[9];
    const float* b_uq  = (const float*)d_in[10];
    const float* W_qr  = (const float*)d_in[11];
    const float* b_qr  = (const float*)d_in[12];
    const float* W_kr  = (const float*)d_in[13];
    const float* b_kr  = (const float*)d_in[14];
    const float* W_o   = (const float*)d_in[15];
    const float* b_o   = (const float*)d_in[16];
    (void)b_uk;

    float* out      = (float*)d_out;
    float* out_ckv  = out + (long long)ROWS * D_MODEL;
    float* out_krot = out_ckv + (long long)ROWS * D_KV;

    float* cat1  = (float*)symv(g_cat1);
    bf16*  cat1h = (bf16*)symv(g_cat1h);
    bf16*  cat1l = (bf16*)symv(g_cat1l);
    bf16*  hh    = (bf16*)symv(g_hh);
    bf16*  hl    = (bf16*)symv(g_hl);
    bf16*  w1h   = (bf16*)symv(g_w1h);
    bf16*  w1l   = (bf16*)symv(g_w1l);
    bf16*  uqph  = (bf16*)symv(g_uqph);
    bf16*  uqpl  = (bf16*)symv(g_uqpl);
    bf16*  ukph  = (bf16*)symv(g_ukph);
    bf16*  ukpl  = (bf16*)symv(g_ukpl);
    bf16*  wqkrh = (bf16*)symv(g_wqkrh);
    bf16*  wqkrl = (bf16*)symv(g_wqkrl);
    float* bqkr  = (float*)symv(g_bqkr);
    float* qe    = (float*)symv(g_qe);
    bf16*  qph   = (bf16*)symv(g_qph);
    bf16*  qpl   = (bf16*)symv(g_qpl);
    bf16*  kph   = (bf16*)symv(g_kph);
    bf16*  kpl   = (bf16*)symv(g_kpl);
    bf16*  ckvth = (bf16*)symv(g_ckvth);
    bf16*  ckvtl = (bf16*)symv(g_ckvtl);
    bf16*  lath  = (bf16*)symv(g_lath);
    bf16*  latl  = (bf16*)symv(g_latl);
    bf16*  uvsh  = (bf16*)symv(g_uvsh);
    bf16*  uvsl  = (bf16*)symv(g_uvsl);
    bf16*  woh   = (bf16*)symv(g_woh);
    bf16*  wol   = (bf16*)symv(g_wol);
    bf16*  wcth  = (bf16*)symv(g_wcth);
    bf16*  wctl  = (bf16*)symv(g_wctl);
    float* b1    = (float*)symv(g_b1);
    float* beff  = (float*)symv(g_beff);
    float* beffp = (float*)symv(g_beffp);

    cudaFuncSetAttribute(gemm_mma, cudaFuncAttributeMaxDynamicSharedMemorySize, GEMM_SMEM);
    cudaFuncSetAttribute(flash_attn, cudaFuncAttributeMaxDynamicSharedMemorySize, FA_SMEM);

    const float scale = 1.0f / sqrtf((float)D_HEAD);
    cudaStream_t s0 = 0, s1 = g_aux.s1, s2 = g_aux.s2, s3 = g_aux.s3;

    // ---- fork ----
    cudaEventRecord(g_aux.evFork, s0);
    cudaStreamWaitEvent(s1, g_aux.evFork, 0);
    cudaStreamWaitEvent(s2, g_aux.evFork, 0);
    cudaStreamWaitEvent(s3, g_aux.evFork, 0);

    // ======== s1: W1 prep, then Wqk-absorption chain ========
    cudaMemcpyAsync(b1,      b_dkv, 128*sizeof(float), cudaMemcpyDeviceToDevice, s1);
    cudaMemcpyAsync(b1+128,  b_dq,  128*sizeof(float), cudaMemcpyDeviceToDevice, s1);
    cudaMemcpyAsync(b1+256,  b_kr,  128*sizeof(float), cudaMemcpyDeviceToDevice, s1);
    tsplit_on(s1, W_dkv, w1h,               w1l,               D_MODEL, D_KV, D_KV, D_MODEL);
    tsplit_on(s1, W_dq,  w1h + 128*D_MODEL, w1l + 128*D_MODEL, D_MODEL, D_KV, D_KV, D_MODEL);
    tsplit_on(s1, W_kr,  w1h + 256*D_MODEL, w1l + 256*D_MODEL, D_MODEL, D_KV, D_KV, D_MODEL);
    cudaEventRecord(g_aux.evW1, s1);

    cudaMemcpyAsync(bqkr+1024, b_qr, 128*sizeof(float), cudaMemcpyDeviceToDevice, s1);
    tsplit_on(s1, W_qr, wqkrh + 1024*128, wqkrl + 1024*128, D_KV, 128, 128, D_KV);
    pad_split_uqk<<<(8*128*640 + 255)/256, 256, 0, s1>>>(W_uq, W_uk, uqph, uqpl, ukph, ukpl);
    bqk_kernel<<<8, 128, 0, s1>>>(b_uq, W_uk, bqkr);
    gemm_on(s1, 128, 128, 640, ukph, ukpl, 640, uqph, uqpl, 640,
            nullptr, wqkrh, wqkrl, 128, nullptr, 1.0f,
            8, 8, 0, (long long)128*640, 0, (long long)128*640, 0, (long long)128*128);
    cudaEventRecord(g_aux.evA, s1);

    // ======== s2: W_o/W_uv-absorption chain ========
    convert_split_k<<<(128*D_MODEL + 255)/256, 256, 0, s2>>>(W_uv, uvsh, uvsl, 128*D_MODEL);
    tsplit_on(s2, W_o, woh, wol, D_MODEL, D_MODEL, D_MODEL, D_MODEL);
    gemm_on(s2, D_MODEL, 128, 640, woh, wol, D_MODEL, uvsh, uvsl, D_MODEL,
            nullptr, wcth, wctl, 1024, nullptr, 1.0f,
            8, 8, 0, 640, 0, 640, 0, 128);
    beff_partial<<<dim3(D_MODEL/256, 16), 256, 0, s2>>>(b_uv, W_o, beffp);
    beff_reduce<<<(D_MODEL + 255)/256, 256, 0, s2>>>(beffp, b_o, beff);
    cudaEventRecord(g_aux.evB, s2);

    // ======== per-batch activation pipelines (s0 = b0, s3 = b1) ========
    const long long HN = (long long)SS * D_MODEL;     // elems per batch of h
    #define BATCH_CHAIN(st, B, BH, EVF)                                            \
    do {                                                                           \
        const long long r0 = (long long)(B) * SS;                                  \
        convert_split_k<<<(unsigned)((HN + 255)/256), 256, 0, (st)>>>(             \
            h + r0*D_MODEL, hh + r0*D_MODEL, hl + r0*D_MODEL, HN);                 \
        cudaStreamWaitEvent((st), g_aux.evW1, 0);                                  \
        gemm_on((st), SS, NCAT1, D_MODEL,                                          \
                hh + r0*D_MODEL, hl + r0*D_MODEL, D_MODEL, w1h, w1l, D_MODEL,      \
                cat1 + r0*NCAT1, cat1h + r0*NCAT1, cat1l + r0*NCAT1, NCAT1,        \
                b1, 1.0f);                                                         \
        copy_ckv<<<(SS*D_KV + 255)/256, 256, 0, (st)>>>(cat1, out_ckv, (int)r0);   \
        cudaStreamWaitEvent((st), g_aux.evA, 0);                                   \
        gemm_on((st), SS, NQE, 128,                                                \
                cat1h + r0*NCAT1 + 128, cat1l + r0*NCAT1 + 128, NCAT1,             \
                wqkrh, wqkrl, 128,                                                 \
                qe + r0*NQE, nullptr, nullptr, NQE, bqkr, 1.0f);                   \
        {                                                                          \
            long long total = (long long)8*SS*KAUG;                                \
            assemble_qk<<<(unsigned)((total + 255)/256), 256, 0, (st)>>>(          \
                qe, cat1, qph, qpl, kph, kpl, out_krot, (BH));                     \
        }                                                                          \
        tsplit_on((st), cat1 + r0*NCAT1, ckvth + (long long)(B)*128*SS,            \
                  ckvtl + (long long)(B)*128*SS, SS, 128, NCAT1, SS);              \
        flash_attn<<<dim3(SS/64, 8), 256, FA_SMEM, (st)>>>(                        \
            qph, qpl, kph, kpl, ckvth, ckvtl, lath, latl, scale, (BH));            \
        cudaEventRecord((EVF), (st));                                              \
    } while (0)

    BATCH_CHAIN(s0, 0, 0, g_aux.evF0);
    BATCH_CHAIN(s3, 1, 8, g_aux.evF1);

    // ======== final GEMM, per-batch, co-scheduled ========
    cudaStreamWaitEvent(s1, g_aux.evF0, 0);
    cudaStreamWaitEvent(s1, g_aux.evB, 0);
    gemm_on(s1, SS, D_MODEL, 1024, lath, latl, 1024, wcth, wctl, 1024,
            out, nullptr, nullptr, D_MODEL, beff, 1.0f);
    cudaEventRecord(g_aux.evH0, s1);

    cudaStreamWaitEvent(s0, g_aux.evF1, 0);
    cudaStreamWaitEvent(s0, g_aux.evB, 0);
    gemm_on(s0, SS, D_MODEL, 1024,
            lath + (long long)SS*1024, latl + (long long)SS*1024, 1024,
            wcth, wctl, 1024,
            out + (long long)SS*D_MODEL, nullptr, nullptr, D_MODEL, beff, 1.0f);

    cudaStreamWaitEvent(s0, g_aux.evH0, 0);
}

// round 11
// speedup vs baseline: 9.6630x; 1.0284x over previous
#include <cuda_runtime.h>
#include <cuda_bf16.h>
#include <cuda_fp16.h>
#include <math.h>
#include <stdint.h>

#define D_MODEL 5120
#define N_HEADS 8
#define D_KV    128
#define D_ROPE  16
#define D_HEAD  640
#define SPLIT   624
#define BB      2
#define SS      2048
#define ROWS    (BB*SS)          // 4096
#define NCAT1   384              // dkv(128) + dq(128) + kr(128)
#define KAUG    192              // layout width; only 144 cols real
#define NQE     1152             // 1024 (Wqk) + 128 (Wqr)

typedef __nv_bfloat16 bf16;
typedef __half fp16;

// ---------------- scratch (device globals) ----------------------------------
__device__ __align__(16) float g_cat1 [ROWS*NCAT1];
__device__ __align__(16) bf16  g_cat1h[ROWS*NCAT1];
__device__ __align__(16) bf16  g_cat1l[ROWS*NCAT1];
__device__ __align__(16) bf16  g_hh  [(size_t)ROWS*D_MODEL];
__device__ __align__(16) bf16  g_hl  [(size_t)ROWS*D_MODEL];
__device__ __align__(16) bf16  g_w1h [NCAT1*D_MODEL];
__device__ __align__(16) bf16  g_w1l [NCAT1*D_MODEL];
__device__ __align__(16) bf16  g_uqph[8*128*640];
__device__ __align__(16) bf16  g_uqpl[8*128*640];
__device__ __align__(16) bf16  g_ukph[8*128*640];
__device__ __align__(16) bf16  g_ukpl[8*128*640];
__device__ __align__(16) bf16  g_wqkrh[NQE*128];
__device__ __align__(16) bf16  g_wqkrl[NQE*128];
__device__ __align__(16) float g_bqkr[NQE];
__device__ __align__(16) float g_qe  [(size_t)ROWS*NQE];
__device__ __align__(16) fp16  g_qph [(size_t)16*SS*KAUG];
__device__ __align__(16) fp16  g_qpl [(size_t)16*SS*KAUG];
__device__ __align__(16) fp16  g_kph [(size_t)16*SS*KAUG];
__device__ __align__(16) bf16  g_ckvth[BB*128*SS];
__device__ __align__(16) bf16  g_ckvtl[BB*128*SS];
__device__ __align__(16) bf16  g_lath[(size_t)ROWS*1024];
__device__ __align__(16) bf16  g_latl[(size_t)ROWS*1024];
__device__ __align__(16) bf16  g_uvsh[128*D_MODEL];
__device__ __align__(16) bf16  g_uvsl[128*D_MODEL];
__device__ __align__(16) bf16  g_woh [(size_t)D_MODEL*D_MODEL];
__device__ __align__(16) bf16  g_wol [(size_t)D_MODEL*D_MODEL];
__device__ __align__(16) bf16  g_wcth[(size_t)D_MODEL*1024];
__device__ __align__(16) bf16  g_wctl[(size_t)D_MODEL*1024];
__device__ __align__(16) float g_b1  [NCAT1];
__device__ __align__(16) float g_beff[D_MODEL];
__device__ __align__(16) float g_beffp[16*D_MODEL];

// ---------------- streams/events ---------------------------------------------
struct AuxStreams {
    cudaStream_t s1, s2, s3;
    cudaEvent_t  evFork, evW1, evA, evB, evF0, evF1, evH0;
    AuxStreams() {
        cudaStreamCreateWithFlags(&s1, cudaStreamNonBlocking);
        cudaStreamCreateWithFlags(&s2, cudaStreamNonBlocking);
        cudaStreamCreateWithFlags(&s3, cudaStreamNonBlocking);
        cudaEventCreateWithFlags(&evFork, cudaEventDisableTiming);
        cudaEventCreateWithFlags(&evW1,   cudaEventDisableTiming);
        cudaEventCreateWithFlags(&evA,    cudaEventDisableTiming);
        cudaEventCreateWithFlags(&evB,    cudaEventDisableTiming);
        cudaEventCreateWithFlags(&evF0,   cudaEventDisableTiming);
        cudaEventCreateWithFlags(&evF1,   cudaEventDisableTiming);
        cudaEventCreateWithFlags(&evH0,   cudaEventDisableTiming);
    }
};
static AuxStreams g_aux;

// ---------------- PTX helpers ------------------------------------------------
__device__ __forceinline__ uint32_t smem_u32(const void* p) {
    uint32_t a;
    asm("{ .reg .u64 t; cvta.to.shared.u64 t, %1; cvt.u32.u64 %0, t; }"
        : "=r"(a) : "l"(p));
    return a;
}

__device__ __forceinline__ void cp16(uint32_t dst, const void* src) {
    asm volatile("cp.async.cg.shared.global [%0], [%1], 16;\n"
                 :: "r"(dst), "l"(__cvta_generic_to_global(src)));
}
#define CP_COMMIT() asm volatile("cp.async.commit_group;\n" ::: "memory")
#define CP_WAIT1()  asm volatile("cp.async.wait_group 1;\n" ::: "memory")
#define CP_WAIT0()  asm volatile("cp.async.wait_group 0;\n" ::: "memory")

__device__ __forceinline__ void ldm4(uint32_t* r, uint32_t a) {
    asm volatile("ldmatrix.sync.aligned.m8n8.x4.shared.b16 {%0,%1,%2,%3}, [%4];"
                 : "=r"(r[0]), "=r"(r[1]), "=r"(r[2]), "=r"(r[3]) : "r"(a));
}

__device__ __forceinline__ void mma16816(float* c, const uint32_t* a, const uint32_t* b) {
    asm volatile(
        "mma.sync.aligned.m16n8k16.row.col.f32.bf16.bf16.f32 "
        "{%0,%1,%2,%3},{%4,%5,%6,%7},{%8,%9},{%0,%1,%2,%3};\n"
        : "+f"(c[0]), "+f"(c[1]), "+f"(c[2]), "+f"(c[3])
        : "r"(a[0]), "r"(a[1]), "r"(a[2]), "r"(a[3]), "r"(b[0]), "r"(b[1]));
}

__device__ __forceinline__ void mma16816h(float* c, const uint32_t* a, const uint32_t* b) {
    asm volatile(
        "mma.sync.aligned.m16n8k16.row.col.f32.f16.f16.f32 "
        "{%0,%1,%2,%3},{%4,%5,%6,%7},{%8,%9},{%0,%1,%2,%3};\n"
        : "+f"(c[0]), "+f"(c[1]), "+f"(c[2]), "+f"(c[3])
        : "r"(a[0]), "r"(a[1]), "r"(a[2]), "r"(a[3]), "r"(b[0]), "r"(b[1]));
}

__device__ __forceinline__ uint32_t pack2(float a, float b) {
    __nv_bfloat162 t = __floats2bfloat162_rn(a, b);
    return *reinterpret_cast<const uint32_t*>(&t);
}

__device__ __forceinline__ void split_bf16(float v, bf16& h, bf16& l) {
    h = __float2bfloat16(v);
    l = __float2bfloat16(v - __bfloat162float(h));
}

__device__ __forceinline__ void split_pack(float a, float b, uint32_t& ph, uint32_t& pl) {
    bf16 ha = __float2bfloat16(a), hb = __float2bfloat16(b);
    ph = ((uint32_t)*(uint16_t*)&hb << 16) | (uint32_t)*(uint16_t*)&ha;
    pl = pack2(a - __bfloat162float(ha), b - __bfloat162float(hb));
}

__device__ __forceinline__ void split_fp16(float v, fp16& h, fp16& l) {
    h = __float2half(v);
    l = __float2half(v - __half2float(h));
}

// ---------------- bf16x3 mma.sync GEMM ---------------------------------------
#define STAGE_BYTES 65536
#define GEMM_SMEM   (3*STAGE_BYTES)

__global__ void __launch_bounds__(256, 1)
gemm_mma(int M, int N, int K,
         const bf16* __restrict__ Ah_, const bf16* __restrict__ Al_, long long lda,
         const bf16* __restrict__ Bh_, const bf16* __restrict__ Bl_, long long ldb,
         float* __restrict__ C, bf16* __restrict__ Ch, bf16* __restrict__ Cl,
         long long ldc,
         const float* __restrict__ bias, float alpha,
         int zdiv,
         long long sA1, long long sA2,
         long long sB1, long long sB2,
         long long sC1, long long sC2)
{
    extern __shared__ __align__(1024) char smem[];
    const uint32_t sb = smem_u32(smem);

    {
        int z  = blockIdx.z;
        int z1 = z / zdiv, z2 = z % zdiv;
        Ah_ += z1*sA1 + z2*sA2;  Al_ += z1*sA1 + z2*sA2;
        Bh_ += z1*sB1 + z2*sB2;  Bl_ += z1*sB1 + z2*sB2;
        long long co = z1*sC1 + z2*sC2;
        if (C)  C  += co;
        if (Ch) { Ch += co; Cl += co; }
    }

    const int tid  = threadIdx.x;
    const int wid  = tid >> 5;
    const int lane = tid & 31;
    const int wm   = (wid >> 2) * 64;
    const int wn   = (wid & 3) * 32;
    const int g    = lane >> 2, tg = lane & 3;
    const int m0   = blockIdx.y * 128;
    const int n0   = blockIdx.x * 128;

    const int lrow = tid >> 1;
    const int half = tid & 1;
    const bf16* pAh = Ah_ + (long long)(m0 + lrow)*lda;
    const bf16* pAl = Al_ + (long long)(m0 + lrow)*lda;
    const bf16* pBh = Bh_ + (long long)(n0 + lrow)*ldb;
    const bf16* pBl = Bl_ + (long long)(n0 + lrow)*ldb;
    const uint32_t lswz = (uint32_t)(lrow & 7);

    const int nk = K / 64;

    const int piece = lane >> 3, rr = lane & 7;
    const int rowA  = wm + (piece & 1)*8 + rr;
    const int rowB  = wn + (piece >> 1)*8 + rr;
    const int cA    = piece >> 1;
    const int cB    = piece & 1;

    float acc[4][4][4];
    #pragma unroll
    for (int i = 0; i < 4; i++)
        #pragma unroll
        for (int j = 0; j < 4; j++)
            #pragma unroll
            for (int k = 0; k < 4; k++) acc[i][j][k] = 0.0f;

    #define ISSUE(t) do {                                                     \
        uint32_t s0_ = sb + ((t) % 3) * STAGE_BYTES;                          \
        const int k0_ = (t) * 64;                                             \
        _Pragma("unroll")                                                     \
        for (int j = 0; j < 4; j++) {                                         \
            int ch_ = half*4 + j;                                             \
            uint32_t d_ = (uint32_t)(lrow*128 + (((uint32_t)ch_ ^ lswz) << 4)); \
            cp16(s0_ +         d_, pAh + k0_ + ch_*8);                        \
            cp16(s0_ + 16384 + d_, pAl + k0_ + ch_*8);                        \
            cp16(s0_ + 32768 + d_, pBh + k0_ + ch_*8);                        \
            cp16(s0_ + 49152 + d_, pBl + k0_ + ch_*8);                        \
        }                                                                     \
        CP_COMMIT();                                                          \
    } while (0)

    ISSUE(0);
    if (nk > 1) ISSUE(1);

    for (int t = 0; t < nk; t++) {
        if (t + 1 < nk) { CP_WAIT1(); } else { CP_WAIT0(); }
        __syncthreads();
        if (t + 2 < nk) ISSUE(t + 2);

        const uint32_t Ab = sb + (t % 3) * STAGE_BYTES;
        const uint32_t Bb = Ab + 32768;

        #pragma unroll
        for (int ks = 0; ks < 4; ks++) {
            uint32_t ah[4][4], al[4][4], bh[4][2], bl[4][2];
            const uint32_t aoff = (uint32_t)(rowA*128 + (((ks*2 + cA) ^ (rowA & 7)) << 4));
            const uint32_t boff = (uint32_t)(rowB*128 + (((ks*2 + cB) ^ (rowB & 7)) << 4));
            #pragma unroll
            for (int mt = 0; mt < 4; mt++) {
                ldm4(ah[mt], Ab +          aoff + mt*2048);
                ldm4(al[mt], Ab + 16384 +  aoff + mt*2048);
            }
            #pragma unroll
            for (int ntp = 0; ntp < 2; ntp++) {
                uint32_t rb[4];
                ldm4(rb, Bb +          boff + ntp*2048);
                bh[ntp*2][0]   = rb[0]; bh[ntp*2][1]   = rb[1];
                bh[ntp*2+1][0] = rb[2]; bh[ntp*2+1][1] = rb[3];
                ldm4(rb, Bb + 16384 +  boff + ntp*2048);
                bl[ntp*2][0]   = rb[0]; bl[ntp*2][1]   = rb[1];
                bl[ntp*2+1][0] = rb[2]; bl[ntp*2+1][1] = rb[3];
            }
            #pragma unroll
            for (int mt = 0; mt < 4; mt++)
                #pragma unroll
                for (int nt = 0; nt < 4; nt++) {
                    mma16816(acc[mt][nt], ah[mt], bh[nt]);
                    mma16816(acc[mt][nt], al[mt], bh[nt]);
                    mma16816(acc[mt][nt], ah[mt], bl[nt]);
                }
        }
    }

    #pragma unroll
    for (int mt = 0; mt < 4; mt++) {
        int row = m0 + wm + mt*16 + g;
        #pragma unroll
        for (int nt = 0; nt < 4; nt++) {
            int col = n0 + wn + nt*8 + tg*2;
            float b0 = 0.0f, b1 = 0.0f;
            if (bias) { b0 = bias[col]; b1 = bias[col+1]; }
            float v00 = acc[mt][nt][0]*alpha + b0;
            float v01 = acc[mt][nt][1]*alpha + b1;
            float v10 = acc[mt][nt][2]*alpha + b0;
            float v11 = acc[mt][nt][3]*alpha + b1;
            if (C) {
                *(float2*)(C + (long long)row*ldc + col)     = make_float2(v00, v01);
                *(float2*)(C + (long long)(row+8)*ldc + col) = make_float2(v10, v11);
            }
            if (Ch) {
                uint32_t ph, pl;
                split_pack(v00, v01, ph, pl);
                *(uint32_t*)(Ch + (long long)row*ldc + col) = ph;
                *(uint32_t*)(Cl + (long long)row*ldc + col) = pl;
                split_pack(v10, v11, ph, pl);
                *(uint32_t*)(Ch + (long long)(row+8)*ldc + col) = ph;
                *(uint32_t*)(Cl + (long long)(row+8)*ldc + col) = pl;
            }
        }
    }
}

// ---------------- fused flash attention ---------------------------------------
// QK: fp16 2-MMA (Qh*Kh + Ql*Kh).  PV: bf16 3-MMA (unchanged).
// smem: Q hi/lo 49152 | 2 stages x (Khi 24576 + Vh 16384 + Vl 16384) | P 16384 | red
#define FA_NC    32
#define FA_STG   57344
#define FA_Q     0
#define FA_S0    49152
#define FA_P     163840
#define FA_REDM  180224
#define FA_REDS  181248
#define FA_SMEM  182272
#define FA_NKS   9

__global__ void __launch_bounds__(256, 1)
flash_attn(const fp16* __restrict__ qph, const fp16* __restrict__ qpl,
           const fp16* __restrict__ kph,
           const bf16* __restrict__ vth, const bf16* __restrict__ vtl,
           bf16* __restrict__ lath, bf16* __restrict__ latl,
           float scale, int bh_base)
{
    extern __shared__ __align__(1024) char smem[];
    const uint32_t sb = smem_u32(smem);

    const int tid  = threadIdx.x;
    const int wid  = tid >> 5;
    const int lane = tid & 31;
    const int wm2  = wid >> 2;
    const int wn4  = wid & 3;
    const int g    = lane >> 2, tg = lane & 3;
    const int piece = lane >> 3, rr = lane & 7;

    const int bh = blockIdx.y + bh_base;
    const int b  = bh >> 3;
    const int qb = blockIdx.x;

    const fp16* qbh = qph + ((size_t)bh*SS + (size_t)qb*64)*KAUG;
    const fp16* qbl = qpl + ((size_t)bh*SS + (size_t)qb*64)*KAUG;
    const fp16* kbh = kph + (size_t)bh*SS*KAUG;
    const bf16* vbh = vth + (size_t)b*128*SS;
    const bf16* vbl = vtl + (size_t)b*128*SS;

    #pragma unroll
    for (int i = 0; i < 6; i++) {
        int idx = i*256 + tid;
        int row = idx / 24, cc = idx % 24;
        if (cc < 18) {
            int kt = cc >> 3, c8 = cc & 7;
            uint32_t d = (uint32_t)(kt*8192 + row*128 + (((uint32_t)c8 ^ (row & 7)) << 4));
            cp16(sb + FA_Q +         d, qbh + row*KAUG + cc*8);
            cp16(sb + FA_Q + 24576 + d, qbl + row*KAUG + cc*8);
        }
    }
    CP_COMMIT();

    #define FA_ISSUE(t) do {                                                   \
        uint32_t st_ = sb + FA_S0 + ((t) & 1) * FA_STG;                        \
        const int t0_ = (t) * 64;                                              \
        _Pragma("unroll")                                                      \
        for (int i = 0; i < 6; i++) {                                          \
            int idx = i*256 + tid;                                             \
            int row = idx / 24, cc = idx % 24;                                 \
            if (cc < 18) {                                                     \
                int kt = cc >> 3, c8 = cc & 7;                                 \
                uint32_t d = (uint32_t)(kt*8192 + row*128 + (((uint32_t)c8 ^ (row & 7)) << 4)); \
                cp16(st_ + d, kbh + (size_t)(t0_+row)*KAUG + cc*8);            \
            }                                                                  \
        }                                                                      \
        _Pragma("unroll")                                                      \
        for (int i = 0; i < 4; i++) {                                          \
            int idx = i*256 + tid;                                             \
            int row = idx >> 3, c8 = idx & 7;                                  \
            uint32_t d = (uint32_t)(row*128 + (((uint32_t)c8 ^ (row & 7)) << 4)); \
            cp16(st_ + 24576 + d, vbh + (size_t)row*SS + t0_ + c8*8);          \
            cp16(st_ + 40960 + d, vbl + (size_t)row*SS + t0_ + c8*8);          \
        }                                                                      \
        CP_COMMIT();                                                           \
    } while (0)

    FA_ISSUE(0);

    float accv[2][4][4];
    #pragma unroll
    for (int i = 0; i < 2; i++)
        #pragma unroll
        for (int j = 0; j < 4; j++)
            #pragma unroll
            for (int k = 0; k < 4; k++) accv[i][j][k] = 0.0f;
    float Mrow[4] = {-1e30f, -1e30f, -1e30f, -1e30f};
    float Lrow[4] = {0.0f, 0.0f, 0.0f, 0.0f};

    float* redm = (float*)(smem + FA_REDM);
    float* reds = (float*)(smem + FA_REDS);

    for (int t = 0; t < FA_NC; t++) {
        CP_WAIT0();
        __syncthreads();
        if (t + 1 < FA_NC) FA_ISSUE(t + 1);

        const uint32_t KB = sb + FA_S0 + (t & 1) * FA_STG;
        const uint32_t VB = KB + 24576;

        float sacc[2][2][4];
        #pragma unroll
        for (int i = 0; i < 2; i++)
            #pragma unroll
            for (int j = 0; j < 2; j++)
                #pragma unroll
                for (int k = 0; k < 4; k++) sacc[i][j][k] = 0.0f;

        #pragma unroll
        for (int ks = 0; ks < FA_NKS; ks++) {
            const int kt = ks >> 2, ks2 = ks & 3;
            uint32_t ah[2][4], al[2][4];
            #pragma unroll
            for (int mt = 0; mt < 2; mt++) {
                int rowA = wm2*32 + mt*16 + (piece & 1)*8 + rr;
                uint32_t off = (uint32_t)(kt*8192 + rowA*128 +
                    (((ks2*2 + (piece >> 1)) ^ (rowA & 7)) << 4));
                ldm4(ah[mt], sb + FA_Q +         off);
                ldm4(al[mt], sb + FA_Q + 24576 + off);
            }
            int rowB = wn4*16 + (piece >> 1)*8 + rr;
            uint32_t offB = (uint32_t)(kt*8192 + rowB*128 +
                (((ks2*2 + (piece & 1)) ^ (rowB & 7)) << 4));
            uint32_t rbh[4];
            ldm4(rbh, KB + offB);
            #pragma unroll
            for (int mt = 0; mt < 2; mt++)
                #pragma unroll
                for (int nt = 0; nt < 2; nt++) {
                    mma16816h(sacc[mt][nt], ah[mt], rbh + nt*2);
                    mma16816h(sacc[mt][nt], al[mt], rbh + nt*2);
                }
        }

        float mloc[4] = {-1e30f, -1e30f, -1e30f, -1e30f};
        #pragma unroll
        for (int mt = 0; mt < 2; mt++)
            #pragma unroll
            for (int nt = 0; nt < 2; nt++)
                #pragma unroll
                for (int c = 0; c < 4; c++) {
                    sacc[mt][nt][c] *= scale;
                    int slot = mt*2 + (c >> 1);
                    mloc[slot] = fmaxf(mloc[slot], sacc[mt][nt][c]);
                }
        #pragma unroll
        for (int s = 0; s < 4; s++) {
            mloc[s] = fmaxf(mloc[s], __shfl_xor_sync(0xffffffffu, mloc[s], 1));
            mloc[s] = fmaxf(mloc[s], __shfl_xor_sync(0xffffffffu, mloc[s], 2));
        }
        if (tg == 0) {
            #pragma unroll
            for (int mt = 0; mt < 2; mt++)
                #pragma unroll
                for (int h2 = 0; h2 < 2; h2++) {
                    int r = wm2*32 + mt*16 + h2*8 + g;
                    redm[wn4*64 + r] = mloc[mt*2 + h2];
                }
        }
        __syncthreads();

        float fsc[4];
        #pragma unroll
        for (int mt = 0; mt < 2; mt++)
            #pragma unroll
            for (int h2 = 0; h2 < 2; h2++) {
                int r = wm2*32 + mt*16 + h2*8 + g;
                float cm = fmaxf(fmaxf(redm[r], redm[64 + r]),
                                 fmaxf(redm[128 + r], redm[192 + r]));
                int slot = mt*2 + h2;
                float mn = fmaxf(Mrow[slot], cm);
                fsc[slot] = __expf(Mrow[slot] - mn);
                Mrow[slot] = mn;
            }

        float sl[4] = {0.0f, 0.0f, 0.0f, 0.0f};
        #pragma unroll
        for (int mt = 0; mt < 2; mt++)
            #pragma unroll
            for (int nt = 0; nt < 2; nt++)
                #pragma unroll
                for (int c = 0; c < 4; c++) {
                    int slot = mt*2 + (c >> 1);
                    float p = __expf(sacc[mt][nt][c] - Mrow[slot]);
                    sacc[mt][nt][c] = p;
                    sl[slot] += p;
                }
        #pragma unroll
        for (int mt = 0; mt < 2; mt++)
            #pragma unroll
            for (int nt = 0; nt < 4; nt++)
                #pragma unroll
                for (int c = 0; c < 4; c++)
                    accv[mt][nt][c] *= fsc[mt*2 + (c >> 1)];
        #pragma unroll
        for (int s = 0; s < 4; s++) {
            sl[s] += __shfl_xor_sync(0xffffffffu, sl[s], 1);
            sl[s] += __shfl_xor_sync(0xffffffffu, sl[s], 2);
        }
        if (tg == 0) {
            #pragma unroll
            for (int mt = 0; mt < 2; mt++)
                #pragma unroll
                for (int h2 = 0; h2 < 2; h2++) {
                    int r = wm2*32 + mt*16 + h2*8 + g;
                    reds[wn4*64 + r] = sl[mt*2 + h2];
                }
        }
        #pragma unroll
        for (int mt = 0; mt < 2; mt++)
            #pragma unroll
            for (int nt = 0; nt < 2; nt++)
                #pragma unroll
                for (int h2 = 0; h2 < 2; h2++) {
                    int r = wm2*32 + mt*16 + h2*8 + g;
                    int cidx = wn4*2 + nt;
                    uint32_t addr = (uint32_t)(r*128 + ((cidx ^ (r & 7)) << 4) + tg*4);
                    uint32_t ph, pl;
                    split_pack(sacc[mt][nt][2*h2], sacc[mt][nt][2*h2+1], ph, pl);
                    *(uint32_t*)(smem + FA_P +        addr) = ph;
                    *(uint32_t*)(smem + FA_P + 8192 + addr) = pl;
                }
        __syncthreads();

        #pragma unroll
        for (int mt = 0; mt < 2; mt++)
            #pragma unroll
            for (int h2 = 0; h2 < 2; h2++) {
                int r = wm2*32 + mt*16 + h2*8 + g;
                float ssum = reds[r] + reds[64 + r] + reds[128 + r] + reds[192 + r];
                int slot = mt*2 + h2;
                Lrow[slot] = Lrow[slot] * fsc[slot] + ssum;
            }

        #pragma unroll
        for (int ksv = 0; ksv < 4; ksv++) {
            uint32_t pah[2][4], pal[2][4];
            #pragma unroll
            for (int mt = 0; mt < 2; mt++) {
                int rowA = wm2*32 + mt*16 + (piece & 1)*8 + rr;
                uint32_t off = (uint32_t)(rowA*128 +
                    (((ksv*2 + (piece >> 1)) ^ (rowA & 7)) << 4));
                ldm4(pah[mt], sb + FA_P +        off);
                ldm4(pal[mt], sb + FA_P + 8192 + off);
            }
            uint32_t vh[2][4], vl[2][4];
            #pragma unroll
            for (int ntp = 0; ntp < 2; ntp++) {
                int rowB = wn4*32 + ntp*16 + (piece >> 1)*8 + rr;
                uint32_t offB = (uint32_t)(rowB*128 +
                    (((ksv*2 + (piece & 1)) ^ (rowB & 7)) << 4));
                ldm4(vh[ntp], VB +         offB);
                ldm4(vl[ntp], VB + 16384 + offB);
            }
            #pragma unroll
            for (int mt = 0; mt < 2; mt++)
                #pragma unroll
                for (int nt = 0; nt < 4; nt++) {
                    const uint32_t* bhp = vh[nt >> 1] + (nt & 1)*2;
                    const uint32_t* blp = vl[nt >> 1] + (nt & 1)*2;
                    mma16816(accv[mt][nt], pah[mt], bhp);
                    mma16816(accv[mt][nt], pal[mt], bhp);
                    mma16816(accv[mt][nt], pah[mt], blp);
                }
        }
    }

    float inv[4];
    #pragma unroll
    for (int s = 0; s < 4; s++) inv[s] = 1.0f / Lrow[s];

    const int h = bh & 7;
    #pragma unroll
    for (int mt = 0; mt < 2; mt++) {
        #pragma unroll
        for (int nt = 0; nt < 4; nt++) {
            int col = h*128 + wn4*32 + nt*8 + tg*2;
            #pragma unroll
            for (int h2 = 0; h2 < 2; h2++) {
                long long row = (long long)b*SS + qb*64 + wm2*32 + mt*16 + h2*8 + g;
                float v0 = accv[mt][nt][2*h2]   * inv[mt*2 + h2];
                float v1 = accv[mt][nt][2*h2+1] * inv[mt*2 + h2];
                uint32_t ph, pl;
                split_pack(v0, v1, ph, pl);
                *(uint32_t*)(lath + row*1024 + col) = ph;
                *(uint32_t*)(latl + row*1024 + col) = pl;
            }
        }
    }
}

// ---------------- elementwise fp32 -> bf16 hi/lo ------------------------------
__global__ void convert_split_k(const float* __restrict__ in,
                                bf16* __restrict__ oh, bf16* __restrict__ ol,
                                long long n)
{
    long long i = (long long)blockIdx.x * 256 + threadIdx.x;
    if (i < n) {
        bf16 h, l; split_bf16(in[i], h, l);
        oh[i] = h; ol[i] = l;
    }
}

// ---------------- fp32 transpose -> bf16 hi/lo --------------------------------
__global__ void transpose_split_k(const float* __restrict__ in,
                                  bf16* __restrict__ oh, bf16* __restrict__ ol,
                                  int M, int N, int ldi, int ldo,
                                  int zdiv,
                                  long long si1, long long si2,
                                  long long so1, long long so2)
{
    __shared__ float tile[32][33];
    int z = blockIdx.z, z1 = z / zdiv, z2 = z % zdiv;
    in += z1*si1 + z2*si2;
    oh += z1*so1 + z2*so2;
    ol += z1*so1 + z2*so2;

    int x = blockIdx.x*32 + threadIdx.x;
    int y = blockIdx.y*32 + threadIdx.y;
    #pragma unroll
    for (int i = 0; i < 32; i += 8)
        if (x < N && (y+i) < M)
            tile[threadIdx.y+i][threadIdx.x] = in[(long long)(y+i)*ldi + x];
    __syncthreads();
    x = blockIdx.y*32 + threadIdx.x;
    y = blockIdx.x*32 + threadIdx.y;
    #pragma unroll
    for (int i = 0; i < 32; i += 8)
        if (x < M && (y+i) < N) {
            bf16 h, l; split_bf16(tile[threadIdx.x][threadIdx.y+i], h, l);
            oh[(long long)(y+i)*ldo + x] = h;
            ol[(long long)(y+i)*ldo + x] = l;
        }
}

// ---------------- pad+split W_uq / W_uk into [8][128][640] --------------------
__global__ void pad_split_uqk(const float* __restrict__ Wuq,
                              const float* __restrict__ Wuk,
                              bf16* __restrict__ uqh, bf16* __restrict__ uql,
                              bf16* __restrict__ ukh, bf16* __restrict__ ukl)
{
    int idx = blockIdx.x * 256 + threadIdx.x;
    if (idx >= 8*128*640) return;
    int e = idx % 640;
    int c = (idx / 640) & 127;
    int h = idx / (640*128);
    float vq = 0.0f, vk = 0.0f;
    if (e < SPLIT) {
        vq = Wuq[c*4992 + h*SPLIT + e];
        vk = Wuk[c*4992 + h*SPLIT + e];
    }
    bf16 hh, ll;
    split_bf16(vq, hh, ll); uqh[idx] = hh; uql[idx] = ll;
    split_bf16(vk, hh, ll); ukh[idx] = hh; ukl[idx] = ll;
}

// ---------------- bqk -----------------------------------------------------------
__global__ void bqk_kernel(const float* __restrict__ b_uq,
                           const float* __restrict__ W_uk,
                           float* __restrict__ bqk)
{
    int c = threadIdx.x;
    int h = blockIdx.x;
    float acc = 0.0f;
    const float* wrow = W_uk + c*4992 + h*SPLIT;
    const float* brow = b_uq + h*SPLIT;
    for (int e = 0; e < SPLIT; e++)
        acc += brow[e] * wrow[e];
    bqk[h*128 + c] = acc;
}

// ---------------- beff ----------------------------------------------------------
__global__ void beff_partial(const float* __restrict__ b_uv,
                             const float* __restrict__ W_o,
                             float* __restrict__ part)
{
    int o   = blockIdx.x * 256 + threadIdx.x;
    int seg = blockIdx.y;
    float acc = 0.0f;
    int d0 = seg * (D_MODEL/16);
    #pragma unroll 4
    for (int d = d0; d < d0 + D_MODEL/16; d++)
        acc += b_uv[d] * W_o[(size_t)d*D_MODEL + o];
    part[(size_t)seg*D_MODEL + o] = acc;
}

__global__ void beff_reduce(const float* __restrict__ part,
                            const float* __restrict__ b_o,
                            float* __restrict__ be)
{
    int o = blockIdx.x * 256 + threadIdx.x;
    if (o >= D_MODEL) return;
    float acc = b_o[o];
    #pragma unroll
    for (int s = 0; s < 16; s++)
        acc += part[(size_t)s*D_MODEL + o];
    be[o] = acc;
}

// ---------------- assemble Q'/K' (rope) -> fp16 hi/lo; emit k_rot ---------------
__global__ void assemble_qk(const float* __restrict__ qe,
                            const float* __restrict__ cat1,
                            fp16* __restrict__ qph, fp16* __restrict__ qpl,
                            fp16* __restrict__ kph,
                            float* __restrict__ out_krot, int bh_base)
{
    long long idx = (long long)blockIdx.x * 256 + threadIdx.x;
    if (idx >= (long long)8*SS*KAUG) return;
    int j  = (int)(idx % KAUG);
    int s  = (int)((idx / KAUG) & (SS - 1));
    int bh = (int)(idx / ((long long)KAUG*SS)) + bh_base;
    long long gidx = (long long)bh*SS*KAUG + (long long)s*KAUG + j;
    int b  = bh >> 3, h = bh & 7;
    long long row = (long long)b*SS + s;

    float qv = 0.0f, kv = 0.0f;
    if (j < 128) {
        qv = qe[row*NQE + h*128 + j];
        kv = cat1[row*NCAT1 + j];
    } else if (j < 144) {
        int dd = j - 128;
        long long qb = row*NQE + 1024 + h*D_ROPE;
        long long kb = row*NCAT1 + 256 + h*D_ROPE;
        if (dd < 8) {
            const float invf[4] = {1.0f, 0.1f, 0.01f, 0.001f};
            float f = ((float)s / 40.0f) * invf[dd & 3];
            float c_ = cosf(f), sn = sinf(f);
            if (dd < 4) {
                qv = qe[qb+dd]*c_ - qe[qb+dd+4]*sn;
                kv = cat1[kb+dd]*c_ - cat1[kb+dd+4]*sn;
            } else {
                qv = qe[qb+dd]*c_ + qe[qb+dd-4]*sn;
                kv = cat1[kb+dd]*c_ + cat1[kb+dd-4]*sn;
            }
        } else {
            qv = qe[qb+dd];
            kv = cat1[kb+dd];
        }
        out_krot[row*128 + h*D_ROPE + dd] = kv;
    } else {
        return;
    }
    fp16 hh, ll;
    split_fp16(qv, hh, ll);
    qph[gidx] = hh; qpl[gidx] = ll;
    kph[gidx] = __float2half(kv);
}

// ---------------- c_kv output copy (per-batch) ---------------------------------
__global__ void copy_ckv(const float* __restrict__ cat1, float* __restrict__ out,
                         int row0)
{
    int idx = blockIdx.x * 256 + threadIdx.x;
    if (idx < SS * D_KV) {
        int row = row0 + (idx >> 7);
        out[(long long)row*D_KV + (idx & 127)] = cat1[(long long)row*NCAT1 + (idx & 127)];
    }
}

// ---------------- host side ------------------------------------------------------
static inline void* symv(const void* s)
{
    void* p = nullptr;
    cudaGetSymbolAddress(&p, s);
    return p;
}

static void gemm_on(cudaStream_t st, int M, int N, int K,
                    const bf16* Ah, const bf16* Al, long long lda,
                    const bf16* Bh, const bf16* Bl, long long ldb,
                    float* C, bf16* Ch, bf16* Cl, long long ldc,
                    const float* bias, float alpha,
                    int nz = 1, int zdiv = 1,
                    long long sA1 = 0, long long sA2 = 0,
                    long long sB1 = 0, long long sB2 = 0,
                    long long sC1 = 0, long long sC2 = 0)
{
    dim3 grid(N / 128, M / 128, nz);
    gemm_mma<<<grid, 256, GEMM_SMEM, st>>>(M, N, K, Ah, Al, lda, Bh, Bl, ldb,
                                           C, Ch, Cl, ldc, bias, alpha, zdiv,
                                           sA1, sA2, sB1, sB2, sC1, sC2);
}

static void tsplit_on(cudaStream_t st, const float* in, bf16* oh, bf16* ol,
                      int M, int N, int ldi, int ldo)
{
    dim3 grid((N + 31)/32, (M + 31)/32, 1);
    transpose_split_k<<<grid, dim3(32, 8), 0, st>>>(in, oh, ol, M, N, ldi, ldo,
                                                    1, 0, 0, 0, 0);
}

extern "C" void kernel_launch(void* const* d_in, const int* in_sizes, int n_in,
                              void* d_out, int out_size)
{
    const float* h     = (const float*)d_in[0];
    const float* W_dkv = (const float*)d_in[1];
    const float* b_dkv = (const float*)d_in[2];
    const float* W_dq  = (const float*)d_in[3];
    const float* b_dq  = (const float*)d_in[4];
    const float* W_uk  = (const float*)d_in[5];
    const float* b_uk  = (const float*)d_in[6];
    const float* W_uv  = (const float*)d_in[7];
    const float* b_uv  = (const float*)d_in[8];
    const float* W_uq  = (const float*)d_in[9];
    const float* b_uq  = (const float*)d_in[10];
    const float* W_qr  = (const float*)d_in[11];
    const float* b_qr  = (const float*)d_in[12];
    const float* W_kr  = (const float*)d_in[13];
    const float* b_kr  = (const float*)d_in[14];
    const float* W_o   = (const float*)d_in[15];
    const float* b_o   = (const float*)d_in[16];
    (void)b_uk;

    float* out      = (float*)d_out;
    float* out_ckv  = out + (long long)ROWS * D_MODEL;
    float* out_krot = out_ckv + (long long)ROWS * D_KV;

    float* cat1  = (float*)symv(g_cat1);
    bf16*  cat1h = (bf16*)symv(g_cat1h);
    bf16*  cat1l = (bf16*)symv(g_cat1l);
    bf16*  hh    = (bf16*)symv(g_hh);
    bf16*  hl    = (bf16*)symv(g_hl);
    bf16*  w1h   = (bf16*)symv(g_w1h);
    bf16*  w1l   = (bf16*)symv(g_w1l);
    bf16*  uqph  = (bf16*)symv(g_uqph);
    bf16*  uqpl  = (bf16*)symv(g_uqpl);
    bf16*  ukph  = (bf16*)symv(g_ukph);
    bf16*  ukpl  = (bf16*)symv(g_ukpl);
    bf16*  wqkrh = (bf16*)symv(g_wqkrh);
    bf16*  wqkrl = (bf16*)symv(g_wqkrl);
    float* bqkr  = (float*)symv(g_bqkr);
    float* qe    = (float*)symv(g_qe);
    fp16*  qph   = (fp16*)symv(g_qph);
    fp16*  qpl   = (fp16*)symv(g_qpl);
    fp16*  kph   = (fp16*)symv(g_kph);
    bf16*  ckvth = (bf16*)symv(g_ckvth);
    bf16*  ckvtl = (bf16*)symv(g_ckvtl);
    bf16*  lath  = (bf16*)symv(g_lath);
    bf16*  latl  = (bf16*)symv(g_latl);
    bf16*  uvsh  = (bf16*)symv(g_uvsh);
    bf16*  uvsl  = (bf16*)symv(g_uvsl);
    bf16*  woh   = (bf16*)symv(g_woh);
    bf16*  wol   = (bf16*)symv(g_wol);
    bf16*  wcth  = (bf16*)symv(g_wcth);
    bf16*  wctl  = (bf16*)symv(g_wctl);
    float* b1    = (float*)symv(g_b1);
    float* beff  = (float*)symv(g_beff);
    float* beffp = (float*)symv(g_beffp);

    cudaFuncSetAttribute(gemm_mma, cudaFuncAttributeMaxDynamicSharedMemorySize, GEMM_SMEM);
    cudaFuncSetAttribute(flash_attn, cudaFuncAttributeMaxDynamicSharedMemorySize, FA_SMEM);

    const float scale = 1.0f / sqrtf((float)D_HEAD);
    cudaStream_t s0 = 0, s1 = g_aux.s1, s2 = g_aux.s2, s3 = g_aux.s3;

    // ---- fork ----
    cudaEventRecord(g_aux.evFork, s0);
    cudaStreamWaitEvent(s1, g_aux.evFork, 0);
    cudaStreamWaitEvent(s2, g_aux.evFork, 0);
    cudaStreamWaitEvent(s3, g_aux.evFork, 0);

    // ======== s1: W1 prep, then Wqk-absorption chain ========
    cudaMemcpyAsync(b1,      b_dkv, 128*sizeof(float), cudaMemcpyDeviceToDevice, s1);
    cudaMemcpyAsync(b1+128,  b_dq,  128*sizeof(float), cudaMemcpyDeviceToDevice, s1);
    cudaMemcpyAsync(b1+256,  b_kr,  128*sizeof(float), cudaMemcpyDeviceToDevice, s1);
    tsplit_on(s1, W_dkv, w1h,               w1l,               D_MODEL, D_KV, D_KV, D_MODEL);
    tsplit_on(s1, W_dq,  w1h + 128*D_MODEL, w1l + 128*D_MODEL, D_MODEL, D_KV, D_KV, D_MODEL);
    tsplit_on(s1, W_kr,  w1h + 256*D_MODEL, w1l + 256*D_MODEL, D_MODEL, D_KV, D_KV, D_MODEL);
    cudaEventRecord(g_aux.evW1, s1);

    cudaMemcpyAsync(bqkr+1024, b_qr, 128*sizeof(float), cudaMemcpyDeviceToDevice, s1);
    tsplit_on(s1, W_qr, wqkrh + 1024*128, wqkrl + 1024*128, D_KV, 128, 128, D_KV);
    pad_split_uqk<<<(8*128*640 + 255)/256, 256, 0, s1>>>(W_uq, W_uk, uqph, uqpl, ukph, ukpl);
    bqk_kernel<<<8, 128, 0, s1>>>(b_uq, W_uk, bqkr);
    gemm_on(s1, 128, 128, 640, ukph, ukpl, 640, uqph, uqpl, 640,
            nullptr, wqkrh, wqkrl, 128, nullptr, 1.0f,
            8, 8, 0, (long long)128*640, 0, (long long)128*640, 0, (long long)128*128);
    cudaEventRecord(g_aux.evA, s1);

    // ======== s2: W_o/W_uv-absorption chain ========
    convert_split_k<<<(128*D_MODEL + 255)/256, 256, 0, s2>>>(W_uv, uvsh, uvsl, 128*D_MODEL);
    tsplit_on(s2, W_o, woh, wol, D_MODEL, D_MODEL, D_MODEL, D_MODEL);
    gemm_on(s2, D_MODEL, 128, 640, woh, wol, D_MODEL, uvsh, uvsl, D_MODEL,
            nullptr, wcth, wctl, 1024, nullptr, 1.0f,
            8, 8, 0, 640, 0, 640, 0, 128);
    beff_partial<<<dim3(D_MODEL/256, 16), 256, 0, s2>>>(b_uv, W_o, beffp);
    beff_reduce<<<(D_MODEL + 255)/256, 256, 0, s2>>>(beffp, b_o, beff);
    cudaEventRecord(g_aux.evB, s2);

    // ======== per-batch activation pipelines (s0 = b0, s3 = b1) ========
    const long long HN = (long long)SS * D_MODEL;
    #define BATCH_CHAIN(st, B, BH, EVF)                                            \
    do {                                                                           \
        const long long r0 = (long long)(B) * SS;                                  \
        convert_split_k<<<(unsigned)((HN + 255)/256), 256, 0, (st)>>>(             \
            h + r0*D_MODEL, hh + r0*D_MODEL, hl + r0*D_MODEL, HN);                 \
        cudaStreamWaitEvent((st), g_aux.evW1, 0);                                  \
        gemm_on((st), SS, NCAT1, D_MODEL,                                          \
                hh + r0*D_MODEL, hl + r0*D_MODEL, D_MODEL, w1h, w1l, D_MODEL,      \
                cat1 + r0*NCAT1, cat1h + r0*NCAT1, cat1l + r0*NCAT1, NCAT1,        \
                b1, 1.0f);                                                         \
        copy_ckv<<<(SS*D_KV + 255)/256, 256, 0, (st)>>>(cat1, out_ckv, (int)r0);   \
        cudaStreamWaitEvent((st), g_aux.evA, 0);                                   \
        gemm_on((st), SS, NQE, 128,                                                \
                cat1h + r0*NCAT1 + 128, cat1l + r0*NCAT1 + 128, NCAT1,             \
                wqkrh, wqkrl, 128,                                                 \
                qe + r0*NQE, nullptr, nullptr, NQE, bqkr, 1.0f);                   \
        {                                                                          \
            long long total = (long long)8*SS*KAUG;                                \
            assemble_qk<<<(unsigned)((total + 255)/256), 256, 0, (st)>>>(          \
                qe, cat1, qph, qpl, kph, out_krot, (BH));                          \
        }                                                                          \
        tsplit_on((st), cat1 + r0*NCAT1, ckvth + (long long)(B)*128*SS,            \
                  ckvtl + (long long)(B)*128*SS, SS, 128, NCAT1, SS);              \
        flash_attn<<<dim3(SS/64, 8), 256, FA_SMEM, (st)>>>(                        \
            qph, qpl, kph, ckvth, ckvtl, lath, latl, scale, (BH));                 \
        cudaEventRecord((EVF), (st));                                              \
    } while (0)

    BATCH_CHAIN(s0, 0, 0, g_aux.evF0);
    BATCH_CHAIN(s3, 1, 8, g_aux.evF1);

    // ======== final GEMM, per-batch, co-scheduled ========
    cudaStreamWaitEvent(s1, g_aux.evF0, 0);
    cudaStreamWaitEvent(s1, g_aux.evB, 0);
    gemm_on(s1, SS, D_MODEL, 1024, lath, latl, 1024, wcth, wctl, 1024,
            out, nullptr, nullptr, D_MODEL, beff, 1.0f);
    cudaEventRecord(g_aux.evH0, s1);

    cudaStreamWaitEvent(s0, g_aux.evF1, 0);
    cudaStreamWaitEvent(s0, g_aux.evB, 0);
    gemm_on(s0, SS, D_MODEL, 1024,
            lath + (long long)SS*1024, latl + (long long)SS*1024, 1024,
            wcth, wctl, 1024,
            out + (long long)SS*D_MODEL, nullptr, nullptr, D_MODEL, beff, 1.0f);

    cudaStreamWaitEvent(s0, g_aux.evH0, 0);
}

// round 12
// speedup vs baseline: 10.6534x; 1.1025x over previous
#include <cuda_runtime.h>
#include <cuda_bf16.h>
#include <cuda_fp16.h>
#include <math.h>
#include <stdint.h>

#define D_MODEL 5120
#define N_HEADS 8
#define D_KV    128
#define D_ROPE  16
#define D_HEAD  640
#define SPLIT   624
#define BB      2
#define SS      2048
#define ROWS    (BB*SS)          // 4096
#define NCAT1   384              // dkv(128) + dq(128) + kr(128)
#define KAUG    192              // layout width; only 144 cols real
#define NQE     1152             // 1024 (Wqk) + 128 (Wqr)

typedef __nv_bfloat16 bf16;
typedef __half fp16;

// ---------------- scratch (device globals) ----------------------------------
__device__ __align__(16) float g_cat1 [ROWS*NCAT1];
__device__ __align__(16) bf16  g_cat1h[ROWS*NCAT1];
__device__ __align__(16) bf16  g_cat1l[ROWS*NCAT1];
__device__ __align__(16) bf16  g_hh  [(size_t)ROWS*D_MODEL];
__device__ __align__(16) bf16  g_hl  [(size_t)ROWS*D_MODEL];
__device__ __align__(16) bf16  g_w1h [NCAT1*D_MODEL];
__device__ __align__(16) bf16  g_w1l [NCAT1*D_MODEL];
__device__ __align__(16) bf16  g_uqph[8*128*640];
__device__ __align__(16) bf16  g_uqpl[8*128*640];
__device__ __align__(16) bf16  g_ukph[8*128*640];
__device__ __align__(16) bf16  g_ukpl[8*128*640];
__device__ __align__(16) bf16  g_wqkrh[NQE*128];
__device__ __align__(16) bf16  g_wqkrl[NQE*128];
__device__ __align__(16) float g_bqkr[NQE];
__device__ __align__(16) float g_qe  [(size_t)ROWS*NQE];
__device__ __align__(16) fp16  g_qph [(size_t)16*SS*KAUG];
__device__ __align__(16) fp16  g_kph [(size_t)16*SS*KAUG];
__device__ __align__(16) fp16  g_vt16[(size_t)BB*128*SS];
__device__ __align__(16) bf16  g_lath[(size_t)ROWS*1024];
__device__ __align__(16) bf16  g_latl[(size_t)ROWS*1024];
__device__ __align__(16) bf16  g_uvsh[128*D_MODEL];
__device__ __align__(16) bf16  g_uvsl[128*D_MODEL];
__device__ __align__(16) bf16  g_woh [(size_t)D_MODEL*D_MODEL];
__device__ __align__(16) bf16  g_wol [(size_t)D_MODEL*D_MODEL];
__device__ __align__(16) bf16  g_wcth[(size_t)D_MODEL*1024];
__device__ __align__(16) bf16  g_wctl[(size_t)D_MODEL*1024];
__device__ __align__(16) float g_b1  [NCAT1];
__device__ __align__(16) float g_beff[D_MODEL];
__device__ __align__(16) float g_beffp[16*D_MODEL];

// ---------------- streams/events ---------------------------------------------
struct AuxStreams {
    cudaStream_t s1, s2, s3;
    cudaEvent_t  evFork, evW1, evA, evB, evF0, evF1, evH0;
    AuxStreams() {
        cudaStreamCreateWithFlags(&s1, cudaStreamNonBlocking);
        cudaStreamCreateWithFlags(&s2, cudaStreamNonBlocking);
        cudaStreamCreateWithFlags(&s3, cudaStreamNonBlocking);
        cudaEventCreateWithFlags(&evFork, cudaEventDisableTiming);
        cudaEventCreateWithFlags(&evW1,   cudaEventDisableTiming);
        cudaEventCreateWithFlags(&evA,    cudaEventDisableTiming);
        cudaEventCreateWithFlags(&evB,    cudaEventDisableTiming);
        cudaEventCreateWithFlags(&evF0,   cudaEventDisableTiming);
        cudaEventCreateWithFlags(&evF1,   cudaEventDisableTiming);
        cudaEventCreateWithFlags(&evH0,   cudaEventDisableTiming);
    }
};
static AuxStreams g_aux;

// ---------------- PTX helpers ------------------------------------------------
__device__ __forceinline__ uint32_t smem_u32(const void* p) {
    uint32_t a;
    asm("{ .reg .u64 t; cvta.to.shared.u64 t, %1; cvt.u32.u64 %0, t; }"
        : "=r"(a) : "l"(p));
    return a;
}

__device__ __forceinline__ void cp16(uint32_t dst, const void* src) {
    asm volatile("cp.async.cg.shared.global [%0], [%1], 16;\n"
                 :: "r"(dst), "l"(__cvta_generic_to_global(src)));
}
#define CP_COMMIT() asm volatile("cp.async.commit_group;\n" ::: "memory")
#define CP_WAIT1()  asm volatile("cp.async.wait_group 1;\n" ::: "memory")
#define CP_WAIT0()  asm volatile("cp.async.wait_group 0;\n" ::: "memory")

__device__ __forceinline__ void ldm4(uint32_t* r, uint32_t a) {
    asm volatile("ldmatrix.sync.aligned.m8n8.x4.shared.b16 {%0,%1,%2,%3}, [%4];"
                 : "=r"(r[0]), "=r"(r[1]), "=r"(r[2]), "=r"(r[3]) : "r"(a));
}

__device__ __forceinline__ void mma16816(float* c, const uint32_t* a, const uint32_t* b) {
    asm volatile(
        "mma.sync.aligned.m16n8k16.row.col.f32.bf16.bf16.f32 "
        "{%0,%1,%2,%3},{%4,%5,%6,%7},{%8,%9},{%0,%1,%2,%3};\n"
        : "+f"(c[0]), "+f"(c[1]), "+f"(c[2]), "+f"(c[3])
        : "r"(a[0]), "r"(a[1]), "r"(a[2]), "r"(a[3]), "r"(b[0]), "r"(b[1]));
}

__device__ __forceinline__ void mma16816h(float* c, const uint32_t* a, const uint32_t* b) {
    asm volatile(
        "mma.sync.aligned.m16n8k16.row.col.f32.f16.f16.f32 "
        "{%0,%1,%2,%3},{%4,%5,%6,%7},{%8,%9},{%0,%1,%2,%3};\n"
        : "+f"(c[0]), "+f"(c[1]), "+f"(c[2]), "+f"(c[3])
        : "r"(a[0]), "r"(a[1]), "r"(a[2]), "r"(a[3]), "r"(b[0]), "r"(b[1]));
}

__device__ __forceinline__ uint32_t pack2(float a, float b) {
    __nv_bfloat162 t = __floats2bfloat162_rn(a, b);
    return *reinterpret_cast<const uint32_t*>(&t);
}

__device__ __forceinline__ void split_bf16(float v, bf16& h, bf16& l) {
    h = __float2bfloat16(v);
    l = __float2bfloat16(v - __bfloat162float(h));
}

__device__ __forceinline__ void split_pack(float a, float b, uint32_t& ph, uint32_t& pl) {
    bf16 ha = __float2bfloat16(a), hb = __float2bfloat16(b);
    ph = ((uint32_t)*(uint16_t*)&hb << 16) | (uint32_t)*(uint16_t*)&ha;
    pl = pack2(a - __bfloat162float(ha), b - __bfloat162float(hb));
}

__device__ __forceinline__ void split_pack_h(float a, float b, uint32_t& ph, uint32_t& pl) {
    fp16 ha = __float2half(a), hb = __float2half(b);
    ph = ((uint32_t)*(uint16_t*)&hb << 16) | (uint32_t)*(uint16_t*)&ha;
    __half2 t = __floats2half2_rn(a - __half2float(ha), b - __half2float(hb));
    pl = *reinterpret_cast<const uint32_t*>(&t);
}

// ---------------- bf16x3 mma.sync GEMM ---------------------------------------
#define STAGE_BYTES 65536
#define GEMM_SMEM   (3*STAGE_BYTES)

__global__ void __launch_bounds__(256, 1)
gemm_mma(int M, int N, int K,
         const bf16* __restrict__ Ah_, const bf16* __restrict__ Al_, long long lda,
         const bf16* __restrict__ Bh_, const bf16* __restrict__ Bl_, long long ldb,
         float* __restrict__ C, bf16* __restrict__ Ch, bf16* __restrict__ Cl,
         long long ldc,
         const float* __restrict__ bias, float alpha,
         int zdiv,
         long long sA1, long long sA2,
         long long sB1, long long sB2,
         long long sC1, long long sC2)
{
    extern __shared__ __align__(1024) char smem[];
    const uint32_t sb = smem_u32(smem);

    {
        int z  = blockIdx.z;
        int z1 = z / zdiv, z2 = z % zdiv;
        Ah_ += z1*sA1 + z2*sA2;  Al_ += z1*sA1 + z2*sA2;
        Bh_ += z1*sB1 + z2*sB2;  Bl_ += z1*sB1 + z2*sB2;
        long long co = z1*sC1 + z2*sC2;
        if (C)  C  += co;
        if (Ch) { Ch += co; Cl += co; }
    }

    const int tid  = threadIdx.x;
    const int wid  = tid >> 5;
    const int lane = tid & 31;
    const int wm   = (wid >> 2) * 64;
    const int wn   = (wid & 3) * 32;
    const int g    = lane >> 2, tg = lane & 3;
    const int m0   = blockIdx.y * 128;
    const int n0   = blockIdx.x * 128;

    const int lrow = tid >> 1;
    const int half = tid & 1;
    const bf16* pAh = Ah_ + (long long)(m0 + lrow)*lda;
    const bf16* pAl = Al_ + (long long)(m0 + lrow)*lda;
    const bf16* pBh = Bh_ + (long long)(n0 + lrow)*ldb;
    const bf16* pBl = Bl_ + (long long)(n0 + lrow)*ldb;
    const uint32_t lswz = (uint32_t)(lrow & 7);

    const int nk = K / 64;

    const int piece = lane >> 3, rr = lane & 7;
    const int rowA  = wm + (piece & 1)*8 + rr;
    const int rowB  = wn + (piece >> 1)*8 + rr;
    const int cA    = piece >> 1;
    const int cB    = piece & 1;

    float acc[4][4][4];
    #pragma unroll
    for (int i = 0; i < 4; i++)
        #pragma unroll
        for (int j = 0; j < 4; j++)
            #pragma unroll
            for (int k = 0; k < 4; k++) acc[i][j][k] = 0.0f;

    #define ISSUE(t) do {                                                     \
        uint32_t s0_ = sb + ((t) % 3) * STAGE_BYTES;                          \
        const int k0_ = (t) * 64;                                             \
        _Pragma("unroll")                                                     \
        for (int j = 0; j < 4; j++) {                                         \
            int ch_ = half*4 + j;                                             \
            uint32_t d_ = (uint32_t)(lrow*128 + (((uint32_t)ch_ ^ lswz) << 4)); \
            cp16(s0_ +         d_, pAh + k0_ + ch_*8);                        \
            cp16(s0_ + 16384 + d_, pAl + k0_ + ch_*8);                        \
            cp16(s0_ + 32768 + d_, pBh + k0_ + ch_*8);                        \
            cp16(s0_ + 49152 + d_, pBl + k0_ + ch_*8);                        \
        }                                                                     \
        CP_COMMIT();                                                          \
    } while (0)

    ISSUE(0);
    if (nk > 1) ISSUE(1);

    for (int t = 0; t < nk; t++) {
        if (t + 1 < nk) { CP_WAIT1(); } else { CP_WAIT0(); }
        __syncthreads();
        if (t + 2 < nk) ISSUE(t + 2);

        const uint32_t Ab = sb + (t % 3) * STAGE_BYTES;
        const uint32_t Bb = Ab + 32768;

        #pragma unroll
        for (int ks = 0; ks < 4; ks++) {
            uint32_t ah[4][4], al[4][4], bh[4][2], bl[4][2];
            const uint32_t aoff = (uint32_t)(rowA*128 + (((ks*2 + cA) ^ (rowA & 7)) << 4));
            const uint32_t boff = (uint32_t)(rowB*128 + (((ks*2 + cB) ^ (rowB & 7)) << 4));
            #pragma unroll
            for (int mt = 0; mt < 4; mt++) {
                ldm4(ah[mt], Ab +          aoff + mt*2048);
                ldm4(al[mt], Ab + 16384 +  aoff + mt*2048);
            }
            #pragma unroll
            for (int ntp = 0; ntp < 2; ntp++) {
                uint32_t rb[4];
                ldm4(rb, Bb +          boff + ntp*2048);
                bh[ntp*2][0]   = rb[0]; bh[ntp*2][1]   = rb[1];
                bh[ntp*2+1][0] = rb[2]; bh[ntp*2+1][1] = rb[3];
                ldm4(rb, Bb + 16384 +  boff + ntp*2048);
                bl[ntp*2][0]   = rb[0]; bl[ntp*2][1]   = rb[1];
                bl[ntp*2+1][0] = rb[2]; bl[ntp*2+1][1] = rb[3];
            }
            #pragma unroll
            for (int mt = 0; mt < 4; mt++)
                #pragma unroll
                for (int nt = 0; nt < 4; nt++) {
                    mma16816(acc[mt][nt], ah[mt], bh[nt]);
                    mma16816(acc[mt][nt], al[mt], bh[nt]);
                    mma16816(acc[mt][nt], ah[mt], bl[nt]);
                }
        }
    }

    #pragma unroll
    for (int mt = 0; mt < 4; mt++) {
        int row = m0 + wm + mt*16 + g;
        #pragma unroll
        for (int nt = 0; nt < 4; nt++) {
            int col = n0 + wn + nt*8 + tg*2;
            float b0 = 0.0f, b1 = 0.0f;
            if (bias) { b0 = bias[col]; b1 = bias[col+1]; }
            float v00 = acc[mt][nt][0]*alpha + b0;
            float v01 = acc[mt][nt][1]*alpha + b1;
            float v10 = acc[mt][nt][2]*alpha + b0;
            float v11 = acc[mt][nt][3]*alpha + b1;
            if (C) {
                *(float2*)(C + (long long)row*ldc + col)     = make_float2(v00, v01);
                *(float2*)(C + (long long)(row+8)*ldc + col) = make_float2(v10, v11);
            }
            if (Ch) {
                uint32_t ph, pl;
                split_pack(v00, v01, ph, pl);
                *(uint32_t*)(Ch + (long long)row*ldc + col) = ph;
                *(uint32_t*)(Cl + (long long)row*ldc + col) = pl;
                split_pack(v10, v11, ph, pl);
                *(uint32_t*)(Ch + (long long)(row+8)*ldc + col) = ph;
                *(uint32_t*)(Cl + (long long)(row+8)*ldc + col) = pl;
            }
        }
    }
}

// ---------------- fused flash attention ---------------------------------------
// QK: single fp16 MMA (Qh*Kh).  PV: fp16 2-MMA (Ph*V + Pl*V), V single fp16.
// smem: Q 24576 | 2 stages x (K 24576 + V 16384) | P hi/lo 16384 | reductions
#define FA_NC    32
#define FA_STG   40960
#define FA_Q     0
#define FA_S0    24576
#define FA_P     106496
#define FA_REDM  122880
#define FA_REDS  123904
#define FA_SMEM  124928
#define FA_NKS   9

__global__ void __launch_bounds__(256, 1)
flash_attn(const fp16* __restrict__ qph,
           const fp16* __restrict__ kph,
           const fp16* __restrict__ vt,
           bf16* __restrict__ lath, bf16* __restrict__ latl,
           float scale, int bh_base)
{
    extern __shared__ __align__(1024) char smem[];
    const uint32_t sb = smem_u32(smem);

    const int tid  = threadIdx.x;
    const int wid  = tid >> 5;
    const int lane = tid & 31;
    const int wm2  = wid >> 2;
    const int wn4  = wid & 3;
    const int g    = lane >> 2, tg = lane & 3;
    const int piece = lane >> 3, rr = lane & 7;

    const int bh = blockIdx.y + bh_base;
    const int b  = bh >> 3;
    const int qb = blockIdx.x;

    const fp16* qbh = qph + ((size_t)bh*SS + (size_t)qb*64)*KAUG;
    const fp16* kbh = kph + (size_t)bh*SS*KAUG;
    const fp16* vb  = vt  + (size_t)b*128*SS;

    #pragma unroll
    for (int i = 0; i < 6; i++) {
        int idx = i*256 + tid;
        int row = idx / 24, cc = idx % 24;
        if (cc < 18) {
            int kt = cc >> 3, c8 = cc & 7;
            uint32_t d = (uint32_t)(kt*8192 + row*128 + (((uint32_t)c8 ^ (row & 7)) << 4));
            cp16(sb + FA_Q + d, qbh + row*KAUG + cc*8);
        }
    }
    CP_COMMIT();

    #define FA_ISSUE(t) do {                                                   \
        uint32_t st_ = sb + FA_S0 + ((t) & 1) * FA_STG;                        \
        const int t0_ = (t) * 64;                                              \
        _Pragma("unroll")                                                      \
        for (int i = 0; i < 6; i++) {                                          \
            int idx = i*256 + tid;                                             \
            int row = idx / 24, cc = idx % 24;                                 \
            if (cc < 18) {                                                     \
                int kt = cc >> 3, c8 = cc & 7;                                 \
                uint32_t d = (uint32_t)(kt*8192 + row*128 + (((uint32_t)c8 ^ (row & 7)) << 4)); \
                cp16(st_ + d, kbh + (size_t)(t0_+row)*KAUG + cc*8);            \
            }                                                                  \
        }                                                                      \
        _Pragma("unroll")                                                      \
        for (int i = 0; i < 4; i++) {                                          \
            int idx = i*256 + tid;                                             \
            int row = idx >> 3, c8 = idx & 7;                                  \
            uint32_t d = (uint32_t)(row*128 + (((uint32_t)c8 ^ (row & 7)) << 4)); \
            cp16(st_ + 24576 + d, vb + (size_t)row*SS + t0_ + c8*8);           \
        }                                                                      \
        CP_COMMIT();                                                           \
    } while (0)

    FA_ISSUE(0);

    float accv[2][4][4];
    #pragma unroll
    for (int i = 0; i < 2; i++)
        #pragma unroll
        for (int j = 0; j < 4; j++)
            #pragma unroll
            for (int k = 0; k < 4; k++) accv[i][j][k] = 0.0f;
    float Mrow[4] = {-1e30f, -1e30f, -1e30f, -1e30f};
    float Lrow[4] = {0.0f, 0.0f, 0.0f, 0.0f};

    float* redm = (float*)(smem + FA_REDM);
    float* reds = (float*)(smem + FA_REDS);

    for (int t = 0; t < FA_NC; t++) {
        CP_WAIT0();
        __syncthreads();
        if (t + 1 < FA_NC) FA_ISSUE(t + 1);

        const uint32_t KB = sb + FA_S0 + (t & 1) * FA_STG;
        const uint32_t VB = KB + 24576;

        float sacc[2][2][4];
        #pragma unroll
        for (int i = 0; i < 2; i++)
            #pragma unroll
            for (int j = 0; j < 2; j++)
                #pragma unroll
                for (int k = 0; k < 4; k++) sacc[i][j][k] = 0.0f;

        #pragma unroll
        for (int ks = 0; ks < FA_NKS; ks++) {
            const int kt = ks >> 2, ks2 = ks & 3;
            uint32_t ah[2][4];
            #pragma unroll
            for (int mt = 0; mt < 2; mt++) {
                int rowA = wm2*32 + mt*16 + (piece & 1)*8 + rr;
                uint32_t off = (uint32_t)(kt*8192 + rowA*128 +
                    (((ks2*2 + (piece >> 1)) ^ (rowA & 7)) << 4));
                ldm4(ah[mt], sb + FA_Q + off);
            }
            int rowB = wn4*16 + (piece >> 1)*8 + rr;
            uint32_t offB = (uint32_t)(kt*8192 + rowB*128 +
                (((ks2*2 + (piece & 1)) ^ (rowB & 7)) << 4));
            uint32_t rbh[4];
            ldm4(rbh, KB + offB);
            #pragma unroll
            for (int mt = 0; mt < 2; mt++)
                #pragma unroll
                for (int nt = 0; nt < 2; nt++)
                    mma16816h(sacc[mt][nt], ah[mt], rbh + nt*2);
        }

        float mloc[4] = {-1e30f, -1e30f, -1e30f, -1e30f};
        #pragma unroll
        for (int mt = 0; mt < 2; mt++)
            #pragma unroll
            for (int nt = 0; nt < 2; nt++)
                #pragma unroll
                for (int c = 0; c < 4; c++) {
                    sacc[mt][nt][c] *= scale;
                    int slot = mt*2 + (c >> 1);
                    mloc[slot] = fmaxf(mloc[slot], sacc[mt][nt][c]);
                }
        #pragma unroll
        for (int s = 0; s < 4; s++) {
            mloc[s] = fmaxf(mloc[s], __shfl_xor_sync(0xffffffffu, mloc[s], 1));
            mloc[s] = fmaxf(mloc[s], __shfl_xor_sync(0xffffffffu, mloc[s], 2));
        }
        if (tg == 0) {
            #pragma unroll
            for (int mt = 0; mt < 2; mt++)
                #pragma unroll
                for (int h2 = 0; h2 < 2; h2++) {
                    int r = wm2*32 + mt*16 + h2*8 + g;
                    redm[wn4*64 + r] = mloc[mt*2 + h2];
                }
        }
        __syncthreads();

        float fsc[4];
        #pragma unroll
        for (int mt = 0; mt < 2; mt++)
            #pragma unroll
            for (int h2 = 0; h2 < 2; h2++) {
                int r = wm2*32 + mt*16 + h2*8 + g;
                float cm = fmaxf(fmaxf(redm[r], redm[64 + r]),
                                 fmaxf(redm[128 + r], redm[192 + r]));
                int slot = mt*2 + h2;
                float mn = fmaxf(Mrow[slot], cm);
                fsc[slot] = __expf(Mrow[slot] - mn);
                Mrow[slot] = mn;
            }

        float sl[4] = {0.0f, 0.0f, 0.0f, 0.0f};
        #pragma unroll
        for (int mt = 0; mt < 2; mt++)
            #pragma unroll
            for (int nt = 0; nt < 2; nt++)
                #pragma unroll
                for (int c = 0; c < 4; c++) {
                    int slot = mt*2 + (c >> 1);
                    float p = __expf(sacc[mt][nt][c] - Mrow[slot]);
                    sacc[mt][nt][c] = p;
                    sl[slot] += p;
                }
        #pragma unroll
        for (int mt = 0; mt < 2; mt++)
            #pragma unroll
            for (int nt = 0; nt < 4; nt++)
                #pragma unroll
                for (int c = 0; c < 4; c++)
                    accv[mt][nt][c] *= fsc[mt*2 + (c >> 1)];
        #pragma unroll
        for (int s = 0; s < 4; s++) {
            sl[s] += __shfl_xor_sync(0xffffffffu, sl[s], 1);
            sl[s] += __shfl_xor_sync(0xffffffffu, sl[s], 2);
        }
        if (tg == 0) {
            #pragma unroll
            for (int mt = 0; mt < 2; mt++)
                #pragma unroll
                for (int h2 = 0; h2 < 2; h2++) {
                    int r = wm2*32 + mt*16 + h2*8 + g;
                    reds[wn4*64 + r] = sl[mt*2 + h2];
                }
        }
        // write P hi/lo (fp16) to smem
        #pragma unroll
        for (int mt = 0; mt < 2; mt++)
            #pragma unroll
            for (int nt = 0; nt < 2; nt++)
                #pragma unroll
                for (int h2 = 0; h2 < 2; h2++) {
                    int r = wm2*32 + mt*16 + h2*8 + g;
                    int cidx = wn4*2 + nt;
                    uint32_t addr = (uint32_t)(r*128 + ((cidx ^ (r & 7)) << 4) + tg*4);
                    uint32_t ph, pl;
                    split_pack_h(sacc[mt][nt][2*h2], sacc[mt][nt][2*h2+1], ph, pl);
                    *(uint32_t*)(smem + FA_P +        addr) = ph;
                    *(uint32_t*)(smem + FA_P + 8192 + addr) = pl;
                }
        __syncthreads();

        #pragma unroll
        for (int mt = 0; mt < 2; mt++)
            #pragma unroll
            for (int h2 = 0; h2 < 2; h2++) {
                int r = wm2*32 + mt*16 + h2*8 + g;
                float ssum = reds[r] + reds[64 + r] + reds[128 + r] + reds[192 + r];
                int slot = mt*2 + h2;
                Lrow[slot] = Lrow[slot] * fsc[slot] + ssum;
            }

        #pragma unroll
        for (int ksv = 0; ksv < 4; ksv++) {
            uint32_t pah[2][4], pal[2][4];
            #pragma unroll
            for (int mt = 0; mt < 2; mt++) {
                int rowA = wm2*32 + mt*16 + (piece & 1)*8 + rr;
                uint32_t off = (uint32_t)(rowA*128 +
                    (((ksv*2 + (piece >> 1)) ^ (rowA & 7)) << 4));
                ldm4(pah[mt], sb + FA_P +        off);
                ldm4(pal[mt], sb + FA_P + 8192 + off);
            }
            uint32_t vh[2][4];
            #pragma unroll
            for (int ntp = 0; ntp < 2; ntp++) {
                int rowB = wn4*32 + ntp*16 + (piece >> 1)*8 + rr;
                uint32_t offB = (uint32_t)(rowB*128 +
                    (((ksv*2 + (piece & 1)) ^ (rowB & 7)) << 4));
                ldm4(vh[ntp], VB + offB);
            }
            #pragma unroll
            for (int mt = 0; mt < 2; mt++)
                #pragma unroll
                for (int nt = 0; nt < 4; nt++) {
                    const uint32_t* bhp = vh[nt >> 1] + (nt & 1)*2;
                    mma16816h(accv[mt][nt], pah[mt], bhp);
                    mma16816h(accv[mt][nt], pal[mt], bhp);
                }
        }
    }

    float inv[4];
    #pragma unroll
    for (int s = 0; s < 4; s++) inv[s] = 1.0f / Lrow[s];

    const int h = bh & 7;
    #pragma unroll
    for (int mt = 0; mt < 2; mt++) {
        #pragma unroll
        for (int nt = 0; nt < 4; nt++) {
            int col = h*128 + wn4*32 + nt*8 + tg*2;
            #pragma unroll
            for (int h2 = 0; h2 < 2; h2++) {
                long long row = (long long)b*SS + qb*64 + wm2*32 + mt*16 + h2*8 + g;
                float v0 = accv[mt][nt][2*h2]   * inv[mt*2 + h2];
                float v1 = accv[mt][nt][2*h2+1] * inv[mt*2 + h2];
                uint32_t ph, pl;
                split_pack(v0, v1, ph, pl);
                *(uint32_t*)(lath + row*1024 + col) = ph;
                *(uint32_t*)(latl + row*1024 + col) = pl;
            }
        }
    }
}

// ---------------- elementwise fp32 -> bf16 hi/lo ------------------------------
__global__ void convert_split_k(const float* __restrict__ in,
                                bf16* __restrict__ oh, bf16* __restrict__ ol,
                                long long n)
{
    long long i = (long long)blockIdx.x * 256 + threadIdx.x;
    if (i < n) {
        bf16 h, l; split_bf16(in[i], h, l);
        oh[i] = h; ol[i] = l;
    }
}

// ---------------- fp32 transpose -> bf16 hi/lo --------------------------------
__global__ void transpose_split_k(const float* __restrict__ in,
                                  bf16* __restrict__ oh, bf16* __restrict__ ol,
                                  int M, int N, int ldi, int ldo,
                                  int zdiv,
                                  long long si1, long long si2,
                                  long long so1, long long so2)
{
    __shared__ float tile[32][33];
    int z = blockIdx.z, z1 = z / zdiv, z2 = z % zdiv;
    in += z1*si1 + z2*si2;
    oh += z1*so1 + z2*so2;
    ol += z1*so1 + z2*so2;

    int x = blockIdx.x*32 + threadIdx.x;
    int y = blockIdx.y*32 + threadIdx.y;
    #pragma unroll
    for (int i = 0; i < 32; i += 8)
        if (x < N && (y+i) < M)
            tile[threadIdx.y+i][threadIdx.x] = in[(long long)(y+i)*ldi + x];
    __syncthreads();
    x = blockIdx.y*32 + threadIdx.x;
    y = blockIdx.x*32 + threadIdx.y;
    #pragma unroll
    for (int i = 0; i < 32; i += 8)
        if (x < M && (y+i) < N) {
            bf16 h, l; split_bf16(tile[threadIdx.x][threadIdx.y+i], h, l);
            oh[(long long)(y+i)*ldo + x] = h;
            ol[(long long)(y+i)*ldo + x] = l;
        }
}

// ---------------- fp32 transpose -> single fp16 -------------------------------
__global__ void transpose_half_k(const float* __restrict__ in,
                                 fp16* __restrict__ o,
                                 int M, int N, int ldi, int ldo)
{
    __shared__ float tile[32][33];
    int x = blockIdx.x*32 + threadIdx.x;
    int y = blockIdx.y*32 + threadIdx.y;
    #pragma unroll
    for (int i = 0; i < 32; i += 8)
        if (x < N && (y+i) < M)
            tile[threadIdx.y+i][threadIdx.x] = in[(long long)(y+i)*ldi + x];
    __syncthreads();
    x = blockIdx.y*32 + threadIdx.x;
    y = blockIdx.x*32 + threadIdx.y;
    #pragma unroll
    for (int i = 0; i < 32; i += 8)
        if (x < M && (y+i) < N)
            o[(long long)(y+i)*ldo + x] = __float2half(tile[threadIdx.x][threadIdx.y+i]);
}

// ---------------- pad+split W_uq / W_uk into [8][128][640] --------------------
__global__ void pad_split_uqk(const float* __restrict__ Wuq,
                              const float* __restrict__ Wuk,
                              bf16* __restrict__ uqh, bf16* __restrict__ uql,
                              bf16* __restrict__ ukh, bf16* __restrict__ ukl)
{
    int idx = blockIdx.x * 256 + threadIdx.x;
    if (idx >= 8*128*640) return;
    int e = idx % 640;
    int c = (idx / 640) & 127;
    int h = idx / (640*128);
    float vq = 0.0f, vk = 0.0f;
    if (e < SPLIT) {
        vq = Wuq[c*4992 + h*SPLIT + e];
        vk = Wuk[c*4992 + h*SPLIT + e];
    }
    bf16 hh, ll;
    split_bf16(vq, hh, ll); uqh[idx] = hh; uql[idx] = ll;
    split_bf16(vk, hh, ll); ukh[idx] = hh; ukl[idx] = ll;
}

// ---------------- bqk -----------------------------------------------------------
__global__ void bqk_kernel(const float* __restrict__ b_uq,
                           const float* __restrict__ W_uk,
                           float* __restrict__ bqk)
{
    int c = threadIdx.x;
    int h = blockIdx.x;
    float acc = 0.0f;
    const float* wrow = W_uk + c*4992 + h*SPLIT;
    const float* brow = b_uq + h*SPLIT;
    for (int e = 0; e < SPLIT; e++)
        acc += brow[e] * wrow[e];
    bqk[h*128 + c] = acc;
}

// ---------------- beff ----------------------------------------------------------
__global__ void beff_partial(const float* __restrict__ b_uv,
                             const float* __restrict__ W_o,
                             float* __restrict__ part)
{
    int o   = blockIdx.x * 256 + threadIdx.x;
    int seg = blockIdx.y;
    float acc = 0.0f;
    int d0 = seg * (D_MODEL/16);
    #pragma unroll 4
    for (int d = d0; d < d0 + D_MODEL/16; d++)
        acc += b_uv[d] * W_o[(size_t)d*D_MODEL + o];
    part[(size_t)seg*D_MODEL + o] = acc;
}

__global__ void beff_reduce(const float* __restrict__ part,
                            const float* __restrict__ b_o,
                            float* __restrict__ be)
{
    int o = blockIdx.x * 256 + threadIdx.x;
    if (o >= D_MODEL) return;
    float acc = b_o[o];
    #pragma unroll
    for (int s = 0; s < 16; s++)
        acc += part[(size_t)s*D_MODEL + o];
    be[o] = acc;
}

// ---------------- assemble Q'/K' (rope) -> single fp16; emit k_rot --------------
__global__ void assemble_qk(const float* __restrict__ qe,
                            const float* __restrict__ cat1,
                            fp16* __restrict__ qph,
                            fp16* __restrict__ kph,
                            float* __restrict__ out_krot, int bh_base)
{
    long long idx = (long long)blockIdx.x * 256 + threadIdx.x;
    if (idx >= (long long)8*SS*KAUG) return;
    int j  = (int)(idx % KAUG);
    int s  = (int)((idx / KAUG) & (SS - 1));
    int bh = (int)(idx / ((long long)KAUG*SS)) + bh_base;
    long long gidx = (long long)bh*SS*KAUG + (long long)s*KAUG + j;
    int b  = bh >> 3, h = bh & 7;
    long long row = (long long)b*SS + s;

    float qv = 0.0f, kv = 0.0f;
    if (j < 128) {
        qv = qe[row*NQE + h*128 + j];
        kv = cat1[row*NCAT1 + j];
    } else if (j < 144) {
        int dd = j - 128;
        long long qb = row*NQE + 1024 + h*D_ROPE;
        long long kb = row*NCAT1 + 256 + h*D_ROPE;
        if (dd < 8) {
            const float invf[4] = {1.0f, 0.1f, 0.01f, 0.001f};
            float f = ((float)s / 40.0f) * invf[dd & 3];
            float c_ = cosf(f), sn = sinf(f);
            if (dd < 4) {
                qv = qe[qb+dd]*c_ - qe[qb+dd+4]*sn;
                kv = cat1[kb+dd]*c_ - cat1[kb+dd+4]*sn;
            } else {
                qv = qe[qb+dd]*c_ + qe[qb+dd-4]*sn;
                kv = cat1[kb+dd]*c_ + cat1[kb+dd-4]*sn;
            }
        } else {
            qv = qe[qb+dd];
            kv = cat1[kb+dd];
        }
        out_krot[row*128 + h*D_ROPE + dd] = kv;
    } else {
        return;
    }
    qph[gidx] = __float2half(qv);
    kph[gidx] = __float2half(kv);
}

// ---------------- c_kv output copy (per-batch) ---------------------------------
__global__ void copy_ckv(const float* __restrict__ cat1, float* __restrict__ out,
                         int row0)
{
    int idx = blockIdx.x * 256 + threadIdx.x;
    if (idx < SS * D_KV) {
        int row = row0 + (idx >> 7);
        out[(long long)row*D_KV + (idx & 127)] = cat1[(long long)row*NCAT1 + (idx & 127)];
    }
}

// ---------------- host side ------------------------------------------------------
static inline void* symv(const void* s)
{
    void* p = nullptr;
    cudaGetSymbolAddress(&p, s);
    return p;
}

static void gemm_on(cudaStream_t st, int M, int N, int K,
                    const bf16* Ah, const bf16* Al, long long lda,
                    const bf16* Bh, const bf16* Bl, long long ldb,
                    float* C, bf16* Ch, bf16* Cl, long long ldc,
                    const float* bias, float alpha,
                    int nz = 1, int zdiv = 1,
                    long long sA1 = 0, long long sA2 = 0,
                    long long sB1 = 0, long long sB2 = 0,
                    long long sC1 = 0, long long sC2 = 0)
{
    dim3 grid(N / 128, M / 128, nz);
    gemm_mma<<<grid, 256, GEMM_SMEM, st>>>(M, N, K, Ah, Al, lda, Bh, Bl, ldb,
                                           C, Ch, Cl, ldc, bias, alpha, zdiv,
                                           sA1, sA2, sB1, sB2, sC1, sC2);
}

static void tsplit_on(cudaStream_t st, const float* in, bf16* oh, bf16* ol,
                      int M, int N, int ldi, int ldo)
{
    dim3 grid((N + 31)/32, (M + 31)/32, 1);
    transpose_split_k<<<grid, dim3(32, 8), 0, st>>>(in, oh, ol, M, N, ldi, ldo,
                                                    1, 0, 0, 0, 0);
}

extern "C" void kernel_launch(void* const* d_in, const int* in_sizes, int n_in,
                              void* d_out, int out_size)
{
    const float* h     = (const float*)d_in[0];
    const float* W_dkv = (const float*)d_in[1];
    const float* b_dkv = (const float*)d_in[2];
    const float* W_dq  = (const float*)d_in[3];
    const float* b_dq  = (const float*)d_in[4];
    const float* W_uk  = (const float*)d_in[5];
    const float* b_uk  = (const float*)d_in[6];
    const float* W_uv  = (const float*)d_in[7];
    const float* b_uv  = (const float*)d_in[8];
    const float* W_uq  = (const float*)d_in[9];
    const float* b_uq  = (const float*)d_in[10];
    const float* W_qr  = (const float*)d_in[11];
    const float* b_qr  = (const float*)d_in[12];
    const float* W_kr  = (const float*)d_in[13];
    const float* b_kr  = (const float*)d_in[14];
    const float* W_o   = (const float*)d_in[15];
    const float* b_o   = (const float*)d_in[16];
    (void)b_uk;

    float* out      = (float*)d_out;
    float* out_ckv  = out + (long long)ROWS * D_MODEL;
    float* out_krot = out_ckv + (long long)ROWS * D_KV;

    float* cat1  = (float*)symv(g_cat1);
    bf16*  cat1h = (bf16*)symv(g_cat1h);
    bf16*  cat1l = (bf16*)symv(g_cat1l);
    bf16*  hh    = (bf16*)symv(g_hh);
    bf16*  hl    = (bf16*)symv(g_hl);
    bf16*  w1h   = (bf16*)symv(g_w1h);
    bf16*  w1l   = (bf16*)symv(g_w1l);
    bf16*  uqph  = (bf16*)symv(g_uqph);
    bf16*  uqpl  = (bf16*)symv(g_uqpl);
    bf16*  ukph  = (bf16*)symv(g_ukph);
    bf16*  ukpl  = (bf16*)symv(g_ukpl);
    bf16*  wqkrh = (bf16*)symv(g_wqkrh);
    bf16*  wqkrl = (bf16*)symv(g_wqkrl);
    float* bqkr  = (float*)symv(g_bqkr);
    float* qe    = (float*)symv(g_qe);
    fp16*  qph   = (fp16*)symv(g_qph);
    fp16*  kph   = (fp16*)symv(g_kph);
    fp16*  vt16  = (fp16*)symv(g_vt16);
    bf16*  lath  = (bf16*)symv(g_lath);
    bf16*  latl  = (bf16*)symv(g_latl);
    bf16*  uvsh  = (bf16*)symv(g_uvsh);
    bf16*  uvsl  = (bf16*)symv(g_uvsl);
    bf16*  woh   = (bf16*)symv(g_woh);
    bf16*  wol   = (bf16*)symv(g_wol);
    bf16*  wcth  = (bf16*)symv(g_wcth);
    bf16*  wctl  = (bf16*)symv(g_wctl);
    float* b1    = (float*)symv(g_b1);
    float* beff  = (float*)symv(g_beff);
    float* beffp = (float*)symv(g_beffp);

    cudaFuncSetAttribute(gemm_mma, cudaFuncAttributeMaxDynamicSharedMemorySize, GEMM_SMEM);
    cudaFuncSetAttribute(flash_attn, cudaFuncAttributeMaxDynamicSharedMemorySize, FA_SMEM);

    const float scale = 1.0f / sqrtf((float)D_HEAD);
    cudaStream_t s0 = 0, s1 = g_aux.s1, s2 = g_aux.s2, s3 = g_aux.s3;

    // ---- fork ----
    cudaEventRecord(g_aux.evFork, s0);
    cudaStreamWaitEvent(s1, g_aux.evFork, 0);
    cudaStreamWaitEvent(s2, g_aux.evFork, 0);
    cudaStreamWaitEvent(s3, g_aux.evFork, 0);

    // ======== s1: W1 prep, then Wqk-absorption chain ========
    cudaMemcpyAsync(b1,      b_dkv, 128*sizeof(float), cudaMemcpyDeviceToDevice, s1);
    cudaMemcpyAsync(b1+128,  b_dq,  128*sizeof(float), cudaMemcpyDeviceToDevice, s1);
    cudaMemcpyAsync(b1+256,  b_kr,  128*sizeof(float), cudaMemcpyDeviceToDevice, s1);
    tsplit_on(s1, W_dkv, w1h,               w1l,               D_MODEL, D_KV, D_KV, D_MODEL);
    tsplit_on(s1, W_dq,  w1h + 128*D_MODEL, w1l + 128*D_MODEL, D_MODEL, D_KV, D_KV, D_MODEL);
    tsplit_on(s1, W_kr,  w1h + 256*D_MODEL, w1l + 256*D_MODEL, D_MODEL, D_KV, D_KV, D_MODEL);
    cudaEventRecord(g_aux.evW1, s1);

    cudaMemcpyAsync(bqkr+1024, b_qr, 128*sizeof(float), cudaMemcpyDeviceToDevice, s1);
    tsplit_on(s1, W_qr, wqkrh + 1024*128, wqkrl + 1024*128, D_KV, 128, 128, D_KV);
    pad_split_uqk<<<(8*128*640 + 255)/256, 256, 0, s1>>>(W_uq, W_uk, uqph, uqpl, ukph, ukpl);
    bqk_kernel<<<8, 128, 0, s1>>>(b_uq, W_uk, bqkr);
    gemm_on(s1, 128, 128, 640, ukph, ukpl, 640, uqph, uqpl, 640,
            nullptr, wqkrh, wqkrl, 128, nullptr, 1.0f,
            8, 8, 0, (long long)128*640, 0, (long long)128*640, 0, (long long)128*128);
    cudaEventRecord(g_aux.evA, s1);

    // ======== s2: W_o/W_uv-absorption chain ========
    convert_split_k<<<(128*D_MODEL + 255)/256, 256, 0, s2>>>(W_uv, uvsh, uvsl, 128*D_MODEL);
    tsplit_on(s2, W_o, woh, wol, D_MODEL, D_MODEL, D_MODEL, D_MODEL);
    gemm_on(s2, D_MODEL, 128, 640, woh, wol, D_MODEL, uvsh, uvsl, D_MODEL,
            nullptr, wcth, wctl, 1024, nullptr, 1.0f,
            8, 8, 0, 640, 0, 640, 0, 128);
    beff_partial<<<dim3(D_MODEL/256, 16), 256, 0, s2>>>(b_uv, W_o, beffp);
    beff_reduce<<<(D_MODEL + 255)/256, 256, 0, s2>>>(beffp, b_o, beff);
    cudaEventRecord(g_aux.evB, s2);

    // ======== per-batch activation pipelines (s0 = b0, s3 = b1) ========
    const long long HN = (long long)SS * D_MODEL;
    #define BATCH_CHAIN(st, B, BH, EVF)                                            \
    do {                                                                           \
        const long long r0 = (long long)(B) * SS;                                  \
        convert_split_k<<<(unsigned)((HN + 255)/256), 256, 0, (st)>>>(             \
            h + r0*D_MODEL, hh + r0*D_MODEL, hl + r0*D_MODEL, HN);                 \
        cudaStreamWaitEvent((st), g_aux.evW1, 0);                                  \
        gemm_on((st), SS, NCAT1, D_MODEL,                                          \
                hh + r0*D_MODEL, hl + r0*D_MODEL, D_MODEL, w1h, w1l, D_MODEL,      \
                cat1 + r0*NCAT1, cat1h + r0*NCAT1, cat1l + r0*NCAT1, NCAT1,        \
                b1, 1.0f);                                                         \
        copy_ckv<<<(SS*D_KV + 255)/256, 256, 0, (st)>>>(cat1, out_ckv, (int)r0);   \
        cudaStreamWaitEvent((st), g_aux.evA, 0);                                   \
        gemm_on((st), SS, NQE, 128,                                                \
                cat1h + r0*NCAT1 + 128, cat1l + r0*NCAT1 + 128, NCAT1,             \
                wqkrh, wqkrl, 128,                                                 \
                qe + r0*NQE, nullptr, nullptr, NQE, bqkr, 1.0f);                   \
        {                                                                          \
            long long total = (long long)8*SS*KAUG;                                \
            assemble_qk<<<(unsigned)((total + 255)/256), 256, 0, (st)>>>(          \
                qe, cat1, qph, kph, out_krot, (BH));                               \
        }                                                                          \
        {                                                                          \
            dim3 tg_((128 + 31)/32, (SS + 31)/32, 1);                              \
            transpose_half_k<<<tg_, dim3(32, 8), 0, (st)>>>(                       \
                cat1 + r0*NCAT1, vt16 + (long long)(B)*128*SS, SS, 128, NCAT1, SS);\
        }                                                                          \
        flash_attn<<<dim3(SS/64, 8), 256, FA_SMEM, (st)>>>(                        \
            qph, kph, vt16, lath, latl, scale, (BH));                              \
        cudaEventRecord((EVF), (st));                                              \
    } while (0)

    BATCH_CHAIN(s0, 0, 0, g_aux.evF0);
    BATCH_CHAIN(s3, 1, 8, g_aux.evF1);

    // ======== final GEMM, per-batch, co-scheduled ========
    cudaStreamWaitEvent(s1, g_aux.evF0, 0);
    cudaStreamWaitEvent(s1, g_aux.evB, 0);
    gemm_on(s1, SS, D_MODEL, 1024, lath, latl, 1024, wcth, wctl, 1024,
            out, nullptr, nullptr, D_MODEL, beff, 1.0f);
    cudaEventRecord(g_aux.evH0, s1);

    cudaStreamWaitEvent(s0, g_aux.evF1, 0);
    cudaStreamWaitEvent(s0, g_aux.evB, 0);
    gemm_on(s0, SS, D_MODEL, 1024,
            lath + (long long)SS*1024, latl + (long long)SS*1024, 1024,
            wcth, wctl, 1024,
            out + (long long)SS*D_MODEL, nullptr, nullptr, D_MODEL, beff, 1.0f);

    cudaStreamWaitEvent(s0, g_aux.evH0, 0);
}

// round 13
// speedup vs baseline: 12.0903x; 1.1349x over previous
#include <cuda_runtime.h>
#include <cuda_bf16.h>
#include <cuda_fp16.h>
#include <math.h>
#include <stdint.h>

#define D_MODEL 5120
#define N_HEADS 8
#define D_KV    128
#define D_ROPE  16
#define D_HEAD  640
#define SPLIT   624
#define BB      2
#define SS      2048
#define ROWS    (BB*SS)          // 4096
#define NCAT1   384              // dkv(128) + dq(128) + kr(128)
#define KAUG    192              // layout width; only 144 cols real
#define NQE     1152             // 1024 (Wqk) + 128 (Wqr)

typedef __nv_bfloat16 bf16;
typedef __half fp16;

// ---------------- scratch (device globals) ----------------------------------
__device__ __align__(16) float g_cat1 [ROWS*NCAT1];
__device__ __align__(16) bf16  g_cat1h[ROWS*NCAT1];
__device__ __align__(16) bf16  g_cat1l[ROWS*NCAT1];
__device__ __align__(16) bf16  g_hh  [(size_t)ROWS*D_MODEL];
__device__ __align__(16) bf16  g_hl  [(size_t)ROWS*D_MODEL];
__device__ __align__(16) bf16  g_w1h [NCAT1*D_MODEL];
__device__ __align__(16) bf16  g_w1l [NCAT1*D_MODEL];
__device__ __align__(16) bf16  g_uqph[8*128*640];
__device__ __align__(16) bf16  g_uqpl[8*128*640];
__device__ __align__(16) bf16  g_ukph[8*128*640];
__device__ __align__(16) bf16  g_ukpl[8*128*640];
__device__ __align__(16) bf16  g_wqkrh[NQE*128];
__device__ __align__(16) bf16  g_wqkrl[NQE*128];
__device__ __align__(16) float g_bqkr[NQE];
__device__ __align__(16) float g_qe  [(size_t)ROWS*NQE];
__device__ __align__(16) fp16  g_qph [(size_t)16*SS*KAUG];
__device__ __align__(16) fp16  g_kph [(size_t)16*SS*KAUG];
__device__ __align__(16) fp16  g_vt16[(size_t)BB*128*SS];
__device__ __align__(16) fp16  g_lath[(size_t)ROWS*1024];
__device__ __align__(16) fp16  g_latl[(size_t)ROWS*1024];
__device__ __align__(16) bf16  g_uvsh[128*D_MODEL];
__device__ __align__(16) bf16  g_uvsl[128*D_MODEL];
__device__ __align__(16) bf16  g_woh [(size_t)D_MODEL*D_MODEL];
__device__ __align__(16) bf16  g_wol [(size_t)D_MODEL*D_MODEL];
__device__ __align__(16) float g_wcomb[(size_t)D_MODEL*1024];
__device__ __align__(16) fp16  g_wct16[(size_t)D_MODEL*1024];
__device__ __align__(16) float g_b1  [NCAT1];
__device__ __align__(16) float g_beff[D_MODEL];
__device__ __align__(16) float g_beffp[16*D_MODEL];

// ---------------- streams/events ---------------------------------------------
struct AuxStreams {
    cudaStream_t s1, s2, s3;
    cudaEvent_t  evFork, evW1, evA, evB, evF0, evF1, evH0;
    AuxStreams() {
        cudaStreamCreateWithFlags(&s1, cudaStreamNonBlocking);
        cudaStreamCreateWithFlags(&s2, cudaStreamNonBlocking);
        cudaStreamCreateWithFlags(&s3, cudaStreamNonBlocking);
        cudaEventCreateWithFlags(&evFork, cudaEventDisableTiming);
        cudaEventCreateWithFlags(&evW1,   cudaEventDisableTiming);
        cudaEventCreateWithFlags(&evA,    cudaEventDisableTiming);
        cudaEventCreateWithFlags(&evB,    cudaEventDisableTiming);
        cudaEventCreateWithFlags(&evF0,   cudaEventDisableTiming);
        cudaEventCreateWithFlags(&evF1,   cudaEventDisableTiming);
        cudaEventCreateWithFlags(&evH0,   cudaEventDisableTiming);
    }
};
static AuxStreams g_aux;

// ---------------- PTX helpers ------------------------------------------------
__device__ __forceinline__ uint32_t smem_u32(const void* p) {
    uint32_t a;
    asm("{ .reg .u64 t; cvta.to.shared.u64 t, %1; cvt.u32.u64 %0, t; }"
        : "=r"(a) : "l"(p));
    return a;
}

__device__ __forceinline__ void cp16(uint32_t dst, const void* src) {
    asm volatile("cp.async.cg.shared.global [%0], [%1], 16;\n"
                 :: "r"(dst), "l"(__cvta_generic_to_global(src)));
}
#define CP_COMMIT() asm volatile("cp.async.commit_group;\n" ::: "memory")
#define CP_WAIT1()  asm volatile("cp.async.wait_group 1;\n" ::: "memory")
#define CP_WAIT0()  asm volatile("cp.async.wait_group 0;\n" ::: "memory")

__device__ __forceinline__ void ldm4(uint32_t* r, uint32_t a) {
    asm volatile("ldmatrix.sync.aligned.m8n8.x4.shared.b16 {%0,%1,%2,%3}, [%4];"
                 : "=r"(r[0]), "=r"(r[1]), "=r"(r[2]), "=r"(r[3]) : "r"(a));
}

__device__ __forceinline__ void mma16816(float* c, const uint32_t* a, const uint32_t* b) {
    asm volatile(
        "mma.sync.aligned.m16n8k16.row.col.f32.bf16.bf16.f32 "
        "{%0,%1,%2,%3},{%4,%5,%6,%7},{%8,%9},{%0,%1,%2,%3};\n"
        : "+f"(c[0]), "+f"(c[1]), "+f"(c[2]), "+f"(c[3])
        : "r"(a[0]), "r"(a[1]), "r"(a[2]), "r"(a[3]), "r"(b[0]), "r"(b[1]));
}

__device__ __forceinline__ void mma16816h(float* c, const uint32_t* a, const uint32_t* b) {
    asm volatile(
        "mma.sync.aligned.m16n8k16.row.col.f32.f16.f16.f32 "
        "{%0,%1,%2,%3},{%4,%5,%6,%7},{%8,%9},{%0,%1,%2,%3};\n"
        : "+f"(c[0]), "+f"(c[1]), "+f"(c[2]), "+f"(c[3])
        : "r"(a[0]), "r"(a[1]), "r"(a[2]), "r"(a[3]), "r"(b[0]), "r"(b[1]));
}

__device__ __forceinline__ uint32_t pack2(float a, float b) {
    __nv_bfloat162 t = __floats2bfloat162_rn(a, b);
    return *reinterpret_cast<const uint32_t*>(&t);
}

__device__ __forceinline__ void split_bf16(float v, bf16& h, bf16& l) {
    h = __float2bfloat16(v);
    l = __float2bfloat16(v - __bfloat162float(h));
}

__device__ __forceinline__ void split_pack(float a, float b, uint32_t& ph, uint32_t& pl) {
    bf16 ha = __float2bfloat16(a), hb = __float2bfloat16(b);
    ph = ((uint32_t)*(uint16_t*)&hb << 16) | (uint32_t)*(uint16_t*)&ha;
    pl = pack2(a - __bfloat162float(ha), b - __bfloat162float(hb));
}

__device__ __forceinline__ void split_pack_h(float a, float b, uint32_t& ph, uint32_t& pl) {
    fp16 ha = __float2half(a), hb = __float2half(b);
    ph = ((uint32_t)*(uint16_t*)&hb << 16) | (uint32_t)*(uint16_t*)&ha;
    __half2 t = __floats2half2_rn(a - __half2float(ha), b - __half2float(hb));
    pl = *reinterpret_cast<const uint32_t*>(&t);
}

// ---------------- bf16x3 mma.sync GEMM ---------------------------------------
#define STAGE_BYTES 65536
#define GEMM_SMEM   (3*STAGE_BYTES)

__global__ void __launch_bounds__(256, 1)
gemm_mma(int M, int N, int K,
         const bf16* __restrict__ Ah_, const bf16* __restrict__ Al_, long long lda,
         const bf16* __restrict__ Bh_, const bf16* __restrict__ Bl_, long long ldb,
         float* __restrict__ C, bf16* __restrict__ Ch, bf16* __restrict__ Cl,
         long long ldc,
         const float* __restrict__ bias, float alpha,
         int zdiv,
         long long sA1, long long sA2,
         long long sB1, long long sB2,
         long long sC1, long long sC2)
{
    extern __shared__ __align__(1024) char smem[];
    const uint32_t sb = smem_u32(smem);

    {
        int z  = blockIdx.z;
        int z1 = z / zdiv, z2 = z % zdiv;
        Ah_ += z1*sA1 + z2*sA2;  Al_ += z1*sA1 + z2*sA2;
        Bh_ += z1*sB1 + z2*sB2;  Bl_ += z1*sB1 + z2*sB2;
        long long co = z1*sC1 + z2*sC2;
        if (C)  C  += co;
        if (Ch) { Ch += co; Cl += co; }
    }

    const int tid  = threadIdx.x;
    const int wid  = tid >> 5;
    const int lane = tid & 31;
    const int wm   = (wid >> 2) * 64;
    const int wn   = (wid & 3) * 32;
    const int g    = lane >> 2, tg = lane & 3;
    const int m0   = blockIdx.y * 128;
    const int n0   = blockIdx.x * 128;

    const int lrow = tid >> 1;
    const int half = tid & 1;
    const bf16* pAh = Ah_ + (long long)(m0 + lrow)*lda;
    const bf16* pAl = Al_ + (long long)(m0 + lrow)*lda;
    const bf16* pBh = Bh_ + (long long)(n0 + lrow)*ldb;
    const bf16* pBl = Bl_ + (long long)(n0 + lrow)*ldb;
    const uint32_t lswz = (uint32_t)(lrow & 7);

    const int nk = K / 64;

    const int piece = lane >> 3, rr = lane & 7;
    const int rowA  = wm + (piece & 1)*8 + rr;
    const int rowB  = wn + (piece >> 1)*8 + rr;
    const int cA    = piece >> 1;
    const int cB    = piece & 1;

    float acc[4][4][4];
    #pragma unroll
    for (int i = 0; i < 4; i++)
        #pragma unroll
        for (int j = 0; j < 4; j++)
            #pragma unroll
            for (int k = 0; k < 4; k++) acc[i][j][k] = 0.0f;

    #define ISSUE(t) do {                                                     \
        uint32_t s0_ = sb + ((t) % 3) * STAGE_BYTES;                          \
        const int k0_ = (t) * 64;                                             \
        _Pragma("unroll")                                                     \
        for (int j = 0; j < 4; j++) {                                         \
            int ch_ = half*4 + j;                                             \
            uint32_t d_ = (uint32_t)(lrow*128 + (((uint32_t)ch_ ^ lswz) << 4)); \
            cp16(s0_ +         d_, pAh + k0_ + ch_*8);                        \
            cp16(s0_ + 16384 + d_, pAl + k0_ + ch_*8);                        \
            cp16(s0_ + 32768 + d_, pBh + k0_ + ch_*8);                        \
            cp16(s0_ + 49152 + d_, pBl + k0_ + ch_*8);                        \
        }                                                                     \
        CP_COMMIT();                                                          \
    } while (0)

    ISSUE(0);
    if (nk > 1) ISSUE(1);

    for (int t = 0; t < nk; t++) {
        if (t + 1 < nk) { CP_WAIT1(); } else { CP_WAIT0(); }
        __syncthreads();
        if (t + 2 < nk) ISSUE(t + 2);

        const uint32_t Ab = sb + (t % 3) * STAGE_BYTES;
        const uint32_t Bb = Ab + 32768;

        #pragma unroll
        for (int ks = 0; ks < 4; ks++) {
            uint32_t ah[4][4], al[4][4], bh[4][2], bl[4][2];
            const uint32_t aoff = (uint32_t)(rowA*128 + (((ks*2 + cA) ^ (rowA & 7)) << 4));
            const uint32_t boff = (uint32_t)(rowB*128 + (((ks*2 + cB) ^ (rowB & 7)) << 4));
            #pragma unroll
            for (int mt = 0; mt < 4; mt++) {
                ldm4(ah[mt], Ab +          aoff + mt*2048);
                ldm4(al[mt], Ab + 16384 +  aoff + mt*2048);
            }
            #pragma unroll
            for (int ntp = 0; ntp < 2; ntp++) {
                uint32_t rb[4];
                ldm4(rb, Bb +          boff + ntp*2048);
                bh[ntp*2][0]   = rb[0]; bh[ntp*2][1]   = rb[1];
                bh[ntp*2+1][0] = rb[2]; bh[ntp*2+1][1] = rb[3];
                ldm4(rb, Bb + 16384 +  boff + ntp*2048);
                bl[ntp*2][0]   = rb[0]; bl[ntp*2][1]   = rb[1];
                bl[ntp*2+1][0] = rb[2]; bl[ntp*2+1][1] = rb[3];
            }
            #pragma unroll
            for (int mt = 0; mt < 4; mt++)
                #pragma unroll
                for (int nt = 0; nt < 4; nt++) {
                    mma16816(acc[mt][nt], ah[mt], bh[nt]);
                    mma16816(acc[mt][nt], al[mt], bh[nt]);
                    mma16816(acc[mt][nt], ah[mt], bl[nt]);
                }
        }
    }

    #pragma unroll
    for (int mt = 0; mt < 4; mt++) {
        int row = m0 + wm + mt*16 + g;
        #pragma unroll
        for (int nt = 0; nt < 4; nt++) {
            int col = n0 + wn + nt*8 + tg*2;
            float b0 = 0.0f, b1 = 0.0f;
            if (bias) { b0 = bias[col]; b1 = bias[col+1]; }
            float v00 = acc[mt][nt][0]*alpha + b0;
            float v01 = acc[mt][nt][1]*alpha + b1;
            float v10 = acc[mt][nt][2]*alpha + b0;
            float v11 = acc[mt][nt][3]*alpha + b1;
            if (C) {
                *(float2*)(C + (long long)row*ldc + col)     = make_float2(v00, v01);
                *(float2*)(C + (long long)(row+8)*ldc + col) = make_float2(v10, v11);
            }
            if (Ch) {
                uint32_t ph, pl;
                split_pack(v00, v01, ph, pl);
                *(uint32_t*)(Ch + (long long)row*ldc + col) = ph;
                *(uint32_t*)(Cl + (long long)row*ldc + col) = pl;
                split_pack(v10, v11, ph, pl);
                *(uint32_t*)(Ch + (long long)(row+8)*ldc + col) = ph;
                *(uint32_t*)(Cl + (long long)(row+8)*ldc + col) = pl;
            }
        }
    }
}

// ---------------- fp16x2 GEMM: C = A(hi/lo fp16) @ B(fp16)^T + bias ----------
#define H2_STAGE 49152
#define H2_SMEM  (3*H2_STAGE)

__global__ void __launch_bounds__(256, 1)
gemm_h2(int M, int N, int K,
        const fp16* __restrict__ Ah_, const fp16* __restrict__ Al_, long long lda,
        const fp16* __restrict__ Bh_, long long ldb,
        float* __restrict__ C, long long ldc,
        const float* __restrict__ bias, float alpha)
{
    extern __shared__ __align__(1024) char smem[];
    const uint32_t sb = smem_u32(smem);

    const int tid  = threadIdx.x;
    const int wid  = tid >> 5;
    const int lane = tid & 31;
    const int wm   = (wid >> 2) * 64;
    const int wn   = (wid & 3) * 32;
    const int g    = lane >> 2, tg = lane & 3;
    const int m0   = blockIdx.y * 128;
    const int n0   = blockIdx.x * 128;

    const int lrow = tid >> 1;
    const int half = tid & 1;
    const fp16* pAh = Ah_ + (long long)(m0 + lrow)*lda;
    const fp16* pAl = Al_ + (long long)(m0 + lrow)*lda;
    const fp16* pBh = Bh_ + (long long)(n0 + lrow)*ldb;
    const uint32_t lswz = (uint32_t)(lrow & 7);

    const int nk = K / 64;

    const int piece = lane >> 3, rr = lane & 7;
    const int rowA  = wm + (piece & 1)*8 + rr;
    const int rowB  = wn + (piece >> 1)*8 + rr;
    const int cA    = piece >> 1;
    const int cB    = piece & 1;

    float acc[4][4][4];
    #pragma unroll
    for (int i = 0; i < 4; i++)
        #pragma unroll
        for (int j = 0; j < 4; j++)
            #pragma unroll
            for (int k = 0; k < 4; k++) acc[i][j][k] = 0.0f;

    #define H2_ISSUE(t) do {                                                  \
        uint32_t s0_ = sb + ((t) % 3) * H2_STAGE;                             \
        const int k0_ = (t) * 64;                                             \
        _Pragma("unroll")                                                     \
        for (int j = 0; j < 4; j++) {                                         \
            int ch_ = half*4 + j;                                             \
            uint32_t d_ = (uint32_t)(lrow*128 + (((uint32_t)ch_ ^ lswz) << 4)); \
            cp16(s0_ +         d_, pAh + k0_ + ch_*8);                        \
            cp16(s0_ + 16384 + d_, pAl + k0_ + ch_*8);                        \
            cp16(s0_ + 32768 + d_, pBh + k0_ + ch_*8);                        \
        }                                                                     \
        CP_COMMIT();                                                          \
    } while (0)

    H2_ISSUE(0);
    if (nk > 1) H2_ISSUE(1);

    for (int t = 0; t < nk; t++) {
        if (t + 1 < nk) { CP_WAIT1(); } else { CP_WAIT0(); }
        __syncthreads();
        if (t + 2 < nk) H2_ISSUE(t + 2);

        const uint32_t Ab = sb + (t % 3) * H2_STAGE;
        const uint32_t Bb = Ab + 32768;

        #pragma unroll
        for (int ks = 0; ks < 4; ks++) {
            uint32_t ah[4][4], al[4][4], bh[4][2];
            const uint32_t aoff = (uint32_t)(rowA*128 + (((ks*2 + cA) ^ (rowA & 7)) << 4));
            const uint32_t boff = (uint32_t)(rowB*128 + (((ks*2 + cB) ^ (rowB & 7)) << 4));
            #pragma unroll
            for (int mt = 0; mt < 4; mt++) {
                ldm4(ah[mt], Ab +          aoff + mt*2048);
                ldm4(al[mt], Ab + 16384 +  aoff + mt*2048);
            }
            #pragma unroll
            for (int ntp = 0; ntp < 2; ntp++) {
                uint32_t rb[4];
                ldm4(rb, Bb + boff + ntp*2048);
                bh[ntp*2][0]   = rb[0]; bh[ntp*2][1]   = rb[1];
                bh[ntp*2+1][0] = rb[2]; bh[ntp*2+1][1] = rb[3];
            }
            #pragma unroll
            for (int mt = 0; mt < 4; mt++)
                #pragma unroll
                for (int nt = 0; nt < 4; nt++) {
                    mma16816h(acc[mt][nt], ah[mt], bh[nt]);
                    mma16816h(acc[mt][nt], al[mt], bh[nt]);
                }
        }
    }

    #pragma unroll
    for (int mt = 0; mt < 4; mt++) {
        int row = m0 + wm + mt*16 + g;
        #pragma unroll
        for (int nt = 0; nt < 4; nt++) {
            int col = n0 + wn + nt*8 + tg*2;
            float b0 = 0.0f, b1 = 0.0f;
            if (bias) { b0 = bias[col]; b1 = bias[col+1]; }
            *(float2*)(C + (long long)row*ldc + col) =
                make_float2(acc[mt][nt][0]*alpha + b0, acc[mt][nt][1]*alpha + b1);
            *(float2*)(C + (long long)(row+8)*ldc + col) =
                make_float2(acc[mt][nt][2]*alpha + b0, acc[mt][nt][3]*alpha + b1);
        }
    }
}

// ---------------- fused flash attention ---------------------------------------
#define FA_NC    32
#define FA_STG   40960
#define FA_Q     0
#define FA_S0    24576
#define FA_P     106496
#define FA_REDM  122880
#define FA_REDS  123904
#define FA_SMEM  124928
#define FA_NKS   9

__global__ void __launch_bounds__(256, 1)
flash_attn(const fp16* __restrict__ qph,
           const fp16* __restrict__ kph,
           const fp16* __restrict__ vt,
           fp16* __restrict__ lath, fp16* __restrict__ latl,
           float scale, int bh_base)
{
    extern __shared__ __align__(1024) char smem[];
    const uint32_t sb = smem_u32(smem);

    const int tid  = threadIdx.x;
    const int wid  = tid >> 5;
    const int lane = tid & 31;
    const int wm2  = wid >> 2;
    const int wn4  = wid & 3;
    const int g    = lane >> 2, tg = lane & 3;
    const int piece = lane >> 3, rr = lane & 7;

    const int bh = blockIdx.y + bh_base;
    const int b  = bh >> 3;
    const int qb = blockIdx.x;

    const fp16* qbh = qph + ((size_t)bh*SS + (size_t)qb*64)*KAUG;
    const fp16* kbh = kph + (size_t)bh*SS*KAUG;
    const fp16* vb  = vt  + (size_t)b*128*SS;

    #pragma unroll
    for (int i = 0; i < 6; i++) {
        int idx = i*256 + tid;
        int row = idx / 24, cc = idx % 24;
        if (cc < 18) {
            int kt = cc >> 3, c8 = cc & 7;
            uint32_t d = (uint32_t)(kt*8192 + row*128 + (((uint32_t)c8 ^ (row & 7)) << 4));
            cp16(sb + FA_Q + d, qbh + row*KAUG + cc*8);
        }
    }
    CP_COMMIT();

    #define FA_ISSUE(t) do {                                                   \
        uint32_t st_ = sb + FA_S0 + ((t) & 1) * FA_STG;                        \
        const int t0_ = (t) * 64;                                              \
        _Pragma("unroll")                                                      \
        for (int i = 0; i < 6; i++) {                                          \
            int idx = i*256 + tid;                                             \
            int row = idx / 24, cc = idx % 24;                                 \
            if (cc < 18) {                                                     \
                int kt = cc >> 3, c8 = cc & 7;                                 \
                uint32_t d = (uint32_t)(kt*8192 + row*128 + (((uint32_t)c8 ^ (row & 7)) << 4)); \
                cp16(st_ + d, kbh + (size_t)(t0_+row)*KAUG + cc*8);            \
            }                                                                  \
        }                                                                      \
        _Pragma("unroll")                                                      \
        for (int i = 0; i < 4; i++) {                                          \
            int idx = i*256 + tid;                                             \
            int row = idx >> 3, c8 = idx & 7;                                  \
            uint32_t d = (uint32_t)(row*128 + (((uint32_t)c8 ^ (row & 7)) << 4)); \
            cp16(st_ + 24576 + d, vb + (size_t)row*SS + t0_ + c8*8);           \
        }                                                                      \
        CP_COMMIT();                                                           \
    } while (0)

    FA_ISSUE(0);

    float accv[2][4][4];
    #pragma unroll
    for (int i = 0; i < 2; i++)
        #pragma unroll
        for (int j = 0; j < 4; j++)
            #pragma unroll
            for (int k = 0; k < 4; k++) accv[i][j][k] = 0.0f;
    float Mrow[4] = {-1e30f, -1e30f, -1e30f, -1e30f};
    float Lrow[4] = {0.0f, 0.0f, 0.0f, 0.0f};

    float* redm = (float*)(smem + FA_REDM);
    float* reds = (float*)(smem + FA_REDS);

    for (int t = 0; t < FA_NC; t++) {
        CP_WAIT0();
        __syncthreads();
        if (t + 1 < FA_NC) FA_ISSUE(t + 1);

        const uint32_t KB = sb + FA_S0 + (t & 1) * FA_STG;
        const uint32_t VB = KB + 24576;

        float sacc[2][2][4];
        #pragma unroll
        for (int i = 0; i < 2; i++)
            #pragma unroll
            for (int j = 0; j < 2; j++)
                #pragma unroll
                for (int k = 0; k < 4; k++) sacc[i][j][k] = 0.0f;

        #pragma unroll
        for (int ks = 0; ks < FA_NKS; ks++) {
            const int kt = ks >> 2, ks2 = ks & 3;
            uint32_t ah[2][4];
            #pragma unroll
            for (int mt = 0; mt < 2; mt++) {
                int rowA = wm2*32 + mt*16 + (piece & 1)*8 + rr;
                uint32_t off = (uint32_t)(kt*8192 + rowA*128 +
                    (((ks2*2 + (piece >> 1)) ^ (rowA & 7)) << 4));
                ldm4(ah[mt], sb + FA_Q + off);
            }
            int rowB = wn4*16 + (piece >> 1)*8 + rr;
            uint32_t offB = (uint32_t)(kt*8192 + rowB*128 +
                (((ks2*2 + (piece & 1)) ^ (rowB & 7)) << 4));
            uint32_t rbh[4];
            ldm4(rbh, KB + offB);
            #pragma unroll
            for (int mt = 0; mt < 2; mt++)
                #pragma unroll
                for (int nt = 0; nt < 2; nt++)
                    mma16816h(sacc[mt][nt], ah[mt], rbh + nt*2);
        }

        float mloc[4] = {-1e30f, -1e30f, -1e30f, -1e30f};
        #pragma unroll
        for (int mt = 0; mt < 2; mt++)
            #pragma unroll
            for (int nt = 0; nt < 2; nt++)
                #pragma unroll
                for (int c = 0; c < 4; c++) {
                    sacc[mt][nt][c] *= scale;
                    int slot = mt*2 + (c >> 1);
                    mloc[slot] = fmaxf(mloc[slot], sacc[mt][nt][c]);
                }
        #pragma unroll
        for (int s = 0; s < 4; s++) {
            mloc[s] = fmaxf(mloc[s], __shfl_xor_sync(0xffffffffu, mloc[s], 1));
            mloc[s] = fmaxf(mloc[s], __shfl_xor_sync(0xffffffffu, mloc[s], 2));
        }
        if (tg == 0) {
            #pragma unroll
            for (int mt = 0; mt < 2; mt++)
                #pragma unroll
                for (int h2 = 0; h2 < 2; h2++) {
                    int r = wm2*32 + mt*16 + h2*8 + g;
                    redm[wn4*64 + r] = mloc[mt*2 + h2];
                }
        }
        __syncthreads();

        float fsc[4];
        #pragma unroll
        for (int mt = 0; mt < 2; mt++)
            #pragma unroll
            for (int h2 = 0; h2 < 2; h2++) {
                int r = wm2*32 + mt*16 + h2*8 + g;
                float cm = fmaxf(fmaxf(redm[r], redm[64 + r]),
                                 fmaxf(redm[128 + r], redm[192 + r]));
                int slot = mt*2 + h2;
                float mn = fmaxf(Mrow[slot], cm);
                fsc[slot] = __expf(Mrow[slot] - mn);
                Mrow[slot] = mn;
            }

        float sl[4] = {0.0f, 0.0f, 0.0f, 0.0f};
        #pragma unroll
        for (int mt = 0; mt < 2; mt++)
            #pragma unroll
            for (int nt = 0; nt < 2; nt++)
                #pragma unroll
                for (int c = 0; c < 4; c++) {
                    int slot = mt*2 + (c >> 1);
                    float p = __expf(sacc[mt][nt][c] - Mrow[slot]);
                    sacc[mt][nt][c] = p;
                    sl[slot] += p;
                }
        #pragma unroll
        for (int mt = 0; mt < 2; mt++)
            #pragma unroll
            for (int nt = 0; nt < 4; nt++)
                #pragma unroll
                for (int c = 0; c < 4; c++)
                    accv[mt][nt][c] *= fsc[mt*2 + (c >> 1)];
        #pragma unroll
        for (int s = 0; s < 4; s++) {
            sl[s] += __shfl_xor_sync(0xffffffffu, sl[s], 1);
            sl[s] += __shfl_xor_sync(0xffffffffu, sl[s], 2);
        }
        if (tg == 0) {
            #pragma unroll
            for (int mt = 0; mt < 2; mt++)
                #pragma unroll
                for (int h2 = 0; h2 < 2; h2++) {
                    int r = wm2*32 + mt*16 + h2*8 + g;
                    reds[wn4*64 + r] = sl[mt*2 + h2];
                }
        }
        #pragma unroll
        for (int mt = 0; mt < 2; mt++)
            #pragma unroll
            for (int nt = 0; nt < 2; nt++)
                #pragma unroll
                for (int h2 = 0; h2 < 2; h2++) {
                    int r = wm2*32 + mt*16 + h2*8 + g;
                    int cidx = wn4*2 + nt;
                    uint32_t addr = (uint32_t)(r*128 + ((cidx ^ (r & 7)) << 4) + tg*4);
                    uint32_t ph, pl;
                    split_pack_h(sacc[mt][nt][2*h2], sacc[mt][nt][2*h2+1], ph, pl);
                    *(uint32_t*)(smem + FA_P +        addr) = ph;
                    *(uint32_t*)(smem + FA_P + 8192 + addr) = pl;
                }
        __syncthreads();

        #pragma unroll
        for (int mt = 0; mt < 2; mt++)
            #pragma unroll
            for (int h2 = 0; h2 < 2; h2++) {
                int r = wm2*32 + mt*16 + h2*8 + g;
                float ssum = reds[r] + reds[64 + r] + reds[128 + r] + reds[192 + r];
                int slot = mt*2 + h2;
                Lrow[slot] = Lrow[slot] * fsc[slot] + ssum;
            }

        #pragma unroll
        for (int ksv = 0; ksv < 4; ksv++) {
            uint32_t pah[2][4], pal[2][4];
            #pragma unroll
            for (int mt = 0; mt < 2; mt++) {
                int rowA = wm2*32 + mt*16 + (piece & 1)*8 + rr;
                uint32_t off = (uint32_t)(rowA*128 +
                    (((ksv*2 + (piece >> 1)) ^ (rowA & 7)) << 4));
                ldm4(pah[mt], sb + FA_P +        off);
                ldm4(pal[mt], sb + FA_P + 8192 + off);
            }
            uint32_t vh[2][4];
            #pragma unroll
            for (int ntp = 0; ntp < 2; ntp++) {
                int rowB = wn4*32 + ntp*16 + (piece >> 1)*8 + rr;
                uint32_t offB = (uint32_t)(rowB*128 +
                    (((ksv*2 + (piece & 1)) ^ (rowB & 7)) << 4));
                ldm4(vh[ntp], VB + offB);
            }
            #pragma unroll
            for (int mt = 0; mt < 2; mt++)
                #pragma unroll
                for (int nt = 0; nt < 4; nt++) {
                    const uint32_t* bhp = vh[nt >> 1] + (nt & 1)*2;
                    mma16816h(accv[mt][nt], pah[mt], bhp);
                    mma16816h(accv[mt][nt], pal[mt], bhp);
                }
        }
    }

    float inv[4];
    #pragma unroll
    for (int s = 0; s < 4; s++) inv[s] = 1.0f / Lrow[s];

    const int h = bh & 7;
    #pragma unroll
    for (int mt = 0; mt < 2; mt++) {
        #pragma unroll
        for (int nt = 0; nt < 4; nt++) {
            int col = h*128 + wn4*32 + nt*8 + tg*2;
            #pragma unroll
            for (int h2 = 0; h2 < 2; h2++) {
                long long row = (long long)b*SS + qb*64 + wm2*32 + mt*16 + h2*8 + g;
                float v0 = accv[mt][nt][2*h2]   * inv[mt*2 + h2];
                float v1 = accv[mt][nt][2*h2+1] * inv[mt*2 + h2];
                uint32_t ph, pl;
                split_pack_h(v0, v1, ph, pl);
                *(uint32_t*)(lath + row*1024 + col) = ph;
                *(uint32_t*)(latl + row*1024 + col) = pl;
            }
        }
    }
}

// ---------------- elementwise fp32 -> bf16 hi/lo ------------------------------
__global__ void convert_split_k(const float* __restrict__ in,
                                bf16* __restrict__ oh, bf16* __restrict__ ol,
                                long long n)
{
    long long i = (long long)blockIdx.x * 256 + threadIdx.x;
    if (i < n) {
        bf16 h, l; split_bf16(in[i], h, l);
        oh[i] = h; ol[i] = l;
    }
}

// ---------------- elementwise fp32 -> fp16 ------------------------------------
__global__ void convert_half_k(const float* __restrict__ in,
                               fp16* __restrict__ o, long long n)
{
    long long i = (long long)blockIdx.x * 256 + threadIdx.x;
    if (i < n) o[i] = __float2half(in[i]);
}

// ---------------- fp32 transpose -> bf16 hi/lo --------------------------------
__global__ void transpose_split_k(const float* __restrict__ in,
                                  bf16* __restrict__ oh, bf16* __restrict__ ol,
                                  int M, int N, int ldi, int ldo,
                                  int zdiv,
                                  long long si1, long long si2,
                                  long long so1, long long so2)
{
    __shared__ float tile[32][33];
    int z = blockIdx.z, z1 = z / zdiv, z2 = z % zdiv;
    in += z1*si1 + z2*si2;
    oh += z1*so1 + z2*so2;
    ol += z1*so1 + z2*so2;

    int x = blockIdx.x*32 + threadIdx.x;
    int y = blockIdx.y*32 + threadIdx.y;
    #pragma unroll
    for (int i = 0; i < 32; i += 8)
        if (x < N && (y+i) < M)
            tile[threadIdx.y+i][threadIdx.x] = in[(long long)(y+i)*ldi + x];
    __syncthreads();
    x = blockIdx.y*32 + threadIdx.x;
    y = blockIdx.x*32 + threadIdx.y;
    #pragma unroll
    for (int i = 0; i < 32; i += 8)
        if (x < M && (y+i) < N) {
            bf16 h, l; split_bf16(tile[threadIdx.x][threadIdx.y+i], h, l);
            oh[(long long)(y+i)*ldo + x] = h;
            ol[(long long)(y+i)*ldo + x] = l;
        }
}

// ---------------- fp32 transpose -> single fp16 -------------------------------
__global__ void transpose_half_k(const float* __restrict__ in,
                                 fp16* __restrict__ o,
                                 int M, int N, int ldi, int ldo)
{
    __shared__ float tile[32][33];
    int x = blockIdx.x*32 + threadIdx.x;
    int y = blockIdx.y*32 + threadIdx.y;
    #pragma unroll
    for (int i = 0; i < 32; i += 8)
        if (x < N && (y+i) < M)
            tile[threadIdx.y+i][threadIdx.x] = in[(long long)(y+i)*ldi + x];
    __syncthreads();
    x = blockIdx.y*32 + threadIdx.x;
    y = blockIdx.x*32 + threadIdx.y;
    #pragma unroll
    for (int i = 0; i < 32; i += 8)
        if (x < M && (y+i) < N)
            o[(long long)(y+i)*ldo + x] = __float2half(tile[threadIdx.x][threadIdx.y+i]);
}

// ---------------- pad+split W_uq / W_uk into [8][128][640] --------------------
__global__ void pad_split_uqk(const float* __restrict__ Wuq,
                              const float* __restrict__ Wuk,
                              bf16* __restrict__ uqh, bf16* __restrict__ uql,
                              bf16* __restrict__ ukh, bf16* __restrict__ ukl)
{
    int idx = blockIdx.x * 256 + threadIdx.x;
    if (idx >= 8*128*640) return;
    int e = idx % 640;
    int c = (idx / 640) & 127;
    int h = idx / (640*128);
    float vq = 0.0f, vk = 0.0f;
    if (e < SPLIT) {
        vq = Wuq[c*4992 + h*SPLIT + e];
        vk = Wuk[c*4992 + h*SPLIT + e];
    }
    bf16 hh, ll;
    split_bf16(vq, hh, ll); uqh[idx] = hh; uql[idx] = ll;
    split_bf16(vk, hh, ll); ukh[idx] = hh; ukl[idx] = ll;
}

// ---------------- bqk -----------------------------------------------------------
__global__ void bqk_kernel(const float* __restrict__ b_uq,
                           const float* __restrict__ W_uk,
                           float* __restrict__ bqk)
{
    int c = threadIdx.x;
    int h = blockIdx.x;
    float acc = 0.0f;
    const float* wrow = W_uk + c*4992 + h*SPLIT;
    const float* brow = b_uq + h*SPLIT;
    for (int e = 0; e < SPLIT; e++)
        acc += brow[e] * wrow[e];
    bqk[h*128 + c] = acc;
}

// ---------------- beff ----------------------------------------------------------
__global__ void beff_partial(const float* __restrict__ b_uv,
                             const float* __restrict__ W_o,
                             float* __restrict__ part)
{
    int o   = blockIdx.x * 256 + threadIdx.x;
    int seg = blockIdx.y;
    float acc = 0.0f;
    int d0 = seg * (D_MODEL/16);
    #pragma unroll 4
    for (int d = d0; d < d0 + D_MODEL/16; d++)
        acc += b_uv[d] * W_o[(size_t)d*D_MODEL + o];
    part[(size_t)seg*D_MODEL + o] = acc;
}

__global__ void beff_reduce(const float* __restrict__ part,
                            const float* __restrict__ b_o,
                            float* __restrict__ be)
{
    int o = blockIdx.x * 256 + threadIdx.x;
    if (o >= D_MODEL) return;
    float acc = b_o[o];
    #pragma unroll
    for (int s = 0; s < 16; s++)
        acc += part[(size_t)s*D_MODEL + o];
    be[o] = acc;
}

// ---------------- assemble Q'/K' (rope) -> single fp16; emit k_rot --------------
__global__ void assemble_qk(const float* __restrict__ qe,
                            const float* __restrict__ cat1,
                            fp16* __restrict__ qph,
                            fp16* __restrict__ kph,
                            float* __restrict__ out_krot, int bh_base)
{
    long long idx = (long long)blockIdx.x * 256 + threadIdx.x;
    if (idx >= (long long)8*SS*KAUG) return;
    int j  = (int)(idx % KAUG);
    int s  = (int)((idx / KAUG) & (SS - 1));
    int bh = (int)(idx / ((long long)KAUG*SS)) + bh_base;
    long long gidx = (long long)bh*SS*KAUG + (long long)s*KAUG + j;
    int b  = bh >> 3, h = bh & 7;
    long long row = (long long)b*SS + s;

    float qv = 0.0f, kv = 0.0f;
    if (j < 128) {
        qv = qe[row*NQE + h*128 + j];
        kv = cat1[row*NCAT1 + j];
    } else if (j < 144) {
        int dd = j - 128;
        long long qb = row*NQE + 1024 + h*D_ROPE;
        long long kb = row*NCAT1 + 256 + h*D_ROPE;
        if (dd < 8) {
            const float invf[4] = {1.0f, 0.1f, 0.01f, 0.001f};
            float f = ((float)s / 40.0f) * invf[dd & 3];
            float c_ = cosf(f), sn = sinf(f);
            if (dd < 4) {
                qv = qe[qb+dd]*c_ - qe[qb+dd+4]*sn;
                kv = cat1[kb+dd]*c_ - cat1[kb+dd+4]*sn;
            } else {
                qv = qe[qb+dd]*c_ + qe[qb+dd-4]*sn;
                kv = cat1[kb+dd]*c_ + cat1[kb+dd-4]*sn;
            }
        } else {
            qv = qe[qb+dd];
            kv = cat1[kb+dd];
        }
        out_krot[row*128 + h*D_ROPE + dd] = kv;
    } else {
        return;
    }
    qph[gidx] = __float2half(qv);
    kph[gidx] = __float2half(kv);
}

// ---------------- c_kv output copy (per-batch) ---------------------------------
__global__ void copy_ckv(const float* __restrict__ cat1, float* __restrict__ out,
                         int row0)
{
    int idx = blockIdx.x * 256 + threadIdx.x;
    if (idx < SS * D_KV) {
        int row = row0 + (idx >> 7);
        out[(long long)row*D_KV + (idx & 127)] = cat1[(long long)row*NCAT1 + (idx & 127)];
    }
}

// ---------------- host side ------------------------------------------------------
static inline void* symv(const void* s)
{
    void* p = nullptr;
    cudaGetSymbolAddress(&p, s);
    return p;
}

static void gemm_on(cudaStream_t st, int M, int N, int K,
                    const bf16* Ah, const bf16* Al, long long lda,
                    const bf16* Bh, const bf16* Bl, long long ldb,
                    float* C, bf16* Ch, bf16* Cl, long long ldc,
                    const float* bias, float alpha,
                    int nz = 1, int zdiv = 1,
                    long long sA1 = 0, long long sA2 = 0,
                    long long sB1 = 0, long long sB2 = 0,
                    long long sC1 = 0, long long sC2 = 0)
{
    dim3 grid(N / 128, M / 128, nz);
    gemm_mma<<<grid, 256, GEMM_SMEM, st>>>(M, N, K, Ah, Al, lda, Bh, Bl, ldb,
                                           C, Ch, Cl, ldc, bias, alpha, zdiv,
                                           sA1, sA2, sB1, sB2, sC1, sC2);
}

static void tsplit_on(cudaStream_t st, const float* in, bf16* oh, bf16* ol,
                      int M, int N, int ldi, int ldo)
{
    dim3 grid((N + 31)/32, (M + 31)/32, 1);
    transpose_split_k<<<grid, dim3(32, 8), 0, st>>>(in, oh, ol, M, N, ldi, ldo,
                                                    1, 0, 0, 0, 0);
}

extern "C" void kernel_launch(void* const* d_in, const int* in_sizes, int n_in,
                              void* d_out, int out_size)
{
    const float* h     = (const float*)d_in[0];
    const float* W_dkv = (const float*)d_in[1];
    const float* b_dkv = (const float*)d_in[2];
    const float* W_dq  = (const float*)d_in[3];
    const float* b_dq  = (const float*)d_in[4];
    const float* W_uk  = (const float*)d_in[5];
    const float* b_uk  = (const float*)d_in[6];
    const float* W_uv  = (const float*)d_in[7];
    const float* b_uv  = (const float*)d_in[8];
    const float* W_uq  = (const float*)d_in[9];
    const float* b_uq  = (const float*)d_in[10];
    const float* W_qr  = (const float*)d_in[11];
    const float* b_qr  = (const float*)d_in[12];
    const float* W_kr  = (const float*)d_in[13];
    const float* b_kr  = (const float*)d_in[14];
    const float* W_o   = (const float*)d_in[15];
    const float* b_o   = (const float*)d_in[16];
    (void)b_uk;

    float* out      = (float*)d_out;
    float* out_ckv  = out + (long long)ROWS * D_MODEL;
    float* out_krot = out_ckv + (long long)ROWS * D_KV;

    float* cat1  = (float*)symv(g_cat1);
    bf16*  cat1h = (bf16*)symv(g_cat1h);
    bf16*  cat1l = (bf16*)symv(g_cat1l);
    bf16*  hh    = (bf16*)symv(g_hh);
    bf16*  hl    = (bf16*)symv(g_hl);
    bf16*  w1h   = (bf16*)symv(g_w1h);
    bf16*  w1l   = (bf16*)symv(g_w1l);
    bf16*  uqph  = (bf16*)symv(g_uqph);
    bf16*  uqpl  = (bf16*)symv(g_uqpl);
    bf16*  ukph  = (bf16*)symv(g_ukph);
    bf16*  ukpl  = (bf16*)symv(g_ukpl);
    bf16*  wqkrh = (bf16*)symv(g_wqkrh);
    bf16*  wqkrl = (bf16*)symv(g_wqkrl);
    float* bqkr  = (float*)symv(g_bqkr);
    float* qe    = (float*)symv(g_qe);
    fp16*  qph   = (fp16*)symv(g_qph);
    fp16*  kph   = (fp16*)symv(g_kph);
    fp16*  vt16  = (fp16*)symv(g_vt16);
    fp16*  lath  = (fp16*)symv(g_lath);
    fp16*  latl  = (fp16*)symv(g_latl);
    bf16*  uvsh  = (bf16*)symv(g_uvsh);
    bf16*  uvsl  = (bf16*)symv(g_uvsl);
    bf16*  woh   = (bf16*)symv(g_woh);
    bf16*  wol   = (bf16*)symv(g_wol);
    float* wcomb = (float*)symv(g_wcomb);
    fp16*  wct16 = (fp16*)symv(g_wct16);
    float* b1    = (float*)symv(g_b1);
    float* beff  = (float*)symv(g_beff);
    float* beffp = (float*)symv(g_beffp);

    cudaFuncSetAttribute(gemm_mma, cudaFuncAttributeMaxDynamicSharedMemorySize, GEMM_SMEM);
    cudaFuncSetAttribute(gemm_h2,  cudaFuncAttributeMaxDynamicSharedMemorySize, H2_SMEM);
    cudaFuncSetAttribute(flash_attn, cudaFuncAttributeMaxDynamicSharedMemorySize, FA_SMEM);

    const float scale = 1.0f / sqrtf((float)D_HEAD);
    cudaStream_t s0 = 0, s1 = g_aux.s1, s2 = g_aux.s2, s3 = g_aux.s3;

    // ---- fork ----
    cudaEventRecord(g_aux.evFork, s0);
    cudaStreamWaitEvent(s1, g_aux.evFork, 0);
    cudaStreamWaitEvent(s2, g_aux.evFork, 0);
    cudaStreamWaitEvent(s3, g_aux.evFork, 0);

    // ======== s1: W1 prep, then Wqk-absorption chain ========
    cudaMemcpyAsync(b1,      b_dkv, 128*sizeof(float), cudaMemcpyDeviceToDevice, s1);
    cudaMemcpyAsync(b1+128,  b_dq,  128*sizeof(float), cudaMemcpyDeviceToDevice, s1);
    cudaMemcpyAsync(b1+256,  b_kr,  128*sizeof(float), cudaMemcpyDeviceToDevice, s1);
    tsplit_on(s1, W_dkv, w1h,               w1l,               D_MODEL, D_KV, D_KV, D_MODEL);
    tsplit_on(s1, W_dq,  w1h + 128*D_MODEL, w1l + 128*D_MODEL, D_MODEL, D_KV, D_KV, D_MODEL);
    tsplit_on(s1, W_kr,  w1h + 256*D_MODEL, w1l + 256*D_MODEL, D_MODEL, D_KV, D_KV, D_MODEL);
    cudaEventRecord(g_aux.evW1, s1);

    cudaMemcpyAsync(bqkr+1024, b_qr, 128*sizeof(float), cudaMemcpyDeviceToDevice, s1);
    tsplit_on(s1, W_qr, wqkrh + 1024*128, wqkrl + 1024*128, D_KV, 128, 128, D_KV);
    pad_split_uqk<<<(8*128*640 + 255)/256, 256, 0, s1>>>(W_uq, W_uk, uqph, uqpl, ukph, ukpl);
    bqk_kernel<<<8, 128, 0, s1>>>(b_uq, W_uk, bqkr);
    gemm_on(s1, 128, 128, 640, ukph, ukpl, 640, uqph, uqpl, 640,
            nullptr, wqkrh, wqkrl, 128, nullptr, 1.0f,
            8, 8, 0, (long long)128*640, 0, (long long)128*640, 0, (long long)128*128);
    cudaEventRecord(g_aux.evA, s1);

    // ======== s2: W_o/W_uv-absorption chain (fp32 -> fp16 Wcomb) ========
    convert_split_k<<<(128*D_MODEL + 255)/256, 256, 0, s2>>>(W_uv, uvsh, uvsl, 128*D_MODEL);
    tsplit_on(s2, W_o, woh, wol, D_MODEL, D_MODEL, D_MODEL, D_MODEL);
    gemm_on(s2, D_MODEL, 128, 640, woh, wol, D_MODEL, uvsh, uvsl, D_MODEL,
            wcomb, nullptr, nullptr, 1024, nullptr, 1.0f,
            8, 8, 0, 640, 0, 640, 0, 128);
    convert_half_k<<<(unsigned)(((long long)D_MODEL*1024 + 255)/256), 256, 0, s2>>>(
        wcomb, wct16, (long long)D_MODEL*1024);
    beff_partial<<<dim3(D_MODEL/256, 16), 256, 0, s2>>>(b_uv, W_o, beffp);
    beff_reduce<<<(D_MODEL + 255)/256, 256, 0, s2>>>(beffp, b_o, beff);
    cudaEventRecord(g_aux.evB, s2);

    // ======== per-batch activation pipelines (s0 = b0, s3 = b1) ========
    const long long HN = (long long)SS * D_MODEL;
    #define BATCH_CHAIN(st, B, BH, EVF)                                            \
    do {                                                                           \
        const long long r0 = (long long)(B) * SS;                                  \
        convert_split_k<<<(unsigned)((HN + 255)/256), 256, 0, (st)>>>(             \
            h + r0*D_MODEL, hh + r0*D_MODEL, hl + r0*D_MODEL, HN);                 \
        cudaStreamWaitEvent((st), g_aux.evW1, 0);                                  \
        gemm_on((st), SS, NCAT1, D_MODEL,                                          \
                hh + r0*D_MODEL, hl + r0*D_MODEL, D_MODEL, w1h, w1l, D_MODEL,      \
                cat1 + r0*NCAT1, cat1h + r0*NCAT1, cat1l + r0*NCAT1, NCAT1,        \
                b1, 1.0f);                                                         \
        copy_ckv<<<(SS*D_KV + 255)/256, 256, 0, (st)>>>(cat1, out_ckv, (int)r0);   \
        cudaStreamWaitEvent((st), g_aux.evA, 0);                                   \
        gemm_on((st), SS, NQE, 128,                                                \
                cat1h + r0*NCAT1 + 128, cat1l + r0*NCAT1 + 128, NCAT1,             \
                wqkrh, wqkrl, 128,                                                 \
                qe + r0*NQE, nullptr, nullptr, NQE, bqkr, 1.0f);                   \
        {                                                                          \
            long long total = (long long)8*SS*KAUG;                                \
            assemble_qk<<<(unsigned)((total + 255)/256), 256, 0, (st)>>>(          \
                qe, cat1, qph, kph, out_krot, (BH));                               \
        }                                                                          \
        {                                                                          \
            dim3 tg_((128 + 31)/32, (SS + 31)/32, 1);                              \
            transpose_half_k<<<tg_, dim3(32, 8), 0, (st)>>>(                       \
                cat1 + r0*NCAT1, vt16 + (long long)(B)*128*SS, SS, 128, NCAT1, SS);\
        }                                                                          \
        flash_attn<<<dim3(SS/64, 8), 256, FA_SMEM, (st)>>>(                        \
            qph, kph, vt16, lath, latl, scale, (BH));                              \
        cudaEventRecord((EVF), (st));                                              \
    } while (0)

    BATCH_CHAIN(s0, 0, 0, g_aux.evF0);
    BATCH_CHAIN(s3, 1, 8, g_aux.evF1);

    // ======== final GEMM (fp16 x2), per-batch, co-scheduled ========
    cudaStreamWaitEvent(s1, g_aux.evF0, 0);
    cudaStreamWaitEvent(s1, g_aux.evB, 0);
    gemm_h2<<<dim3(D_MODEL/128, SS/128), 256, H2_SMEM, s1>>>(
        SS, D_MODEL, 1024, lath, latl, 1024, wct16, 1024,
        out, D_MODEL, beff, 1.0f);
    cudaEventRecord(g_aux.evH0, s1);

    cudaStreamWaitEvent(s0, g_aux.evF1, 0);
    cudaStreamWaitEvent(s0, g_aux.evB, 0);
    gemm_h2<<<dim3(D_MODEL/128, SS/128), 256, H2_SMEM, s0>>>(
        SS, D_MODEL, 1024,
        lath + (long long)SS*1024, latl + (long long)SS*1024, 1024,
        wct16, 1024,
        out + (long long)SS*D_MODEL, D_MODEL, beff, 1.0f);

    cudaStreamWaitEvent(s0, g_aux.evH0, 0);
}

// round 14
// speedup vs baseline: 14.6815x; 1.2143x over previous
#include <cuda_runtime.h>
#include <cuda_bf16.h>
#include <cuda_fp16.h>
#include <math.h>
#include <stdint.h>

#define D_MODEL 5120
#define N_HEADS 8
#define D_KV    128
#define D_ROPE  16
#define D_HEAD  640
#define SPLIT   624
#define BB      2
#define SS      2048
#define ROWS    (BB*SS)          // 4096
#define NCAT1   384              // dkv(128) + dq(128) + kr(128)
#define KAUG    192              // layout width; only 144 cols real
#define NQE     1152             // 1024 (Wqk) + 128 (Wqr)

typedef __nv_bfloat16 bf16;
typedef __half fp16;

// ---------------- scratch (device globals) ----------------------------------
__device__ __align__(16) float g_cat1 [ROWS*NCAT1];
__device__ __align__(16) bf16  g_cat1h[ROWS*NCAT1];
__device__ __align__(16) bf16  g_cat1l[ROWS*NCAT1];
__device__ __align__(16) fp16  g_hh16[(size_t)ROWS*D_MODEL];
__device__ __align__(16) fp16  g_hl16[(size_t)ROWS*D_MODEL];
__device__ __align__(16) fp16  g_w116[NCAT1*D_MODEL];
__device__ __align__(16) bf16  g_uqph[8*128*640];
__device__ __align__(16) bf16  g_uqpl[8*128*640];
__device__ __align__(16) bf16  g_ukph[8*128*640];
__device__ __align__(16) bf16  g_ukpl[8*128*640];
__device__ __align__(16) bf16  g_wqkrh[NQE*128];
__device__ __align__(16) bf16  g_wqkrl[NQE*128];
__device__ __align__(16) float g_bqkr[NQE];
__device__ __align__(16) float g_qe  [(size_t)ROWS*NQE];
__device__ __align__(16) fp16  g_qph [(size_t)16*SS*KAUG];
__device__ __align__(16) fp16  g_kph [(size_t)16*SS*KAUG];
__device__ __align__(16) fp16  g_vt16[(size_t)BB*128*SS];
__device__ __align__(16) fp16  g_lath[(size_t)ROWS*1024];
__device__ __align__(16) bf16  g_uvsh[128*D_MODEL];
__device__ __align__(16) bf16  g_uvsl[128*D_MODEL];
__device__ __align__(16) bf16  g_woh [(size_t)D_MODEL*D_MODEL];
__device__ __align__(16) bf16  g_wol [(size_t)D_MODEL*D_MODEL];
__device__ __align__(16) float g_wcomb[(size_t)D_MODEL*1024];
__device__ __align__(16) fp16  g_wct16[(size_t)D_MODEL*1024];
__device__ __align__(16) float g_b1  [NCAT1];
__device__ __align__(16) float g_beff[D_MODEL];
__device__ __align__(16) float g_beffp[16*D_MODEL];

// ---------------- streams/events ---------------------------------------------
struct AuxStreams {
    cudaStream_t s1, s2, s3;
    cudaEvent_t  evFork, evW1, evA, evB, evF0, evF1, evH0;
    AuxStreams() {
        cudaStreamCreateWithFlags(&s1, cudaStreamNonBlocking);
        cudaStreamCreateWithFlags(&s2, cudaStreamNonBlocking);
        cudaStreamCreateWithFlags(&s3, cudaStreamNonBlocking);
        cudaEventCreateWithFlags(&evFork, cudaEventDisableTiming);
        cudaEventCreateWithFlags(&evW1,   cudaEventDisableTiming);
        cudaEventCreateWithFlags(&evA,    cudaEventDisableTiming);
        cudaEventCreateWithFlags(&evB,    cudaEventDisableTiming);
        cudaEventCreateWithFlags(&evF0,   cudaEventDisableTiming);
        cudaEventCreateWithFlags(&evF1,   cudaEventDisableTiming);
        cudaEventCreateWithFlags(&evH0,   cudaEventDisableTiming);
    }
};
static AuxStreams g_aux;

// ---------------- PTX helpers ------------------------------------------------
__device__ __forceinline__ uint32_t smem_u32(const void* p) {
    uint32_t a;
    asm("{ .reg .u64 t; cvta.to.shared.u64 t, %1; cvt.u32.u64 %0, t; }"
        : "=r"(a) : "l"(p));
    return a;
}

__device__ __forceinline__ void cp16(uint32_t dst, const void* src) {
    asm volatile("cp.async.cg.shared.global [%0], [%1], 16;\n"
                 :: "r"(dst), "l"(__cvta_generic_to_global(src)));
}
#define CP_COMMIT() asm volatile("cp.async.commit_group;\n" ::: "memory")
#define CP_WAIT1()  asm volatile("cp.async.wait_group 1;\n" ::: "memory")
#define CP_WAIT0()  asm volatile("cp.async.wait_group 0;\n" ::: "memory")

__device__ __forceinline__ void ldm4(uint32_t* r, uint32_t a) {
    asm volatile("ldmatrix.sync.aligned.m8n8.x4.shared.b16 {%0,%1,%2,%3}, [%4];"
                 : "=r"(r[0]), "=r"(r[1]), "=r"(r[2]), "=r"(r[3]) : "r"(a));
}

__device__ __forceinline__ void mma16816(float* c, const uint32_t* a, const uint32_t* b) {
    asm volatile(
        "mma.sync.aligned.m16n8k16.row.col.f32.bf16.bf16.f32 "
        "{%0,%1,%2,%3},{%4,%5,%6,%7},{%8,%9},{%0,%1,%2,%3};\n"
        : "+f"(c[0]), "+f"(c[1]), "+f"(c[2]), "+f"(c[3])
        : "r"(a[0]), "r"(a[1]), "r"(a[2]), "r"(a[3]), "r"(b[0]), "r"(b[1]));
}

__device__ __forceinline__ void mma16816h(float* c, const uint32_t* a, const uint32_t* b) {
    asm volatile(
        "mma.sync.aligned.m16n8k16.row.col.f32.f16.f16.f32 "
        "{%0,%1,%2,%3},{%4,%5,%6,%7},{%8,%9},{%0,%1,%2,%3};\n"
        : "+f"(c[0]), "+f"(c[1]), "+f"(c[2]), "+f"(c[3])
        : "r"(a[0]), "r"(a[1]), "r"(a[2]), "r"(a[3]), "r"(b[0]), "r"(b[1]));
}

__device__ __forceinline__ uint32_t pack2(float a, float b) {
    __nv_bfloat162 t = __floats2bfloat162_rn(a, b);
    return *reinterpret_cast<const uint32_t*>(&t);
}

__device__ __forceinline__ void split_bf16(float v, bf16& h, bf16& l) {
    h = __float2bfloat16(v);
    l = __float2bfloat16(v - __bfloat162float(h));
}

__device__ __forceinline__ void split_pack(float a, float b, uint32_t& ph, uint32_t& pl) {
    bf16 ha = __float2bfloat16(a), hb = __float2bfloat16(b);
    ph = ((uint32_t)*(uint16_t*)&hb << 16) | (uint32_t)*(uint16_t*)&ha;
    pl = pack2(a - __bfloat162float(ha), b - __bfloat162float(hb));
}

__device__ __forceinline__ void split_pack_h(float a, float b, uint32_t& ph, uint32_t& pl) {
    fp16 ha = __float2half(a), hb = __float2half(b);
    ph = ((uint32_t)*(uint16_t*)&hb << 16) | (uint32_t)*(uint16_t*)&ha;
    __half2 t = __floats2half2_rn(a - __half2float(ha), b - __half2float(hb));
    pl = *reinterpret_cast<const uint32_t*>(&t);
}

// ---------------- bf16x3 mma.sync GEMM ---------------------------------------
#define STAGE_BYTES 65536
#define GEMM_SMEM   (3*STAGE_BYTES)

__global__ void __launch_bounds__(256, 1)
gemm_mma(int M, int N, int K,
         const bf16* __restrict__ Ah_, const bf16* __restrict__ Al_, long long lda,
         const bf16* __restrict__ Bh_, const bf16* __restrict__ Bl_, long long ldb,
         float* __restrict__ C, bf16* __restrict__ Ch, bf16* __restrict__ Cl,
         long long ldc,
         const float* __restrict__ bias, float alpha,
         int zdiv,
         long long sA1, long long sA2,
         long long sB1, long long sB2,
         long long sC1, long long sC2)
{
    extern __shared__ __align__(1024) char smem[];
    const uint32_t sb = smem_u32(smem);

    {
        int z  = blockIdx.z;
        int z1 = z / zdiv, z2 = z % zdiv;
        Ah_ += z1*sA1 + z2*sA2;  Al_ += z1*sA1 + z2*sA2;
        Bh_ += z1*sB1 + z2*sB2;  Bl_ += z1*sB1 + z2*sB2;
        long long co = z1*sC1 + z2*sC2;
        if (C)  C  += co;
        if (Ch) { Ch += co; Cl += co; }
    }

    const int tid  = threadIdx.x;
    const int wid  = tid >> 5;
    const int lane = tid & 31;
    const int wm   = (wid >> 2) * 64;
    const int wn   = (wid & 3) * 32;
    const int g    = lane >> 2, tg = lane & 3;
    const int m0   = blockIdx.y * 128;
    const int n0   = blockIdx.x * 128;

    const int lrow = tid >> 1;
    const int half = tid & 1;
    const bf16* pAh = Ah_ + (long long)(m0 + lrow)*lda;
    const bf16* pAl = Al_ + (long long)(m0 + lrow)*lda;
    const bf16* pBh = Bh_ + (long long)(n0 + lrow)*ldb;
    const bf16* pBl = Bl_ + (long long)(n0 + lrow)*ldb;
    const uint32_t lswz = (uint32_t)(lrow & 7);

    const int nk = K / 64;

    const int piece = lane >> 3, rr = lane & 7;
    const int rowA  = wm + (piece & 1)*8 + rr;
    const int rowB  = wn + (piece >> 1)*8 + rr;
    const int cA    = piece >> 1;
    const int cB    = piece & 1;

    float acc[4][4][4];
    #pragma unroll
    for (int i = 0; i < 4; i++)
        #pragma unroll
        for (int j = 0; j < 4; j++)
            #pragma unroll
            for (int k = 0; k < 4; k++) acc[i][j][k] = 0.0f;

    #define ISSUE(t) do {                                                     \
        uint32_t s0_ = sb + ((t) % 3) * STAGE_BYTES;                          \
        const int k0_ = (t) * 64;                                             \
        _Pragma("unroll")                                                     \
        for (int j = 0; j < 4; j++) {                                         \
            int ch_ = half*4 + j;                                             \
            uint32_t d_ = (uint32_t)(lrow*128 + (((uint32_t)ch_ ^ lswz) << 4)); \
            cp16(s0_ +         d_, pAh + k0_ + ch_*8);                        \
            cp16(s0_ + 16384 + d_, pAl + k0_ + ch_*8);                        \
            cp16(s0_ + 32768 + d_, pBh + k0_ + ch_*8);                        \
            cp16(s0_ + 49152 + d_, pBl + k0_ + ch_*8);                        \
        }                                                                     \
        CP_COMMIT();                                                          \
    } while (0)

    ISSUE(0);
    if (nk > 1) ISSUE(1);

    for (int t = 0; t < nk; t++) {
        if (t + 1 < nk) { CP_WAIT1(); } else { CP_WAIT0(); }
        __syncthreads();
        if (t + 2 < nk) ISSUE(t + 2);

        const uint32_t Ab = sb + (t % 3) * STAGE_BYTES;
        const uint32_t Bb = Ab + 32768;

        #pragma unroll
        for (int ks = 0; ks < 4; ks++) {
            uint32_t ah[4][4], al[4][4], bh[4][2], bl[4][2];
            const uint32_t aoff = (uint32_t)(rowA*128 + (((ks*2 + cA) ^ (rowA & 7)) << 4));
            const uint32_t boff = (uint32_t)(rowB*128 + (((ks*2 + cB) ^ (rowB & 7)) << 4));
            #pragma unroll
            for (int mt = 0; mt < 4; mt++) {
                ldm4(ah[mt], Ab +          aoff + mt*2048);
                ldm4(al[mt], Ab + 16384 +  aoff + mt*2048);
            }
            #pragma unroll
            for (int ntp = 0; ntp < 2; ntp++) {
                uint32_t rb[4];
                ldm4(rb, Bb +          boff + ntp*2048);
                bh[ntp*2][0]   = rb[0]; bh[ntp*2][1]   = rb[1];
                bh[ntp*2+1][0] = rb[2]; bh[ntp*2+1][1] = rb[3];
                ldm4(rb, Bb + 16384 +  boff + ntp*2048);
                bl[ntp*2][0]   = rb[0]; bl[ntp*2][1]   = rb[1];
                bl[ntp*2+1][0] = rb[2]; bl[ntp*2+1][1] = rb[3];
            }
            #pragma unroll
            for (int mt = 0; mt < 4; mt++)
                #pragma unroll
                for (int nt = 0; nt < 4; nt++) {
                    mma16816(acc[mt][nt], ah[mt], bh[nt]);
                    mma16816(acc[mt][nt], al[mt], bh[nt]);
                    mma16816(acc[mt][nt], ah[mt], bl[nt]);
                }
        }
    }

    #pragma unroll
    for (int mt = 0; mt < 4; mt++) {
        int row = m0 + wm + mt*16 + g;
        #pragma unroll
        for (int nt = 0; nt < 4; nt++) {
            int col = n0 + wn + nt*8 + tg*2;
            float b0 = 0.0f, b1 = 0.0f;
            if (bias) { b0 = bias[col]; b1 = bias[col+1]; }
            float v00 = acc[mt][nt][0]*alpha + b0;
            float v01 = acc[mt][nt][1]*alpha + b1;
            float v10 = acc[mt][nt][2]*alpha + b0;
            float v11 = acc[mt][nt][3]*alpha + b1;
            if (C) {
                *(float2*)(C + (long long)row*ldc + col)     = make_float2(v00, v01);
                *(float2*)(C + (long long)(row+8)*ldc + col) = make_float2(v10, v11);
            }
            if (Ch) {
                uint32_t ph, pl;
                split_pack(v00, v01, ph, pl);
                *(uint32_t*)(Ch + (long long)row*ldc + col) = ph;
                *(uint32_t*)(Cl + (long long)row*ldc + col) = pl;
                split_pack(v10, v11, ph, pl);
                *(uint32_t*)(Ch + (long long)(row+8)*ldc + col) = ph;
                *(uint32_t*)(Cl + (long long)(row+8)*ldc + col) = pl;
            }
        }
    }
}

// ---------------- fp16 GEMM (NA = # A parts): C = A@B^T + bias ----------------
#define H2_STAGE 49152
#define H2_SMEM  (3*H2_STAGE)

template<int NA>
__global__ void __launch_bounds__(256, 1)
gemm_h2(int M, int N, int K,
        const fp16* __restrict__ Ah_, const fp16* __restrict__ Al_, long long lda,
        const fp16* __restrict__ Bh_, long long ldb,
        float* __restrict__ C, bf16* __restrict__ Ch, bf16* __restrict__ Cl,
        long long ldc,
        const float* __restrict__ bias, float alpha)
{
    extern __shared__ __align__(1024) char smem[];
    const uint32_t sb = smem_u32(smem);

    const int tid  = threadIdx.x;
    const int wid  = tid >> 5;
    const int lane = tid & 31;
    const int wm   = (wid >> 2) * 64;
    const int wn   = (wid & 3) * 32;
    const int g    = lane >> 2, tg = lane & 3;
    const int m0   = blockIdx.y * 128;
    const int n0   = blockIdx.x * 128;

    const int lrow = tid >> 1;
    const int half = tid & 1;
    const fp16* pAh = Ah_ + (long long)(m0 + lrow)*lda;
    const fp16* pAl = (NA == 2) ? (Al_ + (long long)(m0 + lrow)*lda) : nullptr;
    const fp16* pBh = Bh_ + (long long)(n0 + lrow)*ldb;
    const uint32_t lswz = (uint32_t)(lrow & 7);

    const int nk = K / 64;

    const int piece = lane >> 3, rr = lane & 7;
    const int rowA  = wm + (piece & 1)*8 + rr;
    const int rowB  = wn + (piece >> 1)*8 + rr;
    const int cA    = piece >> 1;
    const int cB    = piece & 1;

    float acc[4][4][4];
    #pragma unroll
    for (int i = 0; i < 4; i++)
        #pragma unroll
        for (int j = 0; j < 4; j++)
            #pragma unroll
            for (int k = 0; k < 4; k++) acc[i][j][k] = 0.0f;

    #define H2_ISSUE(t) do {                                                  \
        uint32_t s0_ = sb + ((t) % 3) * H2_STAGE;                             \
        const int k0_ = (t) * 64;                                             \
        _Pragma("unroll")                                                     \
        for (int j = 0; j < 4; j++) {                                         \
            int ch_ = half*4 + j;                                             \
            uint32_t d_ = (uint32_t)(lrow*128 + (((uint32_t)ch_ ^ lswz) << 4)); \
            cp16(s0_ +         d_, pAh + k0_ + ch_*8);                        \
            if (NA == 2) cp16(s0_ + 16384 + d_, pAl + k0_ + ch_*8);           \
            cp16(s0_ + 32768 + d_, pBh + k0_ + ch_*8);                        \
        }                                                                     \
        CP_COMMIT();                                                          \
    } while (0)

    H2_ISSUE(0);
    if (nk > 1) H2_ISSUE(1);

    for (int t = 0; t < nk; t++) {
        if (t + 1 < nk) { CP_WAIT1(); } else { CP_WAIT0(); }
        __syncthreads();
        if (t + 2 < nk) H2_ISSUE(t + 2);

        const uint32_t Ab = sb + (t % 3) * H2_STAGE;
        const uint32_t Bb = Ab + 32768;

        #pragma unroll
        for (int ks = 0; ks < 4; ks++) {
            uint32_t ah[4][4], al[4][4], bh[4][2];
            const uint32_t aoff = (uint32_t)(rowA*128 + (((ks*2 + cA) ^ (rowA & 7)) << 4));
            const uint32_t boff = (uint32_t)(rowB*128 + (((ks*2 + cB) ^ (rowB & 7)) << 4));
            #pragma unroll
            for (int mt = 0; mt < 4; mt++) {
                ldm4(ah[mt], Ab + aoff + mt*2048);
                if (NA == 2) ldm4(al[mt], Ab + 16384 + aoff + mt*2048);
            }
            #pragma unroll
            for (int ntp = 0; ntp < 2; ntp++) {
                uint32_t rb[4];
                ldm4(rb, Bb + boff + ntp*2048);
                bh[ntp*2][0]   = rb[0]; bh[ntp*2][1]   = rb[1];
                bh[ntp*2+1][0] = rb[2]; bh[ntp*2+1][1] = rb[3];
            }
            #pragma unroll
            for (int mt = 0; mt < 4; mt++)
                #pragma unroll
                for (int nt = 0; nt < 4; nt++) {
                    mma16816h(acc[mt][nt], ah[mt], bh[nt]);
                    if (NA == 2) mma16816h(acc[mt][nt], al[mt], bh[nt]);
                }
        }
    }

    #pragma unroll
    for (int mt = 0; mt < 4; mt++) {
        int row = m0 + wm + mt*16 + g;
        #pragma unroll
        for (int nt = 0; nt < 4; nt++) {
            int col = n0 + wn + nt*8 + tg*2;
            float b0 = 0.0f, b1 = 0.0f;
            if (bias) { b0 = bias[col]; b1 = bias[col+1]; }
            float v00 = acc[mt][nt][0]*alpha + b0;
            float v01 = acc[mt][nt][1]*alpha + b1;
            float v10 = acc[mt][nt][2]*alpha + b0;
            float v11 = acc[mt][nt][3]*alpha + b1;
            if (C) {
                *(float2*)(C + (long long)row*ldc + col)     = make_float2(v00, v01);
                *(float2*)(C + (long long)(row+8)*ldc + col) = make_float2(v10, v11);
            }
            if (Ch) {
                uint32_t ph, pl;
                split_pack(v00, v01, ph, pl);
                *(uint32_t*)(Ch + (long long)row*ldc + col) = ph;
                *(uint32_t*)(Cl + (long long)row*ldc + col) = pl;
                split_pack(v10, v11, ph, pl);
                *(uint32_t*)(Ch + (long long)(row+8)*ldc + col) = ph;
                *(uint32_t*)(Cl + (long long)(row+8)*ldc + col) = pl;
            }
        }
    }
}

// ---------------- fused flash attention ---------------------------------------
#define FA_NC    32
#define FA_STG   40960
#define FA_Q     0
#define FA_S0    24576
#define FA_P     106496
#define FA_REDM  122880
#define FA_REDS  123904
#define FA_SMEM  124928
#define FA_NKS   9

__global__ void __launch_bounds__(256, 1)
flash_attn(const fp16* __restrict__ qph,
           const fp16* __restrict__ kph,
           const fp16* __restrict__ vt,
           fp16* __restrict__ lath,
           float scale, int bh_base)
{
    extern __shared__ __align__(1024) char smem[];
    const uint32_t sb = smem_u32(smem);

    const int tid  = threadIdx.x;
    const int wid  = tid >> 5;
    const int lane = tid & 31;
    const int wm2  = wid >> 2;
    const int wn4  = wid & 3;
    const int g    = lane >> 2, tg = lane & 3;
    const int piece = lane >> 3, rr = lane & 7;

    const int bh = blockIdx.y + bh_base;
    const int b  = bh >> 3;
    const int qb = blockIdx.x;

    const fp16* qbh = qph + ((size_t)bh*SS + (size_t)qb*64)*KAUG;
    const fp16* kbh = kph + (size_t)bh*SS*KAUG;
    const fp16* vb  = vt  + (size_t)b*128*SS;

    #pragma unroll
    for (int i = 0; i < 6; i++) {
        int idx = i*256 + tid;
        int row = idx / 24, cc = idx % 24;
        if (cc < 18) {
            int kt = cc >> 3, c8 = cc & 7;
            uint32_t d = (uint32_t)(kt*8192 + row*128 + (((uint32_t)c8 ^ (row & 7)) << 4));
            cp16(sb + FA_Q + d, qbh + row*KAUG + cc*8);
        }
    }
    CP_COMMIT();

    #define FA_ISSUE(t) do {                                                   \
        uint32_t st_ = sb + FA_S0 + ((t) & 1) * FA_STG;                        \
        const int t0_ = (t) * 64;                                              \
        _Pragma("unroll")                                                      \
        for (int i = 0; i < 6; i++) {                                          \
            int idx = i*256 + tid;                                             \
            int row = idx / 24, cc = idx % 24;                                 \
            if (cc < 18) {                                                     \
                int kt = cc >> 3, c8 = cc & 7;                                 \
                uint32_t d = (uint32_t)(kt*8192 + row*128 + (((uint32_t)c8 ^ (row & 7)) << 4)); \
                cp16(st_ + d, kbh + (size_t)(t0_+row)*KAUG + cc*8);            \
            }                                                                  \
        }                                                                      \
        _Pragma("unroll")                                                      \
        for (int i = 0; i < 4; i++) {                                          \
            int idx = i*256 + tid;                                             \
            int row = idx >> 3, c8 = idx & 7;                                  \
            uint32_t d = (uint32_t)(row*128 + (((uint32_t)c8 ^ (row & 7)) << 4)); \
            cp16(st_ + 24576 + d, vb + (size_t)row*SS + t0_ + c8*8);           \
        }                                                                      \
        CP_COMMIT();                                                           \
    } while (0)

    FA_ISSUE(0);

    float accv[2][4][4];
    #pragma unroll
    for (int i = 0; i < 2; i++)
        #pragma unroll
        for (int j = 0; j < 4; j++)
            #pragma unroll
            for (int k = 0; k < 4; k++) accv[i][j][k] = 0.0f;
    float Mrow[4] = {-1e30f, -1e30f, -1e30f, -1e30f};
    float Lrow[4] = {0.0f, 0.0f, 0.0f, 0.0f};

    float* redm = (float*)(smem + FA_REDM);
    float* reds = (float*)(smem + FA_REDS);

    for (int t = 0; t < FA_NC; t++) {
        CP_WAIT0();
        __syncthreads();
        if (t + 1 < FA_NC) FA_ISSUE(t + 1);

        const uint32_t KB = sb + FA_S0 + (t & 1) * FA_STG;
        const uint32_t VB = KB + 24576;

        float sacc[2][2][4];
        #pragma unroll
        for (int i = 0; i < 2; i++)
            #pragma unroll
            for (int j = 0; j < 2; j++)
                #pragma unroll
                for (int k = 0; k < 4; k++) sacc[i][j][k] = 0.0f;

        #pragma unroll
        for (int ks = 0; ks < FA_NKS; ks++) {
            const int kt = ks >> 2, ks2 = ks & 3;
            uint32_t ah[2][4];
            #pragma unroll
            for (int mt = 0; mt < 2; mt++) {
                int rowA = wm2*32 + mt*16 + (piece & 1)*8 + rr;
                uint32_t off = (uint32_t)(kt*8192 + rowA*128 +
                    (((ks2*2 + (piece >> 1)) ^ (rowA & 7)) << 4));
                ldm4(ah[mt], sb + FA_Q + off);
            }
            int rowB = wn4*16 + (piece >> 1)*8 + rr;
            uint32_t offB = (uint32_t)(kt*8192 + rowB*128 +
                (((ks2*2 + (piece & 1)) ^ (rowB & 7)) << 4));
            uint32_t rbh[4];
            ldm4(rbh, KB + offB);
            #pragma unroll
            for (int mt = 0; mt < 2; mt++)
                #pragma unroll
                for (int nt = 0; nt < 2; nt++)
                    mma16816h(sacc[mt][nt], ah[mt], rbh + nt*2);
        }

        float mloc[4] = {-1e30f, -1e30f, -1e30f, -1e30f};
        #pragma unroll
        for (int mt = 0; mt < 2; mt++)
            #pragma unroll
            for (int nt = 0; nt < 2; nt++)
                #pragma unroll
                for (int c = 0; c < 4; c++) {
                    sacc[mt][nt][c] *= scale;
                    int slot = mt*2 + (c >> 1);
                    mloc[slot] = fmaxf(mloc[slot], sacc[mt][nt][c]);
                }
        #pragma unroll
        for (int s = 0; s < 4; s++) {
            mloc[s] = fmaxf(mloc[s], __shfl_xor_sync(0xffffffffu, mloc[s], 1));
            mloc[s] = fmaxf(mloc[s], __shfl_xor_sync(0xffffffffu, mloc[s], 2));
        }
        if (tg == 0) {
            #pragma unroll
            for (int mt = 0; mt < 2; mt++)
                #pragma unroll
                for (int h2 = 0; h2 < 2; h2++) {
                    int r = wm2*32 + mt*16 + h2*8 + g;
                    redm[wn4*64 + r] = mloc[mt*2 + h2];
                }
        }
        __syncthreads();

        float fsc[4];
        #pragma unroll
        for (int mt = 0; mt < 2; mt++)
            #pragma unroll
            for (int h2 = 0; h2 < 2; h2++) {
                int r = wm2*32 + mt*16 + h2*8 + g;
                float cm = fmaxf(fmaxf(redm[r], redm[64 + r]),
                                 fmaxf(redm[128 + r], redm[192 + r]));
                int slot = mt*2 + h2;
                float mn = fmaxf(Mrow[slot], cm);
                fsc[slot] = __expf(Mrow[slot] - mn);
                Mrow[slot] = mn;
            }

        float sl[4] = {0.0f, 0.0f, 0.0f, 0.0f};
        #pragma unroll
        for (int mt = 0; mt < 2; mt++)
            #pragma unroll
            for (int nt = 0; nt < 2; nt++)
                #pragma unroll
                for (int c = 0; c < 4; c++) {
                    int slot = mt*2 + (c >> 1);
                    float p = __expf(sacc[mt][nt][c] - Mrow[slot]);
                    sacc[mt][nt][c] = p;
                    sl[slot] += p;
                }
        #pragma unroll
        for (int mt = 0; mt < 2; mt++)
            #pragma unroll
            for (int nt = 0; nt < 4; nt++)
                #pragma unroll
                for (int c = 0; c < 4; c++)
                    accv[mt][nt][c] *= fsc[mt*2 + (c >> 1)];
        #pragma unroll
        for (int s = 0; s < 4; s++) {
            sl[s] += __shfl_xor_sync(0xffffffffu, sl[s], 1);
            sl[s] += __shfl_xor_sync(0xffffffffu, sl[s], 2);
        }
        if (tg == 0) {
            #pragma unroll
            for (int mt = 0; mt < 2; mt++)
                #pragma unroll
                for (int h2 = 0; h2 < 2; h2++) {
                    int r = wm2*32 + mt*16 + h2*8 + g;
                    reds[wn4*64 + r] = sl[mt*2 + h2];
                }
        }
        #pragma unroll
        for (int mt = 0; mt < 2; mt++)
            #pragma unroll
            for (int nt = 0; nt < 2; nt++)
                #pragma unroll
                for (int h2 = 0; h2 < 2; h2++) {
                    int r = wm2*32 + mt*16 + h2*8 + g;
                    int cidx = wn4*2 + nt;
                    uint32_t addr = (uint32_t)(r*128 + ((cidx ^ (r & 7)) << 4) + tg*4);
                    uint32_t ph, pl;
                    split_pack_h(sacc[mt][nt][2*h2], sacc[mt][nt][2*h2+1], ph, pl);
                    *(uint32_t*)(smem + FA_P +        addr) = ph;
                    *(uint32_t*)(smem + FA_P + 8192 + addr) = pl;
                }
        __syncthreads();

        #pragma unroll
        for (int mt = 0; mt < 2; mt++)
            #pragma unroll
            for (int h2 = 0; h2 < 2; h2++) {
                int r = wm2*32 + mt*16 + h2*8 + g;
                float ssum = reds[r] + reds[64 + r] + reds[128 + r] + reds[192 + r];
                int slot = mt*2 + h2;
                Lrow[slot] = Lrow[slot] * fsc[slot] + ssum;
            }

        #pragma unroll
        for (int ksv = 0; ksv < 4; ksv++) {
            uint32_t pah[2][4], pal[2][4];
            #pragma unroll
            for (int mt = 0; mt < 2; mt++) {
                int rowA = wm2*32 + mt*16 + (piece & 1)*8 + rr;
                uint32_t off = (uint32_t)(rowA*128 +
                    (((ksv*2 + (piece >> 1)) ^ (rowA & 7)) << 4));
                ldm4(pah[mt], sb + FA_P +        off);
                ldm4(pal[mt], sb + FA_P + 8192 + off);
            }
            uint32_t vh[2][4];
            #pragma unroll
            for (int ntp = 0; ntp < 2; ntp++) {
                int rowB = wn4*32 + ntp*16 + (piece >> 1)*8 + rr;
                uint32_t offB = (uint32_t)(rowB*128 +
                    (((ksv*2 + (piece & 1)) ^ (rowB & 7)) << 4));
                ldm4(vh[ntp], VB + offB);
            }
            #pragma unroll
            for (int mt = 0; mt < 2; mt++)
                #pragma unroll
                for (int nt = 0; nt < 4; nt++) {
                    const uint32_t* bhp = vh[nt >> 1] + (nt & 1)*2;
                    mma16816h(accv[mt][nt], pah[mt], bhp);
                    mma16816h(accv[mt][nt], pal[mt], bhp);
                }
        }
    }

    float inv[4];
    #pragma unroll
    for (int s = 0; s < 4; s++) inv[s] = 1.0f / Lrow[s];

    const int h = bh & 7;
    #pragma unroll
    for (int mt = 0; mt < 2; mt++) {
        #pragma unroll
        for (int nt = 0; nt < 4; nt++) {
            int col = h*128 + wn4*32 + nt*8 + tg*2;
            #pragma unroll
            for (int h2 = 0; h2 < 2; h2++) {
                long long row = (long long)b*SS + qb*64 + wm2*32 + mt*16 + h2*8 + g;
                float v0 = accv[mt][nt][2*h2]   * inv[mt*2 + h2];
                float v1 = accv[mt][nt][2*h2+1] * inv[mt*2 + h2];
                __half2 hv = __floats2half2_rn(v0, v1);
                *(uint32_t*)(lath + row*1024 + col) = *reinterpret_cast<uint32_t*>(&hv);
            }
        }
    }
}

// ---------------- elementwise fp32 -> bf16 hi/lo ------------------------------
__global__ void convert_split_k(const float* __restrict__ in,
                                bf16* __restrict__ oh, bf16* __restrict__ ol,
                                long long n)
{
    long long i = (long long)blockIdx.x * 256 + threadIdx.x;
    if (i < n) {
        bf16 h, l; split_bf16(in[i], h, l);
        oh[i] = h; ol[i] = l;
    }
}

// ---------------- elementwise fp32 -> fp16 hi/lo ------------------------------
__global__ void convert_split_h(const float* __restrict__ in,
                                fp16* __restrict__ oh, fp16* __restrict__ ol,
                                long long n)
{
    long long i = (long long)blockIdx.x * 256 + threadIdx.x;
    if (i < n) {
        float v = in[i];
        fp16 hh = __float2half(v);
        oh[i] = hh;
        ol[i] = __float2half(v - __half2float(hh));
    }
}

// ---------------- elementwise fp32 -> fp16 ------------------------------------
__global__ void convert_half_k(const float* __restrict__ in,
                               fp16* __restrict__ o, long long n)
{
    long long i = (long long)blockIdx.x * 256 + threadIdx.x;
    if (i < n) o[i] = __float2half(in[i]);
}

// ---------------- fp32 transpose -> bf16 hi/lo --------------------------------
__global__ void transpose_split_k(const float* __restrict__ in,
                                  bf16* __restrict__ oh, bf16* __restrict__ ol,
                                  int M, int N, int ldi, int ldo,
                                  int zdiv,
                                  long long si1, long long si2,
                                  long long so1, long long so2)
{
    __shared__ float tile[32][33];
    int z = blockIdx.z, z1 = z / zdiv, z2 = z % zdiv;
    in += z1*si1 + z2*si2;
    oh += z1*so1 + z2*so2;
    ol += z1*so1 + z2*so2;

    int x = blockIdx.x*32 + threadIdx.x;
    int y = blockIdx.y*32 + threadIdx.y;
    #pragma unroll
    for (int i = 0; i < 32; i += 8)
        if (x < N && (y+i) < M)
            tile[threadIdx.y+i][threadIdx.x] = in[(long long)(y+i)*ldi + x];
    __syncthreads();
    x = blockIdx.y*32 + threadIdx.x;
    y = blockIdx.x*32 + threadIdx.y;
    #pragma unroll
    for (int i = 0; i < 32; i += 8)
        if (x < M && (y+i) < N) {
            bf16 h, l; split_bf16(tile[threadIdx.x][threadIdx.y+i], h, l);
            oh[(long long)(y+i)*ldo + x] = h;
            ol[(long long)(y+i)*ldo + x] = l;
        }
}

// ---------------- fp32 transpose -> single fp16 -------------------------------
__global__ void transpose_half_k(const float* __restrict__ in,
                                 fp16* __restrict__ o,
                                 int M, int N, int ldi, int ldo)
{
    __shared__ float tile[32][33];
    int x = blockIdx.x*32 + threadIdx.x;
    int y = blockIdx.y*32 + threadIdx.y;
    #pragma unroll
    for (int i = 0; i < 32; i += 8)
        if (x < N && (y+i) < M)
            tile[threadIdx.y+i][threadIdx.x] = in[(long long)(y+i)*ldi + x];
    __syncthreads();
    x = blockIdx.y*32 + threadIdx.x;
    y = blockIdx.x*32 + threadIdx.y;
    #pragma unroll
    for (int i = 0; i < 32; i += 8)
        if (x < M && (y+i) < N)
            o[(long long)(y+i)*ldo + x] = __float2half(tile[threadIdx.x][threadIdx.y+i]);
}

// ---------------- pad+split W_uq / W_uk into [8][128][640] --------------------
__global__ void pad_split_uqk(const float* __restrict__ Wuq,
                              const float* __restrict__ Wuk,
                              bf16* __restrict__ uqh, bf16* __restrict__ uql,
                              bf16* __restrict__ ukh, bf16* __restrict__ ukl)
{
    int idx = blockIdx.x * 256 + threadIdx.x;
    if (idx >= 8*128*640) return;
    int e = idx % 640;
    int c = (idx / 640) & 127;
    int h = idx / (640*128);
    float vq = 0.0f, vk = 0.0f;
    if (e < SPLIT) {
        vq = Wuq[c*4992 + h*SPLIT + e];
        vk = Wuk[c*4992 + h*SPLIT + e];
    }
    bf16 hh, ll;
    split_bf16(vq, hh, ll); uqh[idx] = hh; uql[idx] = ll;
    split_bf16(vk, hh, ll); ukh[idx] = hh; ukl[idx] = ll;
}

// ---------------- bqk -----------------------------------------------------------
__global__ void bqk_kernel(const float* __restrict__ b_uq,
                           const float* __restrict__ W_uk,
                           float* __restrict__ bqk)
{
    int c = threadIdx.x;
    int h = blockIdx.x;
    float acc = 0.0f;
    const float* wrow = W_uk + c*4992 + h*SPLIT;
    const float* brow = b_uq + h*SPLIT;
    for (int e = 0; e < SPLIT; e++)
        acc += brow[e] * wrow[e];
    bqk[h*128 + c] = acc;
}

// ---------------- beff ----------------------------------------------------------
__global__ void beff_partial(const float* __restrict__ b_uv,
                             const float* __restrict__ W_o,
                             float* __restrict__ part)
{
    int o   = blockIdx.x * 256 + threadIdx.x;
    int seg = blockIdx.y;
    float acc = 0.0f;
    int d0 = seg * (D_MODEL/16);
    #pragma unroll 4
    for (int d = d0; d < d0 + D_MODEL/16; d++)
        acc += b_uv[d] * W_o[(size_t)d*D_MODEL + o];
    part[(size_t)seg*D_MODEL + o] = acc;
}

__global__ void beff_reduce(const float* __restrict__ part,
                            const float* __restrict__ b_o,
                            float* __restrict__ be)
{
    int o = blockIdx.x * 256 + threadIdx.x;
    if (o >= D_MODEL) return;
    float acc = b_o[o];
    #pragma unroll
    for (int s = 0; s < 16; s++)
        acc += part[(size_t)s*D_MODEL + o];
    be[o] = acc;
}

// ---------------- assemble Q'/K' (rope) -> single fp16; emit k_rot --------------
__global__ void assemble_qk(const float* __restrict__ qe,
                            const float* __restrict__ cat1,
                            fp16* __restrict__ qph,
                            fp16* __restrict__ kph,
                            float* __restrict__ out_krot, int bh_base)
{
    long long idx = (long long)blockIdx.x * 256 + threadIdx.x;
    if (idx >= (long long)8*SS*KAUG) return;
    int j  = (int)(idx % KAUG);
    int s  = (int)((idx / KAUG) & (SS - 1));
    int bh = (int)(idx / ((long long)KAUG*SS)) + bh_base;
    long long gidx = (long long)bh*SS*KAUG + (long long)s*KAUG + j;
    int b  = bh >> 3, h = bh & 7;
    long long row = (long long)b*SS + s;

    float qv = 0.0f, kv = 0.0f;
    if (j < 128) {
        qv = qe[row*NQE + h*128 + j];
        kv = cat1[row*NCAT1 + j];
    } else if (j < 144) {
        int dd = j - 128;
        long long qb = row*NQE + 1024 + h*D_ROPE;
        long long kb = row*NCAT1 + 256 + h*D_ROPE;
        if (dd < 8) {
            const float invf[4] = {1.0f, 0.1f, 0.01f, 0.001f};
            float f = ((float)s / 40.0f) * invf[dd & 3];
            float c_ = cosf(f), sn = sinf(f);
            if (dd < 4) {
                qv = qe[qb+dd]*c_ - qe[qb+dd+4]*sn;
                kv = cat1[kb+dd]*c_ - cat1[kb+dd+4]*sn;
            } else {
                qv = qe[qb+dd]*c_ + qe[qb+dd-4]*sn;
                kv = cat1[kb+dd]*c_ + cat1[kb+dd-4]*sn;
            }
        } else {
            qv = qe[qb+dd];
            kv = cat1[kb+dd];
        }
        out_krot[row*128 + h*D_ROPE + dd] = kv;
    } else {
        return;
    }
    qph[gidx] = __float2half(qv);
    kph[gidx] = __float2half(kv);
}

// ---------------- c_kv output copy (per-batch) ---------------------------------
__global__ void copy_ckv(const float* __restrict__ cat1, float* __restrict__ out,
                         int row0)
{
    int idx = blockIdx.x * 256 + threadIdx.x;
    if (idx < SS * D_KV) {
        int row = row0 + (idx >> 7);
        out[(long long)row*D_KV + (idx & 127)] = cat1[(long long)row*NCAT1 + (idx & 127)];
    }
}

// ---------------- host side ------------------------------------------------------
static inline void* symv(const void* s)
{
    void* p = nullptr;
    cudaGetSymbolAddress(&p, s);
    return p;
}

static void gemm_on(cudaStream_t st, int M, int N, int K,
                    const bf16* Ah, const bf16* Al, long long lda,
                    const bf16* Bh, const bf16* Bl, long long ldb,
                    float* C, bf16* Ch, bf16* Cl, long long ldc,
                    const float* bias, float alpha,
                    int nz = 1, int zdiv = 1,
                    long long sA1 = 0, long long sA2 = 0,
                    long long sB1 = 0, long long sB2 = 0,
                    long long sC1 = 0, long long sC2 = 0)
{
    dim3 grid(N / 128, M / 128, nz);
    gemm_mma<<<grid, 256, GEMM_SMEM, st>>>(M, N, K, Ah, Al, lda, Bh, Bl, ldb,
                                           C, Ch, Cl, ldc, bias, alpha, zdiv,
                                           sA1, sA2, sB1, sB2, sC1, sC2);
}

static void tsplit_on(cudaStream_t st, const float* in, bf16* oh, bf16* ol,
                      int M, int N, int ldi, int ldo)
{
    dim3 grid((N + 31)/32, (M + 31)/32, 1);
    transpose_split_k<<<grid, dim3(32, 8), 0, st>>>(in, oh, ol, M, N, ldi, ldo,
                                                    1, 0, 0, 0, 0);
}

static void thalf_on(cudaStream_t st, const float* in, fp16* o,
                     int M, int N, int ldi, int ldo)
{
    dim3 grid((N + 31)/32, (M + 31)/32, 1);
    transpose_half_k<<<grid, dim3(32, 8), 0, st>>>(in, o, M, N, ldi, ldo);
}

extern "C" void kernel_launch(void* const* d_in, const int* in_sizes, int n_in,
                              void* d_out, int out_size)
{
    const float* h     = (const float*)d_in[0];
    const float* W_dkv = (const float*)d_in[1];
    const float* b_dkv = (const float*)d_in[2];
    const float* W_dq  = (const float*)d_in[3];
    const float* b_dq  = (const float*)d_in[4];
    const float* W_uk  = (const float*)d_in[5];
    const float* b_uk  = (const float*)d_in[6];
    const float* W_uv  = (const float*)d_in[7];
    const float* b_uv  = (const float*)d_in[8];
    const float* W_uq  = (const float*)d_in[9];
    const float* b_uq  = (const float*)d_in[10];
    const float* W_qr  = (const float*)d_in[11];
    const float* b_qr  = (const float*)d_in[12];
    const float* W_kr  = (const float*)d_in[13];
    const float* b_kr  = (const float*)d_in[14];
    const float* W_o   = (const float*)d_in[15];
    const float* b_o   = (const float*)d_in[16];
    (void)b_uk;

    float* out      = (float*)d_out;
    float* out_ckv  = out + (long long)ROWS * D_MODEL;
    float* out_krot = out_ckv + (long long)ROWS * D_KV;

    float* cat1  = (float*)symv(g_cat1);
    bf16*  cat1h = (bf16*)symv(g_cat1h);
    bf16*  cat1l = (bf16*)symv(g_cat1l);
    fp16*  hh16  = (fp16*)symv(g_hh16);
    fp16*  hl16  = (fp16*)symv(g_hl16);
    fp16*  w116  = (fp16*)symv(g_w116);
    bf16*  uqph  = (bf16*)symv(g_uqph);
    bf16*  uqpl  = (bf16*)symv(g_uqpl);
    bf16*  ukph  = (bf16*)symv(g_ukph);
    bf16*  ukpl  = (bf16*)symv(g_ukpl);
    bf16*  wqkrh = (bf16*)symv(g_wqkrh);
    bf16*  wqkrl = (bf16*)symv(g_wqkrl);
    float* bqkr  = (float*)symv(g_bqkr);
    float* qe    = (float*)symv(g_qe);
    fp16*  qph   = (fp16*)symv(g_qph);
    fp16*  kph   = (fp16*)symv(g_kph);
    fp16*  vt16  = (fp16*)symv(g_vt16);
    fp16*  lath  = (fp16*)symv(g_lath);
    bf16*  uvsh  = (bf16*)symv(g_uvsh);
    bf16*  uvsl  = (bf16*)symv(g_uvsl);
    bf16*  woh   = (bf16*)symv(g_woh);
    bf16*  wol   = (bf16*)symv(g_wol);
    float* wcomb = (float*)symv(g_wcomb);
    fp16*  wct16 = (fp16*)symv(g_wct16);
    float* b1    = (float*)symv(g_b1);
    float* beff  = (float*)symv(g_beff);
    float* beffp = (float*)symv(g_beffp);

    cudaFuncSetAttribute(gemm_mma, cudaFuncAttributeMaxDynamicSharedMemorySize, GEMM_SMEM);
    cudaFuncSetAttribute(gemm_h2<1>, cudaFuncAttributeMaxDynamicSharedMemorySize, H2_SMEM);
    cudaFuncSetAttribute(gemm_h2<2>, cudaFuncAttributeMaxDynamicSharedMemorySize, H2_SMEM);
    cudaFuncSetAttribute(flash_attn, cudaFuncAttributeMaxDynamicSharedMemorySize, FA_SMEM);

    const float scale = 1.0f / sqrtf((float)D_HEAD);
    cudaStream_t s0 = 0, s1 = g_aux.s1, s2 = g_aux.s2, s3 = g_aux.s3;

    // ---- fork ----
    cudaEventRecord(g_aux.evFork, s0);
    cudaStreamWaitEvent(s1, g_aux.evFork, 0);
    cudaStreamWaitEvent(s2, g_aux.evFork, 0);
    cudaStreamWaitEvent(s3, g_aux.evFork, 0);

    // ======== s1: W1 prep (fp16), then Wqk-absorption chain ========
    cudaMemcpyAsync(b1,      b_dkv, 128*sizeof(float), cudaMemcpyDeviceToDevice, s1);
    cudaMemcpyAsync(b1+128,  b_dq,  128*sizeof(float), cudaMemcpyDeviceToDevice, s1);
    cudaMemcpyAsync(b1+256,  b_kr,  128*sizeof(float), cudaMemcpyDeviceToDevice, s1);
    thalf_on(s1, W_dkv, w116,               D_MODEL, D_KV, D_KV, D_MODEL);
    thalf_on(s1, W_dq,  w116 + 128*D_MODEL, D_MODEL, D_KV, D_KV, D_MODEL);
    thalf_on(s1, W_kr,  w116 + 256*D_MODEL, D_MODEL, D_KV, D_KV, D_MODEL);
    cudaEventRecord(g_aux.evW1, s1);

    cudaMemcpyAsync(bqkr+1024, b_qr, 128*sizeof(float), cudaMemcpyDeviceToDevice, s1);
    tsplit_on(s1, W_qr, wqkrh + 1024*128, wqkrl + 1024*128, D_KV, 128, 128, D_KV);
    pad_split_uqk<<<(8*128*640 + 255)/256, 256, 0, s1>>>(W_uq, W_uk, uqph, uqpl, ukph, ukpl);
    bqk_kernel<<<8, 128, 0, s1>>>(b_uq, W_uk, bqkr);
    gemm_on(s1, 128, 128, 640, ukph, ukpl, 640, uqph, uqpl, 640,
            nullptr, wqkrh, wqkrl, 128, nullptr, 1.0f,
            8, 8, 0, (long long)128*640, 0, (long long)128*640, 0, (long long)128*128);
    cudaEventRecord(g_aux.evA, s1);

    // ======== s2: W_o/W_uv-absorption chain (fp32 -> fp16 Wcomb) ========
    convert_split_k<<<(128*D_MODEL + 255)/256, 256, 0, s2>>>(W_uv, uvsh, uvsl, 128*D_MODEL);
    tsplit_on(s2, W_o, woh, wol, D_MODEL, D_MODEL, D_MODEL, D_MODEL);
    gemm_on(s2, D_MODEL, 128, 640, woh, wol, D_MODEL, uvsh, uvsl, D_MODEL,
            wcomb, nullptr, nullptr, 1024, nullptr, 1.0f,
            8, 8, 0, 640, 0, 640, 0, 128);
    convert_half_k<<<(unsigned)(((long long)D_MODEL*1024 + 255)/256), 256, 0, s2>>>(
        wcomb, wct16, (long long)D_MODEL*1024);
    beff_partial<<<dim3(D_MODEL/256, 16), 256, 0, s2>>>(b_uv, W_o, beffp);
    beff_reduce<<<(D_MODEL + 255)/256, 256, 0, s2>>>(beffp, b_o, beff);
    cudaEventRecord(g_aux.evB, s2);

    // ======== per-batch activation pipelines (s0 = b0, s3 = b1) ========
    const long long HN = (long long)SS * D_MODEL;
    #define BATCH_CHAIN(st, B, BH, EVF)                                            \
    do {                                                                           \
        const long long r0 = (long long)(B) * SS;                                  \
        convert_split_h<<<(unsigned)((HN + 255)/256), 256, 0, (st)>>>(             \
            h + r0*D_MODEL, hh16 + r0*D_MODEL, hl16 + r0*D_MODEL, HN);             \
        cudaStreamWaitEvent((st), g_aux.evW1, 0);                                  \
        gemm_h2<2><<<dim3(NCAT1/128, SS/128), 256, H2_SMEM, (st)>>>(               \
            SS, NCAT1, D_MODEL,                                                    \
            hh16 + r0*D_MODEL, hl16 + r0*D_MODEL, D_MODEL, w116, D_MODEL,          \
            cat1 + r0*NCAT1, cat1h + r0*NCAT1, cat1l + r0*NCAT1, NCAT1,            \
            b1, 1.0f);                                                             \
        copy_ckv<<<(SS*D_KV + 255)/256, 256, 0, (st)>>>(cat1, out_ckv, (int)r0);   \
        cudaStreamWaitEvent((st), g_aux.evA, 0);                                   \
        gemm_on((st), SS, NQE, 128,                                                \
                cat1h + r0*NCAT1 + 128, cat1l + r0*NCAT1 + 128, NCAT1,             \
                wqkrh, wqkrl, 128,                                                 \
                qe + r0*NQE, nullptr, nullptr, NQE, bqkr, 1.0f);                   \
        {                                                                          \
            long long total = (long long)8*SS*KAUG;                                \
            assemble_qk<<<(unsigned)((total + 255)/256), 256, 0, (st)>>>(          \
                qe, cat1, qph, kph, out_krot, (BH));                               \
        }                                                                          \
        {                                                                          \
            dim3 tg_((128 + 31)/32, (SS + 31)/32, 1);                              \
            transpose_half_k<<<tg_, dim3(32, 8), 0, (st)>>>(                       \
                cat1 + r0*NCAT1, vt16 + (long long)(B)*128*SS, SS, 128, NCAT1, SS);\
        }                                                                          \
        flash_attn<<<dim3(SS/64, 8), 256, FA_SMEM, (st)>>>(                        \
            qph, kph, vt16, lath, scale, (BH));                                    \
        cudaEventRecord((EVF), (st));                                              \
    } while (0)

    BATCH_CHAIN(s0, 0, 0, g_aux.evF0);
    BATCH_CHAIN(s3, 1, 8, g_aux.evF1);

    // ======== final GEMM (single fp16 x single fp16), per-batch ========
    cudaStreamWaitEvent(s1, g_aux.evF0, 0);
    cudaStreamWaitEvent(s1, g_aux.evB, 0);
    gemm_h2<1><<<dim3(D_MODEL/128, SS/128), 256, H2_SMEM, s1>>>(
        SS, D_MODEL, 1024, lath, nullptr, 1024, wct16, 1024,
        out, nullptr, nullptr, D_MODEL, beff, 1.0f);
    cudaEventRecord(g_aux.evH0, s1);

    cudaStreamWaitEvent(s0, g_aux.evF1, 0);
    cudaStreamWaitEvent(s0, g_aux.evB, 0);
    gemm_h2<1><<<dim3(D_MODEL/128, SS/128), 256, H2_SMEM, s0>>>(
        SS, D_MODEL, 1024,
        lath + (long long)SS*1024, nullptr, 1024,
        wct16, 1024,
        out + (long long)SS*D_MODEL, nullptr, nullptr, D_MODEL, beff, 1.0f);

    cudaStreamWaitEvent(s0, g_aux.evH0, 0);
}